// round 5
// baseline (speedup 1.0000x reference)
#include <cuda_runtime.h>
#include <cuda_fp16.h>
#include <cstdint>
#include <cstddef>

// ---------------------------------------------------------------------------
// Problem constants
// ---------------------------------------------------------------------------
#define E_DIM   1024
#define H_DIM   16
#define D_DIM   64
#define B_DIM   2
#define T_DIM   32
#define N_DIM   256
#define MTOK    (B_DIM * T_DIM * N_DIM)   // 16384 tokens total
#define MTOK_B  (T_DIM * N_DIM)           // 8192 tokens per batch
#define KSEL    256
#define MAXLEN  512
#define RB_ONE  ((2 * MAXLEN - 1) * H_DIM)
#define OUT_ROWS 448                      // 256 + 128 + 64
#define SPLITK_SEL 8

// ---------------------------------------------------------------------------
// Scratch (device globals — no allocations allowed)
// ---------------------------------------------------------------------------
__device__ float g_Q[MTOK * E_DIM];
__device__ float g_Kb[MTOK * E_DIM];
__device__ float g_Vb[MTOK * E_DIM];
__device__ float g_Hb[MTOK * E_DIM];
__device__ float g_SC[MTOK * KSEL];
__device__ float g_SEL[B_DIM * KSEL * E_DIM];

// fp16 split activations: ping (attention out) and pong (projection in)
__device__ __half g_Ah[MTOK * E_DIM];
__device__ __half g_Al[MTOK * E_DIM];
__device__ __half g_Ah2[MTOK * E_DIM];
__device__ __half g_Al2[MTOK * E_DIM];
// transposed fp16 weights: [a][N=E][K=E]
__device__ __half g_WqT[4 * E_DIM * E_DIM];
__device__ __half g_WkT[4 * E_DIM * E_DIM];
__device__ __half g_WvT[4 * E_DIM * E_DIM];
__device__ __half g_WdT[4 * E_DIM * E_DIM];
__device__ __half g_SWT[KSEL * E_DIM];
// selection operands (fp16 hi/lo, transposed)
__device__ __half g_SCTh[B_DIM * KSEL * MTOK_B];
__device__ __half g_SCTl[B_DIM * KSEL * MTOK_B];
__device__ __half g_HTh[B_DIM * E_DIM * MTOK_B];
__device__ __half g_HTl[B_DIM * E_DIM * MTOK_B];

// ---------------------------------------------------------------------------
// PTX helpers (cp.async / ldmatrix / mma.sync — baseline sm_80+ PTX)
// ---------------------------------------------------------------------------
__device__ __forceinline__ void cp_async16(uint32_t dst, const void* src) {
    asm volatile("cp.async.cg.shared.global [%0], [%1], 16;" :: "r"(dst), "l"(src));
}
__device__ __forceinline__ void cp_commit() {
    asm volatile("cp.async.commit_group;" ::: "memory");
}
template <int N>
__device__ __forceinline__ void cp_wait_group() {
    asm volatile("cp.async.wait_group %0;" :: "n"(N) : "memory");
}
__device__ __forceinline__ void ldmatrix_x4(uint32_t* r, uint32_t addr) {
    asm volatile("ldmatrix.sync.aligned.m8n8.x4.shared.b16 {%0,%1,%2,%3}, [%4];"
                 : "=r"(r[0]), "=r"(r[1]), "=r"(r[2]), "=r"(r[3]) : "r"(addr));
}
__device__ __forceinline__ void mma_f16(float* d, const uint32_t* a,
                                        uint32_t b0, uint32_t b1) {
    asm volatile(
        "mma.sync.aligned.m16n8k16.row.col.f32.f16.f16.f32 "
        "{%0,%1,%2,%3}, {%4,%5,%6,%7}, {%8,%9}, {%0,%1,%2,%3};"
        : "+f"(d[0]), "+f"(d[1]), "+f"(d[2]), "+f"(d[3])
        : "r"(a[0]), "r"(a[1]), "r"(a[2]), "r"(a[3]), "r"(b0), "r"(b1));
}

// ---------------------------------------------------------------------------
// fp16x2 GEMM via mma.sync:
//   C[M, Nfull] = (Ah+Al)[M,K] @ B[Nfull,K]^T + bias
// Optional fused fp16 hi/lo output (Ch/Cl) for downstream GEMM input.
// CTA 128x128, k-chunk 32, 3-stage cp.async pipeline.
// 8 warps (4 in M x 2 in N), warp tile 32x64, m16n8k16.
// ---------------------------------------------------------------------------
#define GSTAGES 3
#define ROWPAD  40
#define TILE_BYTES (128 * ROWPAD * 2)         // 10240 per tile
#define STAGE_BYTES (3 * TILE_BYTES)          // Ah, Al, B
#define GEMM_SMEM (GSTAGES * STAGE_BYTES)     // 92160

__global__ __launch_bounds__(256, 2)
void gemm_f16x2(const __half* __restrict__ Ah, const __half* __restrict__ Al,
                const __half* __restrict__ B,
                const float* __restrict__ bias, float* __restrict__ C,
                __half* __restrict__ Ch, __half* __restrict__ Cl,
                int Nfull, int Kfull)
{
    extern __shared__ char smem[];
    const uint32_t sb = (uint32_t)__cvta_generic_to_shared(smem);
    const int tid = threadIdx.x;
    const int lane = tid & 31;
    const int warp = tid >> 5;
    const int wm = warp >> 1;
    const int wn = warp & 1;
    const int m0 = blockIdx.y * 128;
    const int n0 = blockIdx.x * 128;

    const int NCH = Kfull >> 5;

    const int lr0 = tid >> 1;
    const int ls0 = (tid & 1) << 1;

    float acc[2][8][4];
#pragma unroll
    for (int mi = 0; mi < 2; mi++)
#pragma unroll
        for (int ni = 0; ni < 8; ni++)
#pragma unroll
            for (int q = 0; q < 4; q++) acc[mi][ni][q] = 0.f;

    auto load_chunk = [&](int c, int stage) {
        const int kb = c << 5;
        const uint32_t base = sb + stage * STAGE_BYTES;
#pragma unroll
        for (int j = 0; j < 2; j++) {
            const int s4 = ls0 + j;
            const uint32_t soff = (uint32_t)(lr0 * ROWPAD + s4 * 8) * 2;
            const size_t goff = (size_t)lr0 * Kfull + kb + s4 * 8;
            cp_async16(base + soff,                  Ah + (size_t)m0 * Kfull + goff);
            cp_async16(base + TILE_BYTES + soff,     Al + (size_t)m0 * Kfull + goff);
            cp_async16(base + 2 * TILE_BYTES + soff, B  + (size_t)n0 * Kfull + goff);
        }
    };

#pragma unroll
    for (int s = 0; s < GSTAGES - 1; s++) {
        if (s < NCH) load_chunk(s, s);
        cp_commit();
    }

    const int la_i = lane & 7;
    const int la_g = lane >> 3;
    const int a_rowadd = la_i + ((la_g & 1) << 3);
    const int a_coladd = (la_g >> 1) << 3;
    const int b_rowadd = la_i + ((la_g >> 1) << 3);
    const int b_coladd = (la_g & 1) << 3;

    for (int c = 0; c < NCH; c++) {
        const int stage = c % GSTAGES;
        cp_wait_group<GSTAGES - 2>();
        __syncthreads();

        const int nc = c + GSTAGES - 1;
        if (nc < NCH) load_chunk(nc, nc % GSTAGES);
        cp_commit();

        const uint32_t base = sb + stage * STAGE_BYTES;
        const uint32_t Bbase = base + 2 * TILE_BYTES;

#pragma unroll
        for (int k16 = 0; k16 < 32; k16 += 16) {
            uint32_t bf[4][4];
#pragma unroll
            for (int nb = 0; nb < 4; nb++) {
                const int row = wn * 64 + nb * 16 + b_rowadd;
                const int col = k16 + b_coladd;
                ldmatrix_x4(bf[nb], Bbase + (uint32_t)(row * ROWPAD + col) * 2);
            }
#pragma unroll
            for (int seg = 0; seg < 2; seg++) {
                const uint32_t Abase = base + seg * TILE_BYTES;
                uint32_t af[2][4];
#pragma unroll
                for (int mi = 0; mi < 2; mi++) {
                    const int row = wm * 32 + mi * 16 + a_rowadd;
                    const int col = k16 + a_coladd;
                    ldmatrix_x4(af[mi], Abase + (uint32_t)(row * ROWPAD + col) * 2);
                }
#pragma unroll
                for (int nb = 0; nb < 4; nb++)
#pragma unroll
                    for (int mi = 0; mi < 2; mi++) {
                        mma_f16(acc[mi][nb * 2 + 0], af[mi], bf[nb][0], bf[nb][1]);
                        mma_f16(acc[mi][nb * 2 + 1], af[mi], bf[nb][2], bf[nb][3]);
                    }
            }
        }
    }

    // epilogue (+ optional fused fp16 hi/lo emit)
    const int tq = lane >> 2;
    const int tr = lane & 3;
#pragma unroll
    for (int mi = 0; mi < 2; mi++) {
        const int row = m0 + wm * 32 + mi * 16 + tq;
#pragma unroll
        for (int ni = 0; ni < 8; ni++) {
            const int col = n0 + wn * 64 + ni * 8 + tr * 2;
            const float b0 = bias[col], b1 = bias[col + 1];
            float c00 = acc[mi][ni][0] + b0, c01 = acc[mi][ni][1] + b1;
            float c10 = acc[mi][ni][2] + b0, c11 = acc[mi][ni][3] + b1;
            float2 v0; v0.x = c00; v0.y = c01;
            float2 v1; v1.x = c10; v1.y = c11;
            *(float2*)&C[(size_t)row * Nfull + col] = v0;
            *(float2*)&C[(size_t)(row + 8) * Nfull + col] = v1;
            if (Ch) {
                __half h00 = __float2half_rn(c00);
                __half h01 = __float2half_rn(c01);
                __half h10 = __float2half_rn(c10);
                __half h11 = __float2half_rn(c11);
                *(__half2*)&Ch[(size_t)row * Nfull + col]       = __halves2half2(h00, h01);
                *(__half2*)&Ch[(size_t)(row + 8) * Nfull + col] = __halves2half2(h10, h11);
                __half l00 = __float2half_rn(c00 - __half2float(h00));
                __half l01 = __float2half_rn(c01 - __half2float(h01));
                __half l10 = __float2half_rn(c10 - __half2float(h10));
                __half l11 = __float2half_rn(c11 - __half2float(h11));
                *(__half2*)&Cl[(size_t)row * Nfull + col]       = __halves2half2(l00, l01);
                *(__half2*)&Cl[(size_t)(row + 8) * Nfull + col] = __halves2half2(l10, l11);
            }
        }
    }
}

// ---------------------------------------------------------------------------
// Selection GEMM (3-segment fp16 mma, split-K + atomics):
//   per batch b: SEL[k,e] += sum_m SCT[k,m] * HT[e,m]
//   segments: SCTh*HTh + SCTl*HTh + SCTh*HTl   (exact to fp32-class)
// grid (E/128, KSEL/128, B*SPLITK_SEL); 2-stage pipeline, 4 tiles/stage.
// ---------------------------------------------------------------------------
#define SEL_STAGE_BYTES (4 * TILE_BYTES)
#define SEL_SMEM (2 * SEL_STAGE_BYTES)     // 81920

__global__ __launch_bounds__(256)
void gemm_3seg(const __half* __restrict__ SCTh, const __half* __restrict__ SCTl,
               const __half* __restrict__ HTh, const __half* __restrict__ HTl,
               float* __restrict__ Csel)
{
    extern __shared__ char smem[];
    const uint32_t sb = (uint32_t)__cvta_generic_to_shared(smem);
    const int tid = threadIdx.x;
    const int lane = tid & 31;
    const int warp = tid >> 5;
    const int wm = warp >> 1;
    const int wn = warp & 1;
    const int m0 = blockIdx.y * 128;
    const int n0 = blockIdx.x * 128;
    const int b  = blockIdx.z / SPLITK_SEL;
    const int sl = blockIdx.z % SPLITK_SEL;
    const int kbeg = sl * (MTOK_B / SPLITK_SEL);   // 1024
    const int NCH = (MTOK_B / SPLITK_SEL) >> 5;    // 32

    const __half* Ah = SCTh + (size_t)b * KSEL * MTOK_B;
    const __half* Al = SCTl + (size_t)b * KSEL * MTOK_B;
    const __half* Bh = HTh  + (size_t)b * E_DIM * MTOK_B;
    const __half* Bl = HTl  + (size_t)b * E_DIM * MTOK_B;
    float* C = Csel + (size_t)b * KSEL * E_DIM;

    const int lr0 = tid >> 1;
    const int ls0 = (tid & 1) << 1;

    float acc[2][8][4];
#pragma unroll
    for (int mi = 0; mi < 2; mi++)
#pragma unroll
        for (int ni = 0; ni < 8; ni++)
#pragma unroll
            for (int q = 0; q < 4; q++) acc[mi][ni][q] = 0.f;

    auto load_chunk = [&](int c, int stage) {
        const int kb = kbeg + (c << 5);
        const uint32_t base = sb + stage * SEL_STAGE_BYTES;
#pragma unroll
        for (int j = 0; j < 2; j++) {
            const int s4 = ls0 + j;
            const uint32_t soff = (uint32_t)(lr0 * ROWPAD + s4 * 8) * 2;
            const size_t ga = (size_t)(m0 + lr0) * MTOK_B + kb + s4 * 8;
            const size_t gb = (size_t)(n0 + lr0) * MTOK_B + kb + s4 * 8;
            cp_async16(base + soff,                  Ah + ga);
            cp_async16(base + TILE_BYTES + soff,     Al + ga);
            cp_async16(base + 2 * TILE_BYTES + soff, Bh + gb);
            cp_async16(base + 3 * TILE_BYTES + soff, Bl + gb);
        }
    };

    load_chunk(0, 0);
    cp_commit();

    const int la_i = lane & 7;
    const int la_g = lane >> 3;
    const int a_rowadd = la_i + ((la_g & 1) << 3);
    const int a_coladd = (la_g >> 1) << 3;
    const int b_rowadd = la_i + ((la_g >> 1) << 3);
    const int b_coladd = (la_g & 1) << 3;

    for (int c = 0; c < NCH; c++) {
        const int stage = c & 1;
        if (c + 1 < NCH) {
            load_chunk(c + 1, (c + 1) & 1);
            cp_commit();
            cp_wait_group<1>();
        } else {
            cp_wait_group<0>();
        }
        __syncthreads();

        const uint32_t base = sb + stage * SEL_STAGE_BYTES;

#pragma unroll
        for (int k16 = 0; k16 < 32; k16 += 16) {
            uint32_t bhf[4][4], blf[4][4];
#pragma unroll
            for (int nb = 0; nb < 4; nb++) {
                const int row = wn * 64 + nb * 16 + b_rowadd;
                const int col = k16 + b_coladd;
                ldmatrix_x4(bhf[nb], base + 2 * TILE_BYTES + (uint32_t)(row * ROWPAD + col) * 2);
                ldmatrix_x4(blf[nb], base + 3 * TILE_BYTES + (uint32_t)(row * ROWPAD + col) * 2);
            }
            uint32_t ahf[2][4], alf[2][4];
#pragma unroll
            for (int mi = 0; mi < 2; mi++) {
                const int row = wm * 32 + mi * 16 + a_rowadd;
                const int col = k16 + a_coladd;
                ldmatrix_x4(ahf[mi], base + (uint32_t)(row * ROWPAD + col) * 2);
                ldmatrix_x4(alf[mi], base + TILE_BYTES + (uint32_t)(row * ROWPAD + col) * 2);
            }
#pragma unroll
            for (int nb = 0; nb < 4; nb++)
#pragma unroll
                for (int mi = 0; mi < 2; mi++) {
                    mma_f16(acc[mi][nb * 2 + 0], ahf[mi], bhf[nb][0], bhf[nb][1]);
                    mma_f16(acc[mi][nb * 2 + 1], ahf[mi], bhf[nb][2], bhf[nb][3]);
                    mma_f16(acc[mi][nb * 2 + 0], alf[mi], bhf[nb][0], bhf[nb][1]);
                    mma_f16(acc[mi][nb * 2 + 1], alf[mi], bhf[nb][2], bhf[nb][3]);
                    mma_f16(acc[mi][nb * 2 + 0], ahf[mi], blf[nb][0], blf[nb][1]);
                    mma_f16(acc[mi][nb * 2 + 1], ahf[mi], blf[nb][2], blf[nb][3]);
                }
        }
        __syncthreads();
    }

    const int tq = lane >> 2;
    const int tr = lane & 3;
#pragma unroll
    for (int mi = 0; mi < 2; mi++) {
        const int row = m0 + wm * 32 + mi * 16 + tq;
#pragma unroll
        for (int ni = 0; ni < 8; ni++) {
            const int col = n0 + wn * 64 + ni * 8 + tr * 2;
            atomicAdd(&C[(size_t)row * E_DIM + col],           acc[mi][ni][0]);
            atomicAdd(&C[(size_t)row * E_DIM + col + 1],       acc[mi][ni][1]);
            atomicAdd(&C[(size_t)(row + 8) * E_DIM + col],     acc[mi][ni][2]);
            atomicAdd(&C[(size_t)(row + 8) * E_DIM + col + 1], acc[mi][ni][3]);
        }
    }
}

// ---------------------------------------------------------------------------
// fp32 -> fp16 hi/lo split (elementwise, float4 vectorized)
// ---------------------------------------------------------------------------
__global__ void cvt_hilo(const float* __restrict__ x, __half* __restrict__ hi,
                         __half* __restrict__ lo, int n4)
{
    int i = blockIdx.x * blockDim.x + threadIdx.x;
    if (i >= n4) return;
    float4 v = ((const float4*)x)[i];
    __half h0 = __float2half_rn(v.x);
    __half h1 = __float2half_rn(v.y);
    __half h2 = __float2half_rn(v.z);
    __half h3 = __float2half_rn(v.w);
    __half l0 = __float2half_rn(v.x - __half2float(h0));
    __half l1 = __float2half_rn(v.y - __half2float(h1));
    __half l2 = __float2half_rn(v.z - __half2float(h2));
    __half l3 = __float2half_rn(v.w - __half2float(h3));
    __half2* hp = (__half2*)hi;
    __half2* lp = (__half2*)lo;
    hp[2 * i + 0] = __half2(h0, h1);
    hp[2 * i + 1] = __half2(h2, h3);
    lp[2 * i + 0] = __half2(l0, l1);
    lp[2 * i + 1] = __half2(l2, l3);
}

// ---------------------------------------------------------------------------
// Weight transpose + fp16 convert:  W[z][Kd][Nd] fp32 -> WT [z][Nd][Kd] fp16
// ---------------------------------------------------------------------------
__global__ void wt_cvt(const float* __restrict__ W, __half* __restrict__ WT,
                       int Kd, int Nd)
{
    __shared__ float t[32][33];
    const size_t moff = (size_t)blockIdx.z * Kd * Nd;
    const float* Wm = W + moff;
    __half* Hh = WT + moff;

    int nx = blockIdx.x * 32 + threadIdx.x;
    int k0 = blockIdx.y * 32;
#pragma unroll
    for (int j = 0; j < 4; j++) {
        int kk = k0 + threadIdx.y + j * 8;
        t[threadIdx.y + j * 8][threadIdx.x] = Wm[(size_t)kk * Nd + nx];
    }
    __syncthreads();
    int kx = k0 + threadIdx.x;
#pragma unroll
    for (int j = 0; j < 4; j++) {
        int nn = blockIdx.x * 32 + threadIdx.y + j * 8;
        Hh[(size_t)nn * Kd + kx] = __float2half_rn(t[threadIdx.x][threadIdx.y + j * 8]);
    }
}

// ---------------------------------------------------------------------------
// Transpose + hi/lo split: src fp32 [z][R][C] -> dst fp16 [z][C][R] (hi, lo)
// ---------------------------------------------------------------------------
__global__ void transp_hilo(const float* __restrict__ src, __half* __restrict__ dh,
                            __half* __restrict__ dl, int R, int C)
{
    __shared__ float t[32][33];
    const size_t zo = (size_t)blockIdx.z * R * C;
    const float* S = src + zo;
    __half* Dh = dh + zo;
    __half* Dl = dl + zo;

    int cx = blockIdx.x * 32 + threadIdx.x;
    int r0 = blockIdx.y * 32;
#pragma unroll
    for (int j = 0; j < 4; j++) {
        int rr = r0 + threadIdx.y + j * 8;
        t[threadIdx.y + j * 8][threadIdx.x] = S[(size_t)rr * C + cx];
    }
    __syncthreads();
    int rx = r0 + threadIdx.x;
#pragma unroll
    for (int j = 0; j < 4; j++) {
        int cc = blockIdx.x * 32 + threadIdx.y + j * 8;
        float v = t[threadIdx.x][threadIdx.y + j * 8];
        __half h = __float2half_rn(v);
        __half l = __float2half_rn(v - __half2float(h));
        Dh[(size_t)cc * R + rx] = h;
        Dl[(size_t)cc * R + rx] = l;
    }
}

// ---------------------------------------------------------------------------
// Fused relative-bias multihead attention; emits fp16 hi/lo output directly
// ---------------------------------------------------------------------------
template <int S>
__global__ __launch_bounds__(256)
void attn_kernel(const float* __restrict__ Q, const float* __restrict__ K,
                 const float* __restrict__ V,
                 __half* __restrict__ OutH, __half* __restrict__ OutL,
                 const float* __restrict__ rb,
                 int div, int mulq, int mulr, int stepTok)
{
    const int h = blockIdx.x;
    const int g = blockIdx.y;
    const int base_m = (g / div) * mulq + (g % div) * mulr;
    const size_t baseE = (size_t)base_m * E_DIM + h * D_DIM;
    const size_t stepE = (size_t)stepTok * E_DIM;

    extern __shared__ float sm[];
    float2* Kt2 = (float2*)sm;
    float2* Vs2 = Kt2 + 32 * (S + 1);
    float*  rbh = (float*)(Vs2 + S * 32);

    const int tid = threadIdx.x;

    for (int idx = tid; idx < S * 32; idx += 256) {
        int t = idx >> 5, d2 = idx & 31;
        size_t off = baseE + (size_t)t * stepE;
        Kt2[d2 * (S + 1) + t] = *(const float2*)&K[off + 2 * d2];
        Vs2[idx]              = *(const float2*)&V[off + 2 * d2];
    }
    for (int i = tid; i < 2 * S - 1; i += 256)
        rbh[i] = rb[(size_t)(MAXLEN - S + i) * H_DIM + h];
    __syncthreads();

    const int lane = tid & 31;
    const int warp = tid >> 5;
    const int NT = S / 32;

    for (int q = warp; q < S; q += 8) {
        size_t qoff = baseE + (size_t)q * stepE;
        float2 ql = *(const float2*)&Q[qoff + 2 * lane];

        float s[NT];
#pragma unroll
        for (int tb = 0; tb < NT; tb++) s[tb] = 0.f;

#pragma unroll 4
        for (int d2 = 0; d2 < 32; d2++) {
            float qx = __shfl_sync(0xffffffffu, ql.x, d2);
            float qy = __shfl_sync(0xffffffffu, ql.y, d2);
            const float2* kr = &Kt2[d2 * (S + 1) + lane];
#pragma unroll
            for (int tb = 0; tb < NT; tb++) {
                float2 kv = kr[tb * 32];
                s[tb] += qx * kv.x + qy * kv.y;
            }
        }

#pragma unroll
        for (int tb = 0; tb < NT; tb++) {
            int t = tb * 32 + lane;
            s[tb] = s[tb] * 0.125f + rbh[t - q + (S - 1)];
        }

        float mx = s[0];
#pragma unroll
        for (int tb = 1; tb < NT; tb++) mx = fmaxf(mx, s[tb]);
#pragma unroll
        for (int o = 16; o > 0; o >>= 1)
            mx = fmaxf(mx, __shfl_xor_sync(0xffffffffu, mx, o));
        float sum = 0.f;
#pragma unroll
        for (int tb = 0; tb < NT; tb++) { s[tb] = __expf(s[tb] - mx); sum += s[tb]; }
#pragma unroll
        for (int o = 16; o > 0; o >>= 1)
            sum += __shfl_xor_sync(0xffffffffu, sum, o);
        float inv = 1.f / sum;
#pragma unroll
        for (int tb = 0; tb < NT; tb++) s[tb] *= inv;

        float cx = 0.f, cy = 0.f;
#pragma unroll
        for (int tb = 0; tb < NT; tb++) {
            float wv = s[tb];
#pragma unroll 8
            for (int j = 0; j < 32; j++) {
                float wj = __shfl_sync(0xffffffffu, wv, j);
                float2 vv = Vs2[(tb * 32 + j) * 32 + lane];
                cx += wj * vv.x;
                cy += wj * vv.y;
            }
        }
        __half hx = __float2half_rn(cx);
        __half hy = __float2half_rn(cy);
        __half lx = __float2half_rn(cx - __half2float(hx));
        __half ly = __float2half_rn(cy - __half2float(hy));
        *(__half2*)&OutH[qoff + 2 * lane] = __halves2half2(hx, hy);
        *(__half2*)&OutL[qoff + 2 * lane] = __halves2half2(lx, ly);
    }
}

// ---------------------------------------------------------------------------
// Selection softmax over token axis per (b, k), in place
// ---------------------------------------------------------------------------
__global__ __launch_bounds__(256)
void sel_softmax(float* __restrict__ sc)
{
    const int b = blockIdx.x;
    const int k0 = blockIdx.y * 32;
    const int lane = threadIdx.x & 31;
    const int row = threadIdx.x >> 5;

    float* base = sc + (size_t)b * MTOK_B * KSEL + k0 + lane;

    __shared__ float redA[8][32];
    __shared__ float redB[8][32];

    float mx = -1e30f;
    for (int m = row; m < MTOK_B; m += 8)
        mx = fmaxf(mx, base[(size_t)m * KSEL]);
    redA[row][lane] = mx;
    __syncthreads();
    if (row == 0) {
        float v = redA[0][lane];
#pragma unroll
        for (int r = 1; r < 8; r++) v = fmaxf(v, redA[r][lane]);
        redA[0][lane] = v;
    }
    __syncthreads();
    mx = redA[0][lane];

    float sum = 0.f;
    for (int m = row; m < MTOK_B; m += 8)
        sum += __expf(base[(size_t)m * KSEL] - mx);
    redB[row][lane] = sum;
    __syncthreads();
    if (row == 0) {
        float v = 0.f;
#pragma unroll
        for (int r = 0; r < 8; r++) v += redB[r][lane];
        redB[0][lane] = v;
    }
    __syncthreads();
    float inv = 1.f / redB[0][lane];

    for (int m = row; m < MTOK_B; m += 8) {
        float* p = &base[(size_t)m * KSEL];
        *p = __expf(*p - mx) * inv;
    }
}

// ---------------------------------------------------------------------------
// Multi-scale pooling
// ---------------------------------------------------------------------------
__global__ void pool_kernel(const float* __restrict__ sel, float* __restrict__ out)
{
    int idx = blockIdx.x * blockDim.x + threadIdx.x;
    int total = B_DIM * OUT_ROWS * E_DIM;
    if (idx >= total) return;
    int e = idx % E_DIM;
    int r = (idx / E_DIM) % OUT_ROWS;
    int b = idx / (OUT_ROWS * E_DIM);
    const float* sb = sel + (size_t)b * KSEL * E_DIM;
    float v;
    if (r < 256) {
        v = sb[(size_t)r * E_DIM + e];
    } else if (r < 384) {
        int i = (r - 256) * 2;
        v = 0.5f * (sb[(size_t)i * E_DIM + e] + sb[(size_t)(i + 1) * E_DIM + e]);
    } else {
        int i = (r - 384) * 4;
        v = 0.25f * (sb[(size_t)i * E_DIM + e] + sb[(size_t)(i + 1) * E_DIM + e] +
                     sb[(size_t)(i + 2) * E_DIM + e] + sb[(size_t)(i + 3) * E_DIM + e]);
    }
    out[idx] = v;
}

// ---------------------------------------------------------------------------
// Orchestration
// ---------------------------------------------------------------------------
extern "C" void kernel_launch(void* const* d_in, const int* in_sizes, int n_in,
                              void* d_out, int out_size)
{
    (void)in_sizes; (void)n_in; (void)out_size;

    const float* x    = (const float*)d_in[0];
    const float* wq   = (const float*)d_in[1];
    const float* bq   = (const float*)d_in[2];
    const float* wk   = (const float*)d_in[3];
    const float* bk   = (const float*)d_in[4];
    const float* wv   = (const float*)d_in[5];
    const float* bv   = (const float*)d_in[6];
    const float* wd   = (const float*)d_in[7];
    const float* bd   = (const float*)d_in[8];
    const float* rb   = (const float*)d_in[9];
    const float* selw = (const float*)d_in[10];
    const float* selb = (const float*)d_in[11];
    float* out = (float*)d_out;

    float *Qb, *Kb, *Vb, *Hb, *SCb, *SELb;
    cudaGetSymbolAddress((void**)&Qb,  g_Q);
    cudaGetSymbolAddress((void**)&Kb,  g_Kb);
    cudaGetSymbolAddress((void**)&Vb,  g_Vb);
    cudaGetSymbolAddress((void**)&Hb,  g_Hb);
    cudaGetSymbolAddress((void**)&SCb, g_SC);
    cudaGetSymbolAddress((void**)&SELb, g_SEL);

    __half *Ahp, *Alp, *Ah2p, *Al2p, *WqT, *WkT, *WvT, *WdT, *SWT;
    __half *SCTh, *SCTl, *HTh, *HTl;
    cudaGetSymbolAddress((void**)&Ahp, g_Ah);
    cudaGetSymbolAddress((void**)&Alp, g_Al);
    cudaGetSymbolAddress((void**)&Ah2p, g_Ah2);
    cudaGetSymbolAddress((void**)&Al2p, g_Al2);
    cudaGetSymbolAddress((void**)&WqT, g_WqT);
    cudaGetSymbolAddress((void**)&WkT, g_WkT);
    cudaGetSymbolAddress((void**)&WvT, g_WvT);
    cudaGetSymbolAddress((void**)&WdT, g_WdT);
    cudaGetSymbolAddress((void**)&SWT, g_SWT);
    cudaGetSymbolAddress((void**)&SCTh, g_SCTh);
    cudaGetSymbolAddress((void**)&SCTl, g_SCTl);
    cudaGetSymbolAddress((void**)&HTh, g_HTh);
    cudaGetSymbolAddress((void**)&HTl, g_HTl);

    const int smemSp = (32 * (256 + 1) * 2 + 256 * 32 * 2 + (2 * 256 - 1)) * (int)sizeof(float);
    const int smemTe = (32 * (32 + 1) * 2 + 32 * 32 * 2 + (2 * 32 - 1)) * (int)sizeof(float);
    cudaFuncSetAttribute((const void*)attn_kernel<256>,
                         cudaFuncAttributeMaxDynamicSharedMemorySize, smemSp);
    cudaFuncSetAttribute((const void*)gemm_f16x2,
                         cudaFuncAttributeMaxDynamicSharedMemorySize, GEMM_SMEM);
    cudaFuncSetAttribute((const void*)gemm_3seg,
                         cudaFuncAttributeMaxDynamicSharedMemorySize, SEL_SMEM);

    const dim3 blk(256);
    const dim3 tblk(32, 8);
    const int n4 = MTOK * E_DIM / 4;
    const dim3 gcvt((n4 + 255) / 256);
    const dim3 gProj(E_DIM / 128, MTOK / 128);
    const size_t MM = (size_t)E_DIM * E_DIM;

    // --- layer 0, interleaved with weight prep (keeps a GEMM at capture idx 3)
    wt_cvt<<<dim3(E_DIM / 32, E_DIM / 32, 4), tblk>>>(wq, WqT, E_DIM, E_DIM);   // 0
    wt_cvt<<<dim3(E_DIM / 32, E_DIM / 32, 4), tblk>>>(wk, WkT, E_DIM, E_DIM);   // 1
    cvt_hilo<<<gcvt, blk>>>(x, Ah2p, Al2p, n4);                                  // 2
    gemm_f16x2<<<gProj, blk, GEMM_SMEM>>>(Ah2p, Al2p, WqT, bq, Qb,
                                          nullptr, nullptr, E_DIM, E_DIM);       // 3 <- ncu
    wt_cvt<<<dim3(E_DIM / 32, E_DIM / 32, 4), tblk>>>(wv, WvT, E_DIM, E_DIM);   // 4
    gemm_f16x2<<<gProj, blk, GEMM_SMEM>>>(Ah2p, Al2p, WkT, bk, Kb,
                                          nullptr, nullptr, E_DIM, E_DIM);       // 5
    wt_cvt<<<dim3(E_DIM / 32, E_DIM / 32, 4), tblk>>>(wd, WdT, E_DIM, E_DIM);   // 6
    gemm_f16x2<<<gProj, blk, GEMM_SMEM>>>(Ah2p, Al2p, WvT, bv, Vb,
                                          nullptr, nullptr, E_DIM, E_DIM);       // 7
    wt_cvt<<<dim3(KSEL / 32, E_DIM / 32, 1), tblk>>>(selw, SWT, E_DIM, KSEL);   // 8

    for (int a = 0; a < 4; a++) {
        if (a > 0) {
            gemm_f16x2<<<gProj, blk, GEMM_SMEM>>>(Ah2p, Al2p, WqT + a * MM, bq + a * E_DIM, Qb,
                                                  nullptr, nullptr, E_DIM, E_DIM);
            gemm_f16x2<<<gProj, blk, GEMM_SMEM>>>(Ah2p, Al2p, WkT + a * MM, bk + a * E_DIM, Kb,
                                                  nullptr, nullptr, E_DIM, E_DIM);
            gemm_f16x2<<<gProj, blk, GEMM_SMEM>>>(Ah2p, Al2p, WvT + a * MM, bv + a * E_DIM, Vb,
                                                  nullptr, nullptr, E_DIM, E_DIM);
        }

        const float* rba = rb + (size_t)a * RB_ONE;
        if ((a & 1) == 0) {
            attn_kernel<256><<<dim3(H_DIM, B_DIM * T_DIM), blk, smemSp>>>(
                Qb, Kb, Vb, Ahp, Alp, rba, B_DIM * T_DIM, 0, N_DIM, 1);
        } else {
            attn_kernel<32><<<dim3(H_DIM, B_DIM * N_DIM), blk, smemTe>>>(
                Qb, Kb, Vb, Ahp, Alp, rba, N_DIM, T_DIM * N_DIM, 1, N_DIM);
        }

        // output projection: fp32 Hb + fused fp16 hi/lo (input of next layer / sc)
        gemm_f16x2<<<gProj, blk, GEMM_SMEM>>>(Ahp, Alp, WdT + a * MM, bd + a * E_DIM, Hb,
                                              Ah2p, Al2p, E_DIM, E_DIM);
    }

    // selection scores: [MTOK, KSEL]
    gemm_f16x2<<<dim3(KSEL / 128, MTOK / 128), blk, GEMM_SMEM>>>(
        Ah2p, Al2p, SWT, selb, SCb, nullptr, nullptr, KSEL, E_DIM);

    // softmax over token axis per (b, k), in place
    sel_softmax<<<dim3(B_DIM, KSEL / 32), blk>>>(SCb);

    // transposed fp16 hi/lo operands for selection GEMM
    transp_hilo<<<dim3(KSEL / 32, MTOK_B / 32, B_DIM), tblk>>>(SCb, SCTh, SCTl, MTOK_B, KSEL);
    transp_hilo<<<dim3(E_DIM / 32, MTOK_B / 32, B_DIM), tblk>>>(Hb, HTh, HTl, MTOK_B, E_DIM);

    // sel[b,k,e] = sum_m wts[b,m,k] * h[b,m,e]  (3-seg fp16 mma, split-K + atomics)
    cudaMemsetAsync(SELb, 0, (size_t)B_DIM * KSEL * E_DIM * sizeof(float));
    gemm_3seg<<<dim3(E_DIM / 128, KSEL / 128, B_DIM * SPLITK_SEL), blk, SEL_SMEM>>>(
        SCTh, SCTl, HTh, HTl, SELb);

    // multi-scale pooling -> output [B, 448, E]
    int total = B_DIM * OUT_ROWS * E_DIM;
    pool_kernel<<<(total + 255) / 256, 256>>>(SELb, out);
}

// round 6
// speedup vs baseline: 1.1478x; 1.1478x over previous
#include <cuda_runtime.h>
#include <cuda_fp16.h>
#include <cstdint>
#include <cstddef>

// ---------------------------------------------------------------------------
// Problem constants
// ---------------------------------------------------------------------------
#define E_DIM   1024
#define QKV_N   3072
#define H_DIM   16
#define D_DIM   64
#define B_DIM   2
#define T_DIM   32
#define N_DIM   256
#define MTOK    (B_DIM * T_DIM * N_DIM)   // 16384 tokens total
#define MTOK_B  (T_DIM * N_DIM)           // 8192 tokens per batch
#define KSEL    256
#define MAXLEN  512
#define RB_ONE  ((2 * MAXLEN - 1) * H_DIM)
#define OUT_ROWS 448                      // 256 + 128 + 64
#define SPLITK  8

// ---------------------------------------------------------------------------
// Scratch (device globals — no allocations allowed)
// ---------------------------------------------------------------------------
__device__ float g_QKV[MTOK * QKV_N];     // merged Q|K|V per token
__device__ float g_Hb[MTOK * E_DIM];
__device__ float g_SC[MTOK * KSEL];
__device__ float g_SEL[B_DIM * KSEL * E_DIM];

// fp16 split activations: ping (attention out) and pong (projection in)
__device__ __half g_Ah[MTOK * E_DIM];
__device__ __half g_Al[MTOK * E_DIM];
__device__ __half g_Ah2[MTOK * E_DIM];
__device__ __half g_Al2[MTOK * E_DIM];
// transposed fp16 weights
__device__ __half g_WqkvT[4 * 3 * E_DIM * E_DIM];   // [a][q|k|v][N=E][K=E]
__device__ __half g_WdT[4 * E_DIM * E_DIM];
__device__ __half g_SWT[KSEL * E_DIM];
__device__ float  g_Bqkv[4 * QKV_N];                // merged bias per attn idx

// ---------------------------------------------------------------------------
// PTX helpers (cp.async / ldmatrix / mma.sync — baseline sm_80+ PTX)
// ---------------------------------------------------------------------------
__device__ __forceinline__ void cp_async16(uint32_t dst, const void* src) {
    asm volatile("cp.async.cg.shared.global [%0], [%1], 16;" :: "r"(dst), "l"(src));
}
__device__ __forceinline__ void cp_commit() {
    asm volatile("cp.async.commit_group;" ::: "memory");
}
template <int N>
__device__ __forceinline__ void cp_wait_group() {
    asm volatile("cp.async.wait_group %0;" :: "n"(N) : "memory");
}
__device__ __forceinline__ void ldmatrix_x4(uint32_t* r, uint32_t addr) {
    asm volatile("ldmatrix.sync.aligned.m8n8.x4.shared.b16 {%0,%1,%2,%3}, [%4];"
                 : "=r"(r[0]), "=r"(r[1]), "=r"(r[2]), "=r"(r[3]) : "r"(addr));
}
__device__ __forceinline__ void mma_f16(float* d, const uint32_t* a,
                                        uint32_t b0, uint32_t b1) {
    asm volatile(
        "mma.sync.aligned.m16n8k16.row.col.f32.f16.f16.f32 "
        "{%0,%1,%2,%3}, {%4,%5,%6,%7}, {%8,%9}, {%0,%1,%2,%3};"
        : "+f"(d[0]), "+f"(d[1]), "+f"(d[2]), "+f"(d[3])
        : "r"(a[0]), "r"(a[1]), "r"(a[2]), "r"(a[3]), "r"(b0), "r"(b1));
}

// ---------------------------------------------------------------------------
// fp16x2 GEMM via mma.sync:
//   C[M, Nfull] = (Ah+Al)[M,K] @ B[Nfull,K]^T + bias
// Optional fused fp16 hi/lo output (Ch/Cl).
// CTA 128x128, k-chunk 32, 3-stage cp.async pipeline, 2 CTAs/SM.
// 8 warps (4 in M x 2 in N), warp tile 32x64, m16n8k16.
// ---------------------------------------------------------------------------
#define GSTAGES 3
#define ROWPAD  40
#define TILE_BYTES (128 * ROWPAD * 2)         // 10240 per tile
#define STAGE_BYTES (3 * TILE_BYTES)          // Ah, Al, B
#define GEMM_SMEM (GSTAGES * STAGE_BYTES)     // 92160

__global__ __launch_bounds__(256, 2)
void gemm_f16x2(const __half* __restrict__ Ah, const __half* __restrict__ Al,
                const __half* __restrict__ B,
                const float* __restrict__ bias, float* __restrict__ C,
                __half* __restrict__ Ch, __half* __restrict__ Cl,
                int Nfull, int Kfull)
{
    extern __shared__ char smem[];
    const uint32_t sb = (uint32_t)__cvta_generic_to_shared(smem);
    const int tid = threadIdx.x;
    const int lane = tid & 31;
    const int warp = tid >> 5;
    const int wm = warp >> 1;
    const int wn = warp & 1;
    const int m0 = blockIdx.y * 128;
    const int n0 = blockIdx.x * 128;

    const int NCH = Kfull >> 5;

    const int lr0 = tid >> 1;
    const int ls0 = (tid & 1) << 1;

    float acc[2][8][4];
#pragma unroll
    for (int mi = 0; mi < 2; mi++)
#pragma unroll
        for (int ni = 0; ni < 8; ni++)
#pragma unroll
            for (int q = 0; q < 4; q++) acc[mi][ni][q] = 0.f;

    auto load_chunk = [&](int c, int stage) {
        const int kb = c << 5;
        const uint32_t base = sb + stage * STAGE_BYTES;
#pragma unroll
        for (int j = 0; j < 2; j++) {
            const int s4 = ls0 + j;
            const uint32_t soff = (uint32_t)(lr0 * ROWPAD + s4 * 8) * 2;
            const size_t goff = (size_t)lr0 * Kfull + kb + s4 * 8;
            cp_async16(base + soff,                  Ah + (size_t)m0 * Kfull + goff);
            cp_async16(base + TILE_BYTES + soff,     Al + (size_t)m0 * Kfull + goff);
            cp_async16(base + 2 * TILE_BYTES + soff, B  + (size_t)n0 * Kfull + goff);
        }
    };

#pragma unroll
    for (int s = 0; s < GSTAGES - 1; s++) {
        if (s < NCH) load_chunk(s, s);
        cp_commit();
    }

    const int la_i = lane & 7;
    const int la_g = lane >> 3;
    const int a_rowadd = la_i + ((la_g & 1) << 3);
    const int a_coladd = (la_g >> 1) << 3;
    const int b_rowadd = la_i + ((la_g >> 1) << 3);
    const int b_coladd = (la_g & 1) << 3;

    for (int c = 0; c < NCH; c++) {
        const int stage = c % GSTAGES;
        cp_wait_group<GSTAGES - 2>();
        __syncthreads();

        const int nc = c + GSTAGES - 1;
        if (nc < NCH) load_chunk(nc, nc % GSTAGES);
        cp_commit();

        const uint32_t base = sb + stage * STAGE_BYTES;
        const uint32_t Bbase = base + 2 * TILE_BYTES;

#pragma unroll
        for (int k16 = 0; k16 < 32; k16 += 16) {
            uint32_t bf[4][4];
#pragma unroll
            for (int nb = 0; nb < 4; nb++) {
                const int row = wn * 64 + nb * 16 + b_rowadd;
                const int col = k16 + b_coladd;
                ldmatrix_x4(bf[nb], Bbase + (uint32_t)(row * ROWPAD + col) * 2);
            }
#pragma unroll
            for (int seg = 0; seg < 2; seg++) {
                const uint32_t Abase = base + seg * TILE_BYTES;
                uint32_t af[2][4];
#pragma unroll
                for (int mi = 0; mi < 2; mi++) {
                    const int row = wm * 32 + mi * 16 + a_rowadd;
                    const int col = k16 + a_coladd;
                    ldmatrix_x4(af[mi], Abase + (uint32_t)(row * ROWPAD + col) * 2);
                }
#pragma unroll
                for (int nb = 0; nb < 4; nb++)
#pragma unroll
                    for (int mi = 0; mi < 2; mi++) {
                        mma_f16(acc[mi][nb * 2 + 0], af[mi], bf[nb][0], bf[nb][1]);
                        mma_f16(acc[mi][nb * 2 + 1], af[mi], bf[nb][2], bf[nb][3]);
                    }
            }
        }
    }

    // epilogue (+ optional fused fp16 hi/lo emit)
    const int tq = lane >> 2;
    const int tr = lane & 3;
#pragma unroll
    for (int mi = 0; mi < 2; mi++) {
        const int row = m0 + wm * 32 + mi * 16 + tq;
#pragma unroll
        for (int ni = 0; ni < 8; ni++) {
            const int col = n0 + wn * 64 + ni * 8 + tr * 2;
            const float b0 = bias[col], b1 = bias[col + 1];
            float c00 = acc[mi][ni][0] + b0, c01 = acc[mi][ni][1] + b1;
            float c10 = acc[mi][ni][2] + b0, c11 = acc[mi][ni][3] + b1;
            float2 v0; v0.x = c00; v0.y = c01;
            float2 v1; v1.x = c10; v1.y = c11;
            *(float2*)&C[(size_t)row * Nfull + col] = v0;
            *(float2*)&C[(size_t)(row + 8) * Nfull + col] = v1;
            if (Ch) {
                __half h00 = __float2half_rn(c00);
                __half h01 = __float2half_rn(c01);
                __half h10 = __float2half_rn(c10);
                __half h11 = __float2half_rn(c11);
                *(__half2*)&Ch[(size_t)row * Nfull + col]       = __halves2half2(h00, h01);
                *(__half2*)&Ch[(size_t)(row + 8) * Nfull + col] = __halves2half2(h10, h11);
                __half l00 = __float2half_rn(c00 - __half2float(h00));
                __half l01 = __float2half_rn(c01 - __half2float(h01));
                __half l10 = __float2half_rn(c10 - __half2float(h10));
                __half l11 = __float2half_rn(c11 - __half2float(h11));
                *(__half2*)&Cl[(size_t)row * Nfull + col]       = __halves2half2(l00, l01);
                *(__half2*)&Cl[(size_t)(row + 8) * Nfull + col] = __halves2half2(l10, l11);
            }
        }
    }
}

// ---------------------------------------------------------------------------
// fp32 -> fp16 hi/lo split (elementwise, float4 vectorized)
// ---------------------------------------------------------------------------
__global__ void cvt_hilo(const float* __restrict__ x, __half* __restrict__ hi,
                         __half* __restrict__ lo, int n4)
{
    int i = blockIdx.x * blockDim.x + threadIdx.x;
    if (i >= n4) return;
    float4 v = ((const float4*)x)[i];
    __half h0 = __float2half_rn(v.x);
    __half h1 = __float2half_rn(v.y);
    __half h2 = __float2half_rn(v.z);
    __half h3 = __float2half_rn(v.w);
    __half l0 = __float2half_rn(v.x - __half2float(h0));
    __half l1 = __float2half_rn(v.y - __half2float(h1));
    __half l2 = __float2half_rn(v.z - __half2float(h2));
    __half l3 = __float2half_rn(v.w - __half2float(h3));
    __half2* hp = (__half2*)hi;
    __half2* lp = (__half2*)lo;
    hp[2 * i + 0] = __half2(h0, h1);
    hp[2 * i + 1] = __half2(h2, h3);
    lp[2 * i + 0] = __half2(l0, l1);
    lp[2 * i + 1] = __half2(l2, l3);
}

// ---------------------------------------------------------------------------
// Weight transpose + fp16 convert into merged QKV layout:
//   src W [z][Kd][Nd] fp32  ->  dst [z][3][Nd][Kd] fp16 at slot `type`
// ---------------------------------------------------------------------------
__global__ void wt_cvt3(const float* __restrict__ W, __half* __restrict__ WT,
                        int Kd, int Nd, int type)
{
    __shared__ float t[32][33];
    const size_t srcoff = (size_t)blockIdx.z * Kd * Nd;
    const size_t dstoff = ((size_t)blockIdx.z * 3 + type) * Kd * Nd;
    const float* Wm = W + srcoff;
    __half* Hh = WT + dstoff;

    int nx = blockIdx.x * 32 + threadIdx.x;
    int k0 = blockIdx.y * 32;
#pragma unroll
    for (int j = 0; j < 4; j++) {
        int kk = k0 + threadIdx.y + j * 8;
        t[threadIdx.y + j * 8][threadIdx.x] = Wm[(size_t)kk * Nd + nx];
    }
    __syncthreads();
    int kx = k0 + threadIdx.x;
#pragma unroll
    for (int j = 0; j < 4; j++) {
        int nn = blockIdx.x * 32 + threadIdx.y + j * 8;
        Hh[(size_t)nn * Kd + kx] = __float2half_rn(t[threadIdx.x][threadIdx.y + j * 8]);
    }
}

// plain transpose+convert (wd, selw)
__global__ void wt_cvt(const float* __restrict__ W, __half* __restrict__ WT,
                       int Kd, int Nd)
{
    __shared__ float t[32][33];
    const size_t moff = (size_t)blockIdx.z * Kd * Nd;
    const float* Wm = W + moff;
    __half* Hh = WT + moff;

    int nx = blockIdx.x * 32 + threadIdx.x;
    int k0 = blockIdx.y * 32;
#pragma unroll
    for (int j = 0; j < 4; j++) {
        int kk = k0 + threadIdx.y + j * 8;
        t[threadIdx.y + j * 8][threadIdx.x] = Wm[(size_t)kk * Nd + nx];
    }
    __syncthreads();
    int kx = k0 + threadIdx.x;
#pragma unroll
    for (int j = 0; j < 4; j++) {
        int nn = blockIdx.x * 32 + threadIdx.y + j * 8;
        Hh[(size_t)nn * Kd + kx] = __float2half_rn(t[threadIdx.x][threadIdx.y + j * 8]);
    }
}

// merged QKV bias: out[a][0:1024)=bq[a], [1024:2048)=bk[a], [2048:3072)=bv[a]
__global__ void bias_concat(const float* __restrict__ bq, const float* __restrict__ bk,
                            const float* __restrict__ bv, float* __restrict__ out)
{
    int i = blockIdx.x * blockDim.x + threadIdx.x;
    if (i >= 4 * QKV_N) return;
    int a = i / QKV_N;
    int r = i % QKV_N;
    const float* src = (r < E_DIM) ? bq : (r < 2 * E_DIM) ? bk : bv;
    out[i] = src[a * E_DIM + (r & (E_DIM - 1))];
}

// ---------------------------------------------------------------------------
// Split-K pooled-selection GEMM (fp32, atomics) — proven R4 version
// ---------------------------------------------------------------------------
__global__ __launch_bounds__(256, 2)
void gemm_sel_atomic(const float* __restrict__ Wts, const float* __restrict__ Flat,
                     float* __restrict__ Csel)
{
    __shared__ float As[16][128];
    __shared__ float Bs[16][128];

    const int tid = threadIdx.x;
    const int bx = blockIdx.x;
    const int by = blockIdx.y;
    const int b  = blockIdx.z / SPLITK;
    const int sl = blockIdx.z % SPLITK;

    const float* A = Wts  + (size_t)b * MTOK_B * KSEL;
    const float* B = Flat + (size_t)b * MTOK_B * E_DIM;
    float*       C = Csel + (size_t)b * KSEL * E_DIM;

    const int lr = (tid & 31) << 2;
    const int lk = tid >> 5;
    const int tx = tid & 15;
    const int ty = tid >> 4;

    const int kbeg = sl * (MTOK_B / SPLITK);
    const int kend = kbeg + (MTOK_B / SPLITK);

    float acc[8][8];
#pragma unroll
    for (int i = 0; i < 8; i++)
#pragma unroll
        for (int j = 0; j < 8; j++) acc[i][j] = 0.f;

    for (int k0 = kbeg; k0 < kend; k0 += 16) {
        *(float4*)&As[lk][lr]     = *(const float4*)&A[(size_t)(k0 + lk) * KSEL + by * 128 + lr];
        *(float4*)&As[lk + 8][lr] = *(const float4*)&A[(size_t)(k0 + lk + 8) * KSEL + by * 128 + lr];
        *(float4*)&Bs[lk][lr]     = *(const float4*)&B[(size_t)(k0 + lk) * E_DIM + bx * 128 + lr];
        *(float4*)&Bs[lk + 8][lr] = *(const float4*)&B[(size_t)(k0 + lk + 8) * E_DIM + bx * 128 + lr];
        __syncthreads();

#pragma unroll
        for (int kk = 0; kk < 16; kk++) {
            float ar[8], br[8];
            *(float4*)&ar[0] = *(const float4*)&As[kk][ty * 8];
            *(float4*)&ar[4] = *(const float4*)&As[kk][ty * 8 + 4];
            *(float4*)&br[0] = *(const float4*)&Bs[kk][tx * 8];
            *(float4*)&br[4] = *(const float4*)&Bs[kk][tx * 8 + 4];
#pragma unroll
            for (int i = 0; i < 8; i++)
#pragma unroll
                for (int j = 0; j < 8; j++)
                    acc[i][j] += ar[i] * br[j];
        }
        __syncthreads();
    }

#pragma unroll
    for (int i = 0; i < 8; i++) {
        float* cp = C + (size_t)(by * 128 + ty * 8 + i) * E_DIM + bx * 128 + tx * 8;
#pragma unroll
        for (int j = 0; j < 8; j++)
            atomicAdd(&cp[j], acc[i][j]);
    }
}

// ---------------------------------------------------------------------------
// Fused relative-bias multihead attention; reads merged QKV (row stride ldx),
// emits fp16 hi/lo output (row stride E_DIM) directly.
// ---------------------------------------------------------------------------
template <int S>
__global__ __launch_bounds__(256)
void attn_kernel(const float* __restrict__ Q, const float* __restrict__ K,
                 const float* __restrict__ V,
                 __half* __restrict__ OutH, __half* __restrict__ OutL,
                 const float* __restrict__ rb,
                 int div, int mulq, int mulr, int stepTok, int ldx)
{
    const int h = blockIdx.x;
    const int g = blockIdx.y;
    const int base_m = (g / div) * mulq + (g % div) * mulr;
    const size_t baseE = (size_t)base_m * ldx + h * D_DIM;
    const size_t stepE = (size_t)stepTok * ldx;

    extern __shared__ float sm[];
    float2* Kt2 = (float2*)sm;
    float2* Vs2 = Kt2 + 32 * (S + 1);
    float*  rbh = (float*)(Vs2 + S * 32);

    const int tid = threadIdx.x;

    for (int idx = tid; idx < S * 32; idx += 256) {
        int t = idx >> 5, d2 = idx & 31;
        size_t off = baseE + (size_t)t * stepE;
        Kt2[d2 * (S + 1) + t] = *(const float2*)&K[off + 2 * d2];
        Vs2[idx]              = *(const float2*)&V[off + 2 * d2];
    }
    for (int i = tid; i < 2 * S - 1; i += 256)
        rbh[i] = rb[(size_t)(MAXLEN - S + i) * H_DIM + h];
    __syncthreads();

    const int lane = tid & 31;
    const int warp = tid >> 5;
    const int NT = S / 32;

    for (int q = warp; q < S; q += 8) {
        size_t qoff = baseE + (size_t)q * stepE;
        float2 ql = *(const float2*)&Q[qoff + 2 * lane];

        float s[NT];
#pragma unroll
        for (int tb = 0; tb < NT; tb++) s[tb] = 0.f;

#pragma unroll 4
        for (int d2 = 0; d2 < 32; d2++) {
            float qx = __shfl_sync(0xffffffffu, ql.x, d2);
            float qy = __shfl_sync(0xffffffffu, ql.y, d2);
            const float2* kr = &Kt2[d2 * (S + 1) + lane];
#pragma unroll
            for (int tb = 0; tb < NT; tb++) {
                float2 kv = kr[tb * 32];
                s[tb] += qx * kv.x + qy * kv.y;
            }
        }

#pragma unroll
        for (int tb = 0; tb < NT; tb++) {
            int t = tb * 32 + lane;
            s[tb] = s[tb] * 0.125f + rbh[t - q + (S - 1)];
        }

        float mx = s[0];
#pragma unroll
        for (int tb = 1; tb < NT; tb++) mx = fmaxf(mx, s[tb]);
#pragma unroll
        for (int o = 16; o > 0; o >>= 1)
            mx = fmaxf(mx, __shfl_xor_sync(0xffffffffu, mx, o));
        float sum = 0.f;
#pragma unroll
        for (int tb = 0; tb < NT; tb++) { s[tb] = __expf(s[tb] - mx); sum += s[tb]; }
#pragma unroll
        for (int o = 16; o > 0; o >>= 1)
            sum += __shfl_xor_sync(0xffffffffu, sum, o);
        float inv = 1.f / sum;
#pragma unroll
        for (int tb = 0; tb < NT; tb++) s[tb] *= inv;

        float cx = 0.f, cy = 0.f;
#pragma unroll
        for (int tb = 0; tb < NT; tb++) {
            float wv = s[tb];
#pragma unroll 8
            for (int j = 0; j < 32; j++) {
                float wj = __shfl_sync(0xffffffffu, wv, j);
                float2 vv = Vs2[(tb * 32 + j) * 32 + lane];
                cx += wj * vv.x;
                cy += wj * vv.y;
            }
        }
        __half hx = __float2half_rn(cx);
        __half hy = __float2half_rn(cy);
        __half lx = __float2half_rn(cx - __half2float(hx));
        __half ly = __float2half_rn(cy - __half2float(hy));
        const size_t ooff = (size_t)(base_m + q * stepTok) * E_DIM + h * D_DIM + 2 * lane;
        *(__half2*)&OutH[ooff] = __halves2half2(hx, hy);
        *(__half2*)&OutL[ooff] = __halves2half2(lx, ly);
    }
}

// ---------------------------------------------------------------------------
// Selection softmax over token axis per (b, k), in place
// ---------------------------------------------------------------------------
__global__ __launch_bounds__(256)
void sel_softmax(float* __restrict__ sc)
{
    const int b = blockIdx.x;
    const int k0 = blockIdx.y * 32;
    const int lane = threadIdx.x & 31;
    const int row = threadIdx.x >> 5;

    float* base = sc + (size_t)b * MTOK_B * KSEL + k0 + lane;

    __shared__ float redA[8][32];
    __shared__ float redB[8][32];

    float mx = -1e30f;
    for (int m = row; m < MTOK_B; m += 8)
        mx = fmaxf(mx, base[(size_t)m * KSEL]);
    redA[row][lane] = mx;
    __syncthreads();
    if (row == 0) {
        float v = redA[0][lane];
#pragma unroll
        for (int r = 1; r < 8; r++) v = fmaxf(v, redA[r][lane]);
        redA[0][lane] = v;
    }
    __syncthreads();
    mx = redA[0][lane];

    float sum = 0.f;
    for (int m = row; m < MTOK_B; m += 8)
        sum += __expf(base[(size_t)m * KSEL] - mx);
    redB[row][lane] = sum;
    __syncthreads();
    if (row == 0) {
        float v = 0.f;
#pragma unroll
        for (int r = 0; r < 8; r++) v += redB[r][lane];
        redB[0][lane] = v;
    }
    __syncthreads();
    float inv = 1.f / redB[0][lane];

    for (int m = row; m < MTOK_B; m += 8) {
        float* p = &base[(size_t)m * KSEL];
        *p = __expf(*p - mx) * inv;
    }
}

// ---------------------------------------------------------------------------
// Multi-scale pooling
// ---------------------------------------------------------------------------
__global__ void pool_kernel(const float* __restrict__ sel, float* __restrict__ out)
{
    int idx = blockIdx.x * blockDim.x + threadIdx.x;
    int total = B_DIM * OUT_ROWS * E_DIM;
    if (idx >= total) return;
    int e = idx % E_DIM;
    int r = (idx / E_DIM) % OUT_ROWS;
    int b = idx / (OUT_ROWS * E_DIM);
    const float* sb = sel + (size_t)b * KSEL * E_DIM;
    float v;
    if (r < 256) {
        v = sb[(size_t)r * E_DIM + e];
    } else if (r < 384) {
        int i = (r - 256) * 2;
        v = 0.5f * (sb[(size_t)i * E_DIM + e] + sb[(size_t)(i + 1) * E_DIM + e]);
    } else {
        int i = (r - 384) * 4;
        v = 0.25f * (sb[(size_t)i * E_DIM + e] + sb[(size_t)(i + 1) * E_DIM + e] +
                     sb[(size_t)(i + 2) * E_DIM + e] + sb[(size_t)(i + 3) * E_DIM + e]);
    }
    out[idx] = v;
}

// ---------------------------------------------------------------------------
// Orchestration
// ---------------------------------------------------------------------------
extern "C" void kernel_launch(void* const* d_in, const int* in_sizes, int n_in,
                              void* d_out, int out_size)
{
    (void)in_sizes; (void)n_in; (void)out_size;

    const float* x    = (const float*)d_in[0];
    const float* wq   = (const float*)d_in[1];
    const float* bq   = (const float*)d_in[2];
    const float* wk   = (const float*)d_in[3];
    const float* bk   = (const float*)d_in[4];
    const float* wv   = (const float*)d_in[5];
    const float* bv   = (const float*)d_in[6];
    const float* wd   = (const float*)d_in[7];
    const float* bd   = (const float*)d_in[8];
    const float* rb   = (const float*)d_in[9];
    const float* selw = (const float*)d_in[10];
    const float* selb = (const float*)d_in[11];
    float* out = (float*)d_out;

    float *QKVb, *Hb, *SCb, *SELb, *Bqkv;
    cudaGetSymbolAddress((void**)&QKVb, g_QKV);
    cudaGetSymbolAddress((void**)&Hb,  g_Hb);
    cudaGetSymbolAddress((void**)&SCb, g_SC);
    cudaGetSymbolAddress((void**)&SELb, g_SEL);
    cudaGetSymbolAddress((void**)&Bqkv, g_Bqkv);

    __half *Ahp, *Alp, *Ah2p, *Al2p, *WqkvT, *WdT, *SWT;
    cudaGetSymbolAddress((void**)&Ahp, g_Ah);
    cudaGetSymbolAddress((void**)&Alp, g_Al);
    cudaGetSymbolAddress((void**)&Ah2p, g_Ah2);
    cudaGetSymbolAddress((void**)&Al2p, g_Al2);
    cudaGetSymbolAddress((void**)&WqkvT, g_WqkvT);
    cudaGetSymbolAddress((void**)&WdT, g_WdT);
    cudaGetSymbolAddress((void**)&SWT, g_SWT);

    const int smemSp = (32 * (256 + 1) * 2 + 256 * 32 * 2 + (2 * 256 - 1)) * (int)sizeof(float);
    const int smemTe = (32 * (32 + 1) * 2 + 32 * 32 * 2 + (2 * 32 - 1)) * (int)sizeof(float);
    cudaFuncSetAttribute((const void*)attn_kernel<256>,
                         cudaFuncAttributeMaxDynamicSharedMemorySize, smemSp);
    cudaFuncSetAttribute((const void*)gemm_f16x2,
                         cudaFuncAttributeMaxDynamicSharedMemorySize, GEMM_SMEM);

    const dim3 blk(256);
    const dim3 tblk(32, 8);
    const int n4 = MTOK * E_DIM / 4;
    const dim3 gcvt((n4 + 255) / 256);
    const dim3 gQKV(QKV_N / 128, MTOK / 128);   // 24 x 128
    const dim3 gWd(E_DIM / 128, MTOK / 128);    // 8 x 128
    const size_t MM = (size_t)E_DIM * E_DIM;
    const size_t MM3 = 3 * MM;

    // weight prep (GEMM lands at launch idx 5 for ncu)
    wt_cvt3<<<dim3(E_DIM / 32, E_DIM / 32, 4), tblk>>>(wq, WqkvT, E_DIM, E_DIM, 0);  // 0
    wt_cvt3<<<dim3(E_DIM / 32, E_DIM / 32, 4), tblk>>>(wk, WqkvT, E_DIM, E_DIM, 1);  // 1
    wt_cvt3<<<dim3(E_DIM / 32, E_DIM / 32, 4), tblk>>>(wv, WqkvT, E_DIM, E_DIM, 2);  // 2
    bias_concat<<<(4 * QKV_N + 255) / 256, blk>>>(bq, bk, bv, Bqkv);                  // 3
    cvt_hilo<<<gcvt, blk>>>(x, Ah2p, Al2p, n4);                                       // 4
    gemm_f16x2<<<gQKV, blk, GEMM_SMEM>>>(Ah2p, Al2p, WqkvT, Bqkv, QKVb,
                                         nullptr, nullptr, QKV_N, E_DIM);             // 5 <- ncu
    wt_cvt<<<dim3(E_DIM / 32, E_DIM / 32, 4), tblk>>>(wd, WdT, E_DIM, E_DIM);        // 6
    wt_cvt<<<dim3(KSEL / 32, E_DIM / 32, 1), tblk>>>(selw, SWT, E_DIM, KSEL);        // 7

    for (int a = 0; a < 4; a++) {
        if (a > 0) {
            gemm_f16x2<<<gQKV, blk, GEMM_SMEM>>>(Ah2p, Al2p, WqkvT + a * MM3,
                                                 Bqkv + a * QKV_N, QKVb,
                                                 nullptr, nullptr, QKV_N, E_DIM);
        }

        const float* rba = rb + (size_t)a * RB_ONE;
        const float* Qp = QKVb;
        const float* Kp = QKVb + E_DIM;
        const float* Vp = QKVb + 2 * E_DIM;
        if ((a & 1) == 0) {
            attn_kernel<256><<<dim3(H_DIM, B_DIM * T_DIM), blk, smemSp>>>(
                Qp, Kp, Vp, Ahp, Alp, rba, B_DIM * T_DIM, 0, N_DIM, 1, QKV_N);
        } else {
            attn_kernel<32><<<dim3(H_DIM, B_DIM * N_DIM), blk, smemTe>>>(
                Qp, Kp, Vp, Ahp, Alp, rba, N_DIM, T_DIM * N_DIM, 1, N_DIM, QKV_N);
        }

        // output projection: fp32 Hb + fused fp16 hi/lo (input of next layer / sc)
        gemm_f16x2<<<gWd, blk, GEMM_SMEM>>>(Ahp, Alp, WdT + a * MM, bd + a * E_DIM, Hb,
                                            Ah2p, Al2p, E_DIM, E_DIM);
    }

    // selection scores: [MTOK, KSEL]
    gemm_f16x2<<<dim3(KSEL / 128, MTOK / 128), blk, GEMM_SMEM>>>(
        Ah2p, Al2p, SWT, selb, SCb, nullptr, nullptr, KSEL, E_DIM);

    // softmax over token axis per (b, k), in place
    sel_softmax<<<dim3(B_DIM, KSEL / 32), blk>>>(SCb);

    // sel[b,k,e] = sum_m wts[b,m,k] * h[b,m,e]  (fp32 split-K + atomics)
    cudaMemsetAsync(SELb, 0, (size_t)B_DIM * KSEL * E_DIM * sizeof(float));
    gemm_sel_atomic<<<dim3(E_DIM / 128, KSEL / 128, B_DIM * SPLITK), blk>>>(SCb, Hb, SELb);

    // multi-scale pooling -> output [B, 448, E]
    int total = B_DIM * OUT_ROWS * E_DIM;
    pool_kernel<<<(total + 255) / 256, 256>>>(SELb, out);
}

// round 7
// speedup vs baseline: 1.2274x; 1.0694x over previous
#include <cuda_runtime.h>
#include <cuda_fp16.h>
#include <cstdint>
#include <cstddef>

// ---------------------------------------------------------------------------
// Problem constants
// ---------------------------------------------------------------------------
#define E_DIM   1024
#define QKV_N   3072
#define H_DIM   16
#define D_DIM   64
#define B_DIM   2
#define T_DIM   32
#define N_DIM   256
#define MTOK    (B_DIM * T_DIM * N_DIM)   // 16384 tokens total
#define MTOK_B  (T_DIM * N_DIM)           // 8192 tokens per batch
#define KSEL    256
#define MAXLEN  512
#define RB_ONE  ((2 * MAXLEN - 1) * H_DIM)
#define OUT_ROWS 448                      // 256 + 128 + 64
#define SPLITK  8

// ---------------------------------------------------------------------------
// Scratch (device globals — no allocations allowed)
// ---------------------------------------------------------------------------
__device__ float g_QKV[MTOK * QKV_N];     // merged Q|K|V per token (also prep dump)
__device__ float g_Hb[MTOK * E_DIM];
__device__ float g_SC[MTOK * KSEL];
__device__ float g_SEL[B_DIM * KSEL * E_DIM];

// fp16 split activations: ping (attention out) and pong (projection in)
__device__ __half g_Ah[MTOK * E_DIM];
__device__ __half g_Al[MTOK * E_DIM];
__device__ __half g_Ah2[MTOK * E_DIM];
__device__ __half g_Al2[MTOK * E_DIM];
// transposed fp16 weights
__device__ __half g_WqkvTh[4 * 3 * E_DIM * E_DIM];  // [a][q|k|v][N=E][K=E] hi
__device__ __half g_WqkvTl[4 * 3 * E_DIM * E_DIM];  // lo
__device__ __half g_Wd16[4 * E_DIM * E_DIM];        // wd plain (row-major) fp16
__device__ __half g_WdT3[E_DIM * E_DIM];            // wd[3] transposed fp16
__device__ __half g_SWT[KSEL * E_DIM];
__device__ __half g_WcT[3 * QKV_N * E_DIM];         // combined W'^T = (Wd_a Wqkv_{a+1})^T fp16
__device__ float  g_Bqkv[4 * QKV_N];                // merged qkv bias per attn idx
__device__ float  g_Bcomb[3 * QKV_N];               // combined bias bd_a@Wqkv_{a+1}+b_{a+1}
__device__ float  g_Bzero[E_DIM];                   // zero bias (static zero-init)

// ---------------------------------------------------------------------------
// PTX helpers (cp.async / ldmatrix / mma.sync — baseline sm_80+ PTX)
// ---------------------------------------------------------------------------
__device__ __forceinline__ void cp_async16(uint32_t dst, const void* src) {
    asm volatile("cp.async.cg.shared.global [%0], [%1], 16;" :: "r"(dst), "l"(src));
}
__device__ __forceinline__ void cp_commit() {
    asm volatile("cp.async.commit_group;" ::: "memory");
}
template <int N>
__device__ __forceinline__ void cp_wait_group() {
    asm volatile("cp.async.wait_group %0;" :: "n"(N) : "memory");
}
__device__ __forceinline__ void ldmatrix_x4(uint32_t* r, uint32_t addr) {
    asm volatile("ldmatrix.sync.aligned.m8n8.x4.shared.b16 {%0,%1,%2,%3}, [%4];"
                 : "=r"(r[0]), "=r"(r[1]), "=r"(r[2]), "=r"(r[3]) : "r"(addr));
}
__device__ __forceinline__ void mma_f16(float* d, const uint32_t* a,
                                        uint32_t b0, uint32_t b1) {
    asm volatile(
        "mma.sync.aligned.m16n8k16.row.col.f32.f16.f16.f32 "
        "{%0,%1,%2,%3}, {%4,%5,%6,%7}, {%8,%9}, {%0,%1,%2,%3};"
        : "+f"(d[0]), "+f"(d[1]), "+f"(d[2]), "+f"(d[3])
        : "r"(a[0]), "r"(a[1]), "r"(a[2]), "r"(a[3]), "r"(b0), "r"(b1));
}

// ---------------------------------------------------------------------------
// fp16x2 GEMM via mma.sync (z-batchable):
//   C[z][M, Nfull] = (Ah+Al)[z][M,K] @ B[z][Nfull,K]^T + bias
// Optional fused fp16 hi (Ch) and lo (Cl) outputs.
// CTA 128x128, k-chunk 32, 3-stage cp.async pipeline, 2 CTAs/SM.
// ---------------------------------------------------------------------------
#define GSTAGES 3
#define ROWPAD  40
#define TILE_BYTES (128 * ROWPAD * 2)
#define STAGE_BYTES (3 * TILE_BYTES)
#define GEMM_SMEM (GSTAGES * STAGE_BYTES)     // 92160

__global__ __launch_bounds__(256, 2)
void gemm_f16x2(const __half* __restrict__ Ah, const __half* __restrict__ Al,
                const __half* __restrict__ B,
                const float* __restrict__ bias, float* __restrict__ C,
                __half* __restrict__ Ch, __half* __restrict__ Cl,
                int Nfull, int Kfull,
                size_t zA, size_t zB, size_t zC)
{
    extern __shared__ char smem[];
    const uint32_t sb = (uint32_t)__cvta_generic_to_shared(smem);
    const int tid = threadIdx.x;
    const int lane = tid & 31;
    const int warp = tid >> 5;
    const int wm = warp >> 1;
    const int wn = warp & 1;
    const int m0 = blockIdx.y * 128;
    const int n0 = blockIdx.x * 128;

    Ah += (size_t)blockIdx.z * zA;
    Al += (size_t)blockIdx.z * zA;
    B  += (size_t)blockIdx.z * zB;
    C  += (size_t)blockIdx.z * zC;
    if (Ch) Ch += (size_t)blockIdx.z * zC;
    if (Cl) Cl += (size_t)blockIdx.z * zC;

    const int NCH = Kfull >> 5;

    const int lr0 = tid >> 1;
    const int ls0 = (tid & 1) << 1;

    float acc[2][8][4];
#pragma unroll
    for (int mi = 0; mi < 2; mi++)
#pragma unroll
        for (int ni = 0; ni < 8; ni++)
#pragma unroll
            for (int q = 0; q < 4; q++) acc[mi][ni][q] = 0.f;

    auto load_chunk = [&](int c, int stage) {
        const int kb = c << 5;
        const uint32_t base = sb + stage * STAGE_BYTES;
#pragma unroll
        for (int j = 0; j < 2; j++) {
            const int s4 = ls0 + j;
            const uint32_t soff = (uint32_t)(lr0 * ROWPAD + s4 * 8) * 2;
            const size_t goff = (size_t)lr0 * Kfull + kb + s4 * 8;
            cp_async16(base + soff,                  Ah + (size_t)m0 * Kfull + goff);
            cp_async16(base + TILE_BYTES + soff,     Al + (size_t)m0 * Kfull + goff);
            cp_async16(base + 2 * TILE_BYTES + soff, B  + (size_t)n0 * Kfull + goff);
        }
    };

#pragma unroll
    for (int s = 0; s < GSTAGES - 1; s++) {
        if (s < NCH) load_chunk(s, s);
        cp_commit();
    }

    const int la_i = lane & 7;
    const int la_g = lane >> 3;
    const int a_rowadd = la_i + ((la_g & 1) << 3);
    const int a_coladd = (la_g >> 1) << 3;
    const int b_rowadd = la_i + ((la_g >> 1) << 3);
    const int b_coladd = (la_g & 1) << 3;

    for (int c = 0; c < NCH; c++) {
        const int stage = c % GSTAGES;
        cp_wait_group<GSTAGES - 2>();
        __syncthreads();

        const int nc = c + GSTAGES - 1;
        if (nc < NCH) load_chunk(nc, nc % GSTAGES);
        cp_commit();

        const uint32_t base = sb + stage * STAGE_BYTES;
        const uint32_t Bbase = base + 2 * TILE_BYTES;

#pragma unroll
        for (int k16 = 0; k16 < 32; k16 += 16) {
            uint32_t bf[4][4];
#pragma unroll
            for (int nb = 0; nb < 4; nb++) {
                const int row = wn * 64 + nb * 16 + b_rowadd;
                const int col = k16 + b_coladd;
                ldmatrix_x4(bf[nb], Bbase + (uint32_t)(row * ROWPAD + col) * 2);
            }
#pragma unroll
            for (int seg = 0; seg < 2; seg++) {
                const uint32_t Abase = base + seg * TILE_BYTES;
                uint32_t af[2][4];
#pragma unroll
                for (int mi = 0; mi < 2; mi++) {
                    const int row = wm * 32 + mi * 16 + a_rowadd;
                    const int col = k16 + a_coladd;
                    ldmatrix_x4(af[mi], Abase + (uint32_t)(row * ROWPAD + col) * 2);
                }
#pragma unroll
                for (int nb = 0; nb < 4; nb++)
#pragma unroll
                    for (int mi = 0; mi < 2; mi++) {
                        mma_f16(acc[mi][nb * 2 + 0], af[mi], bf[nb][0], bf[nb][1]);
                        mma_f16(acc[mi][nb * 2 + 1], af[mi], bf[nb][2], bf[nb][3]);
                    }
            }
        }
    }

    // epilogue (+ optional fused fp16 hi / lo emit)
    const int tq = lane >> 2;
    const int tr = lane & 3;
#pragma unroll
    for (int mi = 0; mi < 2; mi++) {
        const int row = m0 + wm * 32 + mi * 16 + tq;
#pragma unroll
        for (int ni = 0; ni < 8; ni++) {
            const int col = n0 + wn * 64 + ni * 8 + tr * 2;
            const float b0 = bias[col], b1 = bias[col + 1];
            float c00 = acc[mi][ni][0] + b0, c01 = acc[mi][ni][1] + b1;
            float c10 = acc[mi][ni][2] + b0, c11 = acc[mi][ni][3] + b1;
            float2 v0; v0.x = c00; v0.y = c01;
            float2 v1; v1.x = c10; v1.y = c11;
            *(float2*)&C[(size_t)row * Nfull + col] = v0;
            *(float2*)&C[(size_t)(row + 8) * Nfull + col] = v1;
            if (Ch || Cl) {
                __half h00 = __float2half_rn(c00);
                __half h01 = __float2half_rn(c01);
                __half h10 = __float2half_rn(c10);
                __half h11 = __float2half_rn(c11);
                if (Ch) {
                    *(__half2*)&Ch[(size_t)row * Nfull + col]       = __halves2half2(h00, h01);
                    *(__half2*)&Ch[(size_t)(row + 8) * Nfull + col] = __halves2half2(h10, h11);
                }
                if (Cl) {
                    __half l00 = __float2half_rn(c00 - __half2float(h00));
                    __half l01 = __float2half_rn(c01 - __half2float(h01));
                    __half l10 = __float2half_rn(c10 - __half2float(h10));
                    __half l11 = __float2half_rn(c11 - __half2float(h11));
                    *(__half2*)&Cl[(size_t)row * Nfull + col]       = __halves2half2(l00, l01);
                    *(__half2*)&Cl[(size_t)(row + 8) * Nfull + col] = __halves2half2(l10, l11);
                }
            }
        }
    }
}

// ---------------------------------------------------------------------------
// fp32 -> fp16 hi/lo split (elementwise, float4 vectorized)
// ---------------------------------------------------------------------------
__global__ void cvt_hilo(const float* __restrict__ x, __half* __restrict__ hi,
                         __half* __restrict__ lo, int n4)
{
    int i = blockIdx.x * blockDim.x + threadIdx.x;
    if (i >= n4) return;
    float4 v = ((const float4*)x)[i];
    __half h0 = __float2half_rn(v.x);
    __half h1 = __float2half_rn(v.y);
    __half h2 = __float2half_rn(v.z);
    __half h3 = __float2half_rn(v.w);
    __half l0 = __float2half_rn(v.x - __half2float(h0));
    __half l1 = __float2half_rn(v.y - __half2float(h1));
    __half l2 = __float2half_rn(v.z - __half2float(h2));
    __half l3 = __float2half_rn(v.w - __half2float(h3));
    __half2* hp = (__half2*)hi;
    __half2* lp = (__half2*)lo;
    hp[2 * i + 0] = __half2(h0, h1);
    hp[2 * i + 1] = __half2(h2, h3);
    lp[2 * i + 0] = __half2(l0, l1);
    lp[2 * i + 1] = __half2(l2, l3);
}

// plain fp32 -> fp16 convert (no transpose), float4 vectorized
__global__ void cvt_f16(const float* __restrict__ x, __half* __restrict__ y, int n4)
{
    int i = blockIdx.x * blockDim.x + threadIdx.x;
    if (i >= n4) return;
    float4 v = ((const float4*)x)[i];
    __half2* yp = (__half2*)y;
    yp[2 * i + 0] = __floats2half2_rn(v.x, v.y);
    yp[2 * i + 1] = __floats2half2_rn(v.z, v.w);
}

// ---------------------------------------------------------------------------
// Weight transpose + fp16 hi/lo convert into merged QKV layout:
//   src W [z][Kd][Nd] fp32  ->  dst [z][3][Nd][Kd] fp16 hi/lo at slot `type`
// ---------------------------------------------------------------------------
__global__ void wt_cvt3(const float* __restrict__ W, __half* __restrict__ WTh,
                        __half* __restrict__ WTl, int Kd, int Nd, int type)
{
    __shared__ float t[32][33];
    const size_t srcoff = (size_t)blockIdx.z * Kd * Nd;
    const size_t dstoff = ((size_t)blockIdx.z * 3 + type) * Kd * Nd;
    const float* Wm = W + srcoff;
    __half* Hh = WTh + dstoff;
    __half* Hl = WTl + dstoff;

    int nx = blockIdx.x * 32 + threadIdx.x;
    int k0 = blockIdx.y * 32;
#pragma unroll
    for (int j = 0; j < 4; j++) {
        int kk = k0 + threadIdx.y + j * 8;
        t[threadIdx.y + j * 8][threadIdx.x] = Wm[(size_t)kk * Nd + nx];
    }
    __syncthreads();
    int kx = k0 + threadIdx.x;
#pragma unroll
    for (int j = 0; j < 4; j++) {
        int nn = blockIdx.x * 32 + threadIdx.y + j * 8;
        float v = t[threadIdx.x][threadIdx.y + j * 8];
        __half h = __float2half_rn(v);
        Hh[(size_t)nn * Kd + kx] = h;
        Hl[(size_t)nn * Kd + kx] = __float2half_rn(v - __half2float(h));
    }
}

// plain transpose+convert (wd[3], selw)
__global__ void wt_cvt(const float* __restrict__ W, __half* __restrict__ WT,
                       int Kd, int Nd)
{
    __shared__ float t[32][33];
    const size_t moff = (size_t)blockIdx.z * Kd * Nd;
    const float* Wm = W + moff;
    __half* Hh = WT + moff;

    int nx = blockIdx.x * 32 + threadIdx.x;
    int k0 = blockIdx.y * 32;
#pragma unroll
    for (int j = 0; j < 4; j++) {
        int kk = k0 + threadIdx.y + j * 8;
        t[threadIdx.y + j * 8][threadIdx.x] = Wm[(size_t)kk * Nd + nx];
    }
    __syncthreads();
    int kx = k0 + threadIdx.x;
#pragma unroll
    for (int j = 0; j < 4; j++) {
        int nn = blockIdx.x * 32 + threadIdx.y + j * 8;
        Hh[(size_t)nn * Kd + kx] = __float2half_rn(t[threadIdx.x][threadIdx.y + j * 8]);
    }
}

// merged QKV bias: out[a][0:1024)=bq[a], [1024:2048)=bk[a], [2048:3072)=bv[a]
__global__ void bias_concat(const float* __restrict__ bq, const float* __restrict__ bk,
                            const float* __restrict__ bv, float* __restrict__ out)
{
    int i = blockIdx.x * blockDim.x + threadIdx.x;
    if (i >= 4 * QKV_N) return;
    int a = i / QKV_N;
    int r = i % QKV_N;
    const float* src = (r < E_DIM) ? bq : (r < 2 * E_DIM) ? bk : bv;
    out[i] = src[a * E_DIM + (r & (E_DIM - 1))];
}

// combined bias for folded layers: b'[z][i] = bd[z] @ Wqkv_{z+1}[:,i] + bqkv[z+1][i]
__global__ void bias_comb(const float* __restrict__ wq, const float* __restrict__ wk,
                          const float* __restrict__ wv, const float* __restrict__ bd,
                          const float* __restrict__ bqkv, float* __restrict__ out)
{
    int i = blockIdx.x * blockDim.x + threadIdx.x;   // 0..3071
    int z = blockIdx.y;                              // 0..2 (target layer z+1)
    const float* W = (i < E_DIM) ? wq : (i < 2 * E_DIM) ? wk : wv;
    int col = i & (E_DIM - 1);
    const float* Wm = W + (size_t)(z + 1) * E_DIM * E_DIM;
    const float* bdz = bd + (size_t)z * E_DIM;
    float s = 0.f;
    for (int k = 0; k < E_DIM; k++)
        s += bdz[k] * Wm[(size_t)k * E_DIM + col];
    out[(size_t)z * QKV_N + i] = s + bqkv[(size_t)(z + 1) * QKV_N + i];
}

// ---------------------------------------------------------------------------
// Split-K pooled-selection GEMM (fp32, atomics)
// ---------------------------------------------------------------------------
__global__ __launch_bounds__(256, 2)
void gemm_sel_atomic(const float* __restrict__ Wts, const float* __restrict__ Flat,
                     float* __restrict__ Csel)
{
    __shared__ float As[16][128];
    __shared__ float Bs[16][128];

    const int tid = threadIdx.x;
    const int bx = blockIdx.x;
    const int by = blockIdx.y;
    const int b  = blockIdx.z / SPLITK;
    const int sl = blockIdx.z % SPLITK;

    const float* A = Wts  + (size_t)b * MTOK_B * KSEL;
    const float* B = Flat + (size_t)b * MTOK_B * E_DIM;
    float*       C = Csel + (size_t)b * KSEL * E_DIM;

    const int lr = (tid & 31) << 2;
    const int lk = tid >> 5;
    const int tx = tid & 15;
    const int ty = tid >> 4;

    const int kbeg = sl * (MTOK_B / SPLITK);
    const int kend = kbeg + (MTOK_B / SPLITK);

    float acc[8][8];
#pragma unroll
    for (int i = 0; i < 8; i++)
#pragma unroll
        for (int j = 0; j < 8; j++) acc[i][j] = 0.f;

    for (int k0 = kbeg; k0 < kend; k0 += 16) {
        *(float4*)&As[lk][lr]     = *(const float4*)&A[(size_t)(k0 + lk) * KSEL + by * 128 + lr];
        *(float4*)&As[lk + 8][lr] = *(const float4*)&A[(size_t)(k0 + lk + 8) * KSEL + by * 128 + lr];
        *(float4*)&Bs[lk][lr]     = *(const float4*)&B[(size_t)(k0 + lk) * E_DIM + bx * 128 + lr];
        *(float4*)&Bs[lk + 8][lr] = *(const float4*)&B[(size_t)(k0 + lk + 8) * E_DIM + bx * 128 + lr];
        __syncthreads();

#pragma unroll
        for (int kk = 0; kk < 16; kk++) {
            float ar[8], br[8];
            *(float4*)&ar[0] = *(const float4*)&As[kk][ty * 8];
            *(float4*)&ar[4] = *(const float4*)&As[kk][ty * 8 + 4];
            *(float4*)&br[0] = *(const float4*)&Bs[kk][tx * 8];
            *(float4*)&br[4] = *(const float4*)&Bs[kk][tx * 8 + 4];
#pragma unroll
            for (int i = 0; i < 8; i++)
#pragma unroll
                for (int j = 0; j < 8; j++)
                    acc[i][j] += ar[i] * br[j];
        }
        __syncthreads();
    }

#pragma unroll
    for (int i = 0; i < 8; i++) {
        float* cp = C + (size_t)(by * 128 + ty * 8 + i) * E_DIM + bx * 128 + tx * 8;
#pragma unroll
        for (int j = 0; j < 8; j++)
            atomicAdd(&cp[j], acc[i][j]);
    }
}

// ---------------------------------------------------------------------------
// Fused relative-bias multihead attention; reads merged QKV (row stride ldx),
// emits fp16 hi/lo output (row stride E_DIM) directly.
// ---------------------------------------------------------------------------
template <int S>
__global__ __launch_bounds__(256)
void attn_kernel(const float* __restrict__ Q, const float* __restrict__ K,
                 const float* __restrict__ V,
                 __half* __restrict__ OutH, __half* __restrict__ OutL,
                 const float* __restrict__ rb,
                 int div, int mulq, int mulr, int stepTok, int ldx)
{
    const int h = blockIdx.x;
    const int g = blockIdx.y;
    const int base_m = (g / div) * mulq + (g % div) * mulr;
    const size_t baseE = (size_t)base_m * ldx + h * D_DIM;
    const size_t stepE = (size_t)stepTok * ldx;

    extern __shared__ float sm[];
    float2* Kt2 = (float2*)sm;
    float2* Vs2 = Kt2 + 32 * (S + 1);
    float*  rbh = (float*)(Vs2 + S * 32);

    const int tid = threadIdx.x;

    for (int idx = tid; idx < S * 32; idx += 256) {
        int t = idx >> 5, d2 = idx & 31;
        size_t off = baseE + (size_t)t * stepE;
        Kt2[d2 * (S + 1) + t] = *(const float2*)&K[off + 2 * d2];
        Vs2[idx]              = *(const float2*)&V[off + 2 * d2];
    }
    for (int i = tid; i < 2 * S - 1; i += 256)
        rbh[i] = rb[(size_t)(MAXLEN - S + i) * H_DIM + h];
    __syncthreads();

    const int lane = tid & 31;
    const int warp = tid >> 5;
    const int NT = S / 32;

    for (int q = warp; q < S; q += 8) {
        size_t qoff = baseE + (size_t)q * stepE;
        float2 ql = *(const float2*)&Q[qoff + 2 * lane];

        float s[NT];
#pragma unroll
        for (int tb = 0; tb < NT; tb++) s[tb] = 0.f;

#pragma unroll 4
        for (int d2 = 0; d2 < 32; d2++) {
            float qx = __shfl_sync(0xffffffffu, ql.x, d2);
            float qy = __shfl_sync(0xffffffffu, ql.y, d2);
            const float2* kr = &Kt2[d2 * (S + 1) + lane];
#pragma unroll
            for (int tb = 0; tb < NT; tb++) {
                float2 kv = kr[tb * 32];
                s[tb] += qx * kv.x + qy * kv.y;
            }
        }

#pragma unroll
        for (int tb = 0; tb < NT; tb++) {
            int t = tb * 32 + lane;
            s[tb] = s[tb] * 0.125f + rbh[t - q + (S - 1)];
        }

        float mx = s[0];
#pragma unroll
        for (int tb = 1; tb < NT; tb++) mx = fmaxf(mx, s[tb]);
#pragma unroll
        for (int o = 16; o > 0; o >>= 1)
            mx = fmaxf(mx, __shfl_xor_sync(0xffffffffu, mx, o));
        float sum = 0.f;
#pragma unroll
        for (int tb = 0; tb < NT; tb++) { s[tb] = __expf(s[tb] - mx); sum += s[tb]; }
#pragma unroll
        for (int o = 16; o > 0; o >>= 1)
            sum += __shfl_xor_sync(0xffffffffu, sum, o);
        float inv = 1.f / sum;
#pragma unroll
        for (int tb = 0; tb < NT; tb++) s[tb] *= inv;

        float cx = 0.f, cy = 0.f;
#pragma unroll
        for (int tb = 0; tb < NT; tb++) {
            float wv = s[tb];
#pragma unroll 8
            for (int j = 0; j < 32; j++) {
                float wj = __shfl_sync(0xffffffffu, wv, j);
                float2 vv = Vs2[(tb * 32 + j) * 32 + lane];
                cx += wj * vv.x;
                cy += wj * vv.y;
            }
        }
        __half hx = __float2half_rn(cx);
        __half hy = __float2half_rn(cy);
        __half lx = __float2half_rn(cx - __half2float(hx));
        __half ly = __float2half_rn(cy - __half2float(hy));
        const size_t ooff = (size_t)(base_m + q * stepTok) * E_DIM + h * D_DIM + 2 * lane;
        *(__half2*)&OutH[ooff] = __halves2half2(hx, hy);
        *(__half2*)&OutL[ooff] = __halves2half2(lx, ly);
    }
}

// ---------------------------------------------------------------------------
// Selection softmax over token axis per (b, k), in place
// ---------------------------------------------------------------------------
__global__ __launch_bounds__(256)
void sel_softmax(float* __restrict__ sc)
{
    const int b = blockIdx.x;
    const int k0 = blockIdx.y * 32;
    const int lane = threadIdx.x & 31;
    const int row = threadIdx.x >> 5;

    float* base = sc + (size_t)b * MTOK_B * KSEL + k0 + lane;

    __shared__ float redA[8][32];
    __shared__ float redB[8][32];

    float mx = -1e30f;
    for (int m = row; m < MTOK_B; m += 8)
        mx = fmaxf(mx, base[(size_t)m * KSEL]);
    redA[row][lane] = mx;
    __syncthreads();
    if (row == 0) {
        float v = redA[0][lane];
#pragma unroll
        for (int r = 1; r < 8; r++) v = fmaxf(v, redA[r][lane]);
        redA[0][lane] = v;
    }
    __syncthreads();
    mx = redA[0][lane];

    float sum = 0.f;
    for (int m = row; m < MTOK_B; m += 8)
        sum += __expf(base[(size_t)m * KSEL] - mx);
    redB[row][lane] = sum;
    __syncthreads();
    if (row == 0) {
        float v = 0.f;
#pragma unroll
        for (int r = 0; r < 8; r++) v += redB[r][lane];
        redB[0][lane] = v;
    }
    __syncthreads();
    float inv = 1.f / redB[0][lane];

    for (int m = row; m < MTOK_B; m += 8) {
        float* p = &base[(size_t)m * KSEL];
        *p = __expf(*p - mx) * inv;
    }
}

// ---------------------------------------------------------------------------
// Multi-scale pooling
// ---------------------------------------------------------------------------
__global__ void pool_kernel(const float* __restrict__ sel, float* __restrict__ out)
{
    int idx = blockIdx.x * blockDim.x + threadIdx.x;
    int total = B_DIM * OUT_ROWS * E_DIM;
    if (idx >= total) return;
    int e = idx % E_DIM;
    int r = (idx / E_DIM) % OUT_ROWS;
    int b = idx / (OUT_ROWS * E_DIM);
    const float* sb = sel + (size_t)b * KSEL * E_DIM;
    float v;
    if (r < 256) {
        v = sb[(size_t)r * E_DIM + e];
    } else if (r < 384) {
        int i = (r - 256) * 2;
        v = 0.5f * (sb[(size_t)i * E_DIM + e] + sb[(size_t)(i + 1) * E_DIM + e]);
    } else {
        int i = (r - 384) * 4;
        v = 0.25f * (sb[(size_t)i * E_DIM + e] + sb[(size_t)(i + 1) * E_DIM + e] +
                     sb[(size_t)(i + 2) * E_DIM + e] + sb[(size_t)(i + 3) * E_DIM + e]);
    }
    out[idx] = v;
}

// ---------------------------------------------------------------------------
// Orchestration
// ---------------------------------------------------------------------------
extern "C" void kernel_launch(void* const* d_in, const int* in_sizes, int n_in,
                              void* d_out, int out_size)
{
    (void)in_sizes; (void)n_in; (void)out_size;

    const float* x    = (const float*)d_in[0];
    const float* wq   = (const float*)d_in[1];
    const float* bq   = (const float*)d_in[2];
    const float* wk   = (const float*)d_in[3];
    const float* bk   = (const float*)d_in[4];
    const float* wv   = (const float*)d_in[5];
    const float* bv   = (const float*)d_in[6];
    const float* wd   = (const float*)d_in[7];
    const float* bd   = (const float*)d_in[8];
    const float* rb   = (const float*)d_in[9];
    const float* selw = (const float*)d_in[10];
    const float* selb = (const float*)d_in[11];
    float* out = (float*)d_out;

    float *QKVb, *Hb, *SCb, *SELb, *Bqkv, *Bcomb, *Bzero;
    cudaGetSymbolAddress((void**)&QKVb, g_QKV);
    cudaGetSymbolAddress((void**)&Hb,  g_Hb);
    cudaGetSymbolAddress((void**)&SCb, g_SC);
    cudaGetSymbolAddress((void**)&SELb, g_SEL);
    cudaGetSymbolAddress((void**)&Bqkv, g_Bqkv);
    cudaGetSymbolAddress((void**)&Bcomb, g_Bcomb);
    cudaGetSymbolAddress((void**)&Bzero, g_Bzero);

    __half *Ahp, *Alp, *Ah2p, *Al2p, *WqkvTh, *WqkvTl, *Wd16, *WdT3, *SWT, *WcT;
    cudaGetSymbolAddress((void**)&Ahp, g_Ah);
    cudaGetSymbolAddress((void**)&Alp, g_Al);
    cudaGetSymbolAddress((void**)&Ah2p, g_Ah2);
    cudaGetSymbolAddress((void**)&Al2p, g_Al2);
    cudaGetSymbolAddress((void**)&WqkvTh, g_WqkvTh);
    cudaGetSymbolAddress((void**)&WqkvTl, g_WqkvTl);
    cudaGetSymbolAddress((void**)&Wd16, g_Wd16);
    cudaGetSymbolAddress((void**)&WdT3, g_WdT3);
    cudaGetSymbolAddress((void**)&SWT, g_SWT);
    cudaGetSymbolAddress((void**)&WcT, g_WcT);

    const int smemSp = (32 * (256 + 1) * 2 + 256 * 32 * 2 + (2 * 256 - 1)) * (int)sizeof(float);
    const int smemTe = (32 * (32 + 1) * 2 + 32 * 32 * 2 + (2 * 32 - 1)) * (int)sizeof(float);
    cudaFuncSetAttribute((const void*)attn_kernel<256>,
                         cudaFuncAttributeMaxDynamicSharedMemorySize, smemSp);
    cudaFuncSetAttribute((const void*)gemm_f16x2,
                         cudaFuncAttributeMaxDynamicSharedMemorySize, GEMM_SMEM);

    const dim3 blk(256);
    const dim3 tblk(32, 8);
    const int n4 = MTOK * E_DIM / 4;
    const dim3 gcvt((n4 + 255) / 256);
    const dim3 gQKV(QKV_N / 128, MTOK / 128);   // 24 x 128
    const dim3 gWd(E_DIM / 128, MTOK / 128);    // 8 x 128
    const size_t MM = (size_t)E_DIM * E_DIM;
    const size_t MM3 = 3 * MM;
    const size_t WCS = (size_t)QKV_N * E_DIM;   // per-z combined-weight stride

    // ---- weight prep ----
    wt_cvt3<<<dim3(E_DIM / 32, E_DIM / 32, 4), tblk>>>(wq, WqkvTh, WqkvTl, E_DIM, E_DIM, 0);
    wt_cvt3<<<dim3(E_DIM / 32, E_DIM / 32, 4), tblk>>>(wk, WqkvTh, WqkvTl, E_DIM, E_DIM, 1);
    wt_cvt3<<<dim3(E_DIM / 32, E_DIM / 32, 4), tblk>>>(wv, WqkvTh, WqkvTl, E_DIM, E_DIM, 2);
    bias_concat<<<(4 * QKV_N + 255) / 256, blk>>>(bq, bk, bv, Bqkv);
    cvt_f16<<<(int)((3 * MM / 4 + 255) / 256), blk>>>(wd, Wd16, (int)(3 * MM / 4));

    // combined weights W'^T[z] = (Wd_z @ Wqkv_{z+1})^T, z = 0..2  (batched GEMM)
    // A = Wqkv_{z+1}^T hi/lo [3072,1024], B = Wd_z [1024,1024], C fp32 dump -> QKVb,
    // Ch = WcT fp16 (the operand actually consumed downstream)
    gemm_f16x2<<<dim3(E_DIM / 128, QKV_N / 128, 3), blk, GEMM_SMEM>>>(
        WqkvTh + MM3, WqkvTl + MM3, Wd16, Bzero, QKVb,
        WcT, nullptr, E_DIM, E_DIM, MM3, MM, WCS);

    wt_cvt<<<dim3(E_DIM / 32, E_DIM / 32, 1), tblk>>>(wd + 3 * MM, WdT3, E_DIM, E_DIM);
    wt_cvt<<<dim3(KSEL / 32, E_DIM / 32, 1), tblk>>>(selw, SWT, E_DIM, KSEL);
    bias_comb<<<dim3(QKV_N / 256, 3), blk>>>(wq, wk, wv, bd, Bqkv, Bcomb);
    cvt_hilo<<<gcvt, blk>>>(x, Ah2p, Al2p, n4);

    // ---- layers ----
    for (int a = 0; a < 4; a++) {
        if (a == 0) {
            gemm_f16x2<<<gQKV, blk, GEMM_SMEM>>>(Ah2p, Al2p, WqkvTh, Bqkv, QKVb,
                                                 nullptr, nullptr, QKV_N, E_DIM, 0, 0, 0);
        } else {
            // folded: QKV_a = ctx_{a-1} @ W'_{a-1} + b'_{a-1}
            gemm_f16x2<<<gQKV, blk, GEMM_SMEM>>>(Ahp, Alp, WcT + (a - 1) * WCS,
                                                 Bcomb + (size_t)(a - 1) * QKV_N, QKVb,
                                                 nullptr, nullptr, QKV_N, E_DIM, 0, 0, 0);
        }

        const float* rba = rb + (size_t)a * RB_ONE;
        const float* Qp = QKVb;
        const float* Kp = QKVb + E_DIM;
        const float* Vp = QKVb + 2 * E_DIM;
        if ((a & 1) == 0) {
            attn_kernel<256><<<dim3(H_DIM, B_DIM * T_DIM), blk, smemSp>>>(
                Qp, Kp, Vp, Ahp, Alp, rba, B_DIM * T_DIM, 0, N_DIM, 1, QKV_N);
        } else {
            attn_kernel<32><<<dim3(H_DIM, B_DIM * N_DIM), blk, smemTe>>>(
                Qp, Kp, Vp, Ahp, Alp, rba, N_DIM, T_DIM * N_DIM, 1, N_DIM, QKV_N);
        }
    }

    // final output projection (layer 3 only): Hb fp32 + fused hi/lo for sel score
    gemm_f16x2<<<gWd, blk, GEMM_SMEM>>>(Ahp, Alp, WdT3, bd + 3 * E_DIM, Hb,
                                        Ah2p, Al2p, E_DIM, E_DIM, 0, 0, 0);

    // selection scores: [MTOK, KSEL]
    gemm_f16x2<<<dim3(KSEL / 128, MTOK / 128), blk, GEMM_SMEM>>>(
        Ah2p, Al2p, SWT, selb, SCb, nullptr, nullptr, KSEL, E_DIM, 0, 0, 0);

    // softmax over token axis per (b, k), in place
    sel_softmax<<<dim3(B_DIM, KSEL / 32), blk>>>(SCb);

    // sel[b,k,e] = sum_m wts[b,m,k] * h[b,m,e]  (fp32 split-K + atomics)
    cudaMemsetAsync(SELb, 0, (size_t)B_DIM * KSEL * E_DIM * sizeof(float));
    gemm_sel_atomic<<<dim3(E_DIM / 128, KSEL / 128, B_DIM * SPLITK), blk>>>(SCb, Hb, SELb);

    // multi-scale pooling -> output [B, 448, E]
    int total = B_DIM * OUT_ROWS * E_DIM;
    pool_kernel<<<(total + 255) / 256, 256>>>(SELb, out);
}

// round 8
// speedup vs baseline: 1.4405x; 1.1736x over previous
#include <cuda_runtime.h>
#include <cuda_fp16.h>
#include <cstdint>
#include <cstddef>

// ---------------------------------------------------------------------------
// Problem constants
// ---------------------------------------------------------------------------
#define E_DIM   1024
#define QKV_N   3072
#define H_DIM   16
#define D_DIM   64
#define B_DIM   2
#define T_DIM   32
#define N_DIM   256
#define MTOK    (B_DIM * T_DIM * N_DIM)   // 16384 tokens total
#define MTOK_B  (T_DIM * N_DIM)           // 8192 tokens per batch
#define KSEL    256
#define MAXLEN  512
#define RB_ONE  ((2 * MAXLEN - 1) * H_DIM)
#define OUT_ROWS 448                      // 256 + 128 + 64
#define SPLITK  8

// ---------------------------------------------------------------------------
// Scratch (device globals — no allocations allowed)
// ---------------------------------------------------------------------------
__device__ float g_QKV[MTOK * QKV_N];     // merged Q|K|V per token (also prep dump)
__device__ float g_Hb[MTOK * E_DIM];      // layer-3 ctx fp32 (for selection)
__device__ float g_SC[MTOK * KSEL];
__device__ float g_S1[B_DIM * KSEL * E_DIM];   // wts^T @ ctx
__device__ float g_SEL[B_DIM * KSEL * E_DIM];  // final selected tokens

// fp16 split activations: ping (attention out) and pong (projection in)
__device__ __half g_Ah[MTOK * E_DIM];
__device__ __half g_Al[MTOK * E_DIM];
__device__ __half g_Ah2[MTOK * E_DIM];
__device__ __half g_Al2[MTOK * E_DIM];
// transposed fp16 weights
__device__ __half g_WqkvTh[4 * 3 * E_DIM * E_DIM];  // [a][q|k|v][N=E][K=E] hi
__device__ __half g_WqkvTl[4 * 3 * E_DIM * E_DIM];  // lo
__device__ __half g_Wd16[4 * E_DIM * E_DIM];        // wd plain (row-major) fp16
__device__ __half g_WdT3[E_DIM * E_DIM];            // wd[3] transposed fp16
__device__ __half g_WcT[3 * QKV_N * E_DIM];         // combined W'^T = (Wd_a Wqkv_{a+1})^T fp16
__device__ __half g_SWTh[KSEL * E_DIM];             // selw^T hi
__device__ __half g_SWTl[KSEL * E_DIM];             // selw^T lo
__device__ __half g_Bsel[KSEL * E_DIM];             // (Wd3 @ selw)^T fp16
__device__ float  g_Bqkv[4 * QKV_N];                // merged qkv bias per attn idx
__device__ float  g_Bcomb[3 * QKV_N];               // combined bias bd_a@Wqkv_{a+1}+b_{a+1}
__device__ float  g_Bias2[KSEL];                    // bd3@selw + selb
__device__ float  g_Bzero[E_DIM];                   // zero bias (static zero-init)

// ---------------------------------------------------------------------------
// PTX helpers (cp.async / ldmatrix / mma.sync — baseline sm_80+ PTX)
// ---------------------------------------------------------------------------
__device__ __forceinline__ void cp_async16(uint32_t dst, const void* src) {
    asm volatile("cp.async.cg.shared.global [%0], [%1], 16;" :: "r"(dst), "l"(src));
}
__device__ __forceinline__ void cp_commit() {
    asm volatile("cp.async.commit_group;" ::: "memory");
}
template <int N>
__device__ __forceinline__ void cp_wait_group() {
    asm volatile("cp.async.wait_group %0;" :: "n"(N) : "memory");
}
__device__ __forceinline__ void ldmatrix_x4(uint32_t* r, uint32_t addr) {
    asm volatile("ldmatrix.sync.aligned.m8n8.x4.shared.b16 {%0,%1,%2,%3}, [%4];"
                 : "=r"(r[0]), "=r"(r[1]), "=r"(r[2]), "=r"(r[3]) : "r"(addr));
}
__device__ __forceinline__ void mma_f16(float* d, const uint32_t* a,
                                        uint32_t b0, uint32_t b1) {
    asm volatile(
        "mma.sync.aligned.m16n8k16.row.col.f32.f16.f16.f32 "
        "{%0,%1,%2,%3}, {%4,%5,%6,%7}, {%8,%9}, {%0,%1,%2,%3};"
        : "+f"(d[0]), "+f"(d[1]), "+f"(d[2]), "+f"(d[3])
        : "r"(a[0]), "r"(a[1]), "r"(a[2]), "r"(a[3]), "r"(b0), "r"(b1));
}

// ---------------------------------------------------------------------------
// fp16 GEMM via mma.sync, templated on A-segments (1 = Ah only, 2 = Ah+Al):
//   C[z][M, Nfull] = (Ah[+Al])[z][M,K] @ B[z][Nfull,K]^T + bias
// Optional fused fp16 hi (Ch) and lo (Cl) outputs. z-batchable.
// CTA 128x128, k-chunk 32, 3-stage cp.async pipeline, 2 CTAs/SM.
// ---------------------------------------------------------------------------
#define GSTAGES 3
#define ROWPAD  40
#define TILE_BYTES (128 * ROWPAD * 2)

template <int SEGS>
__global__ __launch_bounds__(256, 2)
void gemm_f16(const __half* __restrict__ Ah, const __half* __restrict__ Al,
              const __half* __restrict__ B,
              const float* __restrict__ bias, float* __restrict__ C,
              __half* __restrict__ Ch, __half* __restrict__ Cl,
              int Nfull, int Kfull,
              size_t zA, size_t zB, size_t zC)
{
    constexpr int STB = (SEGS + 1) * TILE_BYTES;   // tiles per stage: A segs + B

    extern __shared__ char smem[];
    const uint32_t sb = (uint32_t)__cvta_generic_to_shared(smem);
    const int tid = threadIdx.x;
    const int lane = tid & 31;
    const int warp = tid >> 5;
    const int wm = warp >> 1;
    const int wn = warp & 1;
    const int m0 = blockIdx.y * 128;
    const int n0 = blockIdx.x * 128;

    Ah += (size_t)blockIdx.z * zA;
    if (SEGS == 2) Al += (size_t)blockIdx.z * zA;
    B  += (size_t)blockIdx.z * zB;
    C  += (size_t)blockIdx.z * zC;
    if (Ch) Ch += (size_t)blockIdx.z * zC;
    if (Cl) Cl += (size_t)blockIdx.z * zC;

    const int NCH = Kfull >> 5;

    const int lr0 = tid >> 1;
    const int ls0 = (tid & 1) << 1;

    float acc[2][8][4];
#pragma unroll
    for (int mi = 0; mi < 2; mi++)
#pragma unroll
        for (int ni = 0; ni < 8; ni++)
#pragma unroll
            for (int q = 0; q < 4; q++) acc[mi][ni][q] = 0.f;

    auto load_chunk = [&](int c, int stage) {
        const int kb = c << 5;
        const uint32_t base = sb + stage * STB;
#pragma unroll
        for (int j = 0; j < 2; j++) {
            const int s4 = ls0 + j;
            const uint32_t soff = (uint32_t)(lr0 * ROWPAD + s4 * 8) * 2;
            const size_t goff = (size_t)lr0 * Kfull + kb + s4 * 8;
            cp_async16(base + soff, Ah + (size_t)m0 * Kfull + goff);
            if (SEGS == 2)
                cp_async16(base + TILE_BYTES + soff, Al + (size_t)m0 * Kfull + goff);
            cp_async16(base + SEGS * TILE_BYTES + soff, B + (size_t)n0 * Kfull + goff);
        }
    };

#pragma unroll
    for (int s = 0; s < GSTAGES - 1; s++) {
        if (s < NCH) load_chunk(s, s);
        cp_commit();
    }

    const int la_i = lane & 7;
    const int la_g = lane >> 3;
    const int a_rowadd = la_i + ((la_g & 1) << 3);
    const int a_coladd = (la_g >> 1) << 3;
    const int b_rowadd = la_i + ((la_g >> 1) << 3);
    const int b_coladd = (la_g & 1) << 3;

    for (int c = 0; c < NCH; c++) {
        const int stage = c % GSTAGES;
        cp_wait_group<GSTAGES - 2>();
        __syncthreads();

        const int nc = c + GSTAGES - 1;
        if (nc < NCH) load_chunk(nc, nc % GSTAGES);
        cp_commit();

        const uint32_t base = sb + stage * STB;
        const uint32_t Bbase = base + SEGS * TILE_BYTES;

#pragma unroll
        for (int k16 = 0; k16 < 32; k16 += 16) {
            uint32_t bf[4][4];
#pragma unroll
            for (int nb = 0; nb < 4; nb++) {
                const int row = wn * 64 + nb * 16 + b_rowadd;
                const int col = k16 + b_coladd;
                ldmatrix_x4(bf[nb], Bbase + (uint32_t)(row * ROWPAD + col) * 2);
            }
#pragma unroll
            for (int seg = 0; seg < SEGS; seg++) {
                const uint32_t Abase = base + seg * TILE_BYTES;
                uint32_t af[2][4];
#pragma unroll
                for (int mi = 0; mi < 2; mi++) {
                    const int row = wm * 32 + mi * 16 + a_rowadd;
                    const int col = k16 + a_coladd;
                    ldmatrix_x4(af[mi], Abase + (uint32_t)(row * ROWPAD + col) * 2);
                }
#pragma unroll
                for (int nb = 0; nb < 4; nb++)
#pragma unroll
                    for (int mi = 0; mi < 2; mi++) {
                        mma_f16(acc[mi][nb * 2 + 0], af[mi], bf[nb][0], bf[nb][1]);
                        mma_f16(acc[mi][nb * 2 + 1], af[mi], bf[nb][2], bf[nb][3]);
                    }
            }
        }
    }

    // epilogue (+ optional fused fp16 hi / lo emit)
    const int tq = lane >> 2;
    const int tr = lane & 3;
#pragma unroll
    for (int mi = 0; mi < 2; mi++) {
        const int row = m0 + wm * 32 + mi * 16 + tq;
#pragma unroll
        for (int ni = 0; ni < 8; ni++) {
            const int col = n0 + wn * 64 + ni * 8 + tr * 2;
            const float b0 = bias[col], b1 = bias[col + 1];
            float c00 = acc[mi][ni][0] + b0, c01 = acc[mi][ni][1] + b1;
            float c10 = acc[mi][ni][2] + b0, c11 = acc[mi][ni][3] + b1;
            float2 v0; v0.x = c00; v0.y = c01;
            float2 v1; v1.x = c10; v1.y = c11;
            *(float2*)&C[(size_t)row * Nfull + col] = v0;
            *(float2*)&C[(size_t)(row + 8) * Nfull + col] = v1;
            if (Ch || Cl) {
                __half h00 = __float2half_rn(c00);
                __half h01 = __float2half_rn(c01);
                __half h10 = __float2half_rn(c10);
                __half h11 = __float2half_rn(c11);
                if (Ch) {
                    *(__half2*)&Ch[(size_t)row * Nfull + col]       = __halves2half2(h00, h01);
                    *(__half2*)&Ch[(size_t)(row + 8) * Nfull + col] = __halves2half2(h10, h11);
                }
                if (Cl) {
                    __half l00 = __float2half_rn(c00 - __half2float(h00));
                    __half l01 = __float2half_rn(c01 - __half2float(h01));
                    __half l10 = __float2half_rn(c10 - __half2float(h10));
                    __half l11 = __float2half_rn(c11 - __half2float(h11));
                    *(__half2*)&Cl[(size_t)row * Nfull + col]       = __halves2half2(l00, l01);
                    *(__half2*)&Cl[(size_t)(row + 8) * Nfull + col] = __halves2half2(l10, l11);
                }
            }
        }
    }
}

// ---------------------------------------------------------------------------
// fp32 -> fp16 hi/lo split (elementwise, float4 vectorized)
// ---------------------------------------------------------------------------
__global__ void cvt_hilo(const float* __restrict__ x, __half* __restrict__ hi,
                         __half* __restrict__ lo, int n4)
{
    int i = blockIdx.x * blockDim.x + threadIdx.x;
    if (i >= n4) return;
    float4 v = ((const float4*)x)[i];
    __half h0 = __float2half_rn(v.x);
    __half h1 = __float2half_rn(v.y);
    __half h2 = __float2half_rn(v.z);
    __half h3 = __float2half_rn(v.w);
    __half l0 = __float2half_rn(v.x - __half2float(h0));
    __half l1 = __float2half_rn(v.y - __half2float(h1));
    __half l2 = __float2half_rn(v.z - __half2float(h2));
    __half l3 = __float2half_rn(v.w - __half2float(h3));
    __half2* hp = (__half2*)hi;
    __half2* lp = (__half2*)lo;
    hp[2 * i + 0] = __half2(h0, h1);
    hp[2 * i + 1] = __half2(h2, h3);
    lp[2 * i + 0] = __half2(l0, l1);
    lp[2 * i + 1] = __half2(l2, l3);
}

// plain fp32 -> fp16 convert (no transpose), float4 vectorized
__global__ void cvt_f16(const float* __restrict__ x, __half* __restrict__ y, int n4)
{
    int i = blockIdx.x * blockDim.x + threadIdx.x;
    if (i >= n4) return;
    float4 v = ((const float4*)x)[i];
    __half2* yp = (__half2*)y;
    yp[2 * i + 0] = __floats2half2_rn(v.x, v.y);
    yp[2 * i + 1] = __floats2half2_rn(v.z, v.w);
}

// ---------------------------------------------------------------------------
// Weight transpose + fp16 hi/lo convert (3-slot layout when slots=3):
//   src W [z][Kd][Nd] fp32  ->  dst [(z*slots+type)][Nd][Kd] fp16 hi/lo
// ---------------------------------------------------------------------------
__global__ void wt_cvt3(const float* __restrict__ W, __half* __restrict__ WTh,
                        __half* __restrict__ WTl, int Kd, int Nd, int type, int slots)
{
    __shared__ float t[32][33];
    const size_t srcoff = (size_t)blockIdx.z * Kd * Nd;
    const size_t dstoff = ((size_t)blockIdx.z * slots + type) * Kd * Nd;
    const float* Wm = W + srcoff;
    __half* Hh = WTh + dstoff;
    __half* Hl = WTl + dstoff;

    int nx = blockIdx.x * 32 + threadIdx.x;
    int k0 = blockIdx.y * 32;
#pragma unroll
    for (int j = 0; j < 4; j++) {
        int kk = k0 + threadIdx.y + j * 8;
        t[threadIdx.y + j * 8][threadIdx.x] = Wm[(size_t)kk * Nd + nx];
    }
    __syncthreads();
    int kx = k0 + threadIdx.x;
#pragma unroll
    for (int j = 0; j < 4; j++) {
        int nn = blockIdx.x * 32 + threadIdx.y + j * 8;
        float v = t[threadIdx.x][threadIdx.y + j * 8];
        __half h = __float2half_rn(v);
        Hh[(size_t)nn * Kd + kx] = h;
        Hl[(size_t)nn * Kd + kx] = __float2half_rn(v - __half2float(h));
    }
}

// plain transpose+convert (wd[3])
__global__ void wt_cvt(const float* __restrict__ W, __half* __restrict__ WT,
                       int Kd, int Nd)
{
    __shared__ float t[32][33];
    const size_t moff = (size_t)blockIdx.z * Kd * Nd;
    const float* Wm = W + moff;
    __half* Hh = WT + moff;

    int nx = blockIdx.x * 32 + threadIdx.x;
    int k0 = blockIdx.y * 32;
#pragma unroll
    for (int j = 0; j < 4; j++) {
        int kk = k0 + threadIdx.y + j * 8;
        t[threadIdx.y + j * 8][threadIdx.x] = Wm[(size_t)kk * Nd + nx];
    }
    __syncthreads();
    int kx = k0 + threadIdx.x;
#pragma unroll
    for (int j = 0; j < 4; j++) {
        int nn = blockIdx.x * 32 + threadIdx.y + j * 8;
        Hh[(size_t)nn * Kd + kx] = __float2half_rn(t[threadIdx.x][threadIdx.y + j * 8]);
    }
}

// merged QKV bias: out[a][0:1024)=bq[a], [1024:2048)=bk[a], [2048:3072)=bv[a]
__global__ void bias_concat(const float* __restrict__ bq, const float* __restrict__ bk,
                            const float* __restrict__ bv, float* __restrict__ out)
{
    int i = blockIdx.x * blockDim.x + threadIdx.x;
    if (i >= 4 * QKV_N) return;
    int a = i / QKV_N;
    int r = i % QKV_N;
    const float* src = (r < E_DIM) ? bq : (r < 2 * E_DIM) ? bk : bv;
    out[i] = src[a * E_DIM + (r & (E_DIM - 1))];
}

// combined bias for folded layers: b'[z][i] = bd[z] @ Wqkv_{z+1}[:,i] + bqkv[z+1][i]
__global__ void bias_comb(const float* __restrict__ wq, const float* __restrict__ wk,
                          const float* __restrict__ wv, const float* __restrict__ bd,
                          const float* __restrict__ bqkv, float* __restrict__ out)
{
    int i = blockIdx.x * blockDim.x + threadIdx.x;   // 0..3071
    int z = blockIdx.y;                              // 0..2 (target layer z+1)
    const float* W = (i < E_DIM) ? wq : (i < 2 * E_DIM) ? wk : wv;
    int col = i & (E_DIM - 1);
    const float* Wm = W + (size_t)(z + 1) * E_DIM * E_DIM;
    const float* bdz = bd + (size_t)z * E_DIM;
    float s = 0.f;
    for (int k = 0; k < E_DIM; k++)
        s += bdz[k] * Wm[(size_t)k * E_DIM + col];
    out[(size_t)z * QKV_N + i] = s + bqkv[(size_t)(z + 1) * QKV_N + i];
}

// selection score bias: out[k] = bd3 @ selw[:,k] + selb[k]
__global__ void bias_sel(const float* __restrict__ selw, const float* __restrict__ selb,
                         const float* __restrict__ bd3, float* __restrict__ out)
{
    int k = blockIdx.x * blockDim.x + threadIdx.x;
    if (k >= KSEL) return;
    float s = 0.f;
    for (int e = 0; e < E_DIM; e++)
        s += bd3[e] * selw[(size_t)e * KSEL + k];
    out[k] = s + selb[k];
}

// ---------------------------------------------------------------------------
// Split-K selection GEMM (fp32, atomics): S1[b,k,e] += sum_m wts[b,m,k]*ctx[b,m,e]
// ---------------------------------------------------------------------------
__global__ __launch_bounds__(256, 2)
void gemm_sel_atomic(const float* __restrict__ Wts, const float* __restrict__ Flat,
                     float* __restrict__ Csel)
{
    __shared__ float As[16][128];
    __shared__ float Bs[16][128];

    const int tid = threadIdx.x;
    const int bx = blockIdx.x;
    const int by = blockIdx.y;
    const int b  = blockIdx.z / SPLITK;
    const int sl = blockIdx.z % SPLITK;

    const float* A = Wts  + (size_t)b * MTOK_B * KSEL;
    const float* B = Flat + (size_t)b * MTOK_B * E_DIM;
    float*       C = Csel + (size_t)b * KSEL * E_DIM;

    const int lr = (tid & 31) << 2;
    const int lk = tid >> 5;
    const int tx = tid & 15;
    const int ty = tid >> 4;

    const int kbeg = sl * (MTOK_B / SPLITK);
    const int kend = kbeg + (MTOK_B / SPLITK);

    float acc[8][8];
#pragma unroll
    for (int i = 0; i < 8; i++)
#pragma unroll
        for (int j = 0; j < 8; j++) acc[i][j] = 0.f;

    for (int k0 = kbeg; k0 < kend; k0 += 16) {
        *(float4*)&As[lk][lr]     = *(const float4*)&A[(size_t)(k0 + lk) * KSEL + by * 128 + lr];
        *(float4*)&As[lk + 8][lr] = *(const float4*)&A[(size_t)(k0 + lk + 8) * KSEL + by * 128 + lr];
        *(float4*)&Bs[lk][lr]     = *(const float4*)&B[(size_t)(k0 + lk) * E_DIM + bx * 128 + lr];
        *(float4*)&Bs[lk + 8][lr] = *(const float4*)&B[(size_t)(k0 + lk + 8) * E_DIM + bx * 128 + lr];
        __syncthreads();

#pragma unroll
        for (int kk = 0; kk < 16; kk++) {
            float ar[8], br[8];
            *(float4*)&ar[0] = *(const float4*)&As[kk][ty * 8];
            *(float4*)&ar[4] = *(const float4*)&As[kk][ty * 8 + 4];
            *(float4*)&br[0] = *(const float4*)&Bs[kk][tx * 8];
            *(float4*)&br[4] = *(const float4*)&Bs[kk][tx * 8 + 4];
#pragma unroll
            for (int i = 0; i < 8; i++)
#pragma unroll
                for (int j = 0; j < 8; j++)
                    acc[i][j] += ar[i] * br[j];
        }
        __syncthreads();
    }

#pragma unroll
    for (int i = 0; i < 8; i++) {
        float* cp = C + (size_t)(by * 128 + ty * 8 + i) * E_DIM + bx * 128 + tx * 8;
#pragma unroll
        for (int j = 0; j < 8; j++)
            atomicAdd(&cp[j], acc[i][j]);
    }
}

// ---------------------------------------------------------------------------
// Fused relative-bias multihead attention; reads merged QKV (row stride ldx),
// emits fp16 hi/lo output (row stride E_DIM) + optional fp32 ctx.
// ---------------------------------------------------------------------------
template <int S>
__global__ __launch_bounds__(256)
void attn_kernel(const float* __restrict__ Q, const float* __restrict__ K,
                 const float* __restrict__ V,
                 __half* __restrict__ OutH, __half* __restrict__ OutL,
                 float* __restrict__ OutF,
                 const float* __restrict__ rb,
                 int div, int mulq, int mulr, int stepTok, int ldx)
{
    const int h = blockIdx.x;
    const int g = blockIdx.y;
    const int base_m = (g / div) * mulq + (g % div) * mulr;
    const size_t baseE = (size_t)base_m * ldx + h * D_DIM;
    const size_t stepE = (size_t)stepTok * ldx;

    extern __shared__ float sm[];
    float2* Kt2 = (float2*)sm;
    float2* Vs2 = Kt2 + 32 * (S + 1);
    float*  rbh = (float*)(Vs2 + S * 32);

    const int tid = threadIdx.x;

    for (int idx = tid; idx < S * 32; idx += 256) {
        int t = idx >> 5, d2 = idx & 31;
        size_t off = baseE + (size_t)t * stepE;
        Kt2[d2 * (S + 1) + t] = *(const float2*)&K[off + 2 * d2];
        Vs2[idx]              = *(const float2*)&V[off + 2 * d2];
    }
    for (int i = tid; i < 2 * S - 1; i += 256)
        rbh[i] = rb[(size_t)(MAXLEN - S + i) * H_DIM + h];
    __syncthreads();

    const int lane = tid & 31;
    const int warp = tid >> 5;
    const int NT = S / 32;

    for (int q = warp; q < S; q += 8) {
        size_t qoff = baseE + (size_t)q * stepE;
        float2 ql = *(const float2*)&Q[qoff + 2 * lane];

        float s[NT];
#pragma unroll
        for (int tb = 0; tb < NT; tb++) s[tb] = 0.f;

#pragma unroll 4
        for (int d2 = 0; d2 < 32; d2++) {
            float qx = __shfl_sync(0xffffffffu, ql.x, d2);
            float qy = __shfl_sync(0xffffffffu, ql.y, d2);
            const float2* kr = &Kt2[d2 * (S + 1) + lane];
#pragma unroll
            for (int tb = 0; tb < NT; tb++) {
                float2 kv = kr[tb * 32];
                s[tb] += qx * kv.x + qy * kv.y;
            }
        }

#pragma unroll
        for (int tb = 0; tb < NT; tb++) {
            int t = tb * 32 + lane;
            s[tb] = s[tb] * 0.125f + rbh[t - q + (S - 1)];
        }

        float mx = s[0];
#pragma unroll
        for (int tb = 1; tb < NT; tb++) mx = fmaxf(mx, s[tb]);
#pragma unroll
        for (int o = 16; o > 0; o >>= 1)
            mx = fmaxf(mx, __shfl_xor_sync(0xffffffffu, mx, o));
        float sum = 0.f;
#pragma unroll
        for (int tb = 0; tb < NT; tb++) { s[tb] = __expf(s[tb] - mx); sum += s[tb]; }
#pragma unroll
        for (int o = 16; o > 0; o >>= 1)
            sum += __shfl_xor_sync(0xffffffffu, sum, o);
        float inv = 1.f / sum;
#pragma unroll
        for (int tb = 0; tb < NT; tb++) s[tb] *= inv;

        float cx = 0.f, cy = 0.f;
#pragma unroll
        for (int tb = 0; tb < NT; tb++) {
            float wv = s[tb];
#pragma unroll 8
            for (int j = 0; j < 32; j++) {
                float wj = __shfl_sync(0xffffffffu, wv, j);
                float2 vv = Vs2[(tb * 32 + j) * 32 + lane];
                cx += wj * vv.x;
                cy += wj * vv.y;
            }
        }
        __half hx = __float2half_rn(cx);
        __half hy = __float2half_rn(cy);
        __half lx = __float2half_rn(cx - __half2float(hx));
        __half ly = __float2half_rn(cy - __half2float(hy));
        const size_t ooff = (size_t)(base_m + q * stepTok) * E_DIM + h * D_DIM + 2 * lane;
        *(__half2*)&OutH[ooff] = __halves2half2(hx, hy);
        *(__half2*)&OutL[ooff] = __halves2half2(lx, ly);
        if (OutF) {
            float2 cf; cf.x = cx; cf.y = cy;
            *(float2*)&OutF[ooff] = cf;
        }
    }
}

// ---------------------------------------------------------------------------
// Selection softmax over token axis per (b, k), in place
// ---------------------------------------------------------------------------
__global__ __launch_bounds__(256)
void sel_softmax(float* __restrict__ sc)
{
    const int b = blockIdx.x;
    const int k0 = blockIdx.y * 32;
    const int lane = threadIdx.x & 31;
    const int row = threadIdx.x >> 5;

    float* base = sc + (size_t)b * MTOK_B * KSEL + k0 + lane;

    __shared__ float redA[8][32];
    __shared__ float redB[8][32];

    float mx = -1e30f;
    for (int m = row; m < MTOK_B; m += 8)
        mx = fmaxf(mx, base[(size_t)m * KSEL]);
    redA[row][lane] = mx;
    __syncthreads();
    if (row == 0) {
        float v = redA[0][lane];
#pragma unroll
        for (int r = 1; r < 8; r++) v = fmaxf(v, redA[r][lane]);
        redA[0][lane] = v;
    }
    __syncthreads();
    mx = redA[0][lane];

    float sum = 0.f;
    for (int m = row; m < MTOK_B; m += 8)
        sum += __expf(base[(size_t)m * KSEL] - mx);
    redB[row][lane] = sum;
    __syncthreads();
    if (row == 0) {
        float v = 0.f;
#pragma unroll
        for (int r = 0; r < 8; r++) v += redB[r][lane];
        redB[0][lane] = v;
    }
    __syncthreads();
    float inv = 1.f / redB[0][lane];

    for (int m = row; m < MTOK_B; m += 8) {
        float* p = &base[(size_t)m * KSEL];
        *p = __expf(*p - mx) * inv;
    }
}

// ---------------------------------------------------------------------------
// Multi-scale pooling
// ---------------------------------------------------------------------------
__global__ void pool_kernel(const float* __restrict__ sel, float* __restrict__ out)
{
    int idx = blockIdx.x * blockDim.x + threadIdx.x;
    int total = B_DIM * OUT_ROWS * E_DIM;
    if (idx >= total) return;
    int e = idx % E_DIM;
    int r = (idx / E_DIM) % OUT_ROWS;
    int b = idx / (OUT_ROWS * E_DIM);
    const float* sb = sel + (size_t)b * KSEL * E_DIM;
    float v;
    if (r < 256) {
        v = sb[(size_t)r * E_DIM + e];
    } else if (r < 384) {
        int i = (r - 256) * 2;
        v = 0.5f * (sb[(size_t)i * E_DIM + e] + sb[(size_t)(i + 1) * E_DIM + e]);
    } else {
        int i = (r - 384) * 4;
        v = 0.25f * (sb[(size_t)i * E_DIM + e] + sb[(size_t)(i + 1) * E_DIM + e] +
                     sb[(size_t)(i + 2) * E_DIM + e] + sb[(size_t)(i + 3) * E_DIM + e]);
    }
    out[idx] = v;
}

// ---------------------------------------------------------------------------
// Orchestration
// ---------------------------------------------------------------------------
extern "C" void kernel_launch(void* const* d_in, const int* in_sizes, int n_in,
                              void* d_out, int out_size)
{
    (void)in_sizes; (void)n_in; (void)out_size;

    const float* x    = (const float*)d_in[0];
    const float* wq   = (const float*)d_in[1];
    const float* bq   = (const float*)d_in[2];
    const float* wk   = (const float*)d_in[3];
    const float* bk   = (const float*)d_in[4];
    const float* wv   = (const float*)d_in[5];
    const float* bv   = (const float*)d_in[6];
    const float* wd   = (const float*)d_in[7];
    const float* bd   = (const float*)d_in[8];
    const float* rb   = (const float*)d_in[9];
    const float* selw = (const float*)d_in[10];
    const float* selb = (const float*)d_in[11];
    float* out = (float*)d_out;

    float *QKVb, *Hb, *SCb, *S1b, *SELb, *Bqkv, *Bcomb, *Bias2, *Bzero;
    cudaGetSymbolAddress((void**)&QKVb, g_QKV);
    cudaGetSymbolAddress((void**)&Hb,  g_Hb);
    cudaGetSymbolAddress((void**)&SCb, g_SC);
    cudaGetSymbolAddress((void**)&S1b, g_S1);
    cudaGetSymbolAddress((void**)&SELb, g_SEL);
    cudaGetSymbolAddress((void**)&Bqkv, g_Bqkv);
    cudaGetSymbolAddress((void**)&Bcomb, g_Bcomb);
    cudaGetSymbolAddress((void**)&Bias2, g_Bias2);
    cudaGetSymbolAddress((void**)&Bzero, g_Bzero);

    __half *Ahp, *Alp, *Ah2p, *Al2p, *WqkvTh, *WqkvTl, *Wd16, *WdT3, *WcT;
    __half *SWTh, *SWTl, *Bsel;
    cudaGetSymbolAddress((void**)&Ahp, g_Ah);
    cudaGetSymbolAddress((void**)&Alp, g_Al);
    cudaGetSymbolAddress((void**)&Ah2p, g_Ah2);
    cudaGetSymbolAddress((void**)&Al2p, g_Al2);
    cudaGetSymbolAddress((void**)&WqkvTh, g_WqkvTh);
    cudaGetSymbolAddress((void**)&WqkvTl, g_WqkvTl);
    cudaGetSymbolAddress((void**)&Wd16, g_Wd16);
    cudaGetSymbolAddress((void**)&WdT3, g_WdT3);
    cudaGetSymbolAddress((void**)&WcT, g_WcT);
    cudaGetSymbolAddress((void**)&SWTh, g_SWTh);
    cudaGetSymbolAddress((void**)&SWTl, g_SWTl);
    cudaGetSymbolAddress((void**)&Bsel, g_Bsel);

    const int smemSp = (32 * (256 + 1) * 2 + 256 * 32 * 2 + (2 * 256 - 1)) * (int)sizeof(float);
    const int smemTe = (32 * (32 + 1) * 2 + 32 * 32 * 2 + (2 * 32 - 1)) * (int)sizeof(float);
    const int SMEM1 = GSTAGES * 2 * TILE_BYTES;   // 61440
    const int SMEM2 = GSTAGES * 3 * TILE_BYTES;   // 92160
    cudaFuncSetAttribute((const void*)attn_kernel<256>,
                         cudaFuncAttributeMaxDynamicSharedMemorySize, smemSp);
    cudaFuncSetAttribute((const void*)gemm_f16<1>,
                         cudaFuncAttributeMaxDynamicSharedMemorySize, SMEM1);
    cudaFuncSetAttribute((const void*)gemm_f16<2>,
                         cudaFuncAttributeMaxDynamicSharedMemorySize, SMEM2);

    const dim3 blk(256);
    const dim3 tblk(32, 8);
    const int n4 = MTOK * E_DIM / 4;
    const dim3 gcvt((n4 + 255) / 256);
    const dim3 gQKV(QKV_N / 128, MTOK / 128);   // 24 x 128
    const size_t MM = (size_t)E_DIM * E_DIM;
    const size_t MM3 = 3 * MM;
    const size_t WCS = (size_t)QKV_N * E_DIM;

    // ---- weight prep ----
    wt_cvt3<<<dim3(E_DIM / 32, E_DIM / 32, 4), tblk>>>(wq, WqkvTh, WqkvTl, E_DIM, E_DIM, 0, 3);
    wt_cvt3<<<dim3(E_DIM / 32, E_DIM / 32, 4), tblk>>>(wk, WqkvTh, WqkvTl, E_DIM, E_DIM, 1, 3);
    wt_cvt3<<<dim3(E_DIM / 32, E_DIM / 32, 4), tblk>>>(wv, WqkvTh, WqkvTl, E_DIM, E_DIM, 2, 3);
    bias_concat<<<(4 * QKV_N + 255) / 256, blk>>>(bq, bk, bv, Bqkv);
    cvt_f16<<<(int)((4 * MM / 4 + 255) / 256), blk>>>(wd, Wd16, (int)(4 * MM / 4));

    // combined weights W'^T[z] = (Wd_z @ Wqkv_{z+1})^T, z = 0..2 (batched, 2-seg)
    gemm_f16<2><<<dim3(E_DIM / 128, QKV_N / 128, 3), blk, SMEM2>>>(
        WqkvTh + MM3, WqkvTl + MM3, Wd16, Bzero, QKVb,
        WcT, nullptr, E_DIM, E_DIM, MM3, MM, WCS);

    wt_cvt<<<dim3(E_DIM / 32, E_DIM / 32, 1), tblk>>>(wd + 3 * MM, WdT3, E_DIM, E_DIM);
    // selw^T hi/lo  (selw [1024,256] -> [256,1024])
    wt_cvt3<<<dim3(KSEL / 32, E_DIM / 32, 1), tblk>>>(selw, SWTh, SWTl, E_DIM, KSEL, 0, 1);
    // Bsel = (Wd3 @ selw)^T  [256,1024] fp16 (2-seg prep GEMM; fp32 dump to QKVb)
    gemm_f16<2><<<dim3(E_DIM / 128, KSEL / 128), blk, SMEM2>>>(
        SWTh, SWTl, Wd16 + 3 * MM, Bzero, QKVb,
        Bsel, nullptr, E_DIM, E_DIM, 0, 0, 0);
    bias_comb<<<dim3(QKV_N / 256, 3), blk>>>(wq, wk, wv, bd, Bqkv, Bcomb);
    bias_sel<<<1, 256>>>(selw, selb, bd + 3 * E_DIM, Bias2);
    cvt_hilo<<<gcvt, blk>>>(x, Ah2p, Al2p, n4);

    // ---- layers (QKV projections single-segment) ----
    for (int a = 0; a < 4; a++) {
        if (a == 0) {
            gemm_f16<1><<<gQKV, blk, SMEM1>>>(Ah2p, nullptr, WqkvTh, Bqkv, QKVb,
                                              nullptr, nullptr, QKV_N, E_DIM, 0, 0, 0);
        } else {
            gemm_f16<1><<<gQKV, blk, SMEM1>>>(Ahp, nullptr, WcT + (a - 1) * WCS,
                                              Bcomb + (size_t)(a - 1) * QKV_N, QKVb,
                                              nullptr, nullptr, QKV_N, E_DIM, 0, 0, 0);
        }

        const float* rba = rb + (size_t)a * RB_ONE;
        const float* Qp = QKVb;
        const float* Kp = QKVb + E_DIM;
        const float* Vp = QKVb + 2 * E_DIM;
        float* ctxF = (a == 3) ? Hb : nullptr;
        if ((a & 1) == 0) {
            attn_kernel<256><<<dim3(H_DIM, B_DIM * T_DIM), blk, smemSp>>>(
                Qp, Kp, Vp, Ahp, Alp, ctxF, rba, B_DIM * T_DIM, 0, N_DIM, 1, QKV_N);
        } else {
            attn_kernel<32><<<dim3(H_DIM, B_DIM * N_DIM), blk, smemTe>>>(
                Qp, Kp, Vp, Ahp, Alp, ctxF, rba, N_DIM, T_DIM * N_DIM, 1, N_DIM, QKV_N);
        }
    }

    // selection scores on ctx: SC = ctx @ Bsel^T + Bias2   (2-seg, exact ctx)
    gemm_f16<2><<<dim3(KSEL / 128, MTOK / 128), blk, SMEM2>>>(
        Ahp, Alp, Bsel, Bias2, SCb, nullptr, nullptr, KSEL, E_DIM, 0, 0, 0);

    // softmax over token axis per (b, k), in place
    sel_softmax<<<dim3(B_DIM, KSEL / 32), blk>>>(SCb);

    // S1[b,k,e] = sum_m wts[b,m,k] * ctx[b,m,e]  (fp32 split-K + atomics)
    cudaMemsetAsync(S1b, 0, (size_t)B_DIM * KSEL * E_DIM * sizeof(float));
    gemm_sel_atomic<<<dim3(E_DIM / 128, KSEL / 128, B_DIM * SPLITK), blk>>>(SCb, Hb, S1b);

    // SEL = S1 @ Wd3 + bd3  (tiny 2-seg GEMM; sum_m wts = 1 so bias is exact)
    cvt_hilo<<<dim3((B_DIM * KSEL * E_DIM / 4 + 255) / 256), blk>>>(
        S1b, Ah2p, Al2p, B_DIM * KSEL * E_DIM / 4);
    gemm_f16<2><<<dim3(E_DIM / 128, (B_DIM * KSEL) / 128), blk, SMEM2>>>(
        Ah2p, Al2p, WdT3, bd + 3 * E_DIM, SELb, nullptr, nullptr, E_DIM, E_DIM, 0, 0, 0);

    // multi-scale pooling -> output [B, 448, E]
    int total = B_DIM * OUT_ROWS * E_DIM;
    pool_kernel<<<(total + 255) / 256, 256>>>(SELb, out);
}

// round 9
// speedup vs baseline: 1.6675x; 1.1576x over previous
#include <cuda_runtime.h>
#include <cuda_fp16.h>
#include <cstdint>
#include <cstddef>

// ---------------------------------------------------------------------------
// Problem constants
// ---------------------------------------------------------------------------
#define E_DIM   1024
#define QKV_N   3072
#define H_DIM   16
#define D_DIM   64
#define B_DIM   2
#define T_DIM   32
#define N_DIM   256
#define MTOK    (B_DIM * T_DIM * N_DIM)   // 16384 tokens total
#define MTOK_B  (T_DIM * N_DIM)           // 8192 tokens per batch
#define KSEL    256
#define MAXLEN  512
#define RB_ONE  ((2 * MAXLEN - 1) * H_DIM)
#define OUT_ROWS 448                      // 256 + 128 + 64
#define SPLITK  8

// ---------------------------------------------------------------------------
// Scratch (device globals — no allocations allowed)
// ---------------------------------------------------------------------------
__device__ float g_QKV[MTOK * QKV_N];     // merged Q|K|V per token (also prep dump)
__device__ float g_Hb[MTOK * E_DIM];      // layer-3 ctx fp32 (for selection)
__device__ float g_SC[MTOK * KSEL];
__device__ float g_S1[B_DIM * KSEL * E_DIM];   // wts^T @ ctx
__device__ float g_SEL[B_DIM * KSEL * E_DIM];  // final selected tokens

// fp16 split activations: ping (attention out) and pong (projection in)
__device__ __half g_Ah[MTOK * E_DIM];
__device__ __half g_Al[MTOK * E_DIM];
__device__ __half g_Ah2[MTOK * E_DIM];
__device__ __half g_Al2[MTOK * E_DIM];
// transposed fp16 weights
__device__ __half g_WqkvTh[4 * 3 * E_DIM * E_DIM];  // [a][q|k|v][N=E][K=E] hi
__device__ __half g_WqkvTl[4 * 3 * E_DIM * E_DIM];  // lo
__device__ __half g_Wd16[4 * E_DIM * E_DIM];        // wd plain (row-major) fp16
__device__ __half g_WdT3[E_DIM * E_DIM];            // wd[3] transposed fp16
__device__ __half g_WcT[3 * QKV_N * E_DIM];         // combined W'^T = (Wd_a Wqkv_{a+1})^T fp16
__device__ __half g_SWTh[KSEL * E_DIM];             // selw^T hi
__device__ __half g_SWTl[KSEL * E_DIM];             // selw^T lo
__device__ __half g_Bsel[KSEL * E_DIM];             // (Wd3 @ selw)^T fp16
__device__ float  g_Bqkv[4 * QKV_N];                // merged qkv bias per attn idx
__device__ float  g_Bcomb[3 * QKV_N];               // combined bias bd_a@Wqkv_{a+1}+b_{a+1}
__device__ float  g_Bias2[KSEL];                    // bd3@selw + selb
__device__ float  g_Bzero[E_DIM];                   // zero bias (static zero-init)

// ---------------------------------------------------------------------------
// PTX helpers (cp.async / ldmatrix / mma.sync — baseline sm_80+ PTX)
// ---------------------------------------------------------------------------
__device__ __forceinline__ void cp_async16(uint32_t dst, const void* src) {
    asm volatile("cp.async.cg.shared.global [%0], [%1], 16;" :: "r"(dst), "l"(src));
}
__device__ __forceinline__ void cp_commit() {
    asm volatile("cp.async.commit_group;" ::: "memory");
}
template <int N>
__device__ __forceinline__ void cp_wait_group() {
    asm volatile("cp.async.wait_group %0;" :: "n"(N) : "memory");
}
__device__ __forceinline__ void ldmatrix_x4(uint32_t* r, uint32_t addr) {
    asm volatile("ldmatrix.sync.aligned.m8n8.x4.shared.b16 {%0,%1,%2,%3}, [%4];"
                 : "=r"(r[0]), "=r"(r[1]), "=r"(r[2]), "=r"(r[3]) : "r"(addr));
}
__device__ __forceinline__ void mma_f16(float* d, const uint32_t* a,
                                        uint32_t b0, uint32_t b1) {
    asm volatile(
        "mma.sync.aligned.m16n8k16.row.col.f32.f16.f16.f32 "
        "{%0,%1,%2,%3}, {%4,%5,%6,%7}, {%8,%9}, {%0,%1,%2,%3};"
        : "+f"(d[0]), "+f"(d[1]), "+f"(d[2]), "+f"(d[3])
        : "r"(a[0]), "r"(a[1]), "r"(a[2]), "r"(a[3]), "r"(b0), "r"(b1));
}

// ---------------------------------------------------------------------------
// fp16 GEMM via mma.sync, templated on A-segments (1 = Ah only, 2 = Ah+Al):
//   C[z][M, Nfull] = (Ah[+Al])[z][M,K] @ B[z][Nfull,K]^T + bias
// Optional fused fp16 hi (Ch) and lo (Cl) outputs. z-batchable.
// CTA 128x128, k-chunk 32, 3-stage cp.async pipeline, 2 CTAs/SM.
// ---------------------------------------------------------------------------
#define GSTAGES 3
#define ROWPAD  40
#define TILE_BYTES (128 * ROWPAD * 2)

template <int SEGS>
__global__ __launch_bounds__(256, 2)
void gemm_f16(const __half* __restrict__ Ah, const __half* __restrict__ Al,
              const __half* __restrict__ B,
              const float* __restrict__ bias, float* __restrict__ C,
              __half* __restrict__ Ch, __half* __restrict__ Cl,
              int Nfull, int Kfull,
              size_t zA, size_t zB, size_t zC)
{
    constexpr int STB = (SEGS + 1) * TILE_BYTES;   // tiles per stage: A segs + B

    extern __shared__ char smem[];
    const uint32_t sb = (uint32_t)__cvta_generic_to_shared(smem);
    const int tid = threadIdx.x;
    const int lane = tid & 31;
    const int warp = tid >> 5;
    const int wm = warp >> 1;
    const int wn = warp & 1;
    const int m0 = blockIdx.y * 128;
    const int n0 = blockIdx.x * 128;

    Ah += (size_t)blockIdx.z * zA;
    if (SEGS == 2) Al += (size_t)blockIdx.z * zA;
    B  += (size_t)blockIdx.z * zB;
    C  += (size_t)blockIdx.z * zC;
    if (Ch) Ch += (size_t)blockIdx.z * zC;
    if (Cl) Cl += (size_t)blockIdx.z * zC;

    const int NCH = Kfull >> 5;

    const int lr0 = tid >> 1;
    const int ls0 = (tid & 1) << 1;

    float acc[2][8][4];
#pragma unroll
    for (int mi = 0; mi < 2; mi++)
#pragma unroll
        for (int ni = 0; ni < 8; ni++)
#pragma unroll
            for (int q = 0; q < 4; q++) acc[mi][ni][q] = 0.f;

    auto load_chunk = [&](int c, int stage) {
        const int kb = c << 5;
        const uint32_t base = sb + stage * STB;
#pragma unroll
        for (int j = 0; j < 2; j++) {
            const int s4 = ls0 + j;
            const uint32_t soff = (uint32_t)(lr0 * ROWPAD + s4 * 8) * 2;
            const size_t goff = (size_t)lr0 * Kfull + kb + s4 * 8;
            cp_async16(base + soff, Ah + (size_t)m0 * Kfull + goff);
            if (SEGS == 2)
                cp_async16(base + TILE_BYTES + soff, Al + (size_t)m0 * Kfull + goff);
            cp_async16(base + SEGS * TILE_BYTES + soff, B + (size_t)n0 * Kfull + goff);
        }
    };

#pragma unroll
    for (int s = 0; s < GSTAGES - 1; s++) {
        if (s < NCH) load_chunk(s, s);
        cp_commit();
    }

    const int la_i = lane & 7;
    const int la_g = lane >> 3;
    const int a_rowadd = la_i + ((la_g & 1) << 3);
    const int a_coladd = (la_g >> 1) << 3;
    const int b_rowadd = la_i + ((la_g >> 1) << 3);
    const int b_coladd = (la_g & 1) << 3;

    for (int c = 0; c < NCH; c++) {
        const int stage = c % GSTAGES;
        cp_wait_group<GSTAGES - 2>();
        __syncthreads();

        const int nc = c + GSTAGES - 1;
        if (nc < NCH) load_chunk(nc, nc % GSTAGES);
        cp_commit();

        const uint32_t base = sb + stage * STB;
        const uint32_t Bbase = base + SEGS * TILE_BYTES;

#pragma unroll
        for (int k16 = 0; k16 < 32; k16 += 16) {
            uint32_t bf[4][4];
#pragma unroll
            for (int nb = 0; nb < 4; nb++) {
                const int row = wn * 64 + nb * 16 + b_rowadd;
                const int col = k16 + b_coladd;
                ldmatrix_x4(bf[nb], Bbase + (uint32_t)(row * ROWPAD + col) * 2);
            }
#pragma unroll
            for (int seg = 0; seg < SEGS; seg++) {
                const uint32_t Abase = base + seg * TILE_BYTES;
                uint32_t af[2][4];
#pragma unroll
                for (int mi = 0; mi < 2; mi++) {
                    const int row = wm * 32 + mi * 16 + a_rowadd;
                    const int col = k16 + a_coladd;
                    ldmatrix_x4(af[mi], Abase + (uint32_t)(row * ROWPAD + col) * 2);
                }
#pragma unroll
                for (int nb = 0; nb < 4; nb++)
#pragma unroll
                    for (int mi = 0; mi < 2; mi++) {
                        mma_f16(acc[mi][nb * 2 + 0], af[mi], bf[nb][0], bf[nb][1]);
                        mma_f16(acc[mi][nb * 2 + 1], af[mi], bf[nb][2], bf[nb][3]);
                    }
            }
        }
    }

    // epilogue (+ optional fused fp16 hi / lo emit)
    const int tq = lane >> 2;
    const int tr = lane & 3;
#pragma unroll
    for (int mi = 0; mi < 2; mi++) {
        const int row = m0 + wm * 32 + mi * 16 + tq;
#pragma unroll
        for (int ni = 0; ni < 8; ni++) {
            const int col = n0 + wn * 64 + ni * 8 + tr * 2;
            const float b0 = bias[col], b1 = bias[col + 1];
            float c00 = acc[mi][ni][0] + b0, c01 = acc[mi][ni][1] + b1;
            float c10 = acc[mi][ni][2] + b0, c11 = acc[mi][ni][3] + b1;
            float2 v0; v0.x = c00; v0.y = c01;
            float2 v1; v1.x = c10; v1.y = c11;
            *(float2*)&C[(size_t)row * Nfull + col] = v0;
            *(float2*)&C[(size_t)(row + 8) * Nfull + col] = v1;
            if (Ch || Cl) {
                __half h00 = __float2half_rn(c00);
                __half h01 = __float2half_rn(c01);
                __half h10 = __float2half_rn(c10);
                __half h11 = __float2half_rn(c11);
                if (Ch) {
                    *(__half2*)&Ch[(size_t)row * Nfull + col]       = __halves2half2(h00, h01);
                    *(__half2*)&Ch[(size_t)(row + 8) * Nfull + col] = __halves2half2(h10, h11);
                }
                if (Cl) {
                    __half l00 = __float2half_rn(c00 - __half2float(h00));
                    __half l01 = __float2half_rn(c01 - __half2float(h01));
                    __half l10 = __float2half_rn(c10 - __half2float(h10));
                    __half l11 = __float2half_rn(c11 - __half2float(h11));
                    *(__half2*)&Cl[(size_t)row * Nfull + col]       = __halves2half2(l00, l01);
                    *(__half2*)&Cl[(size_t)(row + 8) * Nfull + col] = __halves2half2(l10, l11);
                }
            }
        }
    }
}

// ---------------------------------------------------------------------------
// fp32 -> fp16 hi/lo split (elementwise, float4 vectorized)
// ---------------------------------------------------------------------------
__global__ void cvt_hilo(const float* __restrict__ x, __half* __restrict__ hi,
                         __half* __restrict__ lo, int n4)
{
    int i = blockIdx.x * blockDim.x + threadIdx.x;
    if (i >= n4) return;
    float4 v = ((const float4*)x)[i];
    __half h0 = __float2half_rn(v.x);
    __half h1 = __float2half_rn(v.y);
    __half h2 = __float2half_rn(v.z);
    __half h3 = __float2half_rn(v.w);
    __half l0 = __float2half_rn(v.x - __half2float(h0));
    __half l1 = __float2half_rn(v.y - __half2float(h1));
    __half l2 = __float2half_rn(v.z - __half2float(h2));
    __half l3 = __float2half_rn(v.w - __half2float(h3));
    __half2* hp = (__half2*)hi;
    __half2* lp = (__half2*)lo;
    hp[2 * i + 0] = __half2(h0, h1);
    hp[2 * i + 1] = __half2(h2, h3);
    lp[2 * i + 0] = __half2(l0, l1);
    lp[2 * i + 1] = __half2(l2, l3);
}

// plain fp32 -> fp16 convert (no transpose), float4 vectorized
__global__ void cvt_f16(const float* __restrict__ x, __half* __restrict__ y, int n4)
{
    int i = blockIdx.x * blockDim.x + threadIdx.x;
    if (i >= n4) return;
    float4 v = ((const float4*)x)[i];
    __half2* yp = (__half2*)y;
    yp[2 * i + 0] = __floats2half2_rn(v.x, v.y);
    yp[2 * i + 1] = __floats2half2_rn(v.z, v.w);
}

// ---------------------------------------------------------------------------
// Weight transpose + fp16 hi/lo convert (slots-layout):
//   src W [z][Kd][Nd] fp32  ->  dst [(z*slots+type)][Nd][Kd] fp16 hi/lo
// ---------------------------------------------------------------------------
__global__ void wt_cvt3(const float* __restrict__ W, __half* __restrict__ WTh,
                        __half* __restrict__ WTl, int Kd, int Nd, int type, int slots)
{
    __shared__ float t[32][33];
    const size_t srcoff = (size_t)blockIdx.z * Kd * Nd;
    const size_t dstoff = ((size_t)blockIdx.z * slots + type) * Kd * Nd;
    const float* Wm = W + srcoff;
    __half* Hh = WTh + dstoff;
    __half* Hl = WTl + dstoff;

    int nx = blockIdx.x * 32 + threadIdx.x;
    int k0 = blockIdx.y * 32;
#pragma unroll
    for (int j = 0; j < 4; j++) {
        int kk = k0 + threadIdx.y + j * 8;
        t[threadIdx.y + j * 8][threadIdx.x] = Wm[(size_t)kk * Nd + nx];
    }
    __syncthreads();
    int kx = k0 + threadIdx.x;
#pragma unroll
    for (int j = 0; j < 4; j++) {
        int nn = blockIdx.x * 32 + threadIdx.y + j * 8;
        float v = t[threadIdx.x][threadIdx.y + j * 8];
        __half h = __float2half_rn(v);
        Hh[(size_t)nn * Kd + kx] = h;
        Hl[(size_t)nn * Kd + kx] = __float2half_rn(v - __half2float(h));
    }
}

// plain transpose+convert (wd[3])
__global__ void wt_cvt(const float* __restrict__ W, __half* __restrict__ WT,
                       int Kd, int Nd)
{
    __shared__ float t[32][33];
    const size_t moff = (size_t)blockIdx.z * Kd * Nd;
    const float* Wm = W + moff;
    __half* Hh = WT + moff;

    int nx = blockIdx.x * 32 + threadIdx.x;
    int k0 = blockIdx.y * 32;
#pragma unroll
    for (int j = 0; j < 4; j++) {
        int kk = k0 + threadIdx.y + j * 8;
        t[threadIdx.y + j * 8][threadIdx.x] = Wm[(size_t)kk * Nd + nx];
    }
    __syncthreads();
    int kx = k0 + threadIdx.x;
#pragma unroll
    for (int j = 0; j < 4; j++) {
        int nn = blockIdx.x * 32 + threadIdx.y + j * 8;
        Hh[(size_t)nn * Kd + kx] = __float2half_rn(t[threadIdx.x][threadIdx.y + j * 8]);
    }
}

// merged QKV bias: out[a][0:1024)=bq[a], [1024:2048)=bk[a], [2048:3072)=bv[a]
__global__ void bias_concat(const float* __restrict__ bq, const float* __restrict__ bk,
                            const float* __restrict__ bv, float* __restrict__ out)
{
    int i = blockIdx.x * blockDim.x + threadIdx.x;
    if (i >= 4 * QKV_N) return;
    int a = i / QKV_N;
    int r = i % QKV_N;
    const float* src = (r < E_DIM) ? bq : (r < 2 * E_DIM) ? bk : bv;
    out[i] = src[a * E_DIM + (r & (E_DIM - 1))];
}

// combined bias for folded layers: b'[z][i] = bd[z] @ Wqkv_{z+1}[:,i] + bqkv[z+1][i]
__global__ void bias_comb(const float* __restrict__ wq, const float* __restrict__ wk,
                          const float* __restrict__ wv, const float* __restrict__ bd,
                          const float* __restrict__ bqkv, float* __restrict__ out)
{
    int i = blockIdx.x * blockDim.x + threadIdx.x;   // 0..3071
    int z = blockIdx.y;                              // 0..2 (target layer z+1)
    const float* W = (i < E_DIM) ? wq : (i < 2 * E_DIM) ? wk : wv;
    int col = i & (E_DIM - 1);
    const float* Wm = W + (size_t)(z + 1) * E_DIM * E_DIM;
    const float* bdz = bd + (size_t)z * E_DIM;
    float s = 0.f;
    for (int k = 0; k < E_DIM; k++)
        s += bdz[k] * Wm[(size_t)k * E_DIM + col];
    out[(size_t)z * QKV_N + i] = s + bqkv[(size_t)(z + 1) * QKV_N + i];
}

// selection score bias: out[k] = bd3 @ selw[:,k] + selb[k]
__global__ void bias_sel(const float* __restrict__ selw, const float* __restrict__ selb,
                         const float* __restrict__ bd3, float* __restrict__ out)
{
    int k = blockIdx.x * blockDim.x + threadIdx.x;
    if (k >= KSEL) return;
    float s = 0.f;
    for (int e = 0; e < E_DIM; e++)
        s += bd3[e] * selw[(size_t)e * KSEL + k];
    out[k] = s + selb[k];
}

// ---------------------------------------------------------------------------
// Split-K selection GEMM (fp32, atomics): S1[b,k,e] += sum_m wts[b,m,k]*ctx[b,m,e]
// ---------------------------------------------------------------------------
__global__ __launch_bounds__(256, 2)
void gemm_sel_atomic(const float* __restrict__ Wts, const float* __restrict__ Flat,
                     float* __restrict__ Csel)
{
    __shared__ float As[16][128];
    __shared__ float Bs[16][128];

    const int tid = threadIdx.x;
    const int bx = blockIdx.x;
    const int by = blockIdx.y;
    const int b  = blockIdx.z / SPLITK;
    const int sl = blockIdx.z % SPLITK;

    const float* A = Wts  + (size_t)b * MTOK_B * KSEL;
    const float* B = Flat + (size_t)b * MTOK_B * E_DIM;
    float*       C = Csel + (size_t)b * KSEL * E_DIM;

    const int lr = (tid & 31) << 2;
    const int lk = tid >> 5;
    const int tx = tid & 15;
    const int ty = tid >> 4;

    const int kbeg = sl * (MTOK_B / SPLITK);
    const int kend = kbeg + (MTOK_B / SPLITK);

    float acc[8][8];
#pragma unroll
    for (int i = 0; i < 8; i++)
#pragma unroll
        for (int j = 0; j < 8; j++) acc[i][j] = 0.f;

    for (int k0 = kbeg; k0 < kend; k0 += 16) {
        *(float4*)&As[lk][lr]     = *(const float4*)&A[(size_t)(k0 + lk) * KSEL + by * 128 + lr];
        *(float4*)&As[lk + 8][lr] = *(const float4*)&A[(size_t)(k0 + lk + 8) * KSEL + by * 128 + lr];
        *(float4*)&Bs[lk][lr]     = *(const float4*)&B[(size_t)(k0 + lk) * E_DIM + bx * 128 + lr];
        *(float4*)&Bs[lk + 8][lr] = *(const float4*)&B[(size_t)(k0 + lk + 8) * E_DIM + bx * 128 + lr];
        __syncthreads();

#pragma unroll
        for (int kk = 0; kk < 16; kk++) {
            float ar[8], br[8];
            *(float4*)&ar[0] = *(const float4*)&As[kk][ty * 8];
            *(float4*)&ar[4] = *(const float4*)&As[kk][ty * 8 + 4];
            *(float4*)&br[0] = *(const float4*)&Bs[kk][tx * 8];
            *(float4*)&br[4] = *(const float4*)&Bs[kk][tx * 8 + 4];
#pragma unroll
            for (int i = 0; i < 8; i++)
#pragma unroll
                for (int j = 0; j < 8; j++)
                    acc[i][j] += ar[i] * br[j];
        }
        __syncthreads();
    }

#pragma unroll
    for (int i = 0; i < 8; i++) {
        float* cp = C + (size_t)(by * 128 + ty * 8 + i) * E_DIM + bx * 128 + tx * 8;
#pragma unroll
        for (int j = 0; j < 8; j++)
            atomicAdd(&cp[j], acc[i][j]);
    }
}

// ---------------------------------------------------------------------------
// Fused relative-bias multihead attention; reads merged QKV (row stride ldx),
// emits fp16 hi/lo output (row stride E_DIM) + optional fp32 ctx.
// V stored in smem as fp16 (halves smem -> 2 CTAs/SM for S=256).
// ---------------------------------------------------------------------------
template <int S>
__global__ __launch_bounds__(256)
void attn_kernel(const float* __restrict__ Q, const float* __restrict__ K,
                 const float* __restrict__ V,
                 __half* __restrict__ OutH, __half* __restrict__ OutL,
                 float* __restrict__ OutF,
                 const float* __restrict__ rb,
                 int div, int mulq, int mulr, int stepTok, int ldx)
{
    const int h = blockIdx.x;
    const int g = blockIdx.y;
    const int base_m = (g / div) * mulq + (g % div) * mulr;
    const size_t baseE = (size_t)base_m * ldx + h * D_DIM;
    const size_t stepE = (size_t)stepTok * ldx;

    extern __shared__ float sm[];
    float2*  Kt2 = (float2*)sm;                       // [32][S+1] fp32 d-pair transposed
    __half2* Vsh = (__half2*)(Kt2 + 32 * (S + 1));    // [S][32] fp16 d-pairs
    float*   rbh = (float*)(Vsh + S * 32);            // [2S-1]

    const int tid = threadIdx.x;

    for (int idx = tid; idx < S * 32; idx += 256) {
        int t = idx >> 5, d2 = idx & 31;
        size_t off = baseE + (size_t)t * stepE;
        Kt2[d2 * (S + 1) + t] = *(const float2*)&K[off + 2 * d2];
        float2 vv = *(const float2*)&V[off + 2 * d2];
        Vsh[idx] = __floats2half2_rn(vv.x, vv.y);
    }
    for (int i = tid; i < 2 * S - 1; i += 256)
        rbh[i] = rb[(size_t)(MAXLEN - S + i) * H_DIM + h];
    __syncthreads();

    const int lane = tid & 31;
    const int warp = tid >> 5;
    const int NT = S / 32;

    for (int q = warp; q < S; q += 8) {
        size_t qoff = baseE + (size_t)q * stepE;
        float2 ql = *(const float2*)&Q[qoff + 2 * lane];

        float s[NT];
#pragma unroll
        for (int tb = 0; tb < NT; tb++) s[tb] = 0.f;

#pragma unroll 4
        for (int d2 = 0; d2 < 32; d2++) {
            float qx = __shfl_sync(0xffffffffu, ql.x, d2);
            float qy = __shfl_sync(0xffffffffu, ql.y, d2);
            const float2* kr = &Kt2[d2 * (S + 1) + lane];
#pragma unroll
            for (int tb = 0; tb < NT; tb++) {
                float2 kv = kr[tb * 32];
                s[tb] += qx * kv.x + qy * kv.y;
            }
        }

#pragma unroll
        for (int tb = 0; tb < NT; tb++) {
            int t = tb * 32 + lane;
            s[tb] = s[tb] * 0.125f + rbh[t - q + (S - 1)];
        }

        float mx = s[0];
#pragma unroll
        for (int tb = 1; tb < NT; tb++) mx = fmaxf(mx, s[tb]);
#pragma unroll
        for (int o = 16; o > 0; o >>= 1)
            mx = fmaxf(mx, __shfl_xor_sync(0xffffffffu, mx, o));
        float sum = 0.f;
#pragma unroll
        for (int tb = 0; tb < NT; tb++) { s[tb] = __expf(s[tb] - mx); sum += s[tb]; }
#pragma unroll
        for (int o = 16; o > 0; o >>= 1)
            sum += __shfl_xor_sync(0xffffffffu, sum, o);
        float inv = 1.f / sum;
#pragma unroll
        for (int tb = 0; tb < NT; tb++) s[tb] *= inv;

        float cx = 0.f, cy = 0.f;
#pragma unroll
        for (int tb = 0; tb < NT; tb++) {
            float wv = s[tb];
#pragma unroll 8
            for (int j = 0; j < 32; j++) {
                float wj = __shfl_sync(0xffffffffu, wv, j);
                float2 vf = __half22float2(Vsh[(tb * 32 + j) * 32 + lane]);
                cx += wj * vf.x;
                cy += wj * vf.y;
            }
        }
        __half hx = __float2half_rn(cx);
        __half hy = __float2half_rn(cy);
        __half lx = __float2half_rn(cx - __half2float(hx));
        __half ly = __float2half_rn(cy - __half2float(hy));
        const size_t ooff = (size_t)(base_m + q * stepTok) * E_DIM + h * D_DIM + 2 * lane;
        *(__half2*)&OutH[ooff] = __halves2half2(hx, hy);
        *(__half2*)&OutL[ooff] = __halves2half2(lx, ly);
        if (OutF) {
            float2 cf; cf.x = cx; cf.y = cy;
            *(float2*)&OutF[ooff] = cf;
        }
    }
}

// ---------------------------------------------------------------------------
// Selection softmax over token axis per (b, k), in place
// ---------------------------------------------------------------------------
__global__ __launch_bounds__(256)
void sel_softmax(float* __restrict__ sc)
{
    const int b = blockIdx.x;
    const int k0 = blockIdx.y * 32;
    const int lane = threadIdx.x & 31;
    const int row = threadIdx.x >> 5;

    float* base = sc + (size_t)b * MTOK_B * KSEL + k0 + lane;

    __shared__ float redA[8][32];
    __shared__ float redB[8][32];

    float mx = -1e30f;
    for (int m = row; m < MTOK_B; m += 8)
        mx = fmaxf(mx, base[(size_t)m * KSEL]);
    redA[row][lane] = mx;
    __syncthreads();
    if (row == 0) {
        float v = redA[0][lane];
#pragma unroll
        for (int r = 1; r < 8; r++) v = fmaxf(v, redA[r][lane]);
        redA[0][lane] = v;
    }
    __syncthreads();
    mx = redA[0][lane];

    float sum = 0.f;
    for (int m = row; m < MTOK_B; m += 8)
        sum += __expf(base[(size_t)m * KSEL] - mx);
    redB[row][lane] = sum;
    __syncthreads();
    if (row == 0) {
        float v = 0.f;
#pragma unroll
        for (int r = 0; r < 8; r++) v += redB[r][lane];
        redB[0][lane] = v;
    }
    __syncthreads();
    float inv = 1.f / redB[0][lane];

    for (int m = row; m < MTOK_B; m += 8) {
        float* p = &base[(size_t)m * KSEL];
        *p = __expf(*p - mx) * inv;
    }
}

// ---------------------------------------------------------------------------
// Multi-scale pooling
// ---------------------------------------------------------------------------
__global__ void pool_kernel(const float* __restrict__ sel, float* __restrict__ out)
{
    int idx = blockIdx.x * blockDim.x + threadIdx.x;
    int total = B_DIM * OUT_ROWS * E_DIM;
    if (idx >= total) return;
    int e = idx % E_DIM;
    int r = (idx / E_DIM) % OUT_ROWS;
    int b = idx / (OUT_ROWS * E_DIM);
    const float* sb = sel + (size_t)b * KSEL * E_DIM;
    float v;
    if (r < 256) {
        v = sb[(size_t)r * E_DIM + e];
    } else if (r < 384) {
        int i = (r - 256) * 2;
        v = 0.5f * (sb[(size_t)i * E_DIM + e] + sb[(size_t)(i + 1) * E_DIM + e]);
    } else {
        int i = (r - 384) * 4;
        v = 0.25f * (sb[(size_t)i * E_DIM + e] + sb[(size_t)(i + 1) * E_DIM + e] +
                     sb[(size_t)(i + 2) * E_DIM + e] + sb[(size_t)(i + 3) * E_DIM + e]);
    }
    out[idx] = v;
}

// ---------------------------------------------------------------------------
// Orchestration
// ---------------------------------------------------------------------------
extern "C" void kernel_launch(void* const* d_in, const int* in_sizes, int n_in,
                              void* d_out, int out_size)
{
    (void)in_sizes; (void)n_in; (void)out_size;

    const float* x    = (const float*)d_in[0];
    const float* wq   = (const float*)d_in[1];
    const float* bq   = (const float*)d_in[2];
    const float* wk   = (const float*)d_in[3];
    const float* bk   = (const float*)d_in[4];
    const float* wv   = (const float*)d_in[5];
    const float* bv   = (const float*)d_in[6];
    const float* wd   = (const float*)d_in[7];
    const float* bd   = (const float*)d_in[8];
    const float* rb   = (const float*)d_in[9];
    const float* selw = (const float*)d_in[10];
    const float* selb = (const float*)d_in[11];
    float* out = (float*)d_out;

    float *QKVb, *Hb, *SCb, *S1b, *SELb, *Bqkv, *Bcomb, *Bias2, *Bzero;
    cudaGetSymbolAddress((void**)&QKVb, g_QKV);
    cudaGetSymbolAddress((void**)&Hb,  g_Hb);
    cudaGetSymbolAddress((void**)&SCb, g_SC);
    cudaGetSymbolAddress((void**)&S1b, g_S1);
    cudaGetSymbolAddress((void**)&SELb, g_SEL);
    cudaGetSymbolAddress((void**)&Bqkv, g_Bqkv);
    cudaGetSymbolAddress((void**)&Bcomb, g_Bcomb);
    cudaGetSymbolAddress((void**)&Bias2, g_Bias2);
    cudaGetSymbolAddress((void**)&Bzero, g_Bzero);

    __half *Ahp, *Alp, *Ah2p, *Al2p, *WqkvTh, *WqkvTl, *Wd16, *WdT3, *WcT;
    __half *SWTh, *SWTl, *Bsel;
    cudaGetSymbolAddress((void**)&Ahp, g_Ah);
    cudaGetSymbolAddress((void**)&Alp, g_Al);
    cudaGetSymbolAddress((void**)&Ah2p, g_Ah2);
    cudaGetSymbolAddress((void**)&Al2p, g_Al2);
    cudaGetSymbolAddress((void**)&WqkvTh, g_WqkvTh);
    cudaGetSymbolAddress((void**)&WqkvTl, g_WqkvTl);
    cudaGetSymbolAddress((void**)&Wd16, g_Wd16);
    cudaGetSymbolAddress((void**)&WdT3, g_WdT3);
    cudaGetSymbolAddress((void**)&WcT, g_WcT);
    cudaGetSymbolAddress((void**)&SWTh, g_SWTh);
    cudaGetSymbolAddress((void**)&SWTl, g_SWTl);
    cudaGetSymbolAddress((void**)&Bsel, g_Bsel);

    // attention smem: K fp32 d-pair transposed + V fp16 + rel bias
    const int smemSp = 32 * (256 + 1) * 8 + 256 * 32 * 4 + (2 * 256 - 1) * 4;  // 100604
    const int smemTe = 32 * (32 + 1) * 8 + 32 * 32 * 4 + (2 * 32 - 1) * 4;     // 12796
    const int SMEM1 = GSTAGES * 2 * TILE_BYTES;   // 61440
    const int SMEM2 = GSTAGES * 3 * TILE_BYTES;   // 92160
    cudaFuncSetAttribute((const void*)attn_kernel<256>,
                         cudaFuncAttributeMaxDynamicSharedMemorySize, smemSp);
    cudaFuncSetAttribute((const void*)gemm_f16<1>,
                         cudaFuncAttributeMaxDynamicSharedMemorySize, SMEM1);
    cudaFuncSetAttribute((const void*)gemm_f16<2>,
                         cudaFuncAttributeMaxDynamicSharedMemorySize, SMEM2);

    const dim3 blk(256);
    const dim3 tblk(32, 8);
    const int n4 = MTOK * E_DIM / 4;
    const dim3 gcvt((n4 + 255) / 256);
    const dim3 gQKV(QKV_N / 128, MTOK / 128);   // 24 x 128
    const size_t MM = (size_t)E_DIM * E_DIM;
    const size_t MM3 = 3 * MM;
    const size_t WCS = (size_t)QKV_N * E_DIM;

    // ---- weight prep ----
    wt_cvt3<<<dim3(E_DIM / 32, E_DIM / 32, 4), tblk>>>(wq, WqkvTh, WqkvTl, E_DIM, E_DIM, 0, 3);
    wt_cvt3<<<dim3(E_DIM / 32, E_DIM / 32, 4), tblk>>>(wk, WqkvTh, WqkvTl, E_DIM, E_DIM, 1, 3);
    wt_cvt3<<<dim3(E_DIM / 32, E_DIM / 32, 4), tblk>>>(wv, WqkvTh, WqkvTl, E_DIM, E_DIM, 2, 3);
    bias_concat<<<(4 * QKV_N + 255) / 256, blk>>>(bq, bk, bv, Bqkv);
    cvt_f16<<<(int)((4 * MM / 4 + 255) / 256), blk>>>(wd, Wd16, (int)(4 * MM / 4));

    // combined weights W'^T[z] = (Wd_z @ Wqkv_{z+1})^T, z = 0..2 (batched, 2-seg)
    gemm_f16<2><<<dim3(E_DIM / 128, QKV_N / 128, 3), blk, SMEM2>>>(
        WqkvTh + MM3, WqkvTl + MM3, Wd16, Bzero, QKVb,
        WcT, nullptr, E_DIM, E_DIM, MM3, MM, WCS);

    wt_cvt<<<dim3(E_DIM / 32, E_DIM / 32, 1), tblk>>>(wd + 3 * MM, WdT3, E_DIM, E_DIM);
    wt_cvt3<<<dim3(KSEL / 32, E_DIM / 32, 1), tblk>>>(selw, SWTh, SWTl, E_DIM, KSEL, 0, 1);
    gemm_f16<2><<<dim3(E_DIM / 128, KSEL / 128), blk, SMEM2>>>(
        SWTh, SWTl, Wd16 + 3 * MM, Bzero, QKVb,
        Bsel, nullptr, E_DIM, E_DIM, 0, 0, 0);
    bias_comb<<<dim3(QKV_N / 256, 3), blk>>>(wq, wk, wv, bd, Bqkv, Bcomb);
    bias_sel<<<1, 256>>>(selw, selb, bd + 3 * E_DIM, Bias2);
    cvt_hilo<<<gcvt, blk>>>(x, Ah2p, Al2p, n4);

    // ---- layers (QKV projections single-segment) ----
    for (int a = 0; a < 4; a++) {
        if (a == 0) {
            gemm_f16<1><<<gQKV, blk, SMEM1>>>(Ah2p, nullptr, WqkvTh, Bqkv, QKVb,
                                              nullptr, nullptr, QKV_N, E_DIM, 0, 0, 0);
        } else {
            gemm_f16<1><<<gQKV, blk, SMEM1>>>(Ahp, nullptr, WcT + (a - 1) * WCS,
                                              Bcomb + (size_t)(a - 1) * QKV_N, QKVb,
                                              nullptr, nullptr, QKV_N, E_DIM, 0, 0, 0);
        }

        const float* rba = rb + (size_t)a * RB_ONE;
        const float* Qp = QKVb;
        const float* Kp = QKVb + E_DIM;
        const float* Vp = QKVb + 2 * E_DIM;
        float* ctxF = (a == 3) ? Hb : nullptr;
        if ((a & 1) == 0) {
            attn_kernel<256><<<dim3(H_DIM, B_DIM * T_DIM), blk, smemSp>>>(
                Qp, Kp, Vp, Ahp, Alp, ctxF, rba, B_DIM * T_DIM, 0, N_DIM, 1, QKV_N);
        } else {
            attn_kernel<32><<<dim3(H_DIM, B_DIM * N_DIM), blk, smemTe>>>(
                Qp, Kp, Vp, Ahp, Alp, ctxF, rba, N_DIM, T_DIM * N_DIM, 1, N_DIM, QKV_N);
        }
    }

    // selection scores on ctx: SC = ctx @ Bsel^T + Bias2   (2-seg, exact ctx)
    gemm_f16<2><<<dim3(KSEL / 128, MTOK / 128), blk, SMEM2>>>(
        Ahp, Alp, Bsel, Bias2, SCb, nullptr, nullptr, KSEL, E_DIM, 0, 0, 0);

    // softmax over token axis per (b, k), in place
    sel_softmax<<<dim3(B_DIM, KSEL / 32), blk>>>(SCb);

    // S1[b,k,e] = sum_m wts[b,m,k] * ctx[b,m,e]  (fp32 split-K + atomics)
    cudaMemsetAsync(S1b, 0, (size_t)B_DIM * KSEL * E_DIM * sizeof(float));
    gemm_sel_atomic<<<dim3(E_DIM / 128, KSEL / 128, B_DIM * SPLITK), blk>>>(SCb, Hb, S1b);

    // SEL = S1 @ Wd3 + bd3  (tiny 2-seg GEMM; sum_m wts = 1 so bias is exact)
    cvt_hilo<<<dim3((B_DIM * KSEL * E_DIM / 4 + 255) / 256), blk>>>(
        S1b, Ah2p, Al2p, B_DIM * KSEL * E_DIM / 4);
    gemm_f16<2><<<dim3(E_DIM / 128, (B_DIM * KSEL) / 128), blk, SMEM2>>>(
        Ah2p, Al2p, WdT3, bd + 3 * E_DIM, SELb, nullptr, nullptr, E_DIM, E_DIM, 0, 0, 0);

    // multi-scale pooling -> output [B, 448, E]
    int total = B_DIM * OUT_ROWS * E_DIM;
    pool_kernel<<<(total + 255) / 256, 256>>>(SELb, out);
}

// round 10
// speedup vs baseline: 1.7078x; 1.0242x over previous
#include <cuda_runtime.h>
#include <cuda_fp16.h>
#include <cstdint>
#include <cstddef>

// ---------------------------------------------------------------------------
// Problem constants
// ---------------------------------------------------------------------------
#define E_DIM   1024
#define QKV_N   3072
#define H_DIM   16
#define D_DIM   64
#define B_DIM   2
#define T_DIM   32
#define N_DIM   256
#define MTOK    (B_DIM * T_DIM * N_DIM)   // 16384 tokens total
#define MTOK_B  (T_DIM * N_DIM)           // 8192 tokens per batch
#define KSEL    256
#define MAXLEN  512
#define RB_ONE  ((2 * MAXLEN - 1) * H_DIM)
#define OUT_ROWS 448                      // 256 + 128 + 64
#define SPLITK  8

// ---------------------------------------------------------------------------
// Scratch (device globals — no allocations allowed)
// ---------------------------------------------------------------------------
__device__ __half g_QKVh[MTOK * QKV_N];   // merged Q|K|V per token, fp16
__device__ float g_Hb[MTOK * E_DIM];      // layer-3 ctx fp32 (for selection)
__device__ float g_SC[MTOK * KSEL];
__device__ float g_S1[B_DIM * KSEL * E_DIM];   // wts^T @ ctx
__device__ float g_SEL[B_DIM * KSEL * E_DIM];  // final selected tokens

// fp16 split activations: ping (attention out) and pong (misc)
__device__ __half g_Ah[MTOK * E_DIM];
__device__ __half g_Al[MTOK * E_DIM];
__device__ __half g_Ah2[MTOK * E_DIM];
__device__ __half g_Al2[MTOK * E_DIM];
// transposed fp16 weights
__device__ __half g_WqkvTh[4 * 3 * E_DIM * E_DIM];  // [a][q|k|v][N=E][K=E] hi
__device__ __half g_WqkvTl[4 * 3 * E_DIM * E_DIM];  // lo
__device__ __half g_Wd16[4 * E_DIM * E_DIM];        // wd plain (row-major) fp16
__device__ __half g_WdT3[E_DIM * E_DIM];            // wd[3] transposed fp16
__device__ __half g_WcT[3 * QKV_N * E_DIM];         // combined W'^T = (Wd_a Wqkv_{a+1})^T fp16
__device__ __half g_SWTh[KSEL * E_DIM];             // selw^T hi
__device__ __half g_SWTl[KSEL * E_DIM];             // selw^T lo
__device__ __half g_Bsel[KSEL * E_DIM];             // (Wd3 @ selw)^T fp16
__device__ float  g_Bqkv[4 * QKV_N];                // merged qkv bias per attn idx
__device__ float  g_Bcomb[3 * QKV_N];               // combined bias bd_a@Wqkv_{a+1}+b_{a+1}
__device__ float  g_Bias2[KSEL];                    // bd3@selw + selb
__device__ float  g_Bzero[E_DIM];                   // zero bias (static zero-init)

// ---------------------------------------------------------------------------
// PTX helpers (cp.async / ldmatrix / mma.sync — baseline sm_80+ PTX)
// ---------------------------------------------------------------------------
__device__ __forceinline__ void cp_async16(uint32_t dst, const void* src) {
    asm volatile("cp.async.cg.shared.global [%0], [%1], 16;" :: "r"(dst), "l"(src));
}
__device__ __forceinline__ void cp_commit() {
    asm volatile("cp.async.commit_group;" ::: "memory");
}
template <int N>
__device__ __forceinline__ void cp_wait_group() {
    asm volatile("cp.async.wait_group %0;" :: "n"(N) : "memory");
}
__device__ __forceinline__ void ldmatrix_x4(uint32_t* r, uint32_t addr) {
    asm volatile("ldmatrix.sync.aligned.m8n8.x4.shared.b16 {%0,%1,%2,%3}, [%4];"
                 : "=r"(r[0]), "=r"(r[1]), "=r"(r[2]), "=r"(r[3]) : "r"(addr));
}
__device__ __forceinline__ void mma_f16(float* d, const uint32_t* a,
                                        uint32_t b0, uint32_t b1) {
    asm volatile(
        "mma.sync.aligned.m16n8k16.row.col.f32.f16.f16.f32 "
        "{%0,%1,%2,%3}, {%4,%5,%6,%7}, {%8,%9}, {%0,%1,%2,%3};"
        : "+f"(d[0]), "+f"(d[1]), "+f"(d[2]), "+f"(d[3])
        : "r"(a[0]), "r"(a[1]), "r"(a[2]), "r"(a[3]), "r"(b0), "r"(b1));
}

// ---------------------------------------------------------------------------
// fp16 GEMM via mma.sync, templated on A-segments (1 = Ah only, 2 = Ah+Al):
//   C[z][M, Nfull] = (Ah[+Al])[z][M,K] @ B[z][Nfull,K]^T + bias
// All of C (fp32), Ch (fp16 hi), Cl (fp16 lo) outputs optional. z-batchable.
// CTA 128x128, k-chunk 32, 3-stage cp.async pipeline, 2 CTAs/SM.
// ---------------------------------------------------------------------------
#define GSTAGES 3
#define ROWPAD  40
#define TILE_BYTES (128 * ROWPAD * 2)

template <int SEGS>
__global__ __launch_bounds__(256, 2)
void gemm_f16(const __half* __restrict__ Ah, const __half* __restrict__ Al,
              const __half* __restrict__ B,
              const float* __restrict__ bias, float* __restrict__ C,
              __half* __restrict__ Ch, __half* __restrict__ Cl,
              int Nfull, int Kfull,
              size_t zA, size_t zB, size_t zC)
{
    constexpr int STB = (SEGS + 1) * TILE_BYTES;   // tiles per stage: A segs + B

    extern __shared__ char smem[];
    const uint32_t sb = (uint32_t)__cvta_generic_to_shared(smem);
    const int tid = threadIdx.x;
    const int lane = tid & 31;
    const int warp = tid >> 5;
    const int wm = warp >> 1;
    const int wn = warp & 1;
    const int m0 = blockIdx.y * 128;
    const int n0 = blockIdx.x * 128;

    Ah += (size_t)blockIdx.z * zA;
    if (SEGS == 2) Al += (size_t)blockIdx.z * zA;
    B  += (size_t)blockIdx.z * zB;
    if (C)  C  += (size_t)blockIdx.z * zC;
    if (Ch) Ch += (size_t)blockIdx.z * zC;
    if (Cl) Cl += (size_t)blockIdx.z * zC;

    const int NCH = Kfull >> 5;

    const int lr0 = tid >> 1;
    const int ls0 = (tid & 1) << 1;

    float acc[2][8][4];
#pragma unroll
    for (int mi = 0; mi < 2; mi++)
#pragma unroll
        for (int ni = 0; ni < 8; ni++)
#pragma unroll
            for (int q = 0; q < 4; q++) acc[mi][ni][q] = 0.f;

    auto load_chunk = [&](int c, int stage) {
        const int kb = c << 5;
        const uint32_t base = sb + stage * STB;
#pragma unroll
        for (int j = 0; j < 2; j++) {
            const int s4 = ls0 + j;
            const uint32_t soff = (uint32_t)(lr0 * ROWPAD + s4 * 8) * 2;
            const size_t goff = (size_t)lr0 * Kfull + kb + s4 * 8;
            cp_async16(base + soff, Ah + (size_t)m0 * Kfull + goff);
            if (SEGS == 2)
                cp_async16(base + TILE_BYTES + soff, Al + (size_t)m0 * Kfull + goff);
            cp_async16(base + SEGS * TILE_BYTES + soff, B + (size_t)n0 * Kfull + goff);
        }
    };

#pragma unroll
    for (int s = 0; s < GSTAGES - 1; s++) {
        if (s < NCH) load_chunk(s, s);
        cp_commit();
    }

    const int la_i = lane & 7;
    const int la_g = lane >> 3;
    const int a_rowadd = la_i + ((la_g & 1) << 3);
    const int a_coladd = (la_g >> 1) << 3;
    const int b_rowadd = la_i + ((la_g >> 1) << 3);
    const int b_coladd = (la_g & 1) << 3;

    for (int c = 0; c < NCH; c++) {
        const int stage = c % GSTAGES;
        cp_wait_group<GSTAGES - 2>();
        __syncthreads();

        const int nc = c + GSTAGES - 1;
        if (nc < NCH) load_chunk(nc, nc % GSTAGES);
        cp_commit();

        const uint32_t base = sb + stage * STB;
        const uint32_t Bbase = base + SEGS * TILE_BYTES;

#pragma unroll
        for (int k16 = 0; k16 < 32; k16 += 16) {
            uint32_t bf[4][4];
#pragma unroll
            for (int nb = 0; nb < 4; nb++) {
                const int row = wn * 64 + nb * 16 + b_rowadd;
                const int col = k16 + b_coladd;
                ldmatrix_x4(bf[nb], Bbase + (uint32_t)(row * ROWPAD + col) * 2);
            }
#pragma unroll
            for (int seg = 0; seg < SEGS; seg++) {
                const uint32_t Abase = base + seg * TILE_BYTES;
                uint32_t af[2][4];
#pragma unroll
                for (int mi = 0; mi < 2; mi++) {
                    const int row = wm * 32 + mi * 16 + a_rowadd;
                    const int col = k16 + a_coladd;
                    ldmatrix_x4(af[mi], Abase + (uint32_t)(row * ROWPAD + col) * 2);
                }
#pragma unroll
                for (int nb = 0; nb < 4; nb++)
#pragma unroll
                    for (int mi = 0; mi < 2; mi++) {
                        mma_f16(acc[mi][nb * 2 + 0], af[mi], bf[nb][0], bf[nb][1]);
                        mma_f16(acc[mi][nb * 2 + 1], af[mi], bf[nb][2], bf[nb][3]);
                    }
            }
        }
    }

    // epilogue: optional fp32 / fp16-hi / fp16-lo outputs
    const int tq = lane >> 2;
    const int tr = lane & 3;
#pragma unroll
    for (int mi = 0; mi < 2; mi++) {
        const int row = m0 + wm * 32 + mi * 16 + tq;
#pragma unroll
        for (int ni = 0; ni < 8; ni++) {
            const int col = n0 + wn * 64 + ni * 8 + tr * 2;
            const float b0 = bias[col], b1 = bias[col + 1];
            float c00 = acc[mi][ni][0] + b0, c01 = acc[mi][ni][1] + b1;
            float c10 = acc[mi][ni][2] + b0, c11 = acc[mi][ni][3] + b1;
            if (C) {
                float2 v0; v0.x = c00; v0.y = c01;
                float2 v1; v1.x = c10; v1.y = c11;
                *(float2*)&C[(size_t)row * Nfull + col] = v0;
                *(float2*)&C[(size_t)(row + 8) * Nfull + col] = v1;
            }
            if (Ch || Cl) {
                __half h00 = __float2half_rn(c00);
                __half h01 = __float2half_rn(c01);
                __half h10 = __float2half_rn(c10);
                __half h11 = __float2half_rn(c11);
                if (Ch) {
                    *(__half2*)&Ch[(size_t)row * Nfull + col]       = __halves2half2(h00, h01);
                    *(__half2*)&Ch[(size_t)(row + 8) * Nfull + col] = __halves2half2(h10, h11);
                }
                if (Cl) {
                    __half l00 = __float2half_rn(c00 - __half2float(h00));
                    __half l01 = __float2half_rn(c01 - __half2float(h01));
                    __half l10 = __float2half_rn(c10 - __half2float(h10));
                    __half l11 = __float2half_rn(c11 - __half2float(h11));
                    *(__half2*)&Cl[(size_t)row * Nfull + col]       = __halves2half2(l00, l01);
                    *(__half2*)&Cl[(size_t)(row + 8) * Nfull + col] = __halves2half2(l10, l11);
                }
            }
        }
    }
}

// ---------------------------------------------------------------------------
// fp32 -> fp16 hi/lo split (elementwise, float4 vectorized)
// ---------------------------------------------------------------------------
__global__ void cvt_hilo(const float* __restrict__ x, __half* __restrict__ hi,
                         __half* __restrict__ lo, int n4)
{
    int i = blockIdx.x * blockDim.x + threadIdx.x;
    if (i >= n4) return;
    float4 v = ((const float4*)x)[i];
    __half h0 = __float2half_rn(v.x);
    __half h1 = __float2half_rn(v.y);
    __half h2 = __float2half_rn(v.z);
    __half h3 = __float2half_rn(v.w);
    __half l0 = __float2half_rn(v.x - __half2float(h0));
    __half l1 = __float2half_rn(v.y - __half2float(h1));
    __half l2 = __float2half_rn(v.z - __half2float(h2));
    __half l3 = __float2half_rn(v.w - __half2float(h3));
    __half2* hp = (__half2*)hi;
    __half2* lp = (__half2*)lo;
    hp[2 * i + 0] = __half2(h0, h1);
    hp[2 * i + 1] = __half2(h2, h3);
    lp[2 * i + 0] = __half2(l0, l1);
    lp[2 * i + 1] = __half2(l2, l3);
}

// plain fp32 -> fp16 convert (no transpose), float4 vectorized
__global__ void cvt_f16(const float* __restrict__ x, __half* __restrict__ y, int n4)
{
    int i = blockIdx.x * blockDim.x + threadIdx.x;
    if (i >= n4) return;
    float4 v = ((const float4*)x)[i];
    __half2* yp = (__half2*)y;
    yp[2 * i + 0] = __floats2half2_rn(v.x, v.y);
    yp[2 * i + 1] = __floats2half2_rn(v.z, v.w);
}

// ---------------------------------------------------------------------------
// Weight transpose + fp16 hi/lo convert (slots-layout)
// ---------------------------------------------------------------------------
__global__ void wt_cvt3(const float* __restrict__ W, __half* __restrict__ WTh,
                        __half* __restrict__ WTl, int Kd, int Nd, int type, int slots)
{
    __shared__ float t[32][33];
    const size_t srcoff = (size_t)blockIdx.z * Kd * Nd;
    const size_t dstoff = ((size_t)blockIdx.z * slots + type) * Kd * Nd;
    const float* Wm = W + srcoff;
    __half* Hh = WTh + dstoff;
    __half* Hl = WTl + dstoff;

    int nx = blockIdx.x * 32 + threadIdx.x;
    int k0 = blockIdx.y * 32;
#pragma unroll
    for (int j = 0; j < 4; j++) {
        int kk = k0 + threadIdx.y + j * 8;
        t[threadIdx.y + j * 8][threadIdx.x] = Wm[(size_t)kk * Nd + nx];
    }
    __syncthreads();
    int kx = k0 + threadIdx.x;
#pragma unroll
    for (int j = 0; j < 4; j++) {
        int nn = blockIdx.x * 32 + threadIdx.y + j * 8;
        float v = t[threadIdx.x][threadIdx.y + j * 8];
        __half h = __float2half_rn(v);
        Hh[(size_t)nn * Kd + kx] = h;
        Hl[(size_t)nn * Kd + kx] = __float2half_rn(v - __half2float(h));
    }
}

// plain transpose+convert (wd[3])
__global__ void wt_cvt(const float* __restrict__ W, __half* __restrict__ WT,
                       int Kd, int Nd)
{
    __shared__ float t[32][33];
    const size_t moff = (size_t)blockIdx.z * Kd * Nd;
    const float* Wm = W + moff;
    __half* Hh = WT + moff;

    int nx = blockIdx.x * 32 + threadIdx.x;
    int k0 = blockIdx.y * 32;
#pragma unroll
    for (int j = 0; j < 4; j++) {
        int kk = k0 + threadIdx.y + j * 8;
        t[threadIdx.y + j * 8][threadIdx.x] = Wm[(size_t)kk * Nd + nx];
    }
    __syncthreads();
    int kx = k0 + threadIdx.x;
#pragma unroll
    for (int j = 0; j < 4; j++) {
        int nn = blockIdx.x * 32 + threadIdx.y + j * 8;
        Hh[(size_t)nn * Kd + kx] = __float2half_rn(t[threadIdx.x][threadIdx.y + j * 8]);
    }
}

// merged QKV bias
__global__ void bias_concat(const float* __restrict__ bq, const float* __restrict__ bk,
                            const float* __restrict__ bv, float* __restrict__ out)
{
    int i = blockIdx.x * blockDim.x + threadIdx.x;
    if (i >= 4 * QKV_N) return;
    int a = i / QKV_N;
    int r = i % QKV_N;
    const float* src = (r < E_DIM) ? bq : (r < 2 * E_DIM) ? bk : bv;
    out[i] = src[a * E_DIM + (r & (E_DIM - 1))];
}

// combined bias for folded layers: b'[z][i] = bd[z] @ Wqkv_{z+1}[:,i] + bqkv[z+1][i]
__global__ void bias_comb(const float* __restrict__ wq, const float* __restrict__ wk,
                          const float* __restrict__ wv, const float* __restrict__ bd,
                          const float* __restrict__ bqkv, float* __restrict__ out)
{
    int i = blockIdx.x * blockDim.x + threadIdx.x;
    int z = blockIdx.y;
    const float* W = (i < E_DIM) ? wq : (i < 2 * E_DIM) ? wk : wv;
    int col = i & (E_DIM - 1);
    const float* Wm = W + (size_t)(z + 1) * E_DIM * E_DIM;
    const float* bdz = bd + (size_t)z * E_DIM;
    float s = 0.f;
    for (int k = 0; k < E_DIM; k++)
        s += bdz[k] * Wm[(size_t)k * E_DIM + col];
    out[(size_t)z * QKV_N + i] = s + bqkv[(size_t)(z + 1) * QKV_N + i];
}

// selection score bias: out[k] = bd3 @ selw[:,k] + selb[k]
__global__ void bias_sel(const float* __restrict__ selw, const float* __restrict__ selb,
                         const float* __restrict__ bd3, float* __restrict__ out)
{
    int k = blockIdx.x * blockDim.x + threadIdx.x;
    if (k >= KSEL) return;
    float s = 0.f;
    for (int e = 0; e < E_DIM; e++)
        s += bd3[e] * selw[(size_t)e * KSEL + k];
    out[k] = s + selb[k];
}

// ---------------------------------------------------------------------------
// Split-K selection GEMM (fp32, atomics): S1[b,k,e] += sum_m wts[b,m,k]*ctx[b,m,e]
// ---------------------------------------------------------------------------
__global__ __launch_bounds__(256, 2)
void gemm_sel_atomic(const float* __restrict__ Wts, const float* __restrict__ Flat,
                     float* __restrict__ Csel)
{
    __shared__ float As[16][128];
    __shared__ float Bs[16][128];

    const int tid = threadIdx.x;
    const int bx = blockIdx.x;
    const int by = blockIdx.y;
    const int b  = blockIdx.z / SPLITK;
    const int sl = blockIdx.z % SPLITK;

    const float* A = Wts  + (size_t)b * MTOK_B * KSEL;
    const float* B = Flat + (size_t)b * MTOK_B * E_DIM;
    float*       C = Csel + (size_t)b * KSEL * E_DIM;

    const int lr = (tid & 31) << 2;
    const int lk = tid >> 5;
    const int tx = tid & 15;
    const int ty = tid >> 4;

    const int kbeg = sl * (MTOK_B / SPLITK);
    const int kend = kbeg + (MTOK_B / SPLITK);

    float acc[8][8];
#pragma unroll
    for (int i = 0; i < 8; i++)
#pragma unroll
        for (int j = 0; j < 8; j++) acc[i][j] = 0.f;

    for (int k0 = kbeg; k0 < kend; k0 += 16) {
        *(float4*)&As[lk][lr]     = *(const float4*)&A[(size_t)(k0 + lk) * KSEL + by * 128 + lr];
        *(float4*)&As[lk + 8][lr] = *(const float4*)&A[(size_t)(k0 + lk + 8) * KSEL + by * 128 + lr];
        *(float4*)&Bs[lk][lr]     = *(const float4*)&B[(size_t)(k0 + lk) * E_DIM + bx * 128 + lr];
        *(float4*)&Bs[lk + 8][lr] = *(const float4*)&B[(size_t)(k0 + lk + 8) * E_DIM + bx * 128 + lr];
        __syncthreads();

#pragma unroll
        for (int kk = 0; kk < 16; kk++) {
            float ar[8], br[8];
            *(float4*)&ar[0] = *(const float4*)&As[kk][ty * 8];
            *(float4*)&ar[4] = *(const float4*)&As[kk][ty * 8 + 4];
            *(float4*)&br[0] = *(const float4*)&Bs[kk][tx * 8];
            *(float4*)&br[4] = *(const float4*)&Bs[kk][tx * 8 + 4];
#pragma unroll
            for (int i = 0; i < 8; i++)
#pragma unroll
                for (int j = 0; j < 8; j++)
                    acc[i][j] += ar[i] * br[j];
        }
        __syncthreads();
    }

#pragma unroll
    for (int i = 0; i < 8; i++) {
        float* cp = C + (size_t)(by * 128 + ty * 8 + i) * E_DIM + bx * 128 + tx * 8;
#pragma unroll
        for (int j = 0; j < 8; j++)
            atomicAdd(&cp[j], acc[i][j]);
    }
}

// ---------------------------------------------------------------------------
// Fused relative-bias multihead attention; reads merged fp16 QKV (stride ldx),
// K and V staged in smem as fp16, math in fp32; emits fp16 hi/lo output
// (+ optional fp32 ctx). Spatial smem = 67.7 KB -> 3 CTAs/SM.
// ---------------------------------------------------------------------------
template <int S>
__global__ __launch_bounds__(256)
void attn_kernel(const __half* __restrict__ Q, const __half* __restrict__ K,
                 const __half* __restrict__ V,
                 __half* __restrict__ OutH, __half* __restrict__ OutL,
                 float* __restrict__ OutF,
                 const float* __restrict__ rb,
                 int div, int mulq, int mulr, int stepTok, int ldx)
{
    const int h = blockIdx.x;
    const int g = blockIdx.y;
    const int base_m = (g / div) * mulq + (g % div) * mulr;
    const size_t baseE = (size_t)base_m * ldx + h * D_DIM;
    const size_t stepE = (size_t)stepTok * ldx;

    extern __shared__ float sm[];
    __half2* Kt2 = (__half2*)sm;                      // [32][S+1] fp16 d-pair transposed
    __half2* Vsh = Kt2 + 32 * (S + 1);                // [S][32] fp16 d-pairs
    float*   rbh = (float*)(Vsh + S * 32);            // [2S-1]

    const int tid = threadIdx.x;

    for (int idx = tid; idx < S * 32; idx += 256) {
        int t = idx >> 5, d2 = idx & 31;
        size_t off = baseE + (size_t)t * stepE;
        Kt2[d2 * (S + 1) + t] = *(const __half2*)&K[off + 2 * d2];
        Vsh[idx]              = *(const __half2*)&V[off + 2 * d2];
    }
    for (int i = tid; i < 2 * S - 1; i += 256)
        rbh[i] = rb[(size_t)(MAXLEN - S + i) * H_DIM + h];
    __syncthreads();

    const int lane = tid & 31;
    const int warp = tid >> 5;
    const int NT = S / 32;

    for (int q = warp; q < S; q += 8) {
        size_t qoff = baseE + (size_t)q * stepE;
        float2 ql = __half22float2(*(const __half2*)&Q[qoff + 2 * lane]);

        float s[NT];
#pragma unroll
        for (int tb = 0; tb < NT; tb++) s[tb] = 0.f;

#pragma unroll 4
        for (int d2 = 0; d2 < 32; d2++) {
            float qx = __shfl_sync(0xffffffffu, ql.x, d2);
            float qy = __shfl_sync(0xffffffffu, ql.y, d2);
            const __half2* kr = &Kt2[d2 * (S + 1) + lane];
#pragma unroll
            for (int tb = 0; tb < NT; tb++) {
                float2 kv = __half22float2(kr[tb * 32]);
                s[tb] += qx * kv.x + qy * kv.y;
            }
        }

#pragma unroll
        for (int tb = 0; tb < NT; tb++) {
            int t = tb * 32 + lane;
            s[tb] = s[tb] * 0.125f + rbh[t - q + (S - 1)];
        }

        float mx = s[0];
#pragma unroll
        for (int tb = 1; tb < NT; tb++) mx = fmaxf(mx, s[tb]);
#pragma unroll
        for (int o = 16; o > 0; o >>= 1)
            mx = fmaxf(mx, __shfl_xor_sync(0xffffffffu, mx, o));
        float sum = 0.f;
#pragma unroll
        for (int tb = 0; tb < NT; tb++) { s[tb] = __expf(s[tb] - mx); sum += s[tb]; }
#pragma unroll
        for (int o = 16; o > 0; o >>= 1)
            sum += __shfl_xor_sync(0xffffffffu, sum, o);
        float inv = 1.f / sum;
#pragma unroll
        for (int tb = 0; tb < NT; tb++) s[tb] *= inv;

        float cx = 0.f, cy = 0.f;
#pragma unroll
        for (int tb = 0; tb < NT; tb++) {
            float wv = s[tb];
#pragma unroll 8
            for (int j = 0; j < 32; j++) {
                float wj = __shfl_sync(0xffffffffu, wv, j);
                float2 vf = __half22float2(Vsh[(tb * 32 + j) * 32 + lane]);
                cx += wj * vf.x;
                cy += wj * vf.y;
            }
        }
        __half hx = __float2half_rn(cx);
        __half hy = __float2half_rn(cy);
        __half lx = __float2half_rn(cx - __half2float(hx));
        __half ly = __float2half_rn(cy - __half2float(hy));
        const size_t ooff = (size_t)(base_m + q * stepTok) * E_DIM + h * D_DIM + 2 * lane;
        *(__half2*)&OutH[ooff] = __halves2half2(hx, hy);
        *(__half2*)&OutL[ooff] = __halves2half2(lx, ly);
        if (OutF) {
            float2 cf; cf.x = cx; cf.y = cy;
            *(float2*)&OutF[ooff] = cf;
        }
    }
}

// ---------------------------------------------------------------------------
// Selection softmax over token axis per (b, k), in place
// ---------------------------------------------------------------------------
__global__ __launch_bounds__(256)
void sel_softmax(float* __restrict__ sc)
{
    const int b = blockIdx.x;
    const int k0 = blockIdx.y * 32;
    const int lane = threadIdx.x & 31;
    const int row = threadIdx.x >> 5;

    float* base = sc + (size_t)b * MTOK_B * KSEL + k0 + lane;

    __shared__ float redA[8][32];
    __shared__ float redB[8][32];

    float mx = -1e30f;
    for (int m = row; m < MTOK_B; m += 8)
        mx = fmaxf(mx, base[(size_t)m * KSEL]);
    redA[row][lane] = mx;
    __syncthreads();
    if (row == 0) {
        float v = redA[0][lane];
#pragma unroll
        for (int r = 1; r < 8; r++) v = fmaxf(v, redA[r][lane]);
        redA[0][lane] = v;
    }
    __syncthreads();
    mx = redA[0][lane];

    float sum = 0.f;
    for (int m = row; m < MTOK_B; m += 8)
        sum += __expf(base[(size_t)m * KSEL] - mx);
    redB[row][lane] = sum;
    __syncthreads();
    if (row == 0) {
        float v = 0.f;
#pragma unroll
        for (int r = 0; r < 8; r++) v += redB[r][lane];
        redB[0][lane] = v;
    }
    __syncthreads();
    float inv = 1.f / redB[0][lane];

    for (int m = row; m < MTOK_B; m += 8) {
        float* p = &base[(size_t)m * KSEL];
        *p = __expf(*p - mx) * inv;
    }
}

// ---------------------------------------------------------------------------
// Multi-scale pooling
// ---------------------------------------------------------------------------
__global__ void pool_kernel(const float* __restrict__ sel, float* __restrict__ out)
{
    int idx = blockIdx.x * blockDim.x + threadIdx.x;
    int total = B_DIM * OUT_ROWS * E_DIM;
    if (idx >= total) return;
    int e = idx % E_DIM;
    int r = (idx / E_DIM) % OUT_ROWS;
    int b = idx / (OUT_ROWS * E_DIM);
    const float* sb = sel + (size_t)b * KSEL * E_DIM;
    float v;
    if (r < 256) {
        v = sb[(size_t)r * E_DIM + e];
    } else if (r < 384) {
        int i = (r - 256) * 2;
        v = 0.5f * (sb[(size_t)i * E_DIM + e] + sb[(size_t)(i + 1) * E_DIM + e]);
    } else {
        int i = (r - 384) * 4;
        v = 0.25f * (sb[(size_t)i * E_DIM + e] + sb[(size_t)(i + 1) * E_DIM + e] +
                     sb[(size_t)(i + 2) * E_DIM + e] + sb[(size_t)(i + 3) * E_DIM + e]);
    }
    out[idx] = v;
}

// ---------------------------------------------------------------------------
// Orchestration
// ---------------------------------------------------------------------------
extern "C" void kernel_launch(void* const* d_in, const int* in_sizes, int n_in,
                              void* d_out, int out_size)
{
    (void)in_sizes; (void)n_in; (void)out_size;

    const float* x    = (const float*)d_in[0];
    const float* wq   = (const float*)d_in[1];
    const float* bq   = (const float*)d_in[2];
    const float* wk   = (const float*)d_in[3];
    const float* bk   = (const float*)d_in[4];
    const float* wv   = (const float*)d_in[5];
    const float* bv   = (const float*)d_in[6];
    const float* wd   = (const float*)d_in[7];
    const float* bd   = (const float*)d_in[8];
    const float* rb   = (const float*)d_in[9];
    const float* selw = (const float*)d_in[10];
    const float* selb = (const float*)d_in[11];
    float* out = (float*)d_out;

    float *Hb, *SCb, *S1b, *SELb, *Bqkv, *Bcomb, *Bias2, *Bzero;
    cudaGetSymbolAddress((void**)&Hb,  g_Hb);
    cudaGetSymbolAddress((void**)&SCb, g_SC);
    cudaGetSymbolAddress((void**)&S1b, g_S1);
    cudaGetSymbolAddress((void**)&SELb, g_SEL);
    cudaGetSymbolAddress((void**)&Bqkv, g_Bqkv);
    cudaGetSymbolAddress((void**)&Bcomb, g_Bcomb);
    cudaGetSymbolAddress((void**)&Bias2, g_Bias2);
    cudaGetSymbolAddress((void**)&Bzero, g_Bzero);

    __half *QKVh, *Ahp, *Alp, *Ah2p, *Al2p, *WqkvTh, *WqkvTl, *Wd16, *WdT3, *WcT;
    __half *SWTh, *SWTl, *Bsel;
    cudaGetSymbolAddress((void**)&QKVh, g_QKVh);
    cudaGetSymbolAddress((void**)&Ahp, g_Ah);
    cudaGetSymbolAddress((void**)&Alp, g_Al);
    cudaGetSymbolAddress((void**)&Ah2p, g_Ah2);
    cudaGetSymbolAddress((void**)&Al2p, g_Al2);
    cudaGetSymbolAddress((void**)&WqkvTh, g_WqkvTh);
    cudaGetSymbolAddress((void**)&WqkvTl, g_WqkvTl);
    cudaGetSymbolAddress((void**)&Wd16, g_Wd16);
    cudaGetSymbolAddress((void**)&WdT3, g_WdT3);
    cudaGetSymbolAddress((void**)&WcT, g_WcT);
    cudaGetSymbolAddress((void**)&SWTh, g_SWTh);
    cudaGetSymbolAddress((void**)&SWTl, g_SWTl);
    cudaGetSymbolAddress((void**)&Bsel, g_Bsel);

    // attention smem: K fp16 d-pair transposed + V fp16 + rel bias
    const int smemSp = 32 * (256 + 1) * 4 + 256 * 32 * 4 + (2 * 256 - 1) * 4;  // 67708
    const int smemTe = 32 * (32 + 1) * 4 + 32 * 32 * 4 + (2 * 32 - 1) * 4;     // 8572
    const int SMEM1 = GSTAGES * 2 * TILE_BYTES;   // 61440
    const int SMEM2 = GSTAGES * 3 * TILE_BYTES;   // 92160
    cudaFuncSetAttribute((const void*)attn_kernel<256>,
                         cudaFuncAttributeMaxDynamicSharedMemorySize, smemSp);
    cudaFuncSetAttribute((const void*)gemm_f16<1>,
                         cudaFuncAttributeMaxDynamicSharedMemorySize, SMEM1);
    cudaFuncSetAttribute((const void*)gemm_f16<2>,
                         cudaFuncAttributeMaxDynamicSharedMemorySize, SMEM2);

    const dim3 blk(256);
    const dim3 tblk(32, 8);
    const int n4 = MTOK * E_DIM / 4;
    const dim3 gcvt((n4 + 255) / 256);
    const dim3 gQKV(QKV_N / 128, MTOK / 128);   // 24 x 128
    const size_t MM = (size_t)E_DIM * E_DIM;
    const size_t MM3 = 3 * MM;
    const size_t WCS = (size_t)QKV_N * E_DIM;

    // ---- weight prep ----
    wt_cvt3<<<dim3(E_DIM / 32, E_DIM / 32, 4), tblk>>>(wq, WqkvTh, WqkvTl, E_DIM, E_DIM, 0, 3);
    wt_cvt3<<<dim3(E_DIM / 32, E_DIM / 32, 4), tblk>>>(wk, WqkvTh, WqkvTl, E_DIM, E_DIM, 1, 3);
    wt_cvt3<<<dim3(E_DIM / 32, E_DIM / 32, 4), tblk>>>(wv, WqkvTh, WqkvTl, E_DIM, E_DIM, 2, 3);
    bias_concat<<<(4 * QKV_N + 255) / 256, blk>>>(bq, bk, bv, Bqkv);
    cvt_f16<<<(int)((4 * MM / 4 + 255) / 256), blk>>>(wd, Wd16, (int)(4 * MM / 4));

    // combined weights W'^T[z] = (Wd_z @ Wqkv_{z+1})^T, z = 0..2 (batched, 2-seg)
    gemm_f16<2><<<dim3(E_DIM / 128, QKV_N / 128, 3), blk, SMEM2>>>(
        WqkvTh + MM3, WqkvTl + MM3, Wd16, Bzero, nullptr,
        WcT, nullptr, E_DIM, E_DIM, MM3, MM, WCS);

    wt_cvt<<<dim3(E_DIM / 32, E_DIM / 32, 1), tblk>>>(wd + 3 * MM, WdT3, E_DIM, E_DIM);
    wt_cvt3<<<dim3(KSEL / 32, E_DIM / 32, 1), tblk>>>(selw, SWTh, SWTl, E_DIM, KSEL, 0, 1);
    gemm_f16<2><<<dim3(E_DIM / 128, KSEL / 128), blk, SMEM2>>>(
        SWTh, SWTl, Wd16 + 3 * MM, Bzero, nullptr,
        Bsel, nullptr, E_DIM, E_DIM, 0, 0, 0);
    bias_comb<<<dim3(QKV_N / 256, 3), blk>>>(wq, wk, wv, bd, Bqkv, Bcomb);
    bias_sel<<<1, 256>>>(selw, selb, bd + 3 * E_DIM, Bias2);
    cvt_hilo<<<gcvt, blk>>>(x, Ah2p, Al2p, n4);

    // ---- layers (QKV projections single-segment, fp16 output only) ----
    for (int a = 0; a < 4; a++) {
        if (a == 0) {
            gemm_f16<1><<<gQKV, blk, SMEM1>>>(Ah2p, nullptr, WqkvTh, Bqkv, nullptr,
                                              QKVh, nullptr, QKV_N, E_DIM, 0, 0, 0);
        } else {
            gemm_f16<1><<<gQKV, blk, SMEM1>>>(Ahp, nullptr, WcT + (a - 1) * WCS,
                                              Bcomb + (size_t)(a - 1) * QKV_N, nullptr,
                                              QKVh, nullptr, QKV_N, E_DIM, 0, 0, 0);
        }

        const float* rba = rb + (size_t)a * RB_ONE;
        const __half* Qp = QKVh;
        const __half* Kp = QKVh + E_DIM;
        const __half* Vp = QKVh + 2 * E_DIM;
        float* ctxF = (a == 3) ? Hb : nullptr;
        if ((a & 1) == 0) {
            attn_kernel<256><<<dim3(H_DIM, B_DIM * T_DIM), blk, smemSp>>>(
                Qp, Kp, Vp, Ahp, Alp, ctxF, rba, B_DIM * T_DIM, 0, N_DIM, 1, QKV_N);
        } else {
            attn_kernel<32><<<dim3(H_DIM, B_DIM * N_DIM), blk, smemTe>>>(
                Qp, Kp, Vp, Ahp, Alp, ctxF, rba, N_DIM, T_DIM * N_DIM, 1, N_DIM, QKV_N);
        }
    }

    // selection scores on ctx: SC = ctx @ Bsel^T + Bias2   (2-seg, exact ctx)
    gemm_f16<2><<<dim3(KSEL / 128, MTOK / 128), blk, SMEM2>>>(
        Ahp, Alp, Bsel, Bias2, SCb, nullptr, nullptr, KSEL, E_DIM, 0, 0, 0);

    // softmax over token axis per (b, k), in place
    sel_softmax<<<dim3(B_DIM, KSEL / 32), blk>>>(SCb);

    // S1[b,k,e] = sum_m wts[b,m,k] * ctx[b,m,e]  (fp32 split-K + atomics)
    cudaMemsetAsync(S1b, 0, (size_t)B_DIM * KSEL * E_DIM * sizeof(float));
    gemm_sel_atomic<<<dim3(E_DIM / 128, KSEL / 128, B_DIM * SPLITK), blk>>>(SCb, Hb, S1b);

    // SEL = S1 @ Wd3 + bd3  (tiny 2-seg GEMM)
    cvt_hilo<<<dim3((B_DIM * KSEL * E_DIM / 4 + 255) / 256), blk>>>(
        S1b, Ah2p, Al2p, B_DIM * KSEL * E_DIM / 4);
    gemm_f16<2><<<dim3(E_DIM / 128, (B_DIM * KSEL) / 128), blk, SMEM2>>>(
        Ah2p, Al2p, WdT3, bd + 3 * E_DIM, SELb, nullptr, nullptr, E_DIM, E_DIM, 0, 0, 0);

    // multi-scale pooling -> output [B, 448, E]
    int total = B_DIM * OUT_ROWS * E_DIM;
    pool_kernel<<<(total + 255) / 256, 256>>>(SELb, out);
}

// round 11
// speedup vs baseline: 1.7416x; 1.0198x over previous
#include <cuda_runtime.h>
#include <cuda_fp16.h>
#include <cstdint>
#include <cstddef>

// ---------------------------------------------------------------------------
// Problem constants
// ---------------------------------------------------------------------------
#define E_DIM   1024
#define QKV_N   3072
#define H_DIM   16
#define D_DIM   64
#define B_DIM   2
#define T_DIM   32
#define N_DIM   256
#define MTOK    (B_DIM * T_DIM * N_DIM)   // 16384 tokens total
#define MTOK_B  (T_DIM * N_DIM)           // 8192 tokens per batch
#define KSEL    256
#define MAXLEN  512
#define RB_ONE  ((2 * MAXLEN - 1) * H_DIM)
#define OUT_ROWS 448                      // 256 + 128 + 64
#define SPLITK  8

// ---------------------------------------------------------------------------
// Scratch (device globals — no allocations allowed)
// ---------------------------------------------------------------------------
__device__ __half g_QKVh[MTOK * QKV_N];   // merged Q|K|V per token, fp16
__device__ float g_Hb[MTOK * E_DIM];      // layer-3 ctx fp32 (for selection)
__device__ float g_SC[MTOK * KSEL];
__device__ float g_S1[B_DIM * KSEL * E_DIM];   // wts^T @ ctx
__device__ float g_SEL[B_DIM * KSEL * E_DIM];  // final selected tokens

// fp16 split activations: ping (attention out) and pong (misc)
__device__ __half g_Ah[MTOK * E_DIM];
__device__ __half g_Al[MTOK * E_DIM];
__device__ __half g_Ah2[MTOK * E_DIM];
__device__ __half g_Al2[MTOK * E_DIM];
// transposed fp16 weights
__device__ __half g_WqkvTh[4 * 3 * E_DIM * E_DIM];  // [a][q|k|v][N=E][K=E] hi
__device__ __half g_WqkvTl[4 * 3 * E_DIM * E_DIM];  // lo
__device__ __half g_Wd16[4 * E_DIM * E_DIM];        // wd plain (row-major) fp16
__device__ __half g_WdT3[E_DIM * E_DIM];            // wd[3] transposed fp16
__device__ __half g_WcT[3 * QKV_N * E_DIM];         // combined W'^T = (Wd_a Wqkv_{a+1})^T fp16
__device__ __half g_SWTh[KSEL * E_DIM];             // selw^T hi
__device__ __half g_SWTl[KSEL * E_DIM];             // selw^T lo
__device__ __half g_Bsel[KSEL * E_DIM];             // (Wd3 @ selw)^T fp16
__device__ float  g_Bqkv[4 * QKV_N];                // merged qkv bias per attn idx
__device__ float  g_Bcomb[3 * QKV_N];               // combined bias bd_a@Wqkv_{a+1}+b_{a+1}
__device__ float  g_Bias2[KSEL];                    // bd3@selw + selb
__device__ float  g_Bzero[E_DIM];                   // zero bias (static zero-init)

// ---------------------------------------------------------------------------
// PTX helpers (cp.async / ldmatrix / mma.sync / f32x2 — baseline PTX)
// ---------------------------------------------------------------------------
__device__ __forceinline__ void cp_async16(uint32_t dst, const void* src) {
    asm volatile("cp.async.cg.shared.global [%0], [%1], 16;" :: "r"(dst), "l"(src));
}
__device__ __forceinline__ void cp_commit() {
    asm volatile("cp.async.commit_group;" ::: "memory");
}
template <int N>
__device__ __forceinline__ void cp_wait_group() {
    asm volatile("cp.async.wait_group %0;" :: "n"(N) : "memory");
}
__device__ __forceinline__ void ldmatrix_x4(uint32_t* r, uint32_t addr) {
    asm volatile("ldmatrix.sync.aligned.m8n8.x4.shared.b16 {%0,%1,%2,%3}, [%4];"
                 : "=r"(r[0]), "=r"(r[1]), "=r"(r[2]), "=r"(r[3]) : "r"(addr));
}
__device__ __forceinline__ void mma_f16(float* d, const uint32_t* a,
                                        uint32_t b0, uint32_t b1) {
    asm volatile(
        "mma.sync.aligned.m16n8k16.row.col.f32.f16.f16.f32 "
        "{%0,%1,%2,%3}, {%4,%5,%6,%7}, {%8,%9}, {%0,%1,%2,%3};"
        : "+f"(d[0]), "+f"(d[1]), "+f"(d[2]), "+f"(d[3])
        : "r"(a[0]), "r"(a[1]), "r"(a[2]), "r"(a[3]), "r"(b0), "r"(b1));
}
__device__ __forceinline__ unsigned long long pack_f32x2(float x, float y) {
    unsigned long long r;
    asm("mov.b64 %0, {%1, %2};" : "=l"(r) : "r"(__float_as_uint(x)), "r"(__float_as_uint(y)));
    return r;
}
__device__ __forceinline__ void fma_f32x2(unsigned long long& d,
                                          unsigned long long a, unsigned long long b) {
    asm("fma.rn.f32x2 %0, %1, %2, %0;" : "+l"(d) : "l"(a), "l"(b));
}
__device__ __forceinline__ float sum_f32x2(unsigned long long v) {
    uint32_t lo, hi;
    asm("mov.b64 {%0, %1}, %2;" : "=r"(lo), "=r"(hi) : "l"(v));
    return __uint_as_float(lo) + __uint_as_float(hi);
}

// ---------------------------------------------------------------------------
// fp16 GEMM via mma.sync, templated on A-segments (1 = Ah only, 2 = Ah+Al):
//   C[z][M, Nfull] = (Ah[+Al])[z][M,K] @ B[z][Nfull,K]^T + bias
// All of C (fp32), Ch (fp16 hi), Cl (fp16 lo) outputs optional. z-batchable.
// ---------------------------------------------------------------------------
#define GSTAGES 3
#define ROWPAD  40
#define TILE_BYTES (128 * ROWPAD * 2)

template <int SEGS>
__global__ __launch_bounds__(256, 2)
void gemm_f16(const __half* __restrict__ Ah, const __half* __restrict__ Al,
              const __half* __restrict__ B,
              const float* __restrict__ bias, float* __restrict__ C,
              __half* __restrict__ Ch, __half* __restrict__ Cl,
              int Nfull, int Kfull,
              size_t zA, size_t zB, size_t zC)
{
    constexpr int STB = (SEGS + 1) * TILE_BYTES;

    extern __shared__ char smem[];
    const uint32_t sb = (uint32_t)__cvta_generic_to_shared(smem);
    const int tid = threadIdx.x;
    const int lane = tid & 31;
    const int warp = tid >> 5;
    const int wm = warp >> 1;
    const int wn = warp & 1;
    const int m0 = blockIdx.y * 128;
    const int n0 = blockIdx.x * 128;

    Ah += (size_t)blockIdx.z * zA;
    if (SEGS == 2) Al += (size_t)blockIdx.z * zA;
    B  += (size_t)blockIdx.z * zB;
    if (C)  C  += (size_t)blockIdx.z * zC;
    if (Ch) Ch += (size_t)blockIdx.z * zC;
    if (Cl) Cl += (size_t)blockIdx.z * zC;

    const int NCH = Kfull >> 5;

    const int lr0 = tid >> 1;
    const int ls0 = (tid & 1) << 1;

    float acc[2][8][4];
#pragma unroll
    for (int mi = 0; mi < 2; mi++)
#pragma unroll
        for (int ni = 0; ni < 8; ni++)
#pragma unroll
            for (int q = 0; q < 4; q++) acc[mi][ni][q] = 0.f;

    auto load_chunk = [&](int c, int stage) {
        const int kb = c << 5;
        const uint32_t base = sb + stage * STB;
#pragma unroll
        for (int j = 0; j < 2; j++) {
            const int s4 = ls0 + j;
            const uint32_t soff = (uint32_t)(lr0 * ROWPAD + s4 * 8) * 2;
            const size_t goff = (size_t)lr0 * Kfull + kb + s4 * 8;
            cp_async16(base + soff, Ah + (size_t)m0 * Kfull + goff);
            if (SEGS == 2)
                cp_async16(base + TILE_BYTES + soff, Al + (size_t)m0 * Kfull + goff);
            cp_async16(base + SEGS * TILE_BYTES + soff, B + (size_t)n0 * Kfull + goff);
        }
    };

#pragma unroll
    for (int s = 0; s < GSTAGES - 1; s++) {
        if (s < NCH) load_chunk(s, s);
        cp_commit();
    }

    const int la_i = lane & 7;
    const int la_g = lane >> 3;
    const int a_rowadd = la_i + ((la_g & 1) << 3);
    const int a_coladd = (la_g >> 1) << 3;
    const int b_rowadd = la_i + ((la_g >> 1) << 3);
    const int b_coladd = (la_g & 1) << 3;

    for (int c = 0; c < NCH; c++) {
        const int stage = c % GSTAGES;
        cp_wait_group<GSTAGES - 2>();
        __syncthreads();

        const int nc = c + GSTAGES - 1;
        if (nc < NCH) load_chunk(nc, nc % GSTAGES);
        cp_commit();

        const uint32_t base = sb + stage * STB;
        const uint32_t Bbase = base + SEGS * TILE_BYTES;

#pragma unroll
        for (int k16 = 0; k16 < 32; k16 += 16) {
            uint32_t bf[4][4];
#pragma unroll
            for (int nb = 0; nb < 4; nb++) {
                const int row = wn * 64 + nb * 16 + b_rowadd;
                const int col = k16 + b_coladd;
                ldmatrix_x4(bf[nb], Bbase + (uint32_t)(row * ROWPAD + col) * 2);
            }
#pragma unroll
            for (int seg = 0; seg < SEGS; seg++) {
                const uint32_t Abase = base + seg * TILE_BYTES;
                uint32_t af[2][4];
#pragma unroll
                for (int mi = 0; mi < 2; mi++) {
                    const int row = wm * 32 + mi * 16 + a_rowadd;
                    const int col = k16 + a_coladd;
                    ldmatrix_x4(af[mi], Abase + (uint32_t)(row * ROWPAD + col) * 2);
                }
#pragma unroll
                for (int nb = 0; nb < 4; nb++)
#pragma unroll
                    for (int mi = 0; mi < 2; mi++) {
                        mma_f16(acc[mi][nb * 2 + 0], af[mi], bf[nb][0], bf[nb][1]);
                        mma_f16(acc[mi][nb * 2 + 1], af[mi], bf[nb][2], bf[nb][3]);
                    }
            }
        }
    }

    const int tq = lane >> 2;
    const int tr = lane & 3;
#pragma unroll
    for (int mi = 0; mi < 2; mi++) {
        const int row = m0 + wm * 32 + mi * 16 + tq;
#pragma unroll
        for (int ni = 0; ni < 8; ni++) {
            const int col = n0 + wn * 64 + ni * 8 + tr * 2;
            const float b0 = bias[col], b1 = bias[col + 1];
            float c00 = acc[mi][ni][0] + b0, c01 = acc[mi][ni][1] + b1;
            float c10 = acc[mi][ni][2] + b0, c11 = acc[mi][ni][3] + b1;
            if (C) {
                float2 v0; v0.x = c00; v0.y = c01;
                float2 v1; v1.x = c10; v1.y = c11;
                *(float2*)&C[(size_t)row * Nfull + col] = v0;
                *(float2*)&C[(size_t)(row + 8) * Nfull + col] = v1;
            }
            if (Ch || Cl) {
                __half h00 = __float2half_rn(c00);
                __half h01 = __float2half_rn(c01);
                __half h10 = __float2half_rn(c10);
                __half h11 = __float2half_rn(c11);
                if (Ch) {
                    *(__half2*)&Ch[(size_t)row * Nfull + col]       = __halves2half2(h00, h01);
                    *(__half2*)&Ch[(size_t)(row + 8) * Nfull + col] = __halves2half2(h10, h11);
                }
                if (Cl) {
                    __half l00 = __float2half_rn(c00 - __half2float(h00));
                    __half l01 = __float2half_rn(c01 - __half2float(h01));
                    __half l10 = __float2half_rn(c10 - __half2float(h10));
                    __half l11 = __float2half_rn(c11 - __half2float(h11));
                    *(__half2*)&Cl[(size_t)row * Nfull + col]       = __halves2half2(l00, l01);
                    *(__half2*)&Cl[(size_t)(row + 8) * Nfull + col] = __halves2half2(l10, l11);
                }
            }
        }
    }
}

// ---------------------------------------------------------------------------
// fp32 -> fp16 hi/lo split
// ---------------------------------------------------------------------------
__global__ void cvt_hilo(const float* __restrict__ x, __half* __restrict__ hi,
                         __half* __restrict__ lo, int n4)
{
    int i = blockIdx.x * blockDim.x + threadIdx.x;
    if (i >= n4) return;
    float4 v = ((const float4*)x)[i];
    __half h0 = __float2half_rn(v.x);
    __half h1 = __float2half_rn(v.y);
    __half h2 = __float2half_rn(v.z);
    __half h3 = __float2half_rn(v.w);
    __half l0 = __float2half_rn(v.x - __half2float(h0));
    __half l1 = __float2half_rn(v.y - __half2float(h1));
    __half l2 = __float2half_rn(v.z - __half2float(h2));
    __half l3 = __float2half_rn(v.w - __half2float(h3));
    __half2* hp = (__half2*)hi;
    __half2* lp = (__half2*)lo;
    hp[2 * i + 0] = __half2(h0, h1);
    hp[2 * i + 1] = __half2(h2, h3);
    lp[2 * i + 0] = __half2(l0, l1);
    lp[2 * i + 1] = __half2(l2, l3);
}

__global__ void cvt_f16(const float* __restrict__ x, __half* __restrict__ y, int n4)
{
    int i = blockIdx.x * blockDim.x + threadIdx.x;
    if (i >= n4) return;
    float4 v = ((const float4*)x)[i];
    __half2* yp = (__half2*)y;
    yp[2 * i + 0] = __floats2half2_rn(v.x, v.y);
    yp[2 * i + 1] = __floats2half2_rn(v.z, v.w);
}

// ---------------------------------------------------------------------------
// Weight transpose + fp16 hi/lo convert (slots-layout)
// ---------------------------------------------------------------------------
__global__ void wt_cvt3(const float* __restrict__ W, __half* __restrict__ WTh,
                        __half* __restrict__ WTl, int Kd, int Nd, int type, int slots)
{
    __shared__ float t[32][33];
    const size_t srcoff = (size_t)blockIdx.z * Kd * Nd;
    const size_t dstoff = ((size_t)blockIdx.z * slots + type) * Kd * Nd;
    const float* Wm = W + srcoff;
    __half* Hh = WTh + dstoff;
    __half* Hl = WTl + dstoff;

    int nx = blockIdx.x * 32 + threadIdx.x;
    int k0 = blockIdx.y * 32;
#pragma unroll
    for (int j = 0; j < 4; j++) {
        int kk = k0 + threadIdx.y + j * 8;
        t[threadIdx.y + j * 8][threadIdx.x] = Wm[(size_t)kk * Nd + nx];
    }
    __syncthreads();
    int kx = k0 + threadIdx.x;
#pragma unroll
    for (int j = 0; j < 4; j++) {
        int nn = blockIdx.x * 32 + threadIdx.y + j * 8;
        float v = t[threadIdx.x][threadIdx.y + j * 8];
        __half h = __float2half_rn(v);
        Hh[(size_t)nn * Kd + kx] = h;
        Hl[(size_t)nn * Kd + kx] = __float2half_rn(v - __half2float(h));
    }
}

__global__ void wt_cvt(const float* __restrict__ W, __half* __restrict__ WT,
                       int Kd, int Nd)
{
    __shared__ float t[32][33];
    const size_t moff = (size_t)blockIdx.z * Kd * Nd;
    const float* Wm = W + moff;
    __half* Hh = WT + moff;

    int nx = blockIdx.x * 32 + threadIdx.x;
    int k0 = blockIdx.y * 32;
#pragma unroll
    for (int j = 0; j < 4; j++) {
        int kk = k0 + threadIdx.y + j * 8;
        t[threadIdx.y + j * 8][threadIdx.x] = Wm[(size_t)kk * Nd + nx];
    }
    __syncthreads();
    int kx = k0 + threadIdx.x;
#pragma unroll
    for (int j = 0; j < 4; j++) {
        int nn = blockIdx.x * 32 + threadIdx.y + j * 8;
        Hh[(size_t)nn * Kd + kx] = __float2half_rn(t[threadIdx.x][threadIdx.y + j * 8]);
    }
}

__global__ void bias_concat(const float* __restrict__ bq, const float* __restrict__ bk,
                            const float* __restrict__ bv, float* __restrict__ out)
{
    int i = blockIdx.x * blockDim.x + threadIdx.x;
    if (i >= 4 * QKV_N) return;
    int a = i / QKV_N;
    int r = i % QKV_N;
    const float* src = (r < E_DIM) ? bq : (r < 2 * E_DIM) ? bk : bv;
    out[i] = src[a * E_DIM + (r & (E_DIM - 1))];
}

__global__ void bias_comb(const float* __restrict__ wq, const float* __restrict__ wk,
                          const float* __restrict__ wv, const float* __restrict__ bd,
                          const float* __restrict__ bqkv, float* __restrict__ out)
{
    int i = blockIdx.x * blockDim.x + threadIdx.x;
    int z = blockIdx.y;
    const float* W = (i < E_DIM) ? wq : (i < 2 * E_DIM) ? wk : wv;
    int col = i & (E_DIM - 1);
    const float* Wm = W + (size_t)(z + 1) * E_DIM * E_DIM;
    const float* bdz = bd + (size_t)z * E_DIM;
    float s = 0.f;
    for (int k = 0; k < E_DIM; k++)
        s += bdz[k] * Wm[(size_t)k * E_DIM + col];
    out[(size_t)z * QKV_N + i] = s + bqkv[(size_t)(z + 1) * QKV_N + i];
}

__global__ void bias_sel(const float* __restrict__ selw, const float* __restrict__ selb,
                         const float* __restrict__ bd3, float* __restrict__ out)
{
    int k = blockIdx.x * blockDim.x + threadIdx.x;
    if (k >= KSEL) return;
    float s = 0.f;
    for (int e = 0; e < E_DIM; e++)
        s += bd3[e] * selw[(size_t)e * KSEL + k];
    out[k] = s + selb[k];
}

// ---------------------------------------------------------------------------
// Split-K selection GEMM (fp32, atomics)
// ---------------------------------------------------------------------------
__global__ __launch_bounds__(256, 2)
void gemm_sel_atomic(const float* __restrict__ Wts, const float* __restrict__ Flat,
                     float* __restrict__ Csel)
{
    __shared__ float As[16][128];
    __shared__ float Bs[16][128];

    const int tid = threadIdx.x;
    const int bx = blockIdx.x;
    const int by = blockIdx.y;
    const int b  = blockIdx.z / SPLITK;
    const int sl = blockIdx.z % SPLITK;

    const float* A = Wts  + (size_t)b * MTOK_B * KSEL;
    const float* B = Flat + (size_t)b * MTOK_B * E_DIM;
    float*       C = Csel + (size_t)b * KSEL * E_DIM;

    const int lr = (tid & 31) << 2;
    const int lk = tid >> 5;
    const int tx = tid & 15;
    const int ty = tid >> 4;

    const int kbeg = sl * (MTOK_B / SPLITK);
    const int kend = kbeg + (MTOK_B / SPLITK);

    float acc[8][8];
#pragma unroll
    for (int i = 0; i < 8; i++)
#pragma unroll
        for (int j = 0; j < 8; j++) acc[i][j] = 0.f;

    for (int k0 = kbeg; k0 < kend; k0 += 16) {
        *(float4*)&As[lk][lr]     = *(const float4*)&A[(size_t)(k0 + lk) * KSEL + by * 128 + lr];
        *(float4*)&As[lk + 8][lr] = *(const float4*)&A[(size_t)(k0 + lk + 8) * KSEL + by * 128 + lr];
        *(float4*)&Bs[lk][lr]     = *(const float4*)&B[(size_t)(k0 + lk) * E_DIM + bx * 128 + lr];
        *(float4*)&Bs[lk + 8][lr] = *(const float4*)&B[(size_t)(k0 + lk + 8) * E_DIM + bx * 128 + lr];
        __syncthreads();

#pragma unroll
        for (int kk = 0; kk < 16; kk++) {
            float ar[8], br[8];
            *(float4*)&ar[0] = *(const float4*)&As[kk][ty * 8];
            *(float4*)&ar[4] = *(const float4*)&As[kk][ty * 8 + 4];
            *(float4*)&br[0] = *(const float4*)&Bs[kk][tx * 8];
            *(float4*)&br[4] = *(const float4*)&Bs[kk][tx * 8 + 4];
#pragma unroll
            for (int i = 0; i < 8; i++)
#pragma unroll
                for (int j = 0; j < 8; j++)
                    acc[i][j] += ar[i] * br[j];
        }
        __syncthreads();
    }

#pragma unroll
    for (int i = 0; i < 8; i++) {
        float* cp = C + (size_t)(by * 128 + ty * 8 + i) * E_DIM + bx * 128 + tx * 8;
#pragma unroll
        for (int j = 0; j < 8; j++)
            atomicAdd(&cp[j], acc[i][j]);
    }
}

// ---------------------------------------------------------------------------
// Fused relative-bias multihead attention; fp16 QKV in global (stride ldx).
// K staged in smem as fp32 float2 (packed f32x2 FMA in QK loop), V fp16.
// Emits fp16 hi/lo output (+ optional fp32 ctx).
// ---------------------------------------------------------------------------
template <int S>
__global__ __launch_bounds__(256)
void attn_kernel(const __half* __restrict__ Q, const __half* __restrict__ K,
                 const __half* __restrict__ V,
                 __half* __restrict__ OutH, __half* __restrict__ OutL,
                 float* __restrict__ OutF,
                 const float* __restrict__ rb,
                 int div, int mulq, int mulr, int stepTok, int ldx)
{
    const int h = blockIdx.x;
    const int g = blockIdx.y;
    const int base_m = (g / div) * mulq + (g % div) * mulr;
    const size_t baseE = (size_t)base_m * ldx + h * D_DIM;
    const size_t stepE = (size_t)stepTok * ldx;

    extern __shared__ float sm[];
    float2*  Kt2 = (float2*)sm;                       // [32][S+1] fp32 d-pair transposed
    __half2* Vsh = (__half2*)(Kt2 + 32 * (S + 1));    // [S][32] fp16 d-pairs
    float*   rbh = (float*)(Vsh + S * 32);            // [2S-1]

    const int tid = threadIdx.x;

    for (int idx = tid; idx < S * 32; idx += 256) {
        int t = idx >> 5, d2 = idx & 31;
        size_t off = baseE + (size_t)t * stepE;
        Kt2[d2 * (S + 1) + t] = __half22float2(*(const __half2*)&K[off + 2 * d2]);
        Vsh[idx]              = *(const __half2*)&V[off + 2 * d2];
    }
    for (int i = tid; i < 2 * S - 1; i += 256)
        rbh[i] = rb[(size_t)(MAXLEN - S + i) * H_DIM + h];
    __syncthreads();

    const int lane = tid & 31;
    const int warp = tid >> 5;
    const int NT = S / 32;

    for (int q = warp; q < S; q += 8) {
        size_t qoff = baseE + (size_t)q * stepE;
        float2 ql = __half22float2(*(const __half2*)&Q[qoff + 2 * lane]);

        unsigned long long acc2[NT];
#pragma unroll
        for (int tb = 0; tb < NT; tb++) acc2[tb] = 0ull;

#pragma unroll 4
        for (int d2 = 0; d2 < 32; d2++) {
            float qx = __shfl_sync(0xffffffffu, ql.x, d2);
            float qy = __shfl_sync(0xffffffffu, ql.y, d2);
            unsigned long long q2 = pack_f32x2(qx, qy);
            const unsigned long long* kr =
                (const unsigned long long*)&Kt2[d2 * (S + 1) + lane];
#pragma unroll
            for (int tb = 0; tb < NT; tb++)
                fma_f32x2(acc2[tb], q2, kr[tb * 32]);
        }

        float s[NT];
#pragma unroll
        for (int tb = 0; tb < NT; tb++) {
            int t = tb * 32 + lane;
            s[tb] = sum_f32x2(acc2[tb]) * 0.125f + rbh[t - q + (S - 1)];
        }

        float mx = s[0];
#pragma unroll
        for (int tb = 1; tb < NT; tb++) mx = fmaxf(mx, s[tb]);
#pragma unroll
        for (int o = 16; o > 0; o >>= 1)
            mx = fmaxf(mx, __shfl_xor_sync(0xffffffffu, mx, o));
        float sum = 0.f;
#pragma unroll
        for (int tb = 0; tb < NT; tb++) { s[tb] = __expf(s[tb] - mx); sum += s[tb]; }
#pragma unroll
        for (int o = 16; o > 0; o >>= 1)
            sum += __shfl_xor_sync(0xffffffffu, sum, o);
        float inv = 1.f / sum;
#pragma unroll
        for (int tb = 0; tb < NT; tb++) s[tb] *= inv;

        float cx = 0.f, cy = 0.f;
#pragma unroll
        for (int tb = 0; tb < NT; tb++) {
            float wv = s[tb];
#pragma unroll 8
            for (int j = 0; j < 32; j++) {
                float wj = __shfl_sync(0xffffffffu, wv, j);
                float2 vf = __half22float2(Vsh[(tb * 32 + j) * 32 + lane]);
                cx += wj * vf.x;
                cy += wj * vf.y;
            }
        }
        __half hx = __float2half_rn(cx);
        __half hy = __float2half_rn(cy);
        __half lx = __float2half_rn(cx - __half2float(hx));
        __half ly = __float2half_rn(cy - __half2float(hy));
        const size_t ooff = (size_t)(base_m + q * stepTok) * E_DIM + h * D_DIM + 2 * lane;
        *(__half2*)&OutH[ooff] = __halves2half2(hx, hy);
        *(__half2*)&OutL[ooff] = __halves2half2(lx, ly);
        if (OutF) {
            float2 cf; cf.x = cx; cf.y = cy;
            *(float2*)&OutF[ooff] = cf;
        }
    }
}

// ---------------------------------------------------------------------------
// Selection softmax over token axis per (b, k), in place
// ---------------------------------------------------------------------------
__global__ __launch_bounds__(256)
void sel_softmax(float* __restrict__ sc)
{
    const int b = blockIdx.x;
    const int k0 = blockIdx.y * 32;
    const int lane = threadIdx.x & 31;
    const int row = threadIdx.x >> 5;

    float* base = sc + (size_t)b * MTOK_B * KSEL + k0 + lane;

    __shared__ float redA[8][32];
    __shared__ float redB[8][32];

    float mx = -1e30f;
    for (int m = row; m < MTOK_B; m += 8)
        mx = fmaxf(mx, base[(size_t)m * KSEL]);
    redA[row][lane] = mx;
    __syncthreads();
    if (row == 0) {
        float v = redA[0][lane];
#pragma unroll
        for (int r = 1; r < 8; r++) v = fmaxf(v, redA[r][lane]);
        redA[0][lane] = v;
    }
    __syncthreads();
    mx = redA[0][lane];

    float sum = 0.f;
    for (int m = row; m < MTOK_B; m += 8)
        sum += __expf(base[(size_t)m * KSEL] - mx);
    redB[row][lane] = sum;
    __syncthreads();
    if (row == 0) {
        float v = 0.f;
#pragma unroll
        for (int r = 0; r < 8; r++) v += redB[r][lane];
        redB[0][lane] = v;
    }
    __syncthreads();
    float inv = 1.f / redB[0][lane];

    for (int m = row; m < MTOK_B; m += 8) {
        float* p = &base[(size_t)m * KSEL];
        *p = __expf(*p - mx) * inv;
    }
}

// ---------------------------------------------------------------------------
// Multi-scale pooling
// ---------------------------------------------------------------------------
__global__ void pool_kernel(const float* __restrict__ sel, float* __restrict__ out)
{
    int idx = blockIdx.x * blockDim.x + threadIdx.x;
    int total = B_DIM * OUT_ROWS * E_DIM;
    if (idx >= total) return;
    int e = idx % E_DIM;
    int r = (idx / E_DIM) % OUT_ROWS;
    int b = idx / (OUT_ROWS * E_DIM);
    const float* sb = sel + (size_t)b * KSEL * E_DIM;
    float v;
    if (r < 256) {
        v = sb[(size_t)r * E_DIM + e];
    } else if (r < 384) {
        int i = (r - 256) * 2;
        v = 0.5f * (sb[(size_t)i * E_DIM + e] + sb[(size_t)(i + 1) * E_DIM + e]);
    } else {
        int i = (r - 384) * 4;
        v = 0.25f * (sb[(size_t)i * E_DIM + e] + sb[(size_t)(i + 1) * E_DIM + e] +
                     sb[(size_t)(i + 2) * E_DIM + e] + sb[(size_t)(i + 3) * E_DIM + e]);
    }
    out[idx] = v;
}

// ---------------------------------------------------------------------------
// Orchestration (dual-stream: weight-fold prep overlaps layer-0 compute)
// ---------------------------------------------------------------------------
extern "C" void kernel_launch(void* const* d_in, const int* in_sizes, int n_in,
                              void* d_out, int out_size)
{
    (void)in_sizes; (void)n_in; (void)out_size;

    const float* x    = (const float*)d_in[0];
    const float* wq   = (const float*)d_in[1];
    const float* bq   = (const float*)d_in[2];
    const float* wk   = (const float*)d_in[3];
    const float* bk   = (const float*)d_in[4];
    const float* wv   = (const float*)d_in[5];
    const float* bv   = (const float*)d_in[6];
    const float* wd   = (const float*)d_in[7];
    const float* bd   = (const float*)d_in[8];
    const float* rb   = (const float*)d_in[9];
    const float* selw = (const float*)d_in[10];
    const float* selb = (const float*)d_in[11];
    float* out = (float*)d_out;

    float *Hb, *SCb, *S1b, *SELb, *Bqkv, *Bcomb, *Bias2, *Bzero;
    cudaGetSymbolAddress((void**)&Hb,  g_Hb);
    cudaGetSymbolAddress((void**)&SCb, g_SC);
    cudaGetSymbolAddress((void**)&S1b, g_S1);
    cudaGetSymbolAddress((void**)&SELb, g_SEL);
    cudaGetSymbolAddress((void**)&Bqkv, g_Bqkv);
    cudaGetSymbolAddress((void**)&Bcomb, g_Bcomb);
    cudaGetSymbolAddress((void**)&Bias2, g_Bias2);
    cudaGetSymbolAddress((void**)&Bzero, g_Bzero);

    __half *QKVh, *Ahp, *Alp, *Ah2p, *Al2p, *WqkvTh, *WqkvTl, *Wd16, *WdT3, *WcT;
    __half *SWTh, *SWTl, *Bsel;
    cudaGetSymbolAddress((void**)&QKVh, g_QKVh);
    cudaGetSymbolAddress((void**)&Ahp, g_Ah);
    cudaGetSymbolAddress((void**)&Alp, g_Al);
    cudaGetSymbolAddress((void**)&Ah2p, g_Ah2);
    cudaGetSymbolAddress((void**)&Al2p, g_Al2);
    cudaGetSymbolAddress((void**)&WqkvTh, g_WqkvTh);
    cudaGetSymbolAddress((void**)&WqkvTl, g_WqkvTl);
    cudaGetSymbolAddress((void**)&Wd16, g_Wd16);
    cudaGetSymbolAddress((void**)&WdT3, g_WdT3);
    cudaGetSymbolAddress((void**)&WcT, g_WcT);
    cudaGetSymbolAddress((void**)&SWTh, g_SWTh);
    cudaGetSymbolAddress((void**)&SWTl, g_SWTl);
    cudaGetSymbolAddress((void**)&Bsel, g_Bsel);

    // second stream + fork/join events (created once; no device memory)
    static cudaStream_t s2 = nullptr;
    static cudaEvent_t evF = nullptr, evJ = nullptr;
    if (!s2) {
        cudaStreamCreateWithFlags(&s2, cudaStreamNonBlocking);
        cudaEventCreateWithFlags(&evF, cudaEventDisableTiming);
        cudaEventCreateWithFlags(&evJ, cudaEventDisableTiming);
    }

    // attention smem: K fp32 float2 transposed + V fp16 + rel bias
    const int smemSp = 32 * (256 + 1) * 8 + 256 * 32 * 4 + (2 * 256 - 1) * 4;  // 100604
    const int smemTe = 32 * (32 + 1) * 8 + 32 * 32 * 4 + (2 * 32 - 1) * 4;     // 12796
    const int SMEM1 = GSTAGES * 2 * TILE_BYTES;   // 61440
    const int SMEM2 = GSTAGES * 3 * TILE_BYTES;   // 92160
    cudaFuncSetAttribute((const void*)attn_kernel<256>,
                         cudaFuncAttributeMaxDynamicSharedMemorySize, smemSp);
    cudaFuncSetAttribute((const void*)gemm_f16<1>,
                         cudaFuncAttributeMaxDynamicSharedMemorySize, SMEM1);
    cudaFuncSetAttribute((const void*)gemm_f16<2>,
                         cudaFuncAttributeMaxDynamicSharedMemorySize, SMEM2);

    const dim3 blk(256);
    const dim3 tblk(32, 8);
    const int n4 = MTOK * E_DIM / 4;
    const dim3 gcvt((n4 + 255) / 256);
    const dim3 gQKV(QKV_N / 128, MTOK / 128);   // 24 x 128
    const size_t MM = (size_t)E_DIM * E_DIM;
    const size_t MM3 = 3 * MM;
    const size_t WCS = (size_t)QKV_N * E_DIM;

    // ---- main stream: weights needed for layer 0 ----
    wt_cvt3<<<dim3(E_DIM / 32, E_DIM / 32, 4), tblk>>>(wq, WqkvTh, WqkvTl, E_DIM, E_DIM, 0, 3);
    wt_cvt3<<<dim3(E_DIM / 32, E_DIM / 32, 4), tblk>>>(wk, WqkvTh, WqkvTl, E_DIM, E_DIM, 1, 3);
    wt_cvt3<<<dim3(E_DIM / 32, E_DIM / 32, 4), tblk>>>(wv, WqkvTh, WqkvTl, E_DIM, E_DIM, 2, 3);
    bias_concat<<<(4 * QKV_N + 255) / 256, blk>>>(bq, bk, bv, Bqkv);

    // ---- fork: fold-weight prep on s2, overlapping layer-0 compute ----
    cudaEventRecord(evF, 0);
    cudaStreamWaitEvent(s2, evF, 0);

    cvt_f16<<<(int)((4 * MM / 4 + 255) / 256), blk, 0, s2>>>(wd, Wd16, (int)(4 * MM / 4));
    gemm_f16<2><<<dim3(E_DIM / 128, QKV_N / 128, 3), blk, SMEM2, s2>>>(
        WqkvTh + MM3, WqkvTl + MM3, Wd16, Bzero, nullptr,
        WcT, nullptr, E_DIM, E_DIM, MM3, MM, WCS);
    wt_cvt<<<dim3(E_DIM / 32, E_DIM / 32, 1), tblk, 0, s2>>>(wd + 3 * MM, WdT3, E_DIM, E_DIM);
    wt_cvt3<<<dim3(KSEL / 32, E_DIM / 32, 1), tblk, 0, s2>>>(selw, SWTh, SWTl, E_DIM, KSEL, 0, 1);
    gemm_f16<2><<<dim3(E_DIM / 128, KSEL / 128), blk, SMEM2, s2>>>(
        SWTh, SWTl, Wd16 + 3 * MM, Bzero, nullptr,
        Bsel, nullptr, E_DIM, E_DIM, 0, 0, 0);
    bias_comb<<<dim3(QKV_N / 256, 3), blk, 0, s2>>>(wq, wk, wv, bd, Bqkv, Bcomb);
    bias_sel<<<1, 256, 0, s2>>>(selw, selb, bd + 3 * E_DIM, Bias2);
    cudaEventRecord(evJ, s2);

    // ---- main stream: layer 0 ----
    cvt_hilo<<<gcvt, blk>>>(x, Ah2p, Al2p, n4);
    gemm_f16<1><<<gQKV, blk, SMEM1>>>(Ah2p, nullptr, WqkvTh, Bqkv, nullptr,
                                      QKVh, nullptr, QKV_N, E_DIM, 0, 0, 0);
    {
        const float* rba = rb;
        attn_kernel<256><<<dim3(H_DIM, B_DIM * T_DIM), blk, smemSp>>>(
            QKVh, QKVh + E_DIM, QKVh + 2 * E_DIM, Ahp, Alp, nullptr, rba,
            B_DIM * T_DIM, 0, N_DIM, 1, QKV_N);
    }

    // ---- join: folded weights ready before layer 1 ----
    cudaStreamWaitEvent(0, evJ, 0);

    for (int a = 1; a < 4; a++) {
        gemm_f16<1><<<gQKV, blk, SMEM1>>>(Ahp, nullptr, WcT + (a - 1) * WCS,
                                          Bcomb + (size_t)(a - 1) * QKV_N, nullptr,
                                          QKVh, nullptr, QKV_N, E_DIM, 0, 0, 0);

        const float* rba = rb + (size_t)a * RB_ONE;
        float* ctxF = (a == 3) ? Hb : nullptr;
        if ((a & 1) == 0) {
            attn_kernel<256><<<dim3(H_DIM, B_DIM * T_DIM), blk, smemSp>>>(
                QKVh, QKVh + E_DIM, QKVh + 2 * E_DIM, Ahp, Alp, ctxF, rba,
                B_DIM * T_DIM, 0, N_DIM, 1, QKV_N);
        } else {
            attn_kernel<32><<<dim3(H_DIM, B_DIM * N_DIM), blk, smemTe>>>(
                QKVh, QKVh + E_DIM, QKVh + 2 * E_DIM, Ahp, Alp, ctxF, rba,
                N_DIM, T_DIM * N_DIM, 1, N_DIM, QKV_N);
        }
    }

    // selection scores on ctx: SC = ctx @ Bsel^T + Bias2   (2-seg, exact ctx)
    gemm_f16<2><<<dim3(KSEL / 128, MTOK / 128), blk, SMEM2>>>(
        Ahp, Alp, Bsel, Bias2, SCb, nullptr, nullptr, KSEL, E_DIM, 0, 0, 0);

    // softmax over token axis per (b, k), in place
    sel_softmax<<<dim3(B_DIM, KSEL / 32), blk>>>(SCb);

    // S1[b,k,e] = sum_m wts[b,m,k] * ctx[b,m,e]  (fp32 split-K + atomics)
    cudaMemsetAsync(S1b, 0, (size_t)B_DIM * KSEL * E_DIM * sizeof(float));
    gemm_sel_atomic<<<dim3(E_DIM / 128, KSEL / 128, B_DIM * SPLITK), blk>>>(SCb, Hb, S1b);

    // SEL = S1 @ Wd3 + bd3  (tiny 2-seg GEMM)
    cvt_hilo<<<dim3((B_DIM * KSEL * E_DIM / 4 + 255) / 256), blk>>>(
        S1b, Ah2p, Al2p, B_DIM * KSEL * E_DIM / 4);
    gemm_f16<2><<<dim3(E_DIM / 128, (B_DIM * KSEL) / 128), blk, SMEM2>>>(
        Ah2p, Al2p, WdT3, bd + 3 * E_DIM, SELb, nullptr, nullptr, E_DIM, E_DIM, 0, 0, 0);

    // multi-scale pooling -> output [B, 448, E]
    int total = B_DIM * OUT_ROWS * E_DIM;
    pool_kernel<<<(total + 255) / 256, 256>>>(SELb, out);
}

// round 12
// speedup vs baseline: 2.6053x; 1.4959x over previous
#include <cuda_runtime.h>
#include <cuda_fp16.h>
#include <cstdint>
#include <cstddef>

// ---------------------------------------------------------------------------
// Problem constants
// ---------------------------------------------------------------------------
#define E_DIM   1024
#define QKV_N   3072
#define H_DIM   16
#define D_DIM   64
#define B_DIM   2
#define T_DIM   32
#define N_DIM   256
#define MTOK    (B_DIM * T_DIM * N_DIM)   // 16384 tokens total
#define MTOK_B  (T_DIM * N_DIM)           // 8192 tokens per batch
#define KSEL    256
#define MAXLEN  512
#define RB_ONE  ((2 * MAXLEN - 1) * H_DIM)
#define OUT_ROWS 448                      // 256 + 128 + 64
#define SPLITK  8

// ---------------------------------------------------------------------------
// Scratch (device globals — no allocations allowed)
// ---------------------------------------------------------------------------
__device__ __half g_QKVh[MTOK * QKV_N];   // merged Q|K|V per token, fp16
__device__ float g_Hb[MTOK * E_DIM];      // layer-3 ctx fp32 (for selection)
__device__ float g_SC[MTOK * KSEL];
__device__ float g_S1[B_DIM * KSEL * E_DIM];   // wts^T @ ctx
__device__ float g_SEL[B_DIM * KSEL * E_DIM];  // final selected tokens

// fp16 split activations: ping (attention out) and pong (misc)
__device__ __half g_Ah[MTOK * E_DIM];
__device__ __half g_Al[MTOK * E_DIM];
__device__ __half g_Ah2[MTOK * E_DIM];
__device__ __half g_Al2[MTOK * E_DIM];
// transposed fp16 weights
__device__ __half g_WqkvTh[4 * 3 * E_DIM * E_DIM];  // [a][q|k|v][N=E][K=E] hi
__device__ __half g_WqkvTl[4 * 3 * E_DIM * E_DIM];  // lo
__device__ __half g_Wd16[4 * E_DIM * E_DIM];        // wd plain (row-major) fp16
__device__ __half g_WdT3[E_DIM * E_DIM];            // wd[3] transposed fp16
__device__ __half g_WcT[3 * QKV_N * E_DIM];         // combined W'^T = (Wd_a Wqkv_{a+1})^T fp16
__device__ __half g_SWTh[KSEL * E_DIM];             // selw^T hi
__device__ __half g_SWTl[KSEL * E_DIM];             // selw^T lo
__device__ __half g_Bsel[KSEL * E_DIM];             // (Wd3 @ selw)^T fp16
__device__ float  g_Bqkv[4 * QKV_N];                // merged qkv bias per attn idx
__device__ float  g_Bcomb[3 * QKV_N];               // combined bias bd_a@Wqkv_{a+1}+b_{a+1}
__device__ float  g_Bias2[KSEL];                    // bd3@selw + selb
__device__ float  g_Bzero[E_DIM];                   // zero bias (static zero-init)

// ---------------------------------------------------------------------------
// PTX helpers
// ---------------------------------------------------------------------------
__device__ __forceinline__ void cp_async16(uint32_t dst, const void* src) {
    asm volatile("cp.async.cg.shared.global [%0], [%1], 16;" :: "r"(dst), "l"(src));
}
__device__ __forceinline__ void cp_commit() {
    asm volatile("cp.async.commit_group;" ::: "memory");
}
template <int N>
__device__ __forceinline__ void cp_wait_group() {
    asm volatile("cp.async.wait_group %0;" :: "n"(N) : "memory");
}
__device__ __forceinline__ void ldmatrix_x4(uint32_t* r, uint32_t addr) {
    asm volatile("ldmatrix.sync.aligned.m8n8.x4.shared.b16 {%0,%1,%2,%3}, [%4];"
                 : "=r"(r[0]), "=r"(r[1]), "=r"(r[2]), "=r"(r[3]) : "r"(addr));
}
__device__ __forceinline__ void mma_f16(float* d, const uint32_t* a,
                                        uint32_t b0, uint32_t b1) {
    asm volatile(
        "mma.sync.aligned.m16n8k16.row.col.f32.f16.f16.f32 "
        "{%0,%1,%2,%3}, {%4,%5,%6,%7}, {%8,%9}, {%0,%1,%2,%3};"
        : "+f"(d[0]), "+f"(d[1]), "+f"(d[2]), "+f"(d[3])
        : "r"(a[0]), "r"(a[1]), "r"(a[2]), "r"(a[3]), "r"(b0), "r"(b1));
}
__device__ __forceinline__ unsigned long long pack_f32x2(float x, float y) {
    unsigned long long r;
    asm("mov.b64 %0, {%1, %2};" : "=l"(r) : "r"(__float_as_uint(x)), "r"(__float_as_uint(y)));
    return r;
}
__device__ __forceinline__ void fma_f32x2(unsigned long long& d,
                                          unsigned long long a, unsigned long long b) {
    asm("fma.rn.f32x2 %0, %1, %2, %0;" : "+l"(d) : "l"(a), "l"(b));
}
__device__ __forceinline__ float sum_f32x2(unsigned long long v) {
    uint32_t lo, hi;
    asm("mov.b64 {%0, %1}, %2;" : "=r"(lo), "=r"(hi) : "l"(v));
    return __uint_as_float(lo) + __uint_as_float(hi);
}
__device__ __forceinline__ uint32_t h2pack(float a, float b) {
    __half2 h = __floats2half2_rn(a, b);
    return *(uint32_t*)&h;
}

// ---------------------------------------------------------------------------
// fp16 GEMM via mma.sync (1 or 2 A segments); optional fp32/fp16hi/fp16lo out.
// ---------------------------------------------------------------------------
#define GSTAGES 3
#define ROWPAD  40
#define TILE_BYTES (128 * ROWPAD * 2)

template <int SEGS>
__global__ __launch_bounds__(256, 2)
void gemm_f16(const __half* __restrict__ Ah, const __half* __restrict__ Al,
              const __half* __restrict__ B,
              const float* __restrict__ bias, float* __restrict__ C,
              __half* __restrict__ Ch, __half* __restrict__ Cl,
              int Nfull, int Kfull,
              size_t zA, size_t zB, size_t zC)
{
    constexpr int STB = (SEGS + 1) * TILE_BYTES;

    extern __shared__ char smem[];
    const uint32_t sb = (uint32_t)__cvta_generic_to_shared(smem);
    const int tid = threadIdx.x;
    const int lane = tid & 31;
    const int warp = tid >> 5;
    const int wm = warp >> 1;
    const int wn = warp & 1;
    const int m0 = blockIdx.y * 128;
    const int n0 = blockIdx.x * 128;

    Ah += (size_t)blockIdx.z * zA;
    if (SEGS == 2) Al += (size_t)blockIdx.z * zA;
    B  += (size_t)blockIdx.z * zB;
    if (C)  C  += (size_t)blockIdx.z * zC;
    if (Ch) Ch += (size_t)blockIdx.z * zC;
    if (Cl) Cl += (size_t)blockIdx.z * zC;

    const int NCH = Kfull >> 5;
    const int lr0 = tid >> 1;
    const int ls0 = (tid & 1) << 1;

    float acc[2][8][4];
#pragma unroll
    for (int mi = 0; mi < 2; mi++)
#pragma unroll
        for (int ni = 0; ni < 8; ni++)
#pragma unroll
            for (int q = 0; q < 4; q++) acc[mi][ni][q] = 0.f;

    auto load_chunk = [&](int c, int stage) {
        const int kb = c << 5;
        const uint32_t base = sb + stage * STB;
#pragma unroll
        for (int j = 0; j < 2; j++) {
            const int s4 = ls0 + j;
            const uint32_t soff = (uint32_t)(lr0 * ROWPAD + s4 * 8) * 2;
            const size_t goff = (size_t)lr0 * Kfull + kb + s4 * 8;
            cp_async16(base + soff, Ah + (size_t)m0 * Kfull + goff);
            if (SEGS == 2)
                cp_async16(base + TILE_BYTES + soff, Al + (size_t)m0 * Kfull + goff);
            cp_async16(base + SEGS * TILE_BYTES + soff, B + (size_t)n0 * Kfull + goff);
        }
    };

#pragma unroll
    for (int s = 0; s < GSTAGES - 1; s++) {
        if (s < NCH) load_chunk(s, s);
        cp_commit();
    }

    const int la_i = lane & 7;
    const int la_g = lane >> 3;
    const int a_rowadd = la_i + ((la_g & 1) << 3);
    const int a_coladd = (la_g >> 1) << 3;
    const int b_rowadd = la_i + ((la_g >> 1) << 3);
    const int b_coladd = (la_g & 1) << 3;

    for (int c = 0; c < NCH; c++) {
        const int stage = c % GSTAGES;
        cp_wait_group<GSTAGES - 2>();
        __syncthreads();

        const int nc = c + GSTAGES - 1;
        if (nc < NCH) load_chunk(nc, nc % GSTAGES);
        cp_commit();

        const uint32_t base = sb + stage * STB;
        const uint32_t Bbase = base + SEGS * TILE_BYTES;

#pragma unroll
        for (int k16 = 0; k16 < 32; k16 += 16) {
            uint32_t bf[4][4];
#pragma unroll
            for (int nb = 0; nb < 4; nb++) {
                const int row = wn * 64 + nb * 16 + b_rowadd;
                const int col = k16 + b_coladd;
                ldmatrix_x4(bf[nb], Bbase + (uint32_t)(row * ROWPAD + col) * 2);
            }
#pragma unroll
            for (int seg = 0; seg < SEGS; seg++) {
                const uint32_t Abase = base + seg * TILE_BYTES;
                uint32_t af[2][4];
#pragma unroll
                for (int mi = 0; mi < 2; mi++) {
                    const int row = wm * 32 + mi * 16 + a_rowadd;
                    const int col = k16 + a_coladd;
                    ldmatrix_x4(af[mi], Abase + (uint32_t)(row * ROWPAD + col) * 2);
                }
#pragma unroll
                for (int nb = 0; nb < 4; nb++)
#pragma unroll
                    for (int mi = 0; mi < 2; mi++) {
                        mma_f16(acc[mi][nb * 2 + 0], af[mi], bf[nb][0], bf[nb][1]);
                        mma_f16(acc[mi][nb * 2 + 1], af[mi], bf[nb][2], bf[nb][3]);
                    }
            }
        }
    }

    const int tq = lane >> 2;
    const int tr = lane & 3;
#pragma unroll
    for (int mi = 0; mi < 2; mi++) {
        const int row = m0 + wm * 32 + mi * 16 + tq;
#pragma unroll
        for (int ni = 0; ni < 8; ni++) {
            const int col = n0 + wn * 64 + ni * 8 + tr * 2;
            const float b0 = bias[col], b1 = bias[col + 1];
            float c00 = acc[mi][ni][0] + b0, c01 = acc[mi][ni][1] + b1;
            float c10 = acc[mi][ni][2] + b0, c11 = acc[mi][ni][3] + b1;
            if (C) {
                float2 v0; v0.x = c00; v0.y = c01;
                float2 v1; v1.x = c10; v1.y = c11;
                *(float2*)&C[(size_t)row * Nfull + col] = v0;
                *(float2*)&C[(size_t)(row + 8) * Nfull + col] = v1;
            }
            if (Ch || Cl) {
                __half h00 = __float2half_rn(c00);
                __half h01 = __float2half_rn(c01);
                __half h10 = __float2half_rn(c10);
                __half h11 = __float2half_rn(c11);
                if (Ch) {
                    *(__half2*)&Ch[(size_t)row * Nfull + col]       = __halves2half2(h00, h01);
                    *(__half2*)&Ch[(size_t)(row + 8) * Nfull + col] = __halves2half2(h10, h11);
                }
                if (Cl) {
                    __half l00 = __float2half_rn(c00 - __half2float(h00));
                    __half l01 = __float2half_rn(c01 - __half2float(h01));
                    __half l10 = __float2half_rn(c10 - __half2float(h10));
                    __half l11 = __float2half_rn(c11 - __half2float(h11));
                    *(__half2*)&Cl[(size_t)row * Nfull + col]       = __halves2half2(l00, l01);
                    *(__half2*)&Cl[(size_t)(row + 8) * Nfull + col] = __halves2half2(l10, l11);
                }
            }
        }
    }
}

// ---------------------------------------------------------------------------
// mma.sync spatial attention (S=256, step 1), flash-style online softmax.
// Block: 8 warps x 16 q-rows = 128 rows; grid (H, groups, 2 q-halves).
// smem: K [256][72] fp16 (also Q staging), V^T [64][264] fp16, rbh [511] f32.
// ---------------------------------------------------------------------------
#define AKS_BYTES  (256 * 72 * 2)           // 36864
#define AVT_BYTES  (64 * 264 * 2)           // 33792
#define ATTN_SMEM  (AKS_BYTES + AVT_BYTES + 512 * 4)   // 74704

__global__ __launch_bounds__(256)
void attn_mma(const __half* __restrict__ Q, const __half* __restrict__ K,
              const __half* __restrict__ V,
              __half* __restrict__ OutH, __half* __restrict__ OutL,
              const float* __restrict__ rb, int ldx)
{
    const int h = blockIdx.x;
    const int g = blockIdx.y;
    const int qh = blockIdx.z;
    const int base_m = g * N_DIM;
    const size_t baseE = (size_t)base_m * ldx + h * D_DIM;

    extern __shared__ char sm8[];
    __half* Ks = (__half*)sm8;                       // [256][72]
    __half* Vt = (__half*)(sm8 + AKS_BYTES);         // [64][264]
    float*  rbh = (float*)(sm8 + AKS_BYTES + AVT_BYTES);
    const uint32_t sKs = (uint32_t)__cvta_generic_to_shared(Ks);
    const uint32_t sVt = (uint32_t)__cvta_generic_to_shared(Vt);

    const int tid = threadIdx.x;
    const int lane = tid & 31;
    const int warp = tid >> 5;

    // ---- stage this half's Q rows into Ks region, extract fragments ----
    for (int i = tid; i < 128 * 8; i += 256) {
        int r = i >> 3, cs = i & 7;
        *(float4*)&Ks[r * 72 + cs * 8] =
            *(const float4*)(Q + baseE + (size_t)(qh * 128 + r) * ldx + cs * 8);
    }
    __syncthreads();

    const int la_i = lane & 7;
    const int la_g = lane >> 3;
    const int a_rowadd = la_i + ((la_g & 1) << 3);
    const int a_coladd = (la_g >> 1) << 3;
    const int b_rowadd = la_i + ((la_g >> 1) << 3);
    const int b_coladd = (la_g & 1) << 3;

    uint32_t Qf[4][4];
    const int wq = warp * 16;
#pragma unroll
    for (int kk = 0; kk < 4; kk++)
        ldmatrix_x4(Qf[kk], sKs + (uint32_t)((wq + a_rowadd) * 72 + kk * 16 + a_coladd) * 2);
    __syncthreads();

    // ---- load K, V^T, rel-bias ----
    for (int i = tid; i < 256 * 8; i += 256) {
        int r = i >> 3, cs = i & 7;
        *(float4*)&Ks[r * 72 + cs * 8] =
            *(const float4*)(K + baseE + (size_t)r * ldx + cs * 8);
    }
    for (int i = tid; i < 256 * 32; i += 256) {
        int t = i >> 5, d2 = i & 31;
        __half2 v = *(const __half2*)(V + baseE + (size_t)t * ldx + 2 * d2);
        Vt[(2 * d2) * 264 + t]     = __low2half(v);
        Vt[(2 * d2 + 1) * 264 + t] = __high2half(v);
    }
    for (int i = tid; i < 511; i += 256)
        rbh[i] = rb[(size_t)(MAXLEN - 256 + i) * H_DIM + h];
    __syncthreads();

    const int tq = lane >> 2;
    const int tr = lane & 3;
    const int r0 = qh * 128 + wq + tq;
    const int r1 = r0 + 8;

    float o[8][4];
#pragma unroll
    for (int j = 0; j < 8; j++)
#pragma unroll
        for (int q = 0; q < 4; q++) o[j][q] = 0.f;
    float m0 = -1e30f, m1 = -1e30f, l0 = 0.f, l1 = 0.f;

#pragma unroll
    for (int ch = 0; ch < 4; ch++) {
        float s[8][4];
#pragma unroll
        for (int j = 0; j < 8; j++)
#pragma unroll
            for (int q = 0; q < 4; q++) s[j][q] = 0.f;

        // S-chunk = Q . K^T  (rows wq..+16, cols ch*64..+64)
#pragma unroll
        for (int kk = 0; kk < 4; kk++) {
#pragma unroll
            for (int nb = 0; nb < 4; nb++) {
                uint32_t bf[4];
                ldmatrix_x4(bf, sKs + (uint32_t)((ch * 64 + nb * 16 + b_rowadd) * 72
                                                 + kk * 16 + b_coladd) * 2);
                mma_f16(s[nb * 2 + 0], Qf[kk], bf[0], bf[1]);
                mma_f16(s[nb * 2 + 1], Qf[kk], bf[2], bf[3]);
            }
        }

        // scale + rel bias; chunk row max
        float cm0 = -1e30f, cm1 = -1e30f;
#pragma unroll
        for (int j = 0; j < 8; j++) {
            const int c = ch * 64 + j * 8 + 2 * tr;
            s[j][0] = s[j][0] * 0.125f + rbh[c - r0 + 255];
            s[j][1] = s[j][1] * 0.125f + rbh[c + 1 - r0 + 255];
            s[j][2] = s[j][2] * 0.125f + rbh[c - r1 + 255];
            s[j][3] = s[j][3] * 0.125f + rbh[c + 1 - r1 + 255];
            cm0 = fmaxf(cm0, fmaxf(s[j][0], s[j][1]));
            cm1 = fmaxf(cm1, fmaxf(s[j][2], s[j][3]));
        }
        cm0 = fmaxf(cm0, __shfl_xor_sync(0xffffffffu, cm0, 1));
        cm0 = fmaxf(cm0, __shfl_xor_sync(0xffffffffu, cm0, 2));
        cm1 = fmaxf(cm1, __shfl_xor_sync(0xffffffffu, cm1, 1));
        cm1 = fmaxf(cm1, __shfl_xor_sync(0xffffffffu, cm1, 2));

        const float nm0 = fmaxf(m0, cm0), nm1 = fmaxf(m1, cm1);
        const float sc0 = __expf(m0 - nm0), sc1 = __expf(m1 - nm1);
        float rs0 = 0.f, rs1 = 0.f;
#pragma unroll
        for (int j = 0; j < 8; j++) {
            s[j][0] = __expf(s[j][0] - nm0);
            s[j][1] = __expf(s[j][1] - nm0);
            s[j][2] = __expf(s[j][2] - nm1);
            s[j][3] = __expf(s[j][3] - nm1);
            rs0 += s[j][0] + s[j][1];
            rs1 += s[j][2] + s[j][3];
        }
        rs0 += __shfl_xor_sync(0xffffffffu, rs0, 1);
        rs0 += __shfl_xor_sync(0xffffffffu, rs0, 2);
        rs1 += __shfl_xor_sync(0xffffffffu, rs1, 1);
        rs1 += __shfl_xor_sync(0xffffffffu, rs1, 2);
        l0 = l0 * sc0 + rs0;
        l1 = l1 * sc1 + rs1;
        m0 = nm0; m1 = nm1;
#pragma unroll
        for (int j = 0; j < 8; j++) {
            o[j][0] *= sc0; o[j][1] *= sc0;
            o[j][2] *= sc1; o[j][3] *= sc1;
        }

        // pack P chunk into A fragments (C-frag -> A-frag correspondence)
        uint32_t pa[4][4];
#pragma unroll
        for (int kk = 0; kk < 4; kk++) {
            pa[kk][0] = h2pack(s[2 * kk][0], s[2 * kk][1]);
            pa[kk][1] = h2pack(s[2 * kk][2], s[2 * kk][3]);
            pa[kk][2] = h2pack(s[2 * kk + 1][0], s[2 * kk + 1][1]);
            pa[kk][3] = h2pack(s[2 * kk + 1][2], s[2 * kk + 1][3]);
        }

        // o += P . V   (B = V^T [d][t])
#pragma unroll
        for (int kk = 0; kk < 4; kk++) {
#pragma unroll
            for (int nb = 0; nb < 4; nb++) {
                uint32_t bf[4];
                ldmatrix_x4(bf, sVt + (uint32_t)((nb * 16 + b_rowadd) * 264
                                                 + ch * 64 + kk * 16 + b_coladd) * 2);
                mma_f16(o[nb * 2 + 0], pa[kk], bf[0], bf[1]);
                mma_f16(o[nb * 2 + 1], pa[kk], bf[2], bf[3]);
            }
        }
    }

    const float inv0 = 1.f / l0, inv1 = 1.f / l1;
    const size_t oo0 = (size_t)(base_m + r0) * E_DIM + h * D_DIM;
    const size_t oo1 = (size_t)(base_m + r1) * E_DIM + h * D_DIM;
#pragma unroll
    for (int j = 0; j < 8; j++) {
        const int c = j * 8 + 2 * tr;
        float c00 = o[j][0] * inv0, c01 = o[j][1] * inv0;
        float c10 = o[j][2] * inv1, c11 = o[j][3] * inv1;
        __half h00 = __float2half_rn(c00), h01 = __float2half_rn(c01);
        __half h10 = __float2half_rn(c10), h11 = __float2half_rn(c11);
        *(__half2*)&OutH[oo0 + c] = __halves2half2(h00, h01);
        *(__half2*)&OutH[oo1 + c] = __halves2half2(h10, h11);
        *(__half2*)&OutL[oo0 + c] = __halves2half2(
            __float2half_rn(c00 - __half2float(h00)), __float2half_rn(c01 - __half2float(h01)));
        *(__half2*)&OutL[oo1 + c] = __halves2half2(
            __float2half_rn(c10 - __half2float(h10)), __float2half_rn(c11 - __half2float(h11)));
    }
}

// ---------------------------------------------------------------------------
// misc elementwise / prep kernels
// ---------------------------------------------------------------------------
__global__ void cvt_hilo(const float* __restrict__ x, __half* __restrict__ hi,
                         __half* __restrict__ lo, int n4)
{
    int i = blockIdx.x * blockDim.x + threadIdx.x;
    if (i >= n4) return;
    float4 v = ((const float4*)x)[i];
    __half h0 = __float2half_rn(v.x);
    __half h1 = __float2half_rn(v.y);
    __half h2 = __float2half_rn(v.z);
    __half h3 = __float2half_rn(v.w);
    __half l0 = __float2half_rn(v.x - __half2float(h0));
    __half l1 = __float2half_rn(v.y - __half2float(h1));
    __half l2 = __float2half_rn(v.z - __half2float(h2));
    __half l3 = __float2half_rn(v.w - __half2float(h3));
    __half2* hp = (__half2*)hi;
    __half2* lp = (__half2*)lo;
    hp[2 * i + 0] = __half2(h0, h1);
    hp[2 * i + 1] = __half2(h2, h3);
    lp[2 * i + 0] = __half2(l0, l1);
    lp[2 * i + 1] = __half2(l2, l3);
}

__global__ void cvt_f16(const float* __restrict__ x, __half* __restrict__ y, int n4)
{
    int i = blockIdx.x * blockDim.x + threadIdx.x;
    if (i >= n4) return;
    float4 v = ((const float4*)x)[i];
    __half2* yp = (__half2*)y;
    yp[2 * i + 0] = __floats2half2_rn(v.x, v.y);
    yp[2 * i + 1] = __floats2half2_rn(v.z, v.w);
}

__global__ void wt_cvt3(const float* __restrict__ W, __half* __restrict__ WTh,
                        __half* __restrict__ WTl, int Kd, int Nd, int type, int slots)
{
    __shared__ float t[32][33];
    const size_t srcoff = (size_t)blockIdx.z * Kd * Nd;
    const size_t dstoff = ((size_t)blockIdx.z * slots + type) * Kd * Nd;
    const float* Wm = W + srcoff;
    __half* Hh = WTh + dstoff;
    __half* Hl = WTl + dstoff;

    int nx = blockIdx.x * 32 + threadIdx.x;
    int k0 = blockIdx.y * 32;
#pragma unroll
    for (int j = 0; j < 4; j++) {
        int kk = k0 + threadIdx.y + j * 8;
        t[threadIdx.y + j * 8][threadIdx.x] = Wm[(size_t)kk * Nd + nx];
    }
    __syncthreads();
    int kx = k0 + threadIdx.x;
#pragma unroll
    for (int j = 0; j < 4; j++) {
        int nn = blockIdx.x * 32 + threadIdx.y + j * 8;
        float v = t[threadIdx.x][threadIdx.y + j * 8];
        __half h = __float2half_rn(v);
        Hh[(size_t)nn * Kd + kx] = h;
        Hl[(size_t)nn * Kd + kx] = __float2half_rn(v - __half2float(h));
    }
}

__global__ void wt_cvt(const float* __restrict__ W, __half* __restrict__ WT,
                       int Kd, int Nd)
{
    __shared__ float t[32][33];
    const size_t moff = (size_t)blockIdx.z * Kd * Nd;
    const float* Wm = W + moff;
    __half* Hh = WT + moff;

    int nx = blockIdx.x * 32 + threadIdx.x;
    int k0 = blockIdx.y * 32;
#pragma unroll
    for (int j = 0; j < 4; j++) {
        int kk = k0 + threadIdx.y + j * 8;
        t[threadIdx.y + j * 8][threadIdx.x] = Wm[(size_t)kk * Nd + nx];
    }
    __syncthreads();
    int kx = k0 + threadIdx.x;
#pragma unroll
    for (int j = 0; j < 4; j++) {
        int nn = blockIdx.x * 32 + threadIdx.y + j * 8;
        Hh[(size_t)nn * Kd + kx] = __float2half_rn(t[threadIdx.x][threadIdx.y + j * 8]);
    }
}

__global__ void bias_concat(const float* __restrict__ bq, const float* __restrict__ bk,
                            const float* __restrict__ bv, float* __restrict__ out)
{
    int i = blockIdx.x * blockDim.x + threadIdx.x;
    if (i >= 4 * QKV_N) return;
    int a = i / QKV_N;
    int r = i % QKV_N;
    const float* src = (r < E_DIM) ? bq : (r < 2 * E_DIM) ? bk : bv;
    out[i] = src[a * E_DIM + (r & (E_DIM - 1))];
}

__global__ void bias_comb(const float* __restrict__ wq, const float* __restrict__ wk,
                          const float* __restrict__ wv, const float* __restrict__ bd,
                          const float* __restrict__ bqkv, float* __restrict__ out)
{
    int i = blockIdx.x * blockDim.x + threadIdx.x;
    int z = blockIdx.y;
    const float* W = (i < E_DIM) ? wq : (i < 2 * E_DIM) ? wk : wv;
    int col = i & (E_DIM - 1);
    const float* Wm = W + (size_t)(z + 1) * E_DIM * E_DIM;
    const float* bdz = bd + (size_t)z * E_DIM;
    float s = 0.f;
    for (int k = 0; k < E_DIM; k++)
        s += bdz[k] * Wm[(size_t)k * E_DIM + col];
    out[(size_t)z * QKV_N + i] = s + bqkv[(size_t)(z + 1) * QKV_N + i];
}

__global__ void bias_sel(const float* __restrict__ selw, const float* __restrict__ selb,
                         const float* __restrict__ bd3, float* __restrict__ out)
{
    int k = blockIdx.x * blockDim.x + threadIdx.x;
    if (k >= KSEL) return;
    float s = 0.f;
    for (int e = 0; e < E_DIM; e++)
        s += bd3[e] * selw[(size_t)e * KSEL + k];
    out[k] = s + selb[k];
}

// ---------------------------------------------------------------------------
// Split-K selection GEMM (fp32, atomics)
// ---------------------------------------------------------------------------
__global__ __launch_bounds__(256, 2)
void gemm_sel_atomic(const float* __restrict__ Wts, const float* __restrict__ Flat,
                     float* __restrict__ Csel)
{
    __shared__ float As[16][128];
    __shared__ float Bs[16][128];

    const int tid = threadIdx.x;
    const int bx = blockIdx.x;
    const int by = blockIdx.y;
    const int b  = blockIdx.z / SPLITK;
    const int sl = blockIdx.z % SPLITK;

    const float* A = Wts  + (size_t)b * MTOK_B * KSEL;
    const float* B = Flat + (size_t)b * MTOK_B * E_DIM;
    float*       C = Csel + (size_t)b * KSEL * E_DIM;

    const int lr = (tid & 31) << 2;
    const int lk = tid >> 5;
    const int tx = tid & 15;
    const int ty = tid >> 4;

    const int kbeg = sl * (MTOK_B / SPLITK);
    const int kend = kbeg + (MTOK_B / SPLITK);

    float acc[8][8];
#pragma unroll
    for (int i = 0; i < 8; i++)
#pragma unroll
        for (int j = 0; j < 8; j++) acc[i][j] = 0.f;

    for (int k0 = kbeg; k0 < kend; k0 += 16) {
        *(float4*)&As[lk][lr]     = *(const float4*)&A[(size_t)(k0 + lk) * KSEL + by * 128 + lr];
        *(float4*)&As[lk + 8][lr] = *(const float4*)&A[(size_t)(k0 + lk + 8) * KSEL + by * 128 + lr];
        *(float4*)&Bs[lk][lr]     = *(const float4*)&B[(size_t)(k0 + lk) * E_DIM + bx * 128 + lr];
        *(float4*)&Bs[lk + 8][lr] = *(const float4*)&B[(size_t)(k0 + lk + 8) * E_DIM + bx * 128 + lr];
        __syncthreads();

#pragma unroll
        for (int kk = 0; kk < 16; kk++) {
            float ar[8], br[8];
            *(float4*)&ar[0] = *(const float4*)&As[kk][ty * 8];
            *(float4*)&ar[4] = *(const float4*)&As[kk][ty * 8 + 4];
            *(float4*)&br[0] = *(const float4*)&Bs[kk][tx * 8];
            *(float4*)&br[4] = *(const float4*)&Bs[kk][tx * 8 + 4];
#pragma unroll
            for (int i = 0; i < 8; i++)
#pragma unroll
                for (int j = 0; j < 8; j++)
                    acc[i][j] += ar[i] * br[j];
        }
        __syncthreads();
    }

#pragma unroll
    for (int i = 0; i < 8; i++) {
        float* cp = C + (size_t)(by * 128 + ty * 8 + i) * E_DIM + bx * 128 + tx * 8;
#pragma unroll
        for (int j = 0; j < 8; j++)
            atomicAdd(&cp[j], acc[i][j]);
    }
}

// ---------------------------------------------------------------------------
// SIMT attention (temporal S=32): K fp32 f32x2 QK loop, V fp16
// ---------------------------------------------------------------------------
template <int S>
__global__ __launch_bounds__(256)
void attn_kernel(const __half* __restrict__ Q, const __half* __restrict__ K,
                 const __half* __restrict__ V,
                 __half* __restrict__ OutH, __half* __restrict__ OutL,
                 float* __restrict__ OutF,
                 const float* __restrict__ rb,
                 int div, int mulq, int mulr, int stepTok, int ldx)
{
    const int h = blockIdx.x;
    const int g = blockIdx.y;
    const int base_m = (g / div) * mulq + (g % div) * mulr;
    const size_t baseE = (size_t)base_m * ldx + h * D_DIM;
    const size_t stepE = (size_t)stepTok * ldx;

    extern __shared__ float sm[];
    float2*  Kt2 = (float2*)sm;
    __half2* Vsh = (__half2*)(Kt2 + 32 * (S + 1));
    float*   rbh = (float*)(Vsh + S * 32);

    const int tid = threadIdx.x;

    for (int idx = tid; idx < S * 32; idx += 256) {
        int t = idx >> 5, d2 = idx & 31;
        size_t off = baseE + (size_t)t * stepE;
        Kt2[d2 * (S + 1) + t] = __half22float2(*(const __half2*)&K[off + 2 * d2]);
        Vsh[idx]              = *(const __half2*)&V[off + 2 * d2];
    }
    for (int i = tid; i < 2 * S - 1; i += 256)
        rbh[i] = rb[(size_t)(MAXLEN - S + i) * H_DIM + h];
    __syncthreads();

    const int lane = tid & 31;
    const int warp = tid >> 5;
    const int NT = S / 32;

    for (int q = warp; q < S; q += 8) {
        size_t qoff = baseE + (size_t)q * stepE;
        float2 ql = __half22float2(*(const __half2*)&Q[qoff + 2 * lane]);

        unsigned long long acc2[NT];
#pragma unroll
        for (int tb = 0; tb < NT; tb++) acc2[tb] = 0ull;

#pragma unroll 4
        for (int d2 = 0; d2 < 32; d2++) {
            float qx = __shfl_sync(0xffffffffu, ql.x, d2);
            float qy = __shfl_sync(0xffffffffu, ql.y, d2);
            unsigned long long q2 = pack_f32x2(qx, qy);
            const unsigned long long* kr =
                (const unsigned long long*)&Kt2[d2 * (S + 1) + lane];
#pragma unroll
            for (int tb = 0; tb < NT; tb++)
                fma_f32x2(acc2[tb], q2, kr[tb * 32]);
        }

        float s[NT];
#pragma unroll
        for (int tb = 0; tb < NT; tb++) {
            int t = tb * 32 + lane;
            s[tb] = sum_f32x2(acc2[tb]) * 0.125f + rbh[t - q + (S - 1)];
        }

        float mx = s[0];
#pragma unroll
        for (int tb = 1; tb < NT; tb++) mx = fmaxf(mx, s[tb]);
#pragma unroll
        for (int o = 16; o > 0; o >>= 1)
            mx = fmaxf(mx, __shfl_xor_sync(0xffffffffu, mx, o));
        float sum = 0.f;
#pragma unroll
        for (int tb = 0; tb < NT; tb++) { s[tb] = __expf(s[tb] - mx); sum += s[tb]; }
#pragma unroll
        for (int o = 16; o > 0; o >>= 1)
            sum += __shfl_xor_sync(0xffffffffu, sum, o);
        float inv = 1.f / sum;
#pragma unroll
        for (int tb = 0; tb < NT; tb++) s[tb] *= inv;

        float cx = 0.f, cy = 0.f;
#pragma unroll
        for (int tb = 0; tb < NT; tb++) {
            float wv = s[tb];
#pragma unroll 8
            for (int j = 0; j < 32; j++) {
                float wj = __shfl_sync(0xffffffffu, wv, j);
                float2 vf = __half22float2(Vsh[(tb * 32 + j) * 32 + lane]);
                cx += wj * vf.x;
                cy += wj * vf.y;
            }
        }
        __half hx = __float2half_rn(cx);
        __half hy = __float2half_rn(cy);
        __half lx = __float2half_rn(cx - __half2float(hx));
        __half ly = __float2half_rn(cy - __half2float(hy));
        const size_t ooff = (size_t)(base_m + q * stepTok) * E_DIM + h * D_DIM + 2 * lane;
        *(__half2*)&OutH[ooff] = __halves2half2(hx, hy);
        *(__half2*)&OutL[ooff] = __halves2half2(lx, ly);
        if (OutF) {
            float2 cf; cf.x = cx; cf.y = cy;
            *(float2*)&OutF[ooff] = cf;
        }
    }
}

// ---------------------------------------------------------------------------
// Selection softmax / pooling
// ---------------------------------------------------------------------------
__global__ __launch_bounds__(256)
void sel_softmax(float* __restrict__ sc)
{
    const int b = blockIdx.x;
    const int k0 = blockIdx.y * 32;
    const int lane = threadIdx.x & 31;
    const int row = threadIdx.x >> 5;

    float* base = sc + (size_t)b * MTOK_B * KSEL + k0 + lane;

    __shared__ float redA[8][32];
    __shared__ float redB[8][32];

    float mx = -1e30f;
    for (int m = row; m < MTOK_B; m += 8)
        mx = fmaxf(mx, base[(size_t)m * KSEL]);
    redA[row][lane] = mx;
    __syncthreads();
    if (row == 0) {
        float v = redA[0][lane];
#pragma unroll
        for (int r = 1; r < 8; r++) v = fmaxf(v, redA[r][lane]);
        redA[0][lane] = v;
    }
    __syncthreads();
    mx = redA[0][lane];

    float sum = 0.f;
    for (int m = row; m < MTOK_B; m += 8)
        sum += __expf(base[(size_t)m * KSEL] - mx);
    redB[row][lane] = sum;
    __syncthreads();
    if (row == 0) {
        float v = 0.f;
#pragma unroll
        for (int r = 0; r < 8; r++) v += redB[r][lane];
        redB[0][lane] = v;
    }
    __syncthreads();
    float inv = 1.f / redB[0][lane];

    for (int m = row; m < MTOK_B; m += 8) {
        float* p = &base[(size_t)m * KSEL];
        *p = __expf(*p - mx) * inv;
    }
}

__global__ void pool_kernel(const float* __restrict__ sel, float* __restrict__ out)
{
    int idx = blockIdx.x * blockDim.x + threadIdx.x;
    int total = B_DIM * OUT_ROWS * E_DIM;
    if (idx >= total) return;
    int e = idx % E_DIM;
    int r = (idx / E_DIM) % OUT_ROWS;
    int b = idx / (OUT_ROWS * E_DIM);
    const float* sb = sel + (size_t)b * KSEL * E_DIM;
    float v;
    if (r < 256) {
        v = sb[(size_t)r * E_DIM + e];
    } else if (r < 384) {
        int i = (r - 256) * 2;
        v = 0.5f * (sb[(size_t)i * E_DIM + e] + sb[(size_t)(i + 1) * E_DIM + e]);
    } else {
        int i = (r - 384) * 4;
        v = 0.25f * (sb[(size_t)i * E_DIM + e] + sb[(size_t)(i + 1) * E_DIM + e] +
                     sb[(size_t)(i + 2) * E_DIM + e] + sb[(size_t)(i + 3) * E_DIM + e]);
    }
    out[idx] = v;
}

// ---------------------------------------------------------------------------
// Orchestration (dual-stream weight-fold prep; mma spatial attention)
// ---------------------------------------------------------------------------
extern "C" void kernel_launch(void* const* d_in, const int* in_sizes, int n_in,
                              void* d_out, int out_size)
{
    (void)in_sizes; (void)n_in; (void)out_size;

    const float* x    = (const float*)d_in[0];
    const float* wq   = (const float*)d_in[1];
    const float* bq   = (const float*)d_in[2];
    const float* wk   = (const float*)d_in[3];
    const float* bk   = (const float*)d_in[4];
    const float* wv   = (const float*)d_in[5];
    const float* bv   = (const float*)d_in[6];
    const float* wd   = (const float*)d_in[7];
    const float* bd   = (const float*)d_in[8];
    const float* rb   = (const float*)d_in[9];
    const float* selw = (const float*)d_in[10];
    const float* selb = (const float*)d_in[11];
    float* out = (float*)d_out;

    float *Hb, *SCb, *S1b, *SELb, *Bqkv, *Bcomb, *Bias2, *Bzero;
    cudaGetSymbolAddress((void**)&Hb,  g_Hb);
    cudaGetSymbolAddress((void**)&SCb, g_SC);
    cudaGetSymbolAddress((void**)&S1b, g_S1);
    cudaGetSymbolAddress((void**)&SELb, g_SEL);
    cudaGetSymbolAddress((void**)&Bqkv, g_Bqkv);
    cudaGetSymbolAddress((void**)&Bcomb, g_Bcomb);
    cudaGetSymbolAddress((void**)&Bias2, g_Bias2);
    cudaGetSymbolAddress((void**)&Bzero, g_Bzero);

    __half *QKVh, *Ahp, *Alp, *Ah2p, *Al2p, *WqkvTh, *WqkvTl, *Wd16, *WdT3, *WcT;
    __half *SWTh, *SWTl, *Bsel;
    cudaGetSymbolAddress((void**)&QKVh, g_QKVh);
    cudaGetSymbolAddress((void**)&Ahp, g_Ah);
    cudaGetSymbolAddress((void**)&Alp, g_Al);
    cudaGetSymbolAddress((void**)&Ah2p, g_Ah2);
    cudaGetSymbolAddress((void**)&Al2p, g_Al2);
    cudaGetSymbolAddress((void**)&WqkvTh, g_WqkvTh);
    cudaGetSymbolAddress((void**)&WqkvTl, g_WqkvTl);
    cudaGetSymbolAddress((void**)&Wd16, g_Wd16);
    cudaGetSymbolAddress((void**)&WdT3, g_WdT3);
    cudaGetSymbolAddress((void**)&WcT, g_WcT);
    cudaGetSymbolAddress((void**)&SWTh, g_SWTh);
    cudaGetSymbolAddress((void**)&SWTl, g_SWTl);
    cudaGetSymbolAddress((void**)&Bsel, g_Bsel);

    static cudaStream_t s2 = nullptr;
    static cudaEvent_t evF = nullptr, evJ = nullptr;
    if (!s2) {
        cudaStreamCreateWithFlags(&s2, cudaStreamNonBlocking);
        cudaEventCreateWithFlags(&evF, cudaEventDisableTiming);
        cudaEventCreateWithFlags(&evJ, cudaEventDisableTiming);
    }

    const int smemTe = 32 * (32 + 1) * 8 + 32 * 32 * 4 + (2 * 32 - 1) * 4;     // 12796
    const int SMEM1 = GSTAGES * 2 * TILE_BYTES;   // 61440
    const int SMEM2 = GSTAGES * 3 * TILE_BYTES;   // 92160
    cudaFuncSetAttribute((const void*)attn_mma,
                         cudaFuncAttributeMaxDynamicSharedMemorySize, ATTN_SMEM);
    cudaFuncSetAttribute((const void*)gemm_f16<1>,
                         cudaFuncAttributeMaxDynamicSharedMemorySize, SMEM1);
    cudaFuncSetAttribute((const void*)gemm_f16<2>,
                         cudaFuncAttributeMaxDynamicSharedMemorySize, SMEM2);

    const dim3 blk(256);
    const dim3 tblk(32, 8);
    const int n4 = MTOK * E_DIM / 4;
    const dim3 gcvt((n4 + 255) / 256);
    const dim3 gQKV(QKV_N / 128, MTOK / 128);
    const size_t MM = (size_t)E_DIM * E_DIM;
    const size_t MM3 = 3 * MM;
    const size_t WCS = (size_t)QKV_N * E_DIM;

    // ---- main stream: weights needed for layer 0 ----
    wt_cvt3<<<dim3(E_DIM / 32, E_DIM / 32, 4), tblk>>>(wq, WqkvTh, WqkvTl, E_DIM, E_DIM, 0, 3);
    wt_cvt3<<<dim3(E_DIM / 32, E_DIM / 32, 4), tblk>>>(wk, WqkvTh, WqkvTl, E_DIM, E_DIM, 1, 3);
    wt_cvt3<<<dim3(E_DIM / 32, E_DIM / 32, 4), tblk>>>(wv, WqkvTh, WqkvTl, E_DIM, E_DIM, 2, 3);
    bias_concat<<<(4 * QKV_N + 255) / 256, blk>>>(bq, bk, bv, Bqkv);

    // ---- fork: fold-weight prep on s2 ----
    cudaEventRecord(evF, 0);
    cudaStreamWaitEvent(s2, evF, 0);

    cvt_f16<<<(int)((4 * MM / 4 + 255) / 256), blk, 0, s2>>>(wd, Wd16, (int)(4 * MM / 4));
    gemm_f16<2><<<dim3(E_DIM / 128, QKV_N / 128, 3), blk, SMEM2, s2>>>(
        WqkvTh + MM3, WqkvTl + MM3, Wd16, Bzero, nullptr,
        WcT, nullptr, E_DIM, E_DIM, MM3, MM, WCS);
    wt_cvt<<<dim3(E_DIM / 32, E_DIM / 32, 1), tblk, 0, s2>>>(wd + 3 * MM, WdT3, E_DIM, E_DIM);
    wt_cvt3<<<dim3(KSEL / 32, E_DIM / 32, 1), tblk, 0, s2>>>(selw, SWTh, SWTl, E_DIM, KSEL, 0, 1);
    gemm_f16<2><<<dim3(E_DIM / 128, KSEL / 128), blk, SMEM2, s2>>>(
        SWTh, SWTl, Wd16 + 3 * MM, Bzero, nullptr,
        Bsel, nullptr, E_DIM, E_DIM, 0, 0, 0);
    bias_comb<<<dim3(QKV_N / 256, 3), blk, 0, s2>>>(wq, wk, wv, bd, Bqkv, Bcomb);
    bias_sel<<<1, 256, 0, s2>>>(selw, selb, bd + 3 * E_DIM, Bias2);
    cudaEventRecord(evJ, s2);

    // ---- main stream: layer 0 ----
    cvt_hilo<<<gcvt, blk>>>(x, Ah2p, Al2p, n4);
    gemm_f16<1><<<gQKV, blk, SMEM1>>>(Ah2p, nullptr, WqkvTh, Bqkv, nullptr,
                                      QKVh, nullptr, QKV_N, E_DIM, 0, 0, 0);
    attn_mma<<<dim3(H_DIM, B_DIM * T_DIM, 2), blk, ATTN_SMEM>>>(
        QKVh, QKVh + E_DIM, QKVh + 2 * E_DIM, Ahp, Alp, rb, QKV_N);

    // ---- join: folded weights ready before layer 1 ----
    cudaStreamWaitEvent(0, evJ, 0);

    for (int a = 1; a < 4; a++) {
        gemm_f16<1><<<gQKV, blk, SMEM1>>>(Ahp, nullptr, WcT + (a - 1) * WCS,
                                          Bcomb + (size_t)(a - 1) * QKV_N, nullptr,
                                          QKVh, nullptr, QKV_N, E_DIM, 0, 0, 0);

        const float* rba = rb + (size_t)a * RB_ONE;
        if ((a & 1) == 0) {
            attn_mma<<<dim3(H_DIM, B_DIM * T_DIM, 2), blk, ATTN_SMEM>>>(
                QKVh, QKVh + E_DIM, QKVh + 2 * E_DIM, Ahp, Alp, rba, QKV_N);
        } else {
            float* ctxF = (a == 3) ? Hb : nullptr;
            attn_kernel<32><<<dim3(H_DIM, B_DIM * N_DIM), blk, smemTe>>>(
                QKVh, QKVh + E_DIM, QKVh + 2 * E_DIM, Ahp, Alp, ctxF, rba,
                N_DIM, T_DIM * N_DIM, 1, N_DIM, QKV_N);
        }
    }

    // selection scores on ctx: SC = ctx @ Bsel^T + Bias2
    gemm_f16<2><<<dim3(KSEL / 128, MTOK / 128), blk, SMEM2>>>(
        Ahp, Alp, Bsel, Bias2, SCb, nullptr, nullptr, KSEL, E_DIM, 0, 0, 0);

    sel_softmax<<<dim3(B_DIM, KSEL / 32), blk>>>(SCb);

    cudaMemsetAsync(S1b, 0, (size_t)B_DIM * KSEL * E_DIM * sizeof(float));
    gemm_sel_atomic<<<dim3(E_DIM / 128, KSEL / 128, B_DIM * SPLITK), blk>>>(SCb, Hb, S1b);

    cvt_hilo<<<dim3((B_DIM * KSEL * E_DIM / 4 + 255) / 256), blk>>>(
        S1b, Ah2p, Al2p, B_DIM * KSEL * E_DIM / 4);
    gemm_f16<2><<<dim3(E_DIM / 128, (B_DIM * KSEL) / 128), blk, SMEM2>>>(
        Ah2p, Al2p, WdT3, bd + 3 * E_DIM, SELb, nullptr, nullptr, E_DIM, E_DIM, 0, 0, 0);

    int total = B_DIM * OUT_ROWS * E_DIM;
    pool_kernel<<<(total + 255) / 256, 256>>>(SELb, out);
}

// round 13
// speedup vs baseline: 2.8616x; 1.0984x over previous
#include <cuda_runtime.h>
#include <cuda_fp16.h>
#include <cstdint>
#include <cstddef>

// ---------------------------------------------------------------------------
// Problem constants
// ---------------------------------------------------------------------------
#define E_DIM   1024
#define QKV_N   3072
#define H_DIM   16
#define D_DIM   64
#define B_DIM   2
#define T_DIM   32
#define N_DIM   256
#define MTOK    (B_DIM * T_DIM * N_DIM)   // 16384 tokens total
#define MTOK_B  (T_DIM * N_DIM)           // 8192 tokens per batch
#define KSEL    256
#define MAXLEN  512
#define RB_ONE  ((2 * MAXLEN - 1) * H_DIM)
#define OUT_ROWS 448                      // 256 + 128 + 64
#define SPLITK  8

// ---------------------------------------------------------------------------
// Scratch (device globals — no allocations allowed)
// ---------------------------------------------------------------------------
__device__ __half g_QKVh[MTOK * QKV_N];   // merged Q|K|V per token, fp16
__device__ float g_Hb[MTOK * E_DIM];      // layer-3 ctx fp32 (for selection)
__device__ float g_SC[MTOK * KSEL];
__device__ float g_S1[B_DIM * KSEL * E_DIM];   // wts^T @ ctx
__device__ float g_SEL[B_DIM * KSEL * E_DIM];  // final selected tokens

// fp16 split activations: ping (attention out) and pong (misc)
__device__ __half g_Ah[MTOK * E_DIM];
__device__ __half g_Al[MTOK * E_DIM];
__device__ __half g_Ah2[MTOK * E_DIM];
__device__ __half g_Al2[MTOK * E_DIM];
// transposed fp16 weights
__device__ __half g_WqkvTh[4 * 3 * E_DIM * E_DIM];  // [a][q|k|v][N=E][K=E] hi
__device__ __half g_WqkvTl[4 * 3 * E_DIM * E_DIM];  // lo
__device__ __half g_Wd16[4 * E_DIM * E_DIM];        // wd plain (row-major) fp16
__device__ __half g_WdT3[E_DIM * E_DIM];            // wd[3] transposed fp16
__device__ __half g_WcT[3 * QKV_N * E_DIM];         // combined W'^T = (Wd_a Wqkv_{a+1})^T fp16
__device__ __half g_SWTh[KSEL * E_DIM];             // selw^T hi
__device__ __half g_SWTl[KSEL * E_DIM];             // selw^T lo
__device__ __half g_Bsel[KSEL * E_DIM];             // (Wd3 @ selw)^T fp16
__device__ float  g_Bqkv[4 * QKV_N];                // merged qkv bias per attn idx
__device__ float  g_Bcomb[3 * QKV_N];               // combined bias bd_a@Wqkv_{a+1}+b_{a+1}
__device__ float  g_Bias2[KSEL];                    // bd3@selw + selb
__device__ float  g_Bzero[E_DIM];                   // zero bias (static zero-init)

// ---------------------------------------------------------------------------
// PTX helpers
// ---------------------------------------------------------------------------
__device__ __forceinline__ void cp_async16(uint32_t dst, const void* src) {
    asm volatile("cp.async.cg.shared.global [%0], [%1], 16;" :: "r"(dst), "l"(src));
}
__device__ __forceinline__ void cp_commit() {
    asm volatile("cp.async.commit_group;" ::: "memory");
}
template <int N>
__device__ __forceinline__ void cp_wait_group() {
    asm volatile("cp.async.wait_group %0;" :: "n"(N) : "memory");
}
__device__ __forceinline__ void ldmatrix_x4(uint32_t* r, uint32_t addr) {
    asm volatile("ldmatrix.sync.aligned.m8n8.x4.shared.b16 {%0,%1,%2,%3}, [%4];"
                 : "=r"(r[0]), "=r"(r[1]), "=r"(r[2]), "=r"(r[3]) : "r"(addr));
}
__device__ __forceinline__ void mma_f16(float* d, const uint32_t* a,
                                        uint32_t b0, uint32_t b1) {
    asm volatile(
        "mma.sync.aligned.m16n8k16.row.col.f32.f16.f16.f32 "
        "{%0,%1,%2,%3}, {%4,%5,%6,%7}, {%8,%9}, {%0,%1,%2,%3};"
        : "+f"(d[0]), "+f"(d[1]), "+f"(d[2]), "+f"(d[3])
        : "r"(a[0]), "r"(a[1]), "r"(a[2]), "r"(a[3]), "r"(b0), "r"(b1));
}
__device__ __forceinline__ uint32_t h2pack(float a, float b) {
    __half2 h = __floats2half2_rn(a, b);
    return *(uint32_t*)&h;
}

// ---------------------------------------------------------------------------
// fp16 GEMM via mma.sync (1 or 2 A segments); optional fp32/fp16hi/fp16lo out.
// ---------------------------------------------------------------------------
#define GSTAGES 3
#define ROWPAD  40
#define TILE_BYTES (128 * ROWPAD * 2)

template <int SEGS>
__global__ __launch_bounds__(256, 2)
void gemm_f16(const __half* __restrict__ Ah, const __half* __restrict__ Al,
              const __half* __restrict__ B,
              const float* __restrict__ bias, float* __restrict__ C,
              __half* __restrict__ Ch, __half* __restrict__ Cl,
              int Nfull, int Kfull,
              size_t zA, size_t zB, size_t zC)
{
    constexpr int STB = (SEGS + 1) * TILE_BYTES;

    extern __shared__ char smem[];
    const uint32_t sb = (uint32_t)__cvta_generic_to_shared(smem);
    const int tid = threadIdx.x;
    const int lane = tid & 31;
    const int warp = tid >> 5;
    const int wm = warp >> 1;
    const int wn = warp & 1;
    const int m0 = blockIdx.y * 128;
    const int n0 = blockIdx.x * 128;

    Ah += (size_t)blockIdx.z * zA;
    if (SEGS == 2) Al += (size_t)blockIdx.z * zA;
    B  += (size_t)blockIdx.z * zB;
    if (C)  C  += (size_t)blockIdx.z * zC;
    if (Ch) Ch += (size_t)blockIdx.z * zC;
    if (Cl) Cl += (size_t)blockIdx.z * zC;

    const int NCH = Kfull >> 5;
    const int lr0 = tid >> 1;
    const int ls0 = (tid & 1) << 1;

    float acc[2][8][4];
#pragma unroll
    for (int mi = 0; mi < 2; mi++)
#pragma unroll
        for (int ni = 0; ni < 8; ni++)
#pragma unroll
            for (int q = 0; q < 4; q++) acc[mi][ni][q] = 0.f;

    auto load_chunk = [&](int c, int stage) {
        const int kb = c << 5;
        const uint32_t base = sb + stage * STB;
#pragma unroll
        for (int j = 0; j < 2; j++) {
            const int s4 = ls0 + j;
            const uint32_t soff = (uint32_t)(lr0 * ROWPAD + s4 * 8) * 2;
            const size_t goff = (size_t)lr0 * Kfull + kb + s4 * 8;
            cp_async16(base + soff, Ah + (size_t)m0 * Kfull + goff);
            if (SEGS == 2)
                cp_async16(base + TILE_BYTES + soff, Al + (size_t)m0 * Kfull + goff);
            cp_async16(base + SEGS * TILE_BYTES + soff, B + (size_t)n0 * Kfull + goff);
        }
    };

#pragma unroll
    for (int s = 0; s < GSTAGES - 1; s++) {
        if (s < NCH) load_chunk(s, s);
        cp_commit();
    }

    const int la_i = lane & 7;
    const int la_g = lane >> 3;
    const int a_rowadd = la_i + ((la_g & 1) << 3);
    const int a_coladd = (la_g >> 1) << 3;
    const int b_rowadd = la_i + ((la_g >> 1) << 3);
    const int b_coladd = (la_g & 1) << 3;

    for (int c = 0; c < NCH; c++) {
        const int stage = c % GSTAGES;
        cp_wait_group<GSTAGES - 2>();
        __syncthreads();

        const int nc = c + GSTAGES - 1;
        if (nc < NCH) load_chunk(nc, nc % GSTAGES);
        cp_commit();

        const uint32_t base = sb + stage * STB;
        const uint32_t Bbase = base + SEGS * TILE_BYTES;

#pragma unroll
        for (int k16 = 0; k16 < 32; k16 += 16) {
            uint32_t bf[4][4];
#pragma unroll
            for (int nb = 0; nb < 4; nb++) {
                const int row = wn * 64 + nb * 16 + b_rowadd;
                const int col = k16 + b_coladd;
                ldmatrix_x4(bf[nb], Bbase + (uint32_t)(row * ROWPAD + col) * 2);
            }
#pragma unroll
            for (int seg = 0; seg < SEGS; seg++) {
                const uint32_t Abase = base + seg * TILE_BYTES;
                uint32_t af[2][4];
#pragma unroll
                for (int mi = 0; mi < 2; mi++) {
                    const int row = wm * 32 + mi * 16 + a_rowadd;
                    const int col = k16 + a_coladd;
                    ldmatrix_x4(af[mi], Abase + (uint32_t)(row * ROWPAD + col) * 2);
                }
#pragma unroll
                for (int nb = 0; nb < 4; nb++)
#pragma unroll
                    for (int mi = 0; mi < 2; mi++) {
                        mma_f16(acc[mi][nb * 2 + 0], af[mi], bf[nb][0], bf[nb][1]);
                        mma_f16(acc[mi][nb * 2 + 1], af[mi], bf[nb][2], bf[nb][3]);
                    }
            }
        }
    }

    const int tq = lane >> 2;
    const int tr = lane & 3;
#pragma unroll
    for (int mi = 0; mi < 2; mi++) {
        const int row = m0 + wm * 32 + mi * 16 + tq;
#pragma unroll
        for (int ni = 0; ni < 8; ni++) {
            const int col = n0 + wn * 64 + ni * 8 + tr * 2;
            const float b0 = bias[col], b1 = bias[col + 1];
            float c00 = acc[mi][ni][0] + b0, c01 = acc[mi][ni][1] + b1;
            float c10 = acc[mi][ni][2] + b0, c11 = acc[mi][ni][3] + b1;
            if (C) {
                float2 v0; v0.x = c00; v0.y = c01;
                float2 v1; v1.x = c10; v1.y = c11;
                *(float2*)&C[(size_t)row * Nfull + col] = v0;
                *(float2*)&C[(size_t)(row + 8) * Nfull + col] = v1;
            }
            if (Ch || Cl) {
                __half h00 = __float2half_rn(c00);
                __half h01 = __float2half_rn(c01);
                __half h10 = __float2half_rn(c10);
                __half h11 = __float2half_rn(c11);
                if (Ch) {
                    *(__half2*)&Ch[(size_t)row * Nfull + col]       = __halves2half2(h00, h01);
                    *(__half2*)&Ch[(size_t)(row + 8) * Nfull + col] = __halves2half2(h10, h11);
                }
                if (Cl) {
                    __half l00 = __float2half_rn(c00 - __half2float(h00));
                    __half l01 = __float2half_rn(c01 - __half2float(h01));
                    __half l10 = __float2half_rn(c10 - __half2float(h10));
                    __half l11 = __float2half_rn(c11 - __half2float(h11));
                    *(__half2*)&Cl[(size_t)row * Nfull + col]       = __halves2half2(l00, l01);
                    *(__half2*)&Cl[(size_t)(row + 8) * Nfull + col] = __halves2half2(l10, l11);
                }
            }
        }
    }
}

// ---------------------------------------------------------------------------
// mma.sync spatial attention (S=256, step 1), flash-style online softmax.
// ---------------------------------------------------------------------------
#define AKS_BYTES  (256 * 72 * 2)           // 36864
#define AVT_BYTES  (64 * 264 * 2)           // 33792
#define ATTN_SMEM  (AKS_BYTES + AVT_BYTES + 512 * 4)   // 74704

__global__ __launch_bounds__(256)
void attn_mma(const __half* __restrict__ Q, const __half* __restrict__ K,
              const __half* __restrict__ V,
              __half* __restrict__ OutH, __half* __restrict__ OutL,
              const float* __restrict__ rb, int ldx)
{
    const int h = blockIdx.x;
    const int g = blockIdx.y;
    const int qh = blockIdx.z;
    const int base_m = g * N_DIM;
    const size_t baseE = (size_t)base_m * ldx + h * D_DIM;

    extern __shared__ char sm8[];
    __half* Ks = (__half*)sm8;                       // [256][72]
    __half* Vt = (__half*)(sm8 + AKS_BYTES);         // [64][264]
    float*  rbh = (float*)(sm8 + AKS_BYTES + AVT_BYTES);
    const uint32_t sKs = (uint32_t)__cvta_generic_to_shared(Ks);
    const uint32_t sVt = (uint32_t)__cvta_generic_to_shared(Vt);

    const int tid = threadIdx.x;
    const int lane = tid & 31;
    const int warp = tid >> 5;

    for (int i = tid; i < 128 * 8; i += 256) {
        int r = i >> 3, cs = i & 7;
        *(float4*)&Ks[r * 72 + cs * 8] =
            *(const float4*)(Q + baseE + (size_t)(qh * 128 + r) * ldx + cs * 8);
    }
    __syncthreads();

    const int la_i = lane & 7;
    const int la_g = lane >> 3;
    const int a_rowadd = la_i + ((la_g & 1) << 3);
    const int a_coladd = (la_g >> 1) << 3;
    const int b_rowadd = la_i + ((la_g >> 1) << 3);
    const int b_coladd = (la_g & 1) << 3;

    uint32_t Qf[4][4];
    const int wq = warp * 16;
#pragma unroll
    for (int kk = 0; kk < 4; kk++)
        ldmatrix_x4(Qf[kk], sKs + (uint32_t)((wq + a_rowadd) * 72 + kk * 16 + a_coladd) * 2);
    __syncthreads();

    for (int i = tid; i < 256 * 8; i += 256) {
        int r = i >> 3, cs = i & 7;
        *(float4*)&Ks[r * 72 + cs * 8] =
            *(const float4*)(K + baseE + (size_t)r * ldx + cs * 8);
    }
    for (int i = tid; i < 256 * 32; i += 256) {
        int t = i >> 5, d2 = i & 31;
        __half2 v = *(const __half2*)(V + baseE + (size_t)t * ldx + 2 * d2);
        Vt[(2 * d2) * 264 + t]     = __low2half(v);
        Vt[(2 * d2 + 1) * 264 + t] = __high2half(v);
    }
    for (int i = tid; i < 511; i += 256)
        rbh[i] = rb[(size_t)(MAXLEN - 256 + i) * H_DIM + h];
    __syncthreads();

    const int tq = lane >> 2;
    const int tr = lane & 3;
    const int r0 = qh * 128 + wq + tq;
    const int r1 = r0 + 8;

    float o[8][4];
#pragma unroll
    for (int j = 0; j < 8; j++)
#pragma unroll
        for (int q = 0; q < 4; q++) o[j][q] = 0.f;
    float m0 = -1e30f, m1 = -1e30f, l0 = 0.f, l1 = 0.f;

#pragma unroll
    for (int ch = 0; ch < 4; ch++) {
        float s[8][4];
#pragma unroll
        for (int j = 0; j < 8; j++)
#pragma unroll
            for (int q = 0; q < 4; q++) s[j][q] = 0.f;

#pragma unroll
        for (int kk = 0; kk < 4; kk++) {
#pragma unroll
            for (int nb = 0; nb < 4; nb++) {
                uint32_t bf[4];
                ldmatrix_x4(bf, sKs + (uint32_t)((ch * 64 + nb * 16 + b_rowadd) * 72
                                                 + kk * 16 + b_coladd) * 2);
                mma_f16(s[nb * 2 + 0], Qf[kk], bf[0], bf[1]);
                mma_f16(s[nb * 2 + 1], Qf[kk], bf[2], bf[3]);
            }
        }

        float cm0 = -1e30f, cm1 = -1e30f;
#pragma unroll
        for (int j = 0; j < 8; j++) {
            const int c = ch * 64 + j * 8 + 2 * tr;
            s[j][0] = s[j][0] * 0.125f + rbh[c - r0 + 255];
            s[j][1] = s[j][1] * 0.125f + rbh[c + 1 - r0 + 255];
            s[j][2] = s[j][2] * 0.125f + rbh[c - r1 + 255];
            s[j][3] = s[j][3] * 0.125f + rbh[c + 1 - r1 + 255];
            cm0 = fmaxf(cm0, fmaxf(s[j][0], s[j][1]));
            cm1 = fmaxf(cm1, fmaxf(s[j][2], s[j][3]));
        }
        cm0 = fmaxf(cm0, __shfl_xor_sync(0xffffffffu, cm0, 1));
        cm0 = fmaxf(cm0, __shfl_xor_sync(0xffffffffu, cm0, 2));
        cm1 = fmaxf(cm1, __shfl_xor_sync(0xffffffffu, cm1, 1));
        cm1 = fmaxf(cm1, __shfl_xor_sync(0xffffffffu, cm1, 2));

        const float nm0 = fmaxf(m0, cm0), nm1 = fmaxf(m1, cm1);
        const float sc0 = __expf(m0 - nm0), sc1 = __expf(m1 - nm1);
        float rs0 = 0.f, rs1 = 0.f;
#pragma unroll
        for (int j = 0; j < 8; j++) {
            s[j][0] = __expf(s[j][0] - nm0);
            s[j][1] = __expf(s[j][1] - nm0);
            s[j][2] = __expf(s[j][2] - nm1);
            s[j][3] = __expf(s[j][3] - nm1);
            rs0 += s[j][0] + s[j][1];
            rs1 += s[j][2] + s[j][3];
        }
        rs0 += __shfl_xor_sync(0xffffffffu, rs0, 1);
        rs0 += __shfl_xor_sync(0xffffffffu, rs0, 2);
        rs1 += __shfl_xor_sync(0xffffffffu, rs1, 1);
        rs1 += __shfl_xor_sync(0xffffffffu, rs1, 2);
        l0 = l0 * sc0 + rs0;
        l1 = l1 * sc1 + rs1;
        m0 = nm0; m1 = nm1;
#pragma unroll
        for (int j = 0; j < 8; j++) {
            o[j][0] *= sc0; o[j][1] *= sc0;
            o[j][2] *= sc1; o[j][3] *= sc1;
        }

        uint32_t pa[4][4];
#pragma unroll
        for (int kk = 0; kk < 4; kk++) {
            pa[kk][0] = h2pack(s[2 * kk][0], s[2 * kk][1]);
            pa[kk][1] = h2pack(s[2 * kk][2], s[2 * kk][3]);
            pa[kk][2] = h2pack(s[2 * kk + 1][0], s[2 * kk + 1][1]);
            pa[kk][3] = h2pack(s[2 * kk + 1][2], s[2 * kk + 1][3]);
        }

#pragma unroll
        for (int kk = 0; kk < 4; kk++) {
#pragma unroll
            for (int nb = 0; nb < 4; nb++) {
                uint32_t bf[4];
                ldmatrix_x4(bf, sVt + (uint32_t)((nb * 16 + b_rowadd) * 264
                                                 + ch * 64 + kk * 16 + b_coladd) * 2);
                mma_f16(o[nb * 2 + 0], pa[kk], bf[0], bf[1]);
                mma_f16(o[nb * 2 + 1], pa[kk], bf[2], bf[3]);
            }
        }
    }

    const float inv0 = 1.f / l0, inv1 = 1.f / l1;
    const size_t oo0 = (size_t)(base_m + r0) * E_DIM + h * D_DIM;
    const size_t oo1 = (size_t)(base_m + r1) * E_DIM + h * D_DIM;
#pragma unroll
    for (int j = 0; j < 8; j++) {
        const int c = j * 8 + 2 * tr;
        float c00 = o[j][0] * inv0, c01 = o[j][1] * inv0;
        float c10 = o[j][2] * inv1, c11 = o[j][3] * inv1;
        __half h00 = __float2half_rn(c00), h01 = __float2half_rn(c01);
        __half h10 = __float2half_rn(c10), h11 = __float2half_rn(c11);
        *(__half2*)&OutH[oo0 + c] = __halves2half2(h00, h01);
        *(__half2*)&OutH[oo1 + c] = __halves2half2(h10, h11);
        *(__half2*)&OutL[oo0 + c] = __halves2half2(
            __float2half_rn(c00 - __half2float(h00)), __float2half_rn(c01 - __half2float(h01)));
        *(__half2*)&OutL[oo1 + c] = __halves2half2(
            __float2half_rn(c10 - __half2float(h10)), __float2half_rn(c11 - __half2float(h11)));
    }
}

// ---------------------------------------------------------------------------
// mma.sync temporal attention (S=32, step N_DIM): one warp per (h,b,n) group.
// Per-warp smem buffer: Q/K staging [32][72] then V^T [64][40]; no block syncs
// in hot path. grid (H, 64), 8 warps/block.
// ---------------------------------------------------------------------------
#define TBUF_HALVES 2560                             // max(32*72, 64*40)
#define ATTN_T_SMEM (8 * TBUF_HALVES * 2 + 64 * 4)   // 41216

__global__ __launch_bounds__(256)
void attn_mma_t(const __half* __restrict__ Q, const __half* __restrict__ K,
                const __half* __restrict__ V,
                __half* __restrict__ OutH, __half* __restrict__ OutL,
                float* __restrict__ OutF,
                const float* __restrict__ rb, int ldx)
{
    const int h = blockIdx.x;
    const int tid = threadIdx.x;
    const int lane = tid & 31;
    const int warp = tid >> 5;
    const int g = blockIdx.y * 8 + warp;       // 0..511
    const int b = g >> 8, n = g & 255;
    const int base_m = b * MTOK_B + n;
    const size_t baseE = (size_t)base_m * ldx + h * D_DIM;
    const size_t stepE = (size_t)N_DIM * ldx;

    extern __shared__ char smT[];
    __half* buf = (__half*)smT + warp * TBUF_HALVES;
    float* rbh = (float*)(smT + 8 * TBUF_HALVES * 2);
    const uint32_t sb = (uint32_t)__cvta_generic_to_shared(buf);

    for (int i = tid; i < 63; i += 256)
        rbh[i] = rb[(size_t)(MAXLEN - 32 + i) * H_DIM + h];
    __syncthreads();   // rbh visible to all warps

    const int la_i = lane & 7;
    const int la_g = lane >> 3;
    const int a_rowadd = la_i + ((la_g & 1) << 3);
    const int a_coladd = (la_g >> 1) << 3;
    const int b_rowadd = la_i + ((la_g >> 1) << 3);
    const int b_coladd = (la_g & 1) << 3;
    const int tq = lane >> 2;
    const int tr = lane & 3;

    // ---- stage Q [32][72], extract A-frags ----
#pragma unroll
    for (int j = 0; j < 8; j++) {
        int idx = lane + j * 32;
        int r = idx >> 3, cs = idx & 7;
        *(float4*)&buf[r * 72 + cs * 8] =
            *(const float4*)(Q + baseE + (size_t)r * stepE + cs * 8);
    }
    __syncwarp();
    uint32_t Qf[2][4][4];
#pragma unroll
    for (int mi = 0; mi < 2; mi++)
#pragma unroll
        for (int kk = 0; kk < 4; kk++)
            ldmatrix_x4(Qf[mi][kk],
                        sb + (uint32_t)((mi * 16 + a_rowadd) * 72 + kk * 16 + a_coladd) * 2);
    __syncwarp();

    // ---- stage K, compute scores ----
#pragma unroll
    for (int j = 0; j < 8; j++) {
        int idx = lane + j * 32;
        int r = idx >> 3, cs = idx & 7;
        *(float4*)&buf[r * 72 + cs * 8] =
            *(const float4*)(K + baseE + (size_t)r * stepE + cs * 8);
    }
    __syncwarp();

    float s[2][4][4];
#pragma unroll
    for (int mi = 0; mi < 2; mi++)
#pragma unroll
        for (int ni = 0; ni < 4; ni++)
#pragma unroll
            for (int q = 0; q < 4; q++) s[mi][ni][q] = 0.f;

#pragma unroll
    for (int kk = 0; kk < 4; kk++)
#pragma unroll
        for (int nb = 0; nb < 2; nb++) {
            uint32_t bf[4];
            ldmatrix_x4(bf, sb + (uint32_t)((nb * 16 + b_rowadd) * 72 + kk * 16 + b_coladd) * 2);
#pragma unroll
            for (int mi = 0; mi < 2; mi++) {
                mma_f16(s[mi][nb * 2 + 0], Qf[mi][kk], bf[0], bf[1]);
                mma_f16(s[mi][nb * 2 + 1], Qf[mi][kk], bf[2], bf[3]);
            }
        }
    __syncwarp();

    // ---- stage V^T [64][40] ----
#pragma unroll
    for (int j = 0; j < 32; j++) {
        __half2 v = *(const __half2*)(V + baseE + (size_t)j * stepE + 2 * lane);
        buf[(2 * lane) * 40 + j]     = __low2half(v);
        buf[(2 * lane + 1) * 40 + j] = __high2half(v);
    }
    __syncwarp();

    // ---- bias + full softmax over 32 cols (rows: mi*16+tq and +8) ----
#pragma unroll
    for (int mi = 0; mi < 2; mi++) {
        const int ra = mi * 16 + tq, rb2 = ra + 8;
        float mxa = -1e30f, mxb = -1e30f;
#pragma unroll
        for (int ni = 0; ni < 4; ni++) {
            const int c = ni * 8 + 2 * tr;
            s[mi][ni][0] = s[mi][ni][0] * 0.125f + rbh[c - ra + 31];
            s[mi][ni][1] = s[mi][ni][1] * 0.125f + rbh[c + 1 - ra + 31];
            s[mi][ni][2] = s[mi][ni][2] * 0.125f + rbh[c - rb2 + 31];
            s[mi][ni][3] = s[mi][ni][3] * 0.125f + rbh[c + 1 - rb2 + 31];
            mxa = fmaxf(mxa, fmaxf(s[mi][ni][0], s[mi][ni][1]));
            mxb = fmaxf(mxb, fmaxf(s[mi][ni][2], s[mi][ni][3]));
        }
        mxa = fmaxf(mxa, __shfl_xor_sync(0xffffffffu, mxa, 1));
        mxa = fmaxf(mxa, __shfl_xor_sync(0xffffffffu, mxa, 2));
        mxb = fmaxf(mxb, __shfl_xor_sync(0xffffffffu, mxb, 1));
        mxb = fmaxf(mxb, __shfl_xor_sync(0xffffffffu, mxb, 2));
        float sa = 0.f, sbm = 0.f;
#pragma unroll
        for (int ni = 0; ni < 4; ni++) {
            s[mi][ni][0] = __expf(s[mi][ni][0] - mxa);
            s[mi][ni][1] = __expf(s[mi][ni][1] - mxa);
            s[mi][ni][2] = __expf(s[mi][ni][2] - mxb);
            s[mi][ni][3] = __expf(s[mi][ni][3] - mxb);
            sa += s[mi][ni][0] + s[mi][ni][1];
            sbm += s[mi][ni][2] + s[mi][ni][3];
        }
        sa += __shfl_xor_sync(0xffffffffu, sa, 1);
        sa += __shfl_xor_sync(0xffffffffu, sa, 2);
        sbm += __shfl_xor_sync(0xffffffffu, sbm, 1);
        sbm += __shfl_xor_sync(0xffffffffu, sbm, 2);
        const float ia = 1.f / sa, ib = 1.f / sbm;
#pragma unroll
        for (int ni = 0; ni < 4; ni++) {
            s[mi][ni][0] *= ia; s[mi][ni][1] *= ia;
            s[mi][ni][2] *= ib; s[mi][ni][3] *= ib;
        }
    }

    // ---- pack P to A-frags ----
    uint32_t pa[2][2][4];
#pragma unroll
    for (int mi = 0; mi < 2; mi++)
#pragma unroll
        for (int kk = 0; kk < 2; kk++) {
            pa[mi][kk][0] = h2pack(s[mi][2 * kk][0], s[mi][2 * kk][1]);
            pa[mi][kk][1] = h2pack(s[mi][2 * kk][2], s[mi][2 * kk][3]);
            pa[mi][kk][2] = h2pack(s[mi][2 * kk + 1][0], s[mi][2 * kk + 1][1]);
            pa[mi][kk][3] = h2pack(s[mi][2 * kk + 1][2], s[mi][2 * kk + 1][3]);
        }

    // ---- O = P . V ----
    float o[2][8][4];
#pragma unroll
    for (int mi = 0; mi < 2; mi++)
#pragma unroll
        for (int ni = 0; ni < 8; ni++)
#pragma unroll
            for (int q = 0; q < 4; q++) o[mi][ni][q] = 0.f;

#pragma unroll
    for (int kk = 0; kk < 2; kk++)
#pragma unroll
        for (int nb = 0; nb < 4; nb++) {
            uint32_t bf[4];
            ldmatrix_x4(bf, sb + (uint32_t)((nb * 16 + b_rowadd) * 40 + kk * 16 + b_coladd) * 2);
#pragma unroll
            for (int mi = 0; mi < 2; mi++) {
                mma_f16(o[mi][nb * 2 + 0], pa[mi][kk], bf[0], bf[1]);
                mma_f16(o[mi][nb * 2 + 1], pa[mi][kk], bf[2], bf[3]);
            }
        }

    // ---- emit ----
#pragma unroll
    for (int mi = 0; mi < 2; mi++) {
        const int ra = mi * 16 + tq;
        const size_t oo0 = (size_t)(base_m + ra * N_DIM) * E_DIM + h * D_DIM;
        const size_t oo1 = (size_t)(base_m + (ra + 8) * N_DIM) * E_DIM + h * D_DIM;
#pragma unroll
        for (int ni = 0; ni < 8; ni++) {
            const int c = ni * 8 + 2 * tr;
            float c00 = o[mi][ni][0], c01 = o[mi][ni][1];
            float c10 = o[mi][ni][2], c11 = o[mi][ni][3];
            __half h00 = __float2half_rn(c00), h01 = __float2half_rn(c01);
            __half h10 = __float2half_rn(c10), h11 = __float2half_rn(c11);
            *(__half2*)&OutH[oo0 + c] = __halves2half2(h00, h01);
            *(__half2*)&OutH[oo1 + c] = __halves2half2(h10, h11);
            *(__half2*)&OutL[oo0 + c] = __halves2half2(
                __float2half_rn(c00 - __half2float(h00)),
                __float2half_rn(c01 - __half2float(h01)));
            *(__half2*)&OutL[oo1 + c] = __halves2half2(
                __float2half_rn(c10 - __half2float(h10)),
                __float2half_rn(c11 - __half2float(h11)));
            if (OutF) {
                float2 f0; f0.x = c00; f0.y = c01;
                float2 f1; f1.x = c10; f1.y = c11;
                *(float2*)&OutF[oo0 + c] = f0;
                *(float2*)&OutF[oo1 + c] = f1;
            }
        }
    }
}

// ---------------------------------------------------------------------------
// misc elementwise / prep kernels
// ---------------------------------------------------------------------------
__global__ void cvt_hilo(const float* __restrict__ x, __half* __restrict__ hi,
                         __half* __restrict__ lo, int n4)
{
    int i = blockIdx.x * blockDim.x + threadIdx.x;
    if (i >= n4) return;
    float4 v = ((const float4*)x)[i];
    __half h0 = __float2half_rn(v.x);
    __half h1 = __float2half_rn(v.y);
    __half h2 = __float2half_rn(v.z);
    __half h3 = __float2half_rn(v.w);
    __half l0 = __float2half_rn(v.x - __half2float(h0));
    __half l1 = __float2half_rn(v.y - __half2float(h1));
    __half l2 = __float2half_rn(v.z - __half2float(h2));
    __half l3 = __float2half_rn(v.w - __half2float(h3));
    __half2* hp = (__half2*)hi;
    __half2* lp = (__half2*)lo;
    hp[2 * i + 0] = __half2(h0, h1);
    hp[2 * i + 1] = __half2(h2, h3);
    lp[2 * i + 0] = __half2(l0, l1);
    lp[2 * i + 1] = __half2(l2, l3);
}

__global__ void cvt_f16(const float* __restrict__ x, __half* __restrict__ y, int n4)
{
    int i = blockIdx.x * blockDim.x + threadIdx.x;
    if (i >= n4) return;
    float4 v = ((const float4*)x)[i];
    __half2* yp = (__half2*)y;
    yp[2 * i + 0] = __floats2half2_rn(v.x, v.y);
    yp[2 * i + 1] = __floats2half2_rn(v.z, v.w);
}

__global__ void wt_cvt3(const float* __restrict__ W, __half* __restrict__ WTh,
                        __half* __restrict__ WTl, int Kd, int Nd, int type, int slots)
{
    __shared__ float t[32][33];
    const size_t srcoff = (size_t)blockIdx.z * Kd * Nd;
    const size_t dstoff = ((size_t)blockIdx.z * slots + type) * Kd * Nd;
    const float* Wm = W + srcoff;
    __half* Hh = WTh + dstoff;
    __half* Hl = WTl + dstoff;

    int nx = blockIdx.x * 32 + threadIdx.x;
    int k0 = blockIdx.y * 32;
#pragma unroll
    for (int j = 0; j < 4; j++) {
        int kk = k0 + threadIdx.y + j * 8;
        t[threadIdx.y + j * 8][threadIdx.x] = Wm[(size_t)kk * Nd + nx];
    }
    __syncthreads();
    int kx = k0 + threadIdx.x;
#pragma unroll
    for (int j = 0; j < 4; j++) {
        int nn = blockIdx.x * 32 + threadIdx.y + j * 8;
        float v = t[threadIdx.x][threadIdx.y + j * 8];
        __half h = __float2half_rn(v);
        Hh[(size_t)nn * Kd + kx] = h;
        Hl[(size_t)nn * Kd + kx] = __float2half_rn(v - __half2float(h));
    }
}

__global__ void wt_cvt(const float* __restrict__ W, __half* __restrict__ WT,
                       int Kd, int Nd)
{
    __shared__ float t[32][33];
    const size_t moff = (size_t)blockIdx.z * Kd * Nd;
    const float* Wm = W + moff;
    __half* Hh = WT + moff;

    int nx = blockIdx.x * 32 + threadIdx.x;
    int k0 = blockIdx.y * 32;
#pragma unroll
    for (int j = 0; j < 4; j++) {
        int kk = k0 + threadIdx.y + j * 8;
        t[threadIdx.y + j * 8][threadIdx.x] = Wm[(size_t)kk * Nd + nx];
    }
    __syncthreads();
    int kx = k0 + threadIdx.x;
#pragma unroll
    for (int j = 0; j < 4; j++) {
        int nn = blockIdx.x * 32 + threadIdx.y + j * 8;
        Hh[(size_t)nn * Kd + kx] = __float2half_rn(t[threadIdx.x][threadIdx.y + j * 8]);
    }
}

__global__ void bias_concat(const float* __restrict__ bq, const float* __restrict__ bk,
                            const float* __restrict__ bv, float* __restrict__ out)
{
    int i = blockIdx.x * blockDim.x + threadIdx.x;
    if (i >= 4 * QKV_N) return;
    int a = i / QKV_N;
    int r = i % QKV_N;
    const float* src = (r < E_DIM) ? bq : (r < 2 * E_DIM) ? bk : bv;
    out[i] = src[a * E_DIM + (r & (E_DIM - 1))];
}

__global__ void bias_comb(const float* __restrict__ wq, const float* __restrict__ wk,
                          const float* __restrict__ wv, const float* __restrict__ bd,
                          const float* __restrict__ bqkv, float* __restrict__ out)
{
    int i = blockIdx.x * blockDim.x + threadIdx.x;
    int z = blockIdx.y;
    const float* W = (i < E_DIM) ? wq : (i < 2 * E_DIM) ? wk : wv;
    int col = i & (E_DIM - 1);
    const float* Wm = W + (size_t)(z + 1) * E_DIM * E_DIM;
    const float* bdz = bd + (size_t)z * E_DIM;
    float s = 0.f;
    for (int k = 0; k < E_DIM; k++)
        s += bdz[k] * Wm[(size_t)k * E_DIM + col];
    out[(size_t)z * QKV_N + i] = s + bqkv[(size_t)(z + 1) * QKV_N + i];
}

__global__ void bias_sel(const float* __restrict__ selw, const float* __restrict__ selb,
                         const float* __restrict__ bd3, float* __restrict__ out)
{
    int k = blockIdx.x * blockDim.x + threadIdx.x;
    if (k >= KSEL) return;
    float s = 0.f;
    for (int e = 0; e < E_DIM; e++)
        s += bd3[e] * selw[(size_t)e * KSEL + k];
    out[k] = s + selb[k];
}

// ---------------------------------------------------------------------------
// Split-K selection GEMM (fp32, atomics)
// ---------------------------------------------------------------------------
__global__ __launch_bounds__(256, 2)
void gemm_sel_atomic(const float* __restrict__ Wts, const float* __restrict__ Flat,
                     float* __restrict__ Csel)
{
    __shared__ float As[16][128];
    __shared__ float Bs[16][128];

    const int tid = threadIdx.x;
    const int bx = blockIdx.x;
    const int by = blockIdx.y;
    const int b  = blockIdx.z / SPLITK;
    const int sl = blockIdx.z % SPLITK;

    const float* A = Wts  + (size_t)b * MTOK_B * KSEL;
    const float* B = Flat + (size_t)b * MTOK_B * E_DIM;
    float*       C = Csel + (size_t)b * KSEL * E_DIM;

    const int lr = (tid & 31) << 2;
    const int lk = tid >> 5;
    const int tx = tid & 15;
    const int ty = tid >> 4;

    const int kbeg = sl * (MTOK_B / SPLITK);
    const int kend = kbeg + (MTOK_B / SPLITK);

    float acc[8][8];
#pragma unroll
    for (int i = 0; i < 8; i++)
#pragma unroll
        for (int j = 0; j < 8; j++) acc[i][j] = 0.f;

    for (int k0 = kbeg; k0 < kend; k0 += 16) {
        *(float4*)&As[lk][lr]     = *(const float4*)&A[(size_t)(k0 + lk) * KSEL + by * 128 + lr];
        *(float4*)&As[lk + 8][lr] = *(const float4*)&A[(size_t)(k0 + lk + 8) * KSEL + by * 128 + lr];
        *(float4*)&Bs[lk][lr]     = *(const float4*)&B[(size_t)(k0 + lk) * E_DIM + bx * 128 + lr];
        *(float4*)&Bs[lk + 8][lr] = *(const float4*)&B[(size_t)(k0 + lk + 8) * E_DIM + bx * 128 + lr];
        __syncthreads();

#pragma unroll
        for (int kk = 0; kk < 16; kk++) {
            float ar[8], br[8];
            *(float4*)&ar[0] = *(const float4*)&As[kk][ty * 8];
            *(float4*)&ar[4] = *(const float4*)&As[kk][ty * 8 + 4];
            *(float4*)&br[0] = *(const float4*)&Bs[kk][tx * 8];
            *(float4*)&br[4] = *(const float4*)&Bs[kk][tx * 8 + 4];
#pragma unroll
            for (int i = 0; i < 8; i++)
#pragma unroll
                for (int j = 0; j < 8; j++)
                    acc[i][j] += ar[i] * br[j];
        }
        __syncthreads();
    }

#pragma unroll
    for (int i = 0; i < 8; i++) {
        float* cp = C + (size_t)(by * 128 + ty * 8 + i) * E_DIM + bx * 128 + tx * 8;
#pragma unroll
        for (int j = 0; j < 8; j++)
            atomicAdd(&cp[j], acc[i][j]);
    }
}

// ---------------------------------------------------------------------------
// Selection softmax / pooling
// ---------------------------------------------------------------------------
__global__ __launch_bounds__(256)
void sel_softmax(float* __restrict__ sc)
{
    const int b = blockIdx.x;
    const int k0 = blockIdx.y * 32;
    const int lane = threadIdx.x & 31;
    const int row = threadIdx.x >> 5;

    float* base = sc + (size_t)b * MTOK_B * KSEL + k0 + lane;

    __shared__ float redA[8][32];
    __shared__ float redB[8][32];

    float mx = -1e30f;
    for (int m = row; m < MTOK_B; m += 8)
        mx = fmaxf(mx, base[(size_t)m * KSEL]);
    redA[row][lane] = mx;
    __syncthreads();
    if (row == 0) {
        float v = redA[0][lane];
#pragma unroll
        for (int r = 1; r < 8; r++) v = fmaxf(v, redA[r][lane]);
        redA[0][lane] = v;
    }
    __syncthreads();
    mx = redA[0][lane];

    float sum = 0.f;
    for (int m = row; m < MTOK_B; m += 8)
        sum += __expf(base[(size_t)m * KSEL] - mx);
    redB[row][lane] = sum;
    __syncthreads();
    if (row == 0) {
        float v = 0.f;
#pragma unroll
        for (int r = 0; r < 8; r++) v += redB[r][lane];
        redB[0][lane] = v;
    }
    __syncthreads();
    float inv = 1.f / redB[0][lane];

    for (int m = row; m < MTOK_B; m += 8) {
        float* p = &base[(size_t)m * KSEL];
        *p = __expf(*p - mx) * inv;
    }
}

__global__ void pool_kernel(const float* __restrict__ sel, float* __restrict__ out)
{
    int idx = blockIdx.x * blockDim.x + threadIdx.x;
    int total = B_DIM * OUT_ROWS * E_DIM;
    if (idx >= total) return;
    int e = idx % E_DIM;
    int r = (idx / E_DIM) % OUT_ROWS;
    int b = idx / (OUT_ROWS * E_DIM);
    const float* sb = sel + (size_t)b * KSEL * E_DIM;
    float v;
    if (r < 256) {
        v = sb[(size_t)r * E_DIM + e];
    } else if (r < 384) {
        int i = (r - 256) * 2;
        v = 0.5f * (sb[(size_t)i * E_DIM + e] + sb[(size_t)(i + 1) * E_DIM + e]);
    } else {
        int i = (r - 384) * 4;
        v = 0.25f * (sb[(size_t)i * E_DIM + e] + sb[(size_t)(i + 1) * E_DIM + e] +
                     sb[(size_t)(i + 2) * E_DIM + e] + sb[(size_t)(i + 3) * E_DIM + e]);
    }
    out[idx] = v;
}

// ---------------------------------------------------------------------------
// Orchestration
// ---------------------------------------------------------------------------
extern "C" void kernel_launch(void* const* d_in, const int* in_sizes, int n_in,
                              void* d_out, int out_size)
{
    (void)in_sizes; (void)n_in; (void)out_size;

    const float* x    = (const float*)d_in[0];
    const float* wq   = (const float*)d_in[1];
    const float* bq   = (const float*)d_in[2];
    const float* wk   = (const float*)d_in[3];
    const float* bk   = (const float*)d_in[4];
    const float* wv   = (const float*)d_in[5];
    const float* bv   = (const float*)d_in[6];
    const float* wd   = (const float*)d_in[7];
    const float* bd   = (const float*)d_in[8];
    const float* rb   = (const float*)d_in[9];
    const float* selw = (const float*)d_in[10];
    const float* selb = (const float*)d_in[11];
    float* out = (float*)d_out;

    float *Hb, *SCb, *S1b, *SELb, *Bqkv, *Bcomb, *Bias2, *Bzero;
    cudaGetSymbolAddress((void**)&Hb,  g_Hb);
    cudaGetSymbolAddress((void**)&SCb, g_SC);
    cudaGetSymbolAddress((void**)&S1b, g_S1);
    cudaGetSymbolAddress((void**)&SELb, g_SEL);
    cudaGetSymbolAddress((void**)&Bqkv, g_Bqkv);
    cudaGetSymbolAddress((void**)&Bcomb, g_Bcomb);
    cudaGetSymbolAddress((void**)&Bias2, g_Bias2);
    cudaGetSymbolAddress((void**)&Bzero, g_Bzero);

    __half *QKVh, *Ahp, *Alp, *Ah2p, *Al2p, *WqkvTh, *WqkvTl, *Wd16, *WdT3, *WcT;
    __half *SWTh, *SWTl, *Bsel;
    cudaGetSymbolAddress((void**)&QKVh, g_QKVh);
    cudaGetSymbolAddress((void**)&Ahp, g_Ah);
    cudaGetSymbolAddress((void**)&Alp, g_Al);
    cudaGetSymbolAddress((void**)&Ah2p, g_Ah2);
    cudaGetSymbolAddress((void**)&Al2p, g_Al2);
    cudaGetSymbolAddress((void**)&WqkvTh, g_WqkvTh);
    cudaGetSymbolAddress((void**)&WqkvTl, g_WqkvTl);
    cudaGetSymbolAddress((void**)&Wd16, g_Wd16);
    cudaGetSymbolAddress((void**)&WdT3, g_WdT3);
    cudaGetSymbolAddress((void**)&WcT, g_WcT);
    cudaGetSymbolAddress((void**)&SWTh, g_SWTh);
    cudaGetSymbolAddress((void**)&SWTl, g_SWTl);
    cudaGetSymbolAddress((void**)&Bsel, g_Bsel);

    static cudaStream_t s2 = nullptr;
    static cudaEvent_t evF = nullptr, evJ = nullptr;
    if (!s2) {
        cudaStreamCreateWithFlags(&s2, cudaStreamNonBlocking);
        cudaEventCreateWithFlags(&evF, cudaEventDisableTiming);
        cudaEventCreateWithFlags(&evJ, cudaEventDisableTiming);
    }

    const int SMEM1 = GSTAGES * 2 * TILE_BYTES;   // 61440
    const int SMEM2 = GSTAGES * 3 * TILE_BYTES;   // 92160
    cudaFuncSetAttribute((const void*)attn_mma,
                         cudaFuncAttributeMaxDynamicSharedMemorySize, ATTN_SMEM);
    cudaFuncSetAttribute((const void*)attn_mma_t,
                         cudaFuncAttributeMaxDynamicSharedMemorySize, ATTN_T_SMEM);
    cudaFuncSetAttribute((const void*)gemm_f16<1>,
                         cudaFuncAttributeMaxDynamicSharedMemorySize, SMEM1);
    cudaFuncSetAttribute((const void*)gemm_f16<2>,
                         cudaFuncAttributeMaxDynamicSharedMemorySize, SMEM2);

    const dim3 blk(256);
    const dim3 tblk(32, 8);
    const int n4 = MTOK * E_DIM / 4;
    const dim3 gcvt((n4 + 255) / 256);
    const dim3 gQKV(QKV_N / 128, MTOK / 128);
    const size_t MM = (size_t)E_DIM * E_DIM;
    const size_t MM3 = 3 * MM;
    const size_t WCS = (size_t)QKV_N * E_DIM;

    // ---- main stream: weights needed for layer 0 ----
    wt_cvt3<<<dim3(E_DIM / 32, E_DIM / 32, 4), tblk>>>(wq, WqkvTh, WqkvTl, E_DIM, E_DIM, 0, 3);
    wt_cvt3<<<dim3(E_DIM / 32, E_DIM / 32, 4), tblk>>>(wk, WqkvTh, WqkvTl, E_DIM, E_DIM, 1, 3);
    wt_cvt3<<<dim3(E_DIM / 32, E_DIM / 32, 4), tblk>>>(wv, WqkvTh, WqkvTl, E_DIM, E_DIM, 2, 3);
    bias_concat<<<(4 * QKV_N + 255) / 256, blk>>>(bq, bk, bv, Bqkv);

    // ---- fork: fold-weight prep on s2 ----
    cudaEventRecord(evF, 0);
    cudaStreamWaitEvent(s2, evF, 0);

    cvt_f16<<<(int)((4 * MM / 4 + 255) / 256), blk, 0, s2>>>(wd, Wd16, (int)(4 * MM / 4));
    gemm_f16<2><<<dim3(E_DIM / 128, QKV_N / 128, 3), blk, SMEM2, s2>>>(
        WqkvTh + MM3, WqkvTl + MM3, Wd16, Bzero, nullptr,
        WcT, nullptr, E_DIM, E_DIM, MM3, MM, WCS);
    wt_cvt<<<dim3(E_DIM / 32, E_DIM / 32, 1), tblk, 0, s2>>>(wd + 3 * MM, WdT3, E_DIM, E_DIM);
    wt_cvt3<<<dim3(KSEL / 32, E_DIM / 32, 1), tblk, 0, s2>>>(selw, SWTh, SWTl, E_DIM, KSEL, 0, 1);
    gemm_f16<2><<<dim3(E_DIM / 128, KSEL / 128), blk, SMEM2, s2>>>(
        SWTh, SWTl, Wd16 + 3 * MM, Bzero, nullptr,
        Bsel, nullptr, E_DIM, E_DIM, 0, 0, 0);
    bias_comb<<<dim3(QKV_N / 256, 3), blk, 0, s2>>>(wq, wk, wv, bd, Bqkv, Bcomb);
    bias_sel<<<1, 256, 0, s2>>>(selw, selb, bd + 3 * E_DIM, Bias2);
    cudaEventRecord(evJ, s2);

    // ---- main stream: layer 0 ----
    cvt_hilo<<<gcvt, blk>>>(x, Ah2p, Al2p, n4);
    gemm_f16<1><<<gQKV, blk, SMEM1>>>(Ah2p, nullptr, WqkvTh, Bqkv, nullptr,
                                      QKVh, nullptr, QKV_N, E_DIM, 0, 0, 0);
    attn_mma<<<dim3(H_DIM, B_DIM * T_DIM, 2), blk, ATTN_SMEM>>>(
        QKVh, QKVh + E_DIM, QKVh + 2 * E_DIM, Ahp, Alp, rb, QKV_N);

    // ---- join: folded weights ready before layer 1 ----
    cudaStreamWaitEvent(0, evJ, 0);

    for (int a = 1; a < 4; a++) {
        gemm_f16<1><<<gQKV, blk, SMEM1>>>(Ahp, nullptr, WcT + (a - 1) * WCS,
                                          Bcomb + (size_t)(a - 1) * QKV_N, nullptr,
                                          QKVh, nullptr, QKV_N, E_DIM, 0, 0, 0);

        const float* rba = rb + (size_t)a * RB_ONE;
        if ((a & 1) == 0) {
            attn_mma<<<dim3(H_DIM, B_DIM * T_DIM, 2), blk, ATTN_SMEM>>>(
                QKVh, QKVh + E_DIM, QKVh + 2 * E_DIM, Ahp, Alp, rba, QKV_N);
        } else {
            float* ctxF = (a == 3) ? Hb : nullptr;
            attn_mma_t<<<dim3(H_DIM, (B_DIM * N_DIM) / 8), blk, ATTN_T_SMEM>>>(
                QKVh, QKVh + E_DIM, QKVh + 2 * E_DIM, Ahp, Alp, ctxF, rba, QKV_N);
        }
    }

    // selection scores on ctx: SC = ctx @ Bsel^T + Bias2
    gemm_f16<2><<<dim3(KSEL / 128, MTOK / 128), blk, SMEM2>>>(
        Ahp, Alp, Bsel, Bias2, SCb, nullptr, nullptr, KSEL, E_DIM, 0, 0, 0);

    sel_softmax<<<dim3(B_DIM, KSEL / 32), blk>>>(SCb);

    cudaMemsetAsync(S1b, 0, (size_t)B_DIM * KSEL * E_DIM * sizeof(float));
    gemm_sel_atomic<<<dim3(E_DIM / 128, KSEL / 128, B_DIM * SPLITK), blk>>>(SCb, Hb, S1b);

    cvt_hilo<<<dim3((B_DIM * KSEL * E_DIM / 4 + 255) / 256), blk>>>(
        S1b, Ah2p, Al2p, B_DIM * KSEL * E_DIM / 4);
    gemm_f16<2><<<dim3(E_DIM / 128, (B_DIM * KSEL) / 128), blk, SMEM2>>>(
        Ah2p, Al2p, WdT3, bd + 3 * E_DIM, SELb, nullptr, nullptr, E_DIM, E_DIM, 0, 0, 0);

    int total = B_DIM * OUT_ROWS * E_DIM;
    pool_kernel<<<(total + 255) / 256, 256>>>(SELb, out);
}

// round 14
// speedup vs baseline: 3.0198x; 1.0553x over previous
#include <cuda_runtime.h>
#include <cuda_fp16.h>
#include <cstdint>
#include <cstddef>

// ---------------------------------------------------------------------------
// Problem constants
// ---------------------------------------------------------------------------
#define E_DIM   1024
#define QKV_N   3072
#define H_DIM   16
#define D_DIM   64
#define B_DIM   2
#define T_DIM   32
#define N_DIM   256
#define MTOK    (B_DIM * T_DIM * N_DIM)   // 16384 tokens total
#define MTOK_B  (T_DIM * N_DIM)           // 8192 tokens per batch
#define KSEL    256
#define MAXLEN  512
#define RB_ONE  ((2 * MAXLEN - 1) * H_DIM)
#define OUT_ROWS 448                      // 256 + 128 + 64
#define SPLITK_SEL 8

// ---------------------------------------------------------------------------
// Scratch (device globals — no allocations allowed)
// ---------------------------------------------------------------------------
__device__ __half g_QKVh[MTOK * QKV_N];   // merged Q|K|V per token, fp16
__device__ float g_Hb[MTOK * E_DIM];      // layer-3 ctx fp32 (for selection)
__device__ float g_SC[MTOK * KSEL];
__device__ float g_S1[B_DIM * KSEL * E_DIM];   // wts^T @ ctx
__device__ float g_SEL[B_DIM * KSEL * E_DIM];  // final selected tokens

// fp16 split activations: ping (attention out) and pong (misc)
__device__ __half g_Ah[MTOK * E_DIM];
__device__ __half g_Al[MTOK * E_DIM];
__device__ __half g_Ah2[MTOK * E_DIM];
__device__ __half g_Al2[MTOK * E_DIM];
// transposed fp16 weights
__device__ __half g_WqkvTh[4 * 3 * E_DIM * E_DIM];  // [a][q|k|v][N=E][K=E] hi
__device__ __half g_WqkvTl[4 * 3 * E_DIM * E_DIM];  // lo
__device__ __half g_Wd16[4 * E_DIM * E_DIM];        // wd plain (row-major) fp16
__device__ __half g_WdT3[E_DIM * E_DIM];            // wd[3] transposed fp16
__device__ __half g_WcT[3 * QKV_N * E_DIM];         // combined W'^T = (Wd_a Wqkv_{a+1})^T fp16
__device__ __half g_SWTh[KSEL * E_DIM];             // selw^T hi
__device__ __half g_SWTl[KSEL * E_DIM];             // selw^T lo
__device__ __half g_Bsel[KSEL * E_DIM];             // (Wd3 @ selw)^T fp16
// selection mma operands
__device__ __half g_SCTh[B_DIM * KSEL * MTOK_B];    // wts^T hi
__device__ __half g_SCTl[B_DIM * KSEL * MTOK_B];    // wts^T lo
__device__ __half g_CTh[B_DIM * E_DIM * MTOK_B];    // ctx^T hi
__device__ float  g_Bqkv[4 * QKV_N];                // merged qkv bias per attn idx
__device__ float  g_Bcomb[3 * QKV_N];               // combined bias bd_a@Wqkv_{a+1}+b_{a+1}
__device__ float  g_Bias2[KSEL];                    // bd3@selw + selb
__device__ float  g_Bzero[E_DIM];                   // zero bias (static zero-init)

// ---------------------------------------------------------------------------
// PTX helpers
// ---------------------------------------------------------------------------
__device__ __forceinline__ void cp_async16(uint32_t dst, const void* src) {
    asm volatile("cp.async.cg.shared.global [%0], [%1], 16;" :: "r"(dst), "l"(src));
}
__device__ __forceinline__ void cp_commit() {
    asm volatile("cp.async.commit_group;" ::: "memory");
}
template <int N>
__device__ __forceinline__ void cp_wait_group() {
    asm volatile("cp.async.wait_group %0;" :: "n"(N) : "memory");
}
__device__ __forceinline__ void ldmatrix_x4(uint32_t* r, uint32_t addr) {
    asm volatile("ldmatrix.sync.aligned.m8n8.x4.shared.b16 {%0,%1,%2,%3}, [%4];"
                 : "=r"(r[0]), "=r"(r[1]), "=r"(r[2]), "=r"(r[3]) : "r"(addr));
}
__device__ __forceinline__ void mma_f16(float* d, const uint32_t* a,
                                        uint32_t b0, uint32_t b1) {
    asm volatile(
        "mma.sync.aligned.m16n8k16.row.col.f32.f16.f16.f32 "
        "{%0,%1,%2,%3}, {%4,%5,%6,%7}, {%8,%9}, {%0,%1,%2,%3};"
        : "+f"(d[0]), "+f"(d[1]), "+f"(d[2]), "+f"(d[3])
        : "r"(a[0]), "r"(a[1]), "r"(a[2]), "r"(a[3]), "r"(b0), "r"(b1));
}
__device__ __forceinline__ uint32_t h2pack(float a, float b) {
    __half2 h = __floats2half2_rn(a, b);
    return *(uint32_t*)&h;
}

// ---------------------------------------------------------------------------
// fp16 GEMM via mma.sync (1 or 2 A segments); optional fp32/fp16hi/fp16lo out.
// ---------------------------------------------------------------------------
#define GSTAGES 3
#define ROWPAD  40
#define TILE_BYTES (128 * ROWPAD * 2)

template <int SEGS>
__global__ __launch_bounds__(256, 2)
void gemm_f16(const __half* __restrict__ Ah, const __half* __restrict__ Al,
              const __half* __restrict__ B,
              const float* __restrict__ bias, float* __restrict__ C,
              __half* __restrict__ Ch, __half* __restrict__ Cl,
              int Nfull, int Kfull,
              size_t zA, size_t zB, size_t zC)
{
    constexpr int STB = (SEGS + 1) * TILE_BYTES;

    extern __shared__ char smem[];
    const uint32_t sb = (uint32_t)__cvta_generic_to_shared(smem);
    const int tid = threadIdx.x;
    const int lane = tid & 31;
    const int warp = tid >> 5;
    const int wm = warp >> 1;
    const int wn = warp & 1;
    const int m0 = blockIdx.y * 128;
    const int n0 = blockIdx.x * 128;

    Ah += (size_t)blockIdx.z * zA;
    if (SEGS == 2) Al += (size_t)blockIdx.z * zA;
    B  += (size_t)blockIdx.z * zB;
    if (C)  C  += (size_t)blockIdx.z * zC;
    if (Ch) Ch += (size_t)blockIdx.z * zC;
    if (Cl) Cl += (size_t)blockIdx.z * zC;

    const int NCH = Kfull >> 5;
    const int lr0 = tid >> 1;
    const int ls0 = (tid & 1) << 1;

    float acc[2][8][4];
#pragma unroll
    for (int mi = 0; mi < 2; mi++)
#pragma unroll
        for (int ni = 0; ni < 8; ni++)
#pragma unroll
            for (int q = 0; q < 4; q++) acc[mi][ni][q] = 0.f;

    auto load_chunk = [&](int c, int stage) {
        const int kb = c << 5;
        const uint32_t base = sb + stage * STB;
#pragma unroll
        for (int j = 0; j < 2; j++) {
            const int s4 = ls0 + j;
            const uint32_t soff = (uint32_t)(lr0 * ROWPAD + s4 * 8) * 2;
            const size_t goff = (size_t)lr0 * Kfull + kb + s4 * 8;
            cp_async16(base + soff, Ah + (size_t)m0 * Kfull + goff);
            if (SEGS == 2)
                cp_async16(base + TILE_BYTES + soff, Al + (size_t)m0 * Kfull + goff);
            cp_async16(base + SEGS * TILE_BYTES + soff, B + (size_t)n0 * Kfull + goff);
        }
    };

#pragma unroll
    for (int s = 0; s < GSTAGES - 1; s++) {
        if (s < NCH) load_chunk(s, s);
        cp_commit();
    }

    const int la_i = lane & 7;
    const int la_g = lane >> 3;
    const int a_rowadd = la_i + ((la_g & 1) << 3);
    const int a_coladd = (la_g >> 1) << 3;
    const int b_rowadd = la_i + ((la_g >> 1) << 3);
    const int b_coladd = (la_g & 1) << 3;

    for (int c = 0; c < NCH; c++) {
        const int stage = c % GSTAGES;
        cp_wait_group<GSTAGES - 2>();
        __syncthreads();

        const int nc = c + GSTAGES - 1;
        if (nc < NCH) load_chunk(nc, nc % GSTAGES);
        cp_commit();

        const uint32_t base = sb + stage * STB;
        const uint32_t Bbase = base + SEGS * TILE_BYTES;

#pragma unroll
        for (int k16 = 0; k16 < 32; k16 += 16) {
            uint32_t bf[4][4];
#pragma unroll
            for (int nb = 0; nb < 4; nb++) {
                const int row = wn * 64 + nb * 16 + b_rowadd;
                const int col = k16 + b_coladd;
                ldmatrix_x4(bf[nb], Bbase + (uint32_t)(row * ROWPAD + col) * 2);
            }
#pragma unroll
            for (int seg = 0; seg < SEGS; seg++) {
                const uint32_t Abase = base + seg * TILE_BYTES;
                uint32_t af[2][4];
#pragma unroll
                for (int mi = 0; mi < 2; mi++) {
                    const int row = wm * 32 + mi * 16 + a_rowadd;
                    const int col = k16 + a_coladd;
                    ldmatrix_x4(af[mi], Abase + (uint32_t)(row * ROWPAD + col) * 2);
                }
#pragma unroll
                for (int nb = 0; nb < 4; nb++)
#pragma unroll
                    for (int mi = 0; mi < 2; mi++) {
                        mma_f16(acc[mi][nb * 2 + 0], af[mi], bf[nb][0], bf[nb][1]);
                        mma_f16(acc[mi][nb * 2 + 1], af[mi], bf[nb][2], bf[nb][3]);
                    }
            }
        }
    }

    const int tq = lane >> 2;
    const int tr = lane & 3;
#pragma unroll
    for (int mi = 0; mi < 2; mi++) {
        const int row = m0 + wm * 32 + mi * 16 + tq;
#pragma unroll
        for (int ni = 0; ni < 8; ni++) {
            const int col = n0 + wn * 64 + ni * 8 + tr * 2;
            const float b0 = bias[col], b1 = bias[col + 1];
            float c00 = acc[mi][ni][0] + b0, c01 = acc[mi][ni][1] + b1;
            float c10 = acc[mi][ni][2] + b0, c11 = acc[mi][ni][3] + b1;
            if (C) {
                float2 v0; v0.x = c00; v0.y = c01;
                float2 v1; v1.x = c10; v1.y = c11;
                *(float2*)&C[(size_t)row * Nfull + col] = v0;
                *(float2*)&C[(size_t)(row + 8) * Nfull + col] = v1;
            }
            if (Ch || Cl) {
                __half h00 = __float2half_rn(c00);
                __half h01 = __float2half_rn(c01);
                __half h10 = __float2half_rn(c10);
                __half h11 = __float2half_rn(c11);
                if (Ch) {
                    *(__half2*)&Ch[(size_t)row * Nfull + col]       = __halves2half2(h00, h01);
                    *(__half2*)&Ch[(size_t)(row + 8) * Nfull + col] = __halves2half2(h10, h11);
                }
                if (Cl) {
                    __half l00 = __float2half_rn(c00 - __half2float(h00));
                    __half l01 = __float2half_rn(c01 - __half2float(h01));
                    __half l10 = __float2half_rn(c10 - __half2float(h10));
                    __half l11 = __float2half_rn(c11 - __half2float(h11));
                    *(__half2*)&Cl[(size_t)row * Nfull + col]       = __halves2half2(l00, l01);
                    *(__half2*)&Cl[(size_t)(row + 8) * Nfull + col] = __halves2half2(l10, l11);
                }
            }
        }
    }
}

// ---------------------------------------------------------------------------
// Split-K selection GEMM via mma.sync:
//   S1[b][k,e] += sum_m (SCTh+SCTl)[b][k,m] * CTh[b][e,m]
// grid (E/128, KSEL/128, B*SPLITK_SEL); fp32 atomic epilogue.
// ---------------------------------------------------------------------------
__global__ __launch_bounds__(256, 2)
void gemm_sel_mma(const __half* __restrict__ SCTh, const __half* __restrict__ SCTl,
                  const __half* __restrict__ CTh, float* __restrict__ S1)
{
    constexpr int STB = 3 * TILE_BYTES;

    extern __shared__ char smem[];
    const uint32_t sb = (uint32_t)__cvta_generic_to_shared(smem);
    const int tid = threadIdx.x;
    const int lane = tid & 31;
    const int warp = tid >> 5;
    const int wm = warp >> 1;
    const int wn = warp & 1;
    const int m0 = blockIdx.y * 128;
    const int n0 = blockIdx.x * 128;
    const int b  = blockIdx.z / SPLITK_SEL;
    const int sl = blockIdx.z % SPLITK_SEL;
    const int kbeg = sl * (MTOK_B / SPLITK_SEL);   // 1024
    const int NCH = (MTOK_B / SPLITK_SEL) >> 5;    // 32

    const __half* Ah = SCTh + (size_t)b * KSEL * MTOK_B;
    const __half* Al = SCTl + (size_t)b * KSEL * MTOK_B;
    const __half* B  = CTh  + (size_t)b * E_DIM * MTOK_B;
    float* C = S1 + (size_t)b * KSEL * E_DIM;

    const int lr0 = tid >> 1;
    const int ls0 = (tid & 1) << 1;

    float acc[2][8][4];
#pragma unroll
    for (int mi = 0; mi < 2; mi++)
#pragma unroll
        for (int ni = 0; ni < 8; ni++)
#pragma unroll
            for (int q = 0; q < 4; q++) acc[mi][ni][q] = 0.f;

    auto load_chunk = [&](int c, int stage) {
        const int kb = kbeg + (c << 5);
        const uint32_t base = sb + stage * STB;
#pragma unroll
        for (int j = 0; j < 2; j++) {
            const int s4 = ls0 + j;
            const uint32_t soff = (uint32_t)(lr0 * ROWPAD + s4 * 8) * 2;
            cp_async16(base + soff,
                       Ah + (size_t)(m0 + lr0) * MTOK_B + kb + s4 * 8);
            cp_async16(base + TILE_BYTES + soff,
                       Al + (size_t)(m0 + lr0) * MTOK_B + kb + s4 * 8);
            cp_async16(base + 2 * TILE_BYTES + soff,
                       B + (size_t)(n0 + lr0) * MTOK_B + kb + s4 * 8);
        }
    };

#pragma unroll
    for (int s = 0; s < GSTAGES - 1; s++) {
        if (s < NCH) load_chunk(s, s);
        cp_commit();
    }

    const int la_i = lane & 7;
    const int la_g = lane >> 3;
    const int a_rowadd = la_i + ((la_g & 1) << 3);
    const int a_coladd = (la_g >> 1) << 3;
    const int b_rowadd = la_i + ((la_g >> 1) << 3);
    const int b_coladd = (la_g & 1) << 3;

    for (int c = 0; c < NCH; c++) {
        const int stage = c % GSTAGES;
        cp_wait_group<GSTAGES - 2>();
        __syncthreads();

        const int nc = c + GSTAGES - 1;
        if (nc < NCH) load_chunk(nc, nc % GSTAGES);
        cp_commit();

        const uint32_t base = sb + stage * STB;
        const uint32_t Bbase = base + 2 * TILE_BYTES;

#pragma unroll
        for (int k16 = 0; k16 < 32; k16 += 16) {
            uint32_t bf[4][4];
#pragma unroll
            for (int nb = 0; nb < 4; nb++) {
                const int row = wn * 64 + nb * 16 + b_rowadd;
                const int col = k16 + b_coladd;
                ldmatrix_x4(bf[nb], Bbase + (uint32_t)(row * ROWPAD + col) * 2);
            }
#pragma unroll
            for (int seg = 0; seg < 2; seg++) {
                const uint32_t Abase = base + seg * TILE_BYTES;
                uint32_t af[2][4];
#pragma unroll
                for (int mi = 0; mi < 2; mi++) {
                    const int row = wm * 32 + mi * 16 + a_rowadd;
                    const int col = k16 + a_coladd;
                    ldmatrix_x4(af[mi], Abase + (uint32_t)(row * ROWPAD + col) * 2);
                }
#pragma unroll
                for (int nb = 0; nb < 4; nb++)
#pragma unroll
                    for (int mi = 0; mi < 2; mi++) {
                        mma_f16(acc[mi][nb * 2 + 0], af[mi], bf[nb][0], bf[nb][1]);
                        mma_f16(acc[mi][nb * 2 + 1], af[mi], bf[nb][2], bf[nb][3]);
                    }
            }
        }
    }

    const int tq = lane >> 2;
    const int tr = lane & 3;
#pragma unroll
    for (int mi = 0; mi < 2; mi++) {
        const int row = m0 + wm * 32 + mi * 16 + tq;
#pragma unroll
        for (int ni = 0; ni < 8; ni++) {
            const int col = n0 + wn * 64 + ni * 8 + tr * 2;
            atomicAdd(&C[(size_t)row * E_DIM + col],           acc[mi][ni][0]);
            atomicAdd(&C[(size_t)row * E_DIM + col + 1],       acc[mi][ni][1]);
            atomicAdd(&C[(size_t)(row + 8) * E_DIM + col],     acc[mi][ni][2]);
            atomicAdd(&C[(size_t)(row + 8) * E_DIM + col + 1], acc[mi][ni][3]);
        }
    }
}

// ---------------------------------------------------------------------------
// mma.sync spatial attention (S=256, step 1), flash-style online softmax.
// ---------------------------------------------------------------------------
#define AKS_BYTES  (256 * 72 * 2)           // 36864
#define AVT_BYTES  (64 * 264 * 2)           // 33792
#define ATTN_SMEM  (AKS_BYTES + AVT_BYTES + 512 * 4)   // 74704

__global__ __launch_bounds__(256)
void attn_mma(const __half* __restrict__ Q, const __half* __restrict__ K,
              const __half* __restrict__ V,
              __half* __restrict__ OutH, __half* __restrict__ OutL,
              const float* __restrict__ rb, int ldx)
{
    const int h = blockIdx.x;
    const int g = blockIdx.y;
    const int qh = blockIdx.z;
    const int base_m = g * N_DIM;
    const size_t baseE = (size_t)base_m * ldx + h * D_DIM;

    extern __shared__ char sm8[];
    __half* Ks = (__half*)sm8;                       // [256][72]
    __half* Vt = (__half*)(sm8 + AKS_BYTES);         // [64][264]
    float*  rbh = (float*)(sm8 + AKS_BYTES + AVT_BYTES);
    const uint32_t sKs = (uint32_t)__cvta_generic_to_shared(Ks);
    const uint32_t sVt = (uint32_t)__cvta_generic_to_shared(Vt);

    const int tid = threadIdx.x;
    const int lane = tid & 31;
    const int warp = tid >> 5;

    for (int i = tid; i < 128 * 8; i += 256) {
        int r = i >> 3, cs = i & 7;
        *(float4*)&Ks[r * 72 + cs * 8] =
            *(const float4*)(Q + baseE + (size_t)(qh * 128 + r) * ldx + cs * 8);
    }
    __syncthreads();

    const int la_i = lane & 7;
    const int la_g = lane >> 3;
    const int a_rowadd = la_i + ((la_g & 1) << 3);
    const int a_coladd = (la_g >> 1) << 3;
    const int b_rowadd = la_i + ((la_g >> 1) << 3);
    const int b_coladd = (la_g & 1) << 3;

    uint32_t Qf[4][4];
    const int wq = warp * 16;
#pragma unroll
    for (int kk = 0; kk < 4; kk++)
        ldmatrix_x4(Qf[kk], sKs + (uint32_t)((wq + a_rowadd) * 72 + kk * 16 + a_coladd) * 2);
    __syncthreads();

    for (int i = tid; i < 256 * 8; i += 256) {
        int r = i >> 3, cs = i & 7;
        *(float4*)&Ks[r * 72 + cs * 8] =
            *(const float4*)(K + baseE + (size_t)r * ldx + cs * 8);
    }
    for (int i = tid; i < 256 * 32; i += 256) {
        int t = i >> 5, d2 = i & 31;
        __half2 v = *(const __half2*)(V + baseE + (size_t)t * ldx + 2 * d2);
        Vt[(2 * d2) * 264 + t]     = __low2half(v);
        Vt[(2 * d2 + 1) * 264 + t] = __high2half(v);
    }
    for (int i = tid; i < 511; i += 256)
        rbh[i] = rb[(size_t)(MAXLEN - 256 + i) * H_DIM + h];
    __syncthreads();

    const int tq = lane >> 2;
    const int tr = lane & 3;
    const int r0 = qh * 128 + wq + tq;
    const int r1 = r0 + 8;

    float o[8][4];
#pragma unroll
    for (int j = 0; j < 8; j++)
#pragma unroll
        for (int q = 0; q < 4; q++) o[j][q] = 0.f;
    float m0 = -1e30f, m1 = -1e30f, l0 = 0.f, l1 = 0.f;

#pragma unroll
    for (int ch = 0; ch < 4; ch++) {
        float s[8][4];
#pragma unroll
        for (int j = 0; j < 8; j++)
#pragma unroll
            for (int q = 0; q < 4; q++) s[j][q] = 0.f;

#pragma unroll
        for (int kk = 0; kk < 4; kk++) {
#pragma unroll
            for (int nb = 0; nb < 4; nb++) {
                uint32_t bf[4];
                ldmatrix_x4(bf, sKs + (uint32_t)((ch * 64 + nb * 16 + b_rowadd) * 72
                                                 + kk * 16 + b_coladd) * 2);
                mma_f16(s[nb * 2 + 0], Qf[kk], bf[0], bf[1]);
                mma_f16(s[nb * 2 + 1], Qf[kk], bf[2], bf[3]);
            }
        }

        float cm0 = -1e30f, cm1 = -1e30f;
#pragma unroll
        for (int j = 0; j < 8; j++) {
            const int c = ch * 64 + j * 8 + 2 * tr;
            s[j][0] = s[j][0] * 0.125f + rbh[c - r0 + 255];
            s[j][1] = s[j][1] * 0.125f + rbh[c + 1 - r0 + 255];
            s[j][2] = s[j][2] * 0.125f + rbh[c - r1 + 255];
            s[j][3] = s[j][3] * 0.125f + rbh[c + 1 - r1 + 255];
            cm0 = fmaxf(cm0, fmaxf(s[j][0], s[j][1]));
            cm1 = fmaxf(cm1, fmaxf(s[j][2], s[j][3]));
        }
        cm0 = fmaxf(cm0, __shfl_xor_sync(0xffffffffu, cm0, 1));
        cm0 = fmaxf(cm0, __shfl_xor_sync(0xffffffffu, cm0, 2));
        cm1 = fmaxf(cm1, __shfl_xor_sync(0xffffffffu, cm1, 1));
        cm1 = fmaxf(cm1, __shfl_xor_sync(0xffffffffu, cm1, 2));

        const float nm0 = fmaxf(m0, cm0), nm1 = fmaxf(m1, cm1);
        const float sc0 = __expf(m0 - nm0), sc1 = __expf(m1 - nm1);
        float rs0 = 0.f, rs1 = 0.f;
#pragma unroll
        for (int j = 0; j < 8; j++) {
            s[j][0] = __expf(s[j][0] - nm0);
            s[j][1] = __expf(s[j][1] - nm0);
            s[j][2] = __expf(s[j][2] - nm1);
            s[j][3] = __expf(s[j][3] - nm1);
            rs0 += s[j][0] + s[j][1];
            rs1 += s[j][2] + s[j][3];
        }
        rs0 += __shfl_xor_sync(0xffffffffu, rs0, 1);
        rs0 += __shfl_xor_sync(0xffffffffu, rs0, 2);
        rs1 += __shfl_xor_sync(0xffffffffu, rs1, 1);
        rs1 += __shfl_xor_sync(0xffffffffu, rs1, 2);
        l0 = l0 * sc0 + rs0;
        l1 = l1 * sc1 + rs1;
        m0 = nm0; m1 = nm1;
#pragma unroll
        for (int j = 0; j < 8; j++) {
            o[j][0] *= sc0; o[j][1] *= sc0;
            o[j][2] *= sc1; o[j][3] *= sc1;
        }

        uint32_t pa[4][4];
#pragma unroll
        for (int kk = 0; kk < 4; kk++) {
            pa[kk][0] = h2pack(s[2 * kk][0], s[2 * kk][1]);
            pa[kk][1] = h2pack(s[2 * kk][2], s[2 * kk][3]);
            pa[kk][2] = h2pack(s[2 * kk + 1][0], s[2 * kk + 1][1]);
            pa[kk][3] = h2pack(s[2 * kk + 1][2], s[2 * kk + 1][3]);
        }

#pragma unroll
        for (int kk = 0; kk < 4; kk++) {
#pragma unroll
            for (int nb = 0; nb < 4; nb++) {
                uint32_t bf[4];
                ldmatrix_x4(bf, sVt + (uint32_t)((nb * 16 + b_rowadd) * 264
                                                 + ch * 64 + kk * 16 + b_coladd) * 2);
                mma_f16(o[nb * 2 + 0], pa[kk], bf[0], bf[1]);
                mma_f16(o[nb * 2 + 1], pa[kk], bf[2], bf[3]);
            }
        }
    }

    const float inv0 = 1.f / l0, inv1 = 1.f / l1;
    const size_t oo0 = (size_t)(base_m + r0) * E_DIM + h * D_DIM;
    const size_t oo1 = (size_t)(base_m + r1) * E_DIM + h * D_DIM;
#pragma unroll
    for (int j = 0; j < 8; j++) {
        const int c = j * 8 + 2 * tr;
        float c00 = o[j][0] * inv0, c01 = o[j][1] * inv0;
        float c10 = o[j][2] * inv1, c11 = o[j][3] * inv1;
        __half h00 = __float2half_rn(c00), h01 = __float2half_rn(c01);
        __half h10 = __float2half_rn(c10), h11 = __float2half_rn(c11);
        *(__half2*)&OutH[oo0 + c] = __halves2half2(h00, h01);
        *(__half2*)&OutH[oo1 + c] = __halves2half2(h10, h11);
        *(__half2*)&OutL[oo0 + c] = __halves2half2(
            __float2half_rn(c00 - __half2float(h00)), __float2half_rn(c01 - __half2float(h01)));
        *(__half2*)&OutL[oo1 + c] = __halves2half2(
            __float2half_rn(c10 - __half2float(h10)), __float2half_rn(c11 - __half2float(h11)));
    }
}

// ---------------------------------------------------------------------------
// mma.sync temporal attention (S=32, step N_DIM): one warp per (h,b,n) group.
// ---------------------------------------------------------------------------
#define TBUF_HALVES 2560
#define ATTN_T_SMEM (8 * TBUF_HALVES * 2 + 64 * 4)   // 41216

__global__ __launch_bounds__(256)
void attn_mma_t(const __half* __restrict__ Q, const __half* __restrict__ K,
                const __half* __restrict__ V,
                __half* __restrict__ OutH, __half* __restrict__ OutL,
                float* __restrict__ OutF,
                const float* __restrict__ rb, int ldx)
{
    const int h = blockIdx.x;
    const int tid = threadIdx.x;
    const int lane = tid & 31;
    const int warp = tid >> 5;
    const int g = blockIdx.y * 8 + warp;
    const int b = g >> 8, n = g & 255;
    const int base_m = b * MTOK_B + n;
    const size_t baseE = (size_t)base_m * ldx + h * D_DIM;
    const size_t stepE = (size_t)N_DIM * ldx;

    extern __shared__ char smT[];
    __half* buf = (__half*)smT + warp * TBUF_HALVES;
    float* rbh = (float*)(smT + 8 * TBUF_HALVES * 2);
    const uint32_t sb = (uint32_t)__cvta_generic_to_shared(buf);

    for (int i = tid; i < 63; i += 256)
        rbh[i] = rb[(size_t)(MAXLEN - 32 + i) * H_DIM + h];
    __syncthreads();

    const int la_i = lane & 7;
    const int la_g = lane >> 3;
    const int a_rowadd = la_i + ((la_g & 1) << 3);
    const int a_coladd = (la_g >> 1) << 3;
    const int b_rowadd = la_i + ((la_g >> 1) << 3);
    const int b_coladd = (la_g & 1) << 3;
    const int tq = lane >> 2;
    const int tr = lane & 3;

#pragma unroll
    for (int j = 0; j < 8; j++) {
        int idx = lane + j * 32;
        int r = idx >> 3, cs = idx & 7;
        *(float4*)&buf[r * 72 + cs * 8] =
            *(const float4*)(Q + baseE + (size_t)r * stepE + cs * 8);
    }
    __syncwarp();
    uint32_t Qf[2][4][4];
#pragma unroll
    for (int mi = 0; mi < 2; mi++)
#pragma unroll
        for (int kk = 0; kk < 4; kk++)
            ldmatrix_x4(Qf[mi][kk],
                        sb + (uint32_t)((mi * 16 + a_rowadd) * 72 + kk * 16 + a_coladd) * 2);
    __syncwarp();

#pragma unroll
    for (int j = 0; j < 8; j++) {
        int idx = lane + j * 32;
        int r = idx >> 3, cs = idx & 7;
        *(float4*)&buf[r * 72 + cs * 8] =
            *(const float4*)(K + baseE + (size_t)r * stepE + cs * 8);
    }
    __syncwarp();

    float s[2][4][4];
#pragma unroll
    for (int mi = 0; mi < 2; mi++)
#pragma unroll
        for (int ni = 0; ni < 4; ni++)
#pragma unroll
            for (int q = 0; q < 4; q++) s[mi][ni][q] = 0.f;

#pragma unroll
    for (int kk = 0; kk < 4; kk++)
#pragma unroll
        for (int nb = 0; nb < 2; nb++) {
            uint32_t bf[4];
            ldmatrix_x4(bf, sb + (uint32_t)((nb * 16 + b_rowadd) * 72 + kk * 16 + b_coladd) * 2);
#pragma unroll
            for (int mi = 0; mi < 2; mi++) {
                mma_f16(s[mi][nb * 2 + 0], Qf[mi][kk], bf[0], bf[1]);
                mma_f16(s[mi][nb * 2 + 1], Qf[mi][kk], bf[2], bf[3]);
            }
        }
    __syncwarp();

#pragma unroll
    for (int j = 0; j < 32; j++) {
        __half2 v = *(const __half2*)(V + baseE + (size_t)j * stepE + 2 * lane);
        buf[(2 * lane) * 40 + j]     = __low2half(v);
        buf[(2 * lane + 1) * 40 + j] = __high2half(v);
    }
    __syncwarp();

#pragma unroll
    for (int mi = 0; mi < 2; mi++) {
        const int ra = mi * 16 + tq, rb2 = ra + 8;
        float mxa = -1e30f, mxb = -1e30f;
#pragma unroll
        for (int ni = 0; ni < 4; ni++) {
            const int c = ni * 8 + 2 * tr;
            s[mi][ni][0] = s[mi][ni][0] * 0.125f + rbh[c - ra + 31];
            s[mi][ni][1] = s[mi][ni][1] * 0.125f + rbh[c + 1 - ra + 31];
            s[mi][ni][2] = s[mi][ni][2] * 0.125f + rbh[c - rb2 + 31];
            s[mi][ni][3] = s[mi][ni][3] * 0.125f + rbh[c + 1 - rb2 + 31];
            mxa = fmaxf(mxa, fmaxf(s[mi][ni][0], s[mi][ni][1]));
            mxb = fmaxf(mxb, fmaxf(s[mi][ni][2], s[mi][ni][3]));
        }
        mxa = fmaxf(mxa, __shfl_xor_sync(0xffffffffu, mxa, 1));
        mxa = fmaxf(mxa, __shfl_xor_sync(0xffffffffu, mxa, 2));
        mxb = fmaxf(mxb, __shfl_xor_sync(0xffffffffu, mxb, 1));
        mxb = fmaxf(mxb, __shfl_xor_sync(0xffffffffu, mxb, 2));
        float sa = 0.f, sbm = 0.f;
#pragma unroll
        for (int ni = 0; ni < 4; ni++) {
            s[mi][ni][0] = __expf(s[mi][ni][0] - mxa);
            s[mi][ni][1] = __expf(s[mi][ni][1] - mxa);
            s[mi][ni][2] = __expf(s[mi][ni][2] - mxb);
            s[mi][ni][3] = __expf(s[mi][ni][3] - mxb);
            sa += s[mi][ni][0] + s[mi][ni][1];
            sbm += s[mi][ni][2] + s[mi][ni][3];
        }
        sa += __shfl_xor_sync(0xffffffffu, sa, 1);
        sa += __shfl_xor_sync(0xffffffffu, sa, 2);
        sbm += __shfl_xor_sync(0xffffffffu, sbm, 1);
        sbm += __shfl_xor_sync(0xffffffffu, sbm, 2);
        const float ia = 1.f / sa, ib = 1.f / sbm;
#pragma unroll
        for (int ni = 0; ni < 4; ni++) {
            s[mi][ni][0] *= ia; s[mi][ni][1] *= ia;
            s[mi][ni][2] *= ib; s[mi][ni][3] *= ib;
        }
    }

    uint32_t pa[2][2][4];
#pragma unroll
    for (int mi = 0; mi < 2; mi++)
#pragma unroll
        for (int kk = 0; kk < 2; kk++) {
            pa[mi][kk][0] = h2pack(s[mi][2 * kk][0], s[mi][2 * kk][1]);
            pa[mi][kk][1] = h2pack(s[mi][2 * kk][2], s[mi][2 * kk][3]);
            pa[mi][kk][2] = h2pack(s[mi][2 * kk + 1][0], s[mi][2 * kk + 1][1]);
            pa[mi][kk][3] = h2pack(s[mi][2 * kk + 1][2], s[mi][2 * kk + 1][3]);
        }

    float o[2][8][4];
#pragma unroll
    for (int mi = 0; mi < 2; mi++)
#pragma unroll
        for (int ni = 0; ni < 8; ni++)
#pragma unroll
            for (int q = 0; q < 4; q++) o[mi][ni][q] = 0.f;

#pragma unroll
    for (int kk = 0; kk < 2; kk++)
#pragma unroll
        for (int nb = 0; nb < 4; nb++) {
            uint32_t bf[4];
            ldmatrix_x4(bf, sb + (uint32_t)((nb * 16 + b_rowadd) * 40 + kk * 16 + b_coladd) * 2);
#pragma unroll
            for (int mi = 0; mi < 2; mi++) {
                mma_f16(o[mi][nb * 2 + 0], pa[mi][kk], bf[0], bf[1]);
                mma_f16(o[mi][nb * 2 + 1], pa[mi][kk], bf[2], bf[3]);
            }
        }

#pragma unroll
    for (int mi = 0; mi < 2; mi++) {
        const int ra = mi * 16 + tq;
        const size_t oo0 = (size_t)(base_m + ra * N_DIM) * E_DIM + h * D_DIM;
        const size_t oo1 = (size_t)(base_m + (ra + 8) * N_DIM) * E_DIM + h * D_DIM;
#pragma unroll
        for (int ni = 0; ni < 8; ni++) {
            const int c = ni * 8 + 2 * tr;
            float c00 = o[mi][ni][0], c01 = o[mi][ni][1];
            float c10 = o[mi][ni][2], c11 = o[mi][ni][3];
            __half h00 = __float2half_rn(c00), h01 = __float2half_rn(c01);
            __half h10 = __float2half_rn(c10), h11 = __float2half_rn(c11);
            *(__half2*)&OutH[oo0 + c] = __halves2half2(h00, h01);
            *(__half2*)&OutH[oo1 + c] = __halves2half2(h10, h11);
            *(__half2*)&OutL[oo0 + c] = __halves2half2(
                __float2half_rn(c00 - __half2float(h00)),
                __float2half_rn(c01 - __half2float(h01)));
            *(__half2*)&OutL[oo1 + c] = __halves2half2(
                __float2half_rn(c10 - __half2float(h10)),
                __float2half_rn(c11 - __half2float(h11)));
            if (OutF) {
                float2 f0; f0.x = c00; f0.y = c01;
                float2 f1; f1.x = c10; f1.y = c11;
                *(float2*)&OutF[oo0 + c] = f0;
                *(float2*)&OutF[oo1 + c] = f1;
            }
        }
    }
}

// ---------------------------------------------------------------------------
// misc elementwise / prep kernels
// ---------------------------------------------------------------------------
__global__ void cvt_hilo(const float* __restrict__ x, __half* __restrict__ hi,
                         __half* __restrict__ lo, int n4)
{
    int i = blockIdx.x * blockDim.x + threadIdx.x;
    if (i >= n4) return;
    float4 v = ((const float4*)x)[i];
    __half h0 = __float2half_rn(v.x);
    __half h1 = __float2half_rn(v.y);
    __half h2 = __float2half_rn(v.z);
    __half h3 = __float2half_rn(v.w);
    __half l0 = __float2half_rn(v.x - __half2float(h0));
    __half l1 = __float2half_rn(v.y - __half2float(h1));
    __half l2 = __float2half_rn(v.z - __half2float(h2));
    __half l3 = __float2half_rn(v.w - __half2float(h3));
    __half2* hp = (__half2*)hi;
    __half2* lp = (__half2*)lo;
    hp[2 * i + 0] = __half2(h0, h1);
    hp[2 * i + 1] = __half2(h2, h3);
    lp[2 * i + 0] = __half2(l0, l1);
    lp[2 * i + 1] = __half2(l2, l3);
}

__global__ void cvt_f16(const float* __restrict__ x, __half* __restrict__ y, int n4)
{
    int i = blockIdx.x * blockDim.x + threadIdx.x;
    if (i >= n4) return;
    float4 v = ((const float4*)x)[i];
    __half2* yp = (__half2*)y;
    yp[2 * i + 0] = __floats2half2_rn(v.x, v.y);
    yp[2 * i + 1] = __floats2half2_rn(v.z, v.w);
}

__global__ void wt_cvt3(const float* __restrict__ W, __half* __restrict__ WTh,
                        __half* __restrict__ WTl, int Kd, int Nd, int type, int slots)
{
    __shared__ float t[32][33];
    const size_t srcoff = (size_t)blockIdx.z * Kd * Nd;
    const size_t dstoff = ((size_t)blockIdx.z * slots + type) * Kd * Nd;
    const float* Wm = W + srcoff;
    __half* Hh = WTh + dstoff;
    __half* Hl = WTl + dstoff;

    int nx = blockIdx.x * 32 + threadIdx.x;
    int k0 = blockIdx.y * 32;
#pragma unroll
    for (int j = 0; j < 4; j++) {
        int kk = k0 + threadIdx.y + j * 8;
        t[threadIdx.y + j * 8][threadIdx.x] = Wm[(size_t)kk * Nd + nx];
    }
    __syncthreads();
    int kx = k0 + threadIdx.x;
#pragma unroll
    for (int j = 0; j < 4; j++) {
        int nn = blockIdx.x * 32 + threadIdx.y + j * 8;
        float v = t[threadIdx.x][threadIdx.y + j * 8];
        __half h = __float2half_rn(v);
        Hh[(size_t)nn * Kd + kx] = h;
        Hl[(size_t)nn * Kd + kx] = __float2half_rn(v - __half2float(h));
    }
}

__global__ void wt_cvt(const float* __restrict__ W, __half* __restrict__ WT,
                       int Kd, int Nd)
{
    __shared__ float t[32][33];
    const size_t moff = (size_t)blockIdx.z * Kd * Nd;
    const float* Wm = W + moff;
    __half* Hh = WT + moff;

    int nx = blockIdx.x * 32 + threadIdx.x;
    int k0 = blockIdx.y * 32;
#pragma unroll
    for (int j = 0; j < 4; j++) {
        int kk = k0 + threadIdx.y + j * 8;
        t[threadIdx.y + j * 8][threadIdx.x] = Wm[(size_t)kk * Nd + nx];
    }
    __syncthreads();
    int kx = k0 + threadIdx.x;
#pragma unroll
    for (int j = 0; j < 4; j++) {
        int nn = blockIdx.x * 32 + threadIdx.y + j * 8;
        Hh[(size_t)nn * Kd + kx] = __float2half_rn(t[threadIdx.x][threadIdx.y + j * 8]);
    }
}

// transpose + hi/lo split: src fp32 [z][R][C] -> dst fp16 [z][C][R]
__global__ void transp_hilo(const float* __restrict__ src, __half* __restrict__ dh,
                            __half* __restrict__ dl, int R, int C)
{
    __shared__ float t[32][33];
    const size_t zo = (size_t)blockIdx.z * R * C;
    const float* S = src + zo;
    __half* Dh = dh + zo;
    __half* Dl = dl ? dl + zo : nullptr;

    int cx = blockIdx.x * 32 + threadIdx.x;
    int r0 = blockIdx.y * 32;
#pragma unroll
    for (int j = 0; j < 4; j++) {
        int rr = r0 + threadIdx.y + j * 8;
        t[threadIdx.y + j * 8][threadIdx.x] = S[(size_t)rr * C + cx];
    }
    __syncthreads();
    int rx = r0 + threadIdx.x;
#pragma unroll
    for (int j = 0; j < 4; j++) {
        int cc = blockIdx.x * 32 + threadIdx.y + j * 8;
        float v = t[threadIdx.x][threadIdx.y + j * 8];
        __half h = __float2half_rn(v);
        Dh[(size_t)cc * R + rx] = h;
        if (Dl) Dl[(size_t)cc * R + rx] = __float2half_rn(v - __half2float(h));
    }
}

__global__ void bias_concat(const float* __restrict__ bq, const float* __restrict__ bk,
                            const float* __restrict__ bv, float* __restrict__ out)
{
    int i = blockIdx.x * blockDim.x + threadIdx.x;
    if (i >= 4 * QKV_N) return;
    int a = i / QKV_N;
    int r = i % QKV_N;
    const float* src = (r < E_DIM) ? bq : (r < 2 * E_DIM) ? bk : bv;
    out[i] = src[a * E_DIM + (r & (E_DIM - 1))];
}

__global__ void bias_comb(const float* __restrict__ wq, const float* __restrict__ wk,
                          const float* __restrict__ wv, const float* __restrict__ bd,
                          const float* __restrict__ bqkv, float* __restrict__ out)
{
    int i = blockIdx.x * blockDim.x + threadIdx.x;
    int z = blockIdx.y;
    const float* W = (i < E_DIM) ? wq : (i < 2 * E_DIM) ? wk : wv;
    int col = i & (E_DIM - 1);
    const float* Wm = W + (size_t)(z + 1) * E_DIM * E_DIM;
    const float* bdz = bd + (size_t)z * E_DIM;
    float s = 0.f;
    for (int k = 0; k < E_DIM; k++)
        s += bdz[k] * Wm[(size_t)k * E_DIM + col];
    out[(size_t)z * QKV_N + i] = s + bqkv[(size_t)(z + 1) * QKV_N + i];
}

__global__ void bias_sel(const float* __restrict__ selw, const float* __restrict__ selb,
                         const float* __restrict__ bd3, float* __restrict__ out)
{
    int k = blockIdx.x * blockDim.x + threadIdx.x;
    if (k >= KSEL) return;
    float s = 0.f;
    for (int e = 0; e < E_DIM; e++)
        s += bd3[e] * selw[(size_t)e * KSEL + k];
    out[k] = s + selb[k];
}

// ---------------------------------------------------------------------------
// Selection softmax / pooling
// ---------------------------------------------------------------------------
__global__ __launch_bounds__(256)
void sel_softmax(float* __restrict__ sc)
{
    const int b = blockIdx.x;
    const int k0 = blockIdx.y * 32;
    const int lane = threadIdx.x & 31;
    const int row = threadIdx.x >> 5;

    float* base = sc + (size_t)b * MTOK_B * KSEL + k0 + lane;

    __shared__ float redA[8][32];
    __shared__ float redB[8][32];

    float mx = -1e30f;
    for (int m = row; m < MTOK_B; m += 8)
        mx = fmaxf(mx, base[(size_t)m * KSEL]);
    redA[row][lane] = mx;
    __syncthreads();
    if (row == 0) {
        float v = redA[0][lane];
#pragma unroll
        for (int r = 1; r < 8; r++) v = fmaxf(v, redA[r][lane]);
        redA[0][lane] = v;
    }
    __syncthreads();
    mx = redA[0][lane];

    float sum = 0.f;
    for (int m = row; m < MTOK_B; m += 8)
        sum += __expf(base[(size_t)m * KSEL] - mx);
    redB[row][lane] = sum;
    __syncthreads();
    if (row == 0) {
        float v = 0.f;
#pragma unroll
        for (int r = 0; r < 8; r++) v += redB[r][lane];
        redB[0][lane] = v;
    }
    __syncthreads();
    float inv = 1.f / redB[0][lane];

    for (int m = row; m < MTOK_B; m += 8) {
        float* p = &base[(size_t)m * KSEL];
        *p = __expf(*p - mx) * inv;
    }
}

__global__ void pool_kernel(const float* __restrict__ sel, float* __restrict__ out)
{
    int idx = blockIdx.x * blockDim.x + threadIdx.x;
    int total = B_DIM * OUT_ROWS * E_DIM;
    if (idx >= total) return;
    int e = idx % E_DIM;
    int r = (idx / E_DIM) % OUT_ROWS;
    int b = idx / (OUT_ROWS * E_DIM);
    const float* sb = sel + (size_t)b * KSEL * E_DIM;
    float v;
    if (r < 256) {
        v = sb[(size_t)r * E_DIM + e];
    } else if (r < 384) {
        int i = (r - 256) * 2;
        v = 0.5f * (sb[(size_t)i * E_DIM + e] + sb[(size_t)(i + 1) * E_DIM + e]);
    } else {
        int i = (r - 384) * 4;
        v = 0.25f * (sb[(size_t)i * E_DIM + e] + sb[(size_t)(i + 1) * E_DIM + e] +
                     sb[(size_t)(i + 2) * E_DIM + e] + sb[(size_t)(i + 3) * E_DIM + e]);
    }
    out[idx] = v;
}

// ---------------------------------------------------------------------------
// Orchestration
// ---------------------------------------------------------------------------
extern "C" void kernel_launch(void* const* d_in, const int* in_sizes, int n_in,
                              void* d_out, int out_size)
{
    (void)in_sizes; (void)n_in; (void)out_size;

    const float* x    = (const float*)d_in[0];
    const float* wq   = (const float*)d_in[1];
    const float* bq   = (const float*)d_in[2];
    const float* wk   = (const float*)d_in[3];
    const float* bk   = (const float*)d_in[4];
    const float* wv   = (const float*)d_in[5];
    const float* bv   = (const float*)d_in[6];
    const float* wd   = (const float*)d_in[7];
    const float* bd   = (const float*)d_in[8];
    const float* rb   = (const float*)d_in[9];
    const float* selw = (const float*)d_in[10];
    const float* selb = (const float*)d_in[11];
    float* out = (float*)d_out;

    float *Hb, *SCb, *S1b, *SELb, *Bqkv, *Bcomb, *Bias2, *Bzero;
    cudaGetSymbolAddress((void**)&Hb,  g_Hb);
    cudaGetSymbolAddress((void**)&SCb, g_SC);
    cudaGetSymbolAddress((void**)&S1b, g_S1);
    cudaGetSymbolAddress((void**)&SELb, g_SEL);
    cudaGetSymbolAddress((void**)&Bqkv, g_Bqkv);
    cudaGetSymbolAddress((void**)&Bcomb, g_Bcomb);
    cudaGetSymbolAddress((void**)&Bias2, g_Bias2);
    cudaGetSymbolAddress((void**)&Bzero, g_Bzero);

    __half *QKVh, *Ahp, *Alp, *Ah2p, *Al2p, *WqkvTh, *WqkvTl, *Wd16, *WdT3, *WcT;
    __half *SWTh, *SWTl, *Bsel, *SCTh, *SCTl, *CTh;
    cudaGetSymbolAddress((void**)&QKVh, g_QKVh);
    cudaGetSymbolAddress((void**)&Ahp, g_Ah);
    cudaGetSymbolAddress((void**)&Alp, g_Al);
    cudaGetSymbolAddress((void**)&Ah2p, g_Ah2);
    cudaGetSymbolAddress((void**)&Al2p, g_Al2);
    cudaGetSymbolAddress((void**)&WqkvTh, g_WqkvTh);
    cudaGetSymbolAddress((void**)&WqkvTl, g_WqkvTl);
    cudaGetSymbolAddress((void**)&Wd16, g_Wd16);
    cudaGetSymbolAddress((void**)&WdT3, g_WdT3);
    cudaGetSymbolAddress((void**)&WcT, g_WcT);
    cudaGetSymbolAddress((void**)&SWTh, g_SWTh);
    cudaGetSymbolAddress((void**)&SWTl, g_SWTl);
    cudaGetSymbolAddress((void**)&Bsel, g_Bsel);
    cudaGetSymbolAddress((void**)&SCTh, g_SCTh);
    cudaGetSymbolAddress((void**)&SCTl, g_SCTl);
    cudaGetSymbolAddress((void**)&CTh, g_CTh);

    static cudaStream_t s2 = nullptr;
    static cudaEvent_t evF = nullptr, evJ = nullptr;
    if (!s2) {
        cudaStreamCreateWithFlags(&s2, cudaStreamNonBlocking);
        cudaEventCreateWithFlags(&evF, cudaEventDisableTiming);
        cudaEventCreateWithFlags(&evJ, cudaEventDisableTiming);
    }

    const int SMEM1 = GSTAGES * 2 * TILE_BYTES;   // 61440
    const int SMEM2 = GSTAGES * 3 * TILE_BYTES;   // 92160
    cudaFuncSetAttribute((const void*)attn_mma,
                         cudaFuncAttributeMaxDynamicSharedMemorySize, ATTN_SMEM);
    cudaFuncSetAttribute((const void*)attn_mma_t,
                         cudaFuncAttributeMaxDynamicSharedMemorySize, ATTN_T_SMEM);
    cudaFuncSetAttribute((const void*)gemm_f16<1>,
                         cudaFuncAttributeMaxDynamicSharedMemorySize, SMEM1);
    cudaFuncSetAttribute((const void*)gemm_f16<2>,
                         cudaFuncAttributeMaxDynamicSharedMemorySize, SMEM2);
    cudaFuncSetAttribute((const void*)gemm_sel_mma,
                         cudaFuncAttributeMaxDynamicSharedMemorySize, SMEM2);

    const dim3 blk(256);
    const dim3 tblk(32, 8);
    const int n4 = MTOK * E_DIM / 4;
    const dim3 gcvt((n4 + 255) / 256);
    const dim3 gQKV(QKV_N / 128, MTOK / 128);
    const size_t MM = (size_t)E_DIM * E_DIM;
    const size_t MM3 = 3 * MM;
    const size_t WCS = (size_t)QKV_N * E_DIM;

    // ---- main stream: weights needed for layer 0 ----
    wt_cvt3<<<dim3(E_DIM / 32, E_DIM / 32, 4), tblk>>>(wq, WqkvTh, WqkvTl, E_DIM, E_DIM, 0, 3);
    wt_cvt3<<<dim3(E_DIM / 32, E_DIM / 32, 4), tblk>>>(wk, WqkvTh, WqkvTl, E_DIM, E_DIM, 1, 3);
    wt_cvt3<<<dim3(E_DIM / 32, E_DIM / 32, 4), tblk>>>(wv, WqkvTh, WqkvTl, E_DIM, E_DIM, 2, 3);
    bias_concat<<<(4 * QKV_N + 255) / 256, blk>>>(bq, bk, bv, Bqkv);

    // ---- fork: fold-weight prep on s2 ----
    cudaEventRecord(evF, 0);
    cudaStreamWaitEvent(s2, evF, 0);

    cvt_f16<<<(int)((4 * MM / 4 + 255) / 256), blk, 0, s2>>>(wd, Wd16, (int)(4 * MM / 4));
    gemm_f16<2><<<dim3(E_DIM / 128, QKV_N / 128, 3), blk, SMEM2, s2>>>(
        WqkvTh + MM3, WqkvTl + MM3, Wd16, Bzero, nullptr,
        WcT, nullptr, E_DIM, E_DIM, MM3, MM, WCS);
    wt_cvt<<<dim3(E_DIM / 32, E_DIM / 32, 1), tblk, 0, s2>>>(wd + 3 * MM, WdT3, E_DIM, E_DIM);
    wt_cvt3<<<dim3(KSEL / 32, E_DIM / 32, 1), tblk, 0, s2>>>(selw, SWTh, SWTl, E_DIM, KSEL, 0, 1);
    gemm_f16<2><<<dim3(E_DIM / 128, KSEL / 128), blk, SMEM2, s2>>>(
        SWTh, SWTl, Wd16 + 3 * MM, Bzero, nullptr,
        Bsel, nullptr, E_DIM, E_DIM, 0, 0, 0);
    bias_comb<<<dim3(QKV_N / 256, 3), blk, 0, s2>>>(wq, wk, wv, bd, Bqkv, Bcomb);
    bias_sel<<<1, 256, 0, s2>>>(selw, selb, bd + 3 * E_DIM, Bias2);
    cudaEventRecord(evJ, s2);

    // ---- main stream: layer 0 ----
    cvt_hilo<<<gcvt, blk>>>(x, Ah2p, Al2p, n4);
    gemm_f16<1><<<gQKV, blk, SMEM1>>>(Ah2p, nullptr, WqkvTh, Bqkv, nullptr,
                                      QKVh, nullptr, QKV_N, E_DIM, 0, 0, 0);
    attn_mma<<<dim3(H_DIM, B_DIM * T_DIM, 2), blk, ATTN_SMEM>>>(
        QKVh, QKVh + E_DIM, QKVh + 2 * E_DIM, Ahp, Alp, rb, QKV_N);

    // ---- join: folded weights ready before layer 1 ----
    cudaStreamWaitEvent(0, evJ, 0);

    for (int a = 1; a < 4; a++) {
        gemm_f16<1><<<gQKV, blk, SMEM1>>>(Ahp, nullptr, WcT + (a - 1) * WCS,
                                          Bcomb + (size_t)(a - 1) * QKV_N, nullptr,
                                          QKVh, nullptr, QKV_N, E_DIM, 0, 0, 0);

        const float* rba = rb + (size_t)a * RB_ONE;
        if ((a & 1) == 0) {
            attn_mma<<<dim3(H_DIM, B_DIM * T_DIM, 2), blk, ATTN_SMEM>>>(
                QKVh, QKVh + E_DIM, QKVh + 2 * E_DIM, Ahp, Alp, rba, QKV_N);
        } else {
            float* ctxF = (a == 3) ? Hb : nullptr;
            attn_mma_t<<<dim3(H_DIM, (B_DIM * N_DIM) / 8), blk, ATTN_T_SMEM>>>(
                QKVh, QKVh + E_DIM, QKVh + 2 * E_DIM, Ahp, Alp, ctxF, rba, QKV_N);
        }
    }

    // selection scores on ctx: SC = ctx_hi @ Bsel^T + Bias2
    gemm_f16<1><<<dim3(KSEL / 128, MTOK / 128), blk, SMEM1>>>(
        Ahp, nullptr, Bsel, Bias2, SCb, nullptr, nullptr, KSEL, E_DIM, 0, 0, 0);

    sel_softmax<<<dim3(B_DIM, KSEL / 32), blk>>>(SCb);

    // transposed operands: wts^T hi/lo (exact), ctx^T hi
    transp_hilo<<<dim3(KSEL / 32, MTOK_B / 32, B_DIM), tblk>>>(SCb, SCTh, SCTl, MTOK_B, KSEL);
    transp_hilo<<<dim3(E_DIM / 32, MTOK_B / 32, B_DIM), tblk>>>(Hb, CTh, nullptr, MTOK_B, E_DIM);

    // S1 = wts^T @ ctx  (mma split-K + fp32 atomics)
    cudaMemsetAsync(S1b, 0, (size_t)B_DIM * KSEL * E_DIM * sizeof(float));
    gemm_sel_mma<<<dim3(E_DIM / 128, KSEL / 128, B_DIM * SPLITK_SEL), blk, SMEM2>>>(
        SCTh, SCTl, CTh, S1b);

    // SEL = S1 @ Wd3 + bd3  (tiny 2-seg GEMM)
    cvt_hilo<<<dim3((B_DIM * KSEL * E_DIM / 4 + 255) / 256), blk>>>(
        S1b, Ah2p, Al2p, B_DIM * KSEL * E_DIM / 4);
    gemm_f16<2><<<dim3(E_DIM / 128, (B_DIM * KSEL) / 128), blk, SMEM2>>>(
        Ah2p, Al2p, WdT3, bd + 3 * E_DIM, SELb, nullptr, nullptr, E_DIM, E_DIM, 0, 0, 0);

    int total = B_DIM * OUT_ROWS * E_DIM;
    pool_kernel<<<(total + 255) / 256, 256>>>(SELb, out);
}

// round 15
// speedup vs baseline: 3.4468x; 1.1414x over previous
#include <cuda_runtime.h>
#include <cuda_fp16.h>
#include <cstdint>
#include <cstddef>

// ---------------------------------------------------------------------------
// Problem constants
// ---------------------------------------------------------------------------
#define E_DIM   1024
#define QKV_N   3072
#define H_DIM   16
#define D_DIM   64
#define B_DIM   2
#define T_DIM   32
#define N_DIM   256
#define MTOK    (B_DIM * T_DIM * N_DIM)   // 16384 tokens total
#define MTOK_B  (T_DIM * N_DIM)           // 8192 tokens per batch
#define KSEL    256
#define MAXLEN  512
#define RB_ONE  ((2 * MAXLEN - 1) * H_DIM)
#define OUT_ROWS 448                      // 256 + 128 + 64
#define SPLITK_SEL 8

// ---------------------------------------------------------------------------
// Scratch (device globals — no allocations allowed)
// ---------------------------------------------------------------------------
__device__ __half g_QKVh[MTOK * QKV_N];   // merged Q|K|V per token, fp16
__device__ float g_SC[MTOK * KSEL];
__device__ float g_S1[B_DIM * KSEL * E_DIM];   // wts^T @ ctx
__device__ float g_SEL[B_DIM * KSEL * E_DIM];  // final selected tokens

// fp16 activations
__device__ __half g_Ah[MTOK * E_DIM];     // attention ctx (hi only; hi==value)
__device__ __half g_Ah2[MTOK * E_DIM];
__device__ __half g_Al2[MTOK * E_DIM];
// transposed fp16 weights
__device__ __half g_WqkvTh[4 * 3 * E_DIM * E_DIM];  // [a][q|k|v][N=E][K=E] hi
__device__ __half g_WqkvTl[4 * 3 * E_DIM * E_DIM];  // lo
__device__ __half g_Wd16[4 * E_DIM * E_DIM];        // wd plain (row-major) fp16
__device__ __half g_WdT3[E_DIM * E_DIM];            // wd[3] transposed fp16
__device__ __half g_WcT[3 * QKV_N * E_DIM];         // combined W'^T fp16
__device__ __half g_SWTh[KSEL * E_DIM];             // selw^T hi
__device__ __half g_SWTl[KSEL * E_DIM];             // selw^T lo
__device__ __half g_Bsel[KSEL * E_DIM];             // (Wd3 @ selw)^T fp16
// selection mma operands
__device__ __half g_SCTh[B_DIM * KSEL * MTOK_B];    // wts^T hi
__device__ __half g_SCTl[B_DIM * KSEL * MTOK_B];    // wts^T lo
__device__ __half g_CTh[B_DIM * E_DIM * MTOK_B];    // ctx^T hi
__device__ float  g_Bqkv[4 * QKV_N];
__device__ float  g_Bcomb[3 * QKV_N];
__device__ float  g_Bias2[KSEL];
__device__ float  g_Bzero[E_DIM];

// ---------------------------------------------------------------------------
// PTX helpers
// ---------------------------------------------------------------------------
__device__ __forceinline__ void cp_async16(uint32_t dst, const void* src) {
    asm volatile("cp.async.cg.shared.global [%0], [%1], 16;" :: "r"(dst), "l"(src));
}
__device__ __forceinline__ void cp_commit() {
    asm volatile("cp.async.commit_group;" ::: "memory");
}
template <int N>
__device__ __forceinline__ void cp_wait_group() {
    asm volatile("cp.async.wait_group %0;" :: "n"(N) : "memory");
}
__device__ __forceinline__ void ldmatrix_x4(uint32_t* r, uint32_t addr) {
    asm volatile("ldmatrix.sync.aligned.m8n8.x4.shared.b16 {%0,%1,%2,%3}, [%4];"
                 : "=r"(r[0]), "=r"(r[1]), "=r"(r[2]), "=r"(r[3]) : "r"(addr));
}
__device__ __forceinline__ void mma_f16(float* d, const uint32_t* a,
                                        uint32_t b0, uint32_t b1) {
    asm volatile(
        "mma.sync.aligned.m16n8k16.row.col.f32.f16.f16.f32 "
        "{%0,%1,%2,%3}, {%4,%5,%6,%7}, {%8,%9}, {%0,%1,%2,%3};"
        : "+f"(d[0]), "+f"(d[1]), "+f"(d[2]), "+f"(d[3])
        : "r"(a[0]), "r"(a[1]), "r"(a[2]), "r"(a[3]), "r"(b0), "r"(b1));
}
__device__ __forceinline__ uint32_t h2pack(float a, float b) {
    __half2 h = __floats2half2_rn(a, b);
    return *(uint32_t*)&h;
}

// ---------------------------------------------------------------------------
// fp16 GEMM via mma.sync, k-chunk 64 (tile 128x64, row stride 72).
// 1 or 2 A segments; optional fp32/fp16hi/fp16lo outputs; z-batchable.
// ---------------------------------------------------------------------------
#define GSTAGES 3
#define ROWP  72
#define TILE_B (128 * ROWP * 2)            // 18432 per tile

template <int SEGS>
__global__ __launch_bounds__(256, 2)
void gemm_f16(const __half* __restrict__ Ah, const __half* __restrict__ Al,
              const __half* __restrict__ B,
              const float* __restrict__ bias, float* __restrict__ C,
              __half* __restrict__ Ch, __half* __restrict__ Cl,
              int Nfull, int Kfull,
              size_t zA, size_t zB, size_t zC)
{
    constexpr int STB = (SEGS + 1) * TILE_B;

    extern __shared__ char smem[];
    const uint32_t sb = (uint32_t)__cvta_generic_to_shared(smem);
    const int tid = threadIdx.x;
    const int lane = tid & 31;
    const int warp = tid >> 5;
    const int wm = warp >> 1;
    const int wn = warp & 1;
    const int m0 = blockIdx.y * 128;
    const int n0 = blockIdx.x * 128;

    Ah += (size_t)blockIdx.z * zA;
    if (SEGS == 2) Al += (size_t)blockIdx.z * zA;
    B  += (size_t)blockIdx.z * zB;
    if (C)  C  += (size_t)blockIdx.z * zC;
    if (Ch) Ch += (size_t)blockIdx.z * zC;
    if (Cl) Cl += (size_t)blockIdx.z * zC;

    const int NCH = Kfull >> 6;   // chunks of 64

    float acc[2][8][4];
#pragma unroll
    for (int mi = 0; mi < 2; mi++)
#pragma unroll
        for (int ni = 0; ni < 8; ni++)
#pragma unroll
            for (int q = 0; q < 4; q++) acc[mi][ni][q] = 0.f;

    auto load_chunk = [&](int c, int stage) {
        const int kb = c << 6;
        const uint32_t base = sb + stage * STB;
#pragma unroll
        for (int j = 0; j < 4; j++) {
            const int idx = tid + j * 256;
            const int r = idx >> 3, cs = idx & 7;
            const uint32_t soff = (uint32_t)(r * ROWP + cs * 8) * 2;
            const size_t goff = (size_t)r * Kfull + kb + cs * 8;
            cp_async16(base + soff, Ah + (size_t)m0 * Kfull + goff);
            if (SEGS == 2)
                cp_async16(base + TILE_B + soff, Al + (size_t)m0 * Kfull + goff);
            cp_async16(base + SEGS * TILE_B + soff, B + (size_t)n0 * Kfull + goff);
        }
    };

#pragma unroll
    for (int s = 0; s < GSTAGES - 1; s++) {
        if (s < NCH) load_chunk(s, s);
        cp_commit();
    }

    const int la_i = lane & 7;
    const int la_g = lane >> 3;
    const int a_rowadd = la_i + ((la_g & 1) << 3);
    const int a_coladd = (la_g >> 1) << 3;
    const int b_rowadd = la_i + ((la_g >> 1) << 3);
    const int b_coladd = (la_g & 1) << 3;

    for (int c = 0; c < NCH; c++) {
        const int stage = c % GSTAGES;
        cp_wait_group<GSTAGES - 2>();
        __syncthreads();

        const int nc = c + GSTAGES - 1;
        if (nc < NCH) load_chunk(nc, nc % GSTAGES);
        cp_commit();

        const uint32_t base = sb + stage * STB;
        const uint32_t Bbase = base + SEGS * TILE_B;

#pragma unroll
        for (int k16 = 0; k16 < 64; k16 += 16) {
            uint32_t bf[4][4];
#pragma unroll
            for (int nb = 0; nb < 4; nb++) {
                const int row = wn * 64 + nb * 16 + b_rowadd;
                const int col = k16 + b_coladd;
                ldmatrix_x4(bf[nb], Bbase + (uint32_t)(row * ROWP + col) * 2);
            }
#pragma unroll
            for (int seg = 0; seg < SEGS; seg++) {
                const uint32_t Abase = base + seg * TILE_B;
                uint32_t af[2][4];
#pragma unroll
                for (int mi = 0; mi < 2; mi++) {
                    const int row = wm * 32 + mi * 16 + a_rowadd;
                    const int col = k16 + a_coladd;
                    ldmatrix_x4(af[mi], Abase + (uint32_t)(row * ROWP + col) * 2);
                }
#pragma unroll
                for (int nb = 0; nb < 4; nb++)
#pragma unroll
                    for (int mi = 0; mi < 2; mi++) {
                        mma_f16(acc[mi][nb * 2 + 0], af[mi], bf[nb][0], bf[nb][1]);
                        mma_f16(acc[mi][nb * 2 + 1], af[mi], bf[nb][2], bf[nb][3]);
                    }
            }
        }
    }

    const int tq = lane >> 2;
    const int tr = lane & 3;
#pragma unroll
    for (int mi = 0; mi < 2; mi++) {
        const int row = m0 + wm * 32 + mi * 16 + tq;
#pragma unroll
        for (int ni = 0; ni < 8; ni++) {
            const int col = n0 + wn * 64 + ni * 8 + tr * 2;
            const float b0 = bias[col], b1 = bias[col + 1];
            float c00 = acc[mi][ni][0] + b0, c01 = acc[mi][ni][1] + b1;
            float c10 = acc[mi][ni][2] + b0, c11 = acc[mi][ni][3] + b1;
            if (C) {
                float2 v0; v0.x = c00; v0.y = c01;
                float2 v1; v1.x = c10; v1.y = c11;
                *(float2*)&C[(size_t)row * Nfull + col] = v0;
                *(float2*)&C[(size_t)(row + 8) * Nfull + col] = v1;
            }
            if (Ch || Cl) {
                __half h00 = __float2half_rn(c00);
                __half h01 = __float2half_rn(c01);
                __half h10 = __float2half_rn(c10);
                __half h11 = __float2half_rn(c11);
                if (Ch) {
                    *(__half2*)&Ch[(size_t)row * Nfull + col]       = __halves2half2(h00, h01);
                    *(__half2*)&Ch[(size_t)(row + 8) * Nfull + col] = __halves2half2(h10, h11);
                }
                if (Cl) {
                    __half l00 = __float2half_rn(c00 - __half2float(h00));
                    __half l01 = __float2half_rn(c01 - __half2float(h01));
                    __half l10 = __float2half_rn(c10 - __half2float(h10));
                    __half l11 = __float2half_rn(c11 - __half2float(h11));
                    *(__half2*)&Cl[(size_t)row * Nfull + col]       = __halves2half2(l00, l01);
                    *(__half2*)&Cl[(size_t)(row + 8) * Nfull + col] = __halves2half2(l10, l11);
                }
            }
        }
    }
}

// ---------------------------------------------------------------------------
// Split-K selection GEMM via mma.sync (validated k-chunk 32 form):
//   S1[b][k,e] += sum_m (SCTh+SCTl)[b][k,m] * CTh[b][e,m]
// ---------------------------------------------------------------------------
#define ROWPAD  40
#define TILE_BYTES (128 * ROWPAD * 2)      // 10240

__global__ __launch_bounds__(256, 2)
void gemm_sel_mma(const __half* __restrict__ SCTh, const __half* __restrict__ SCTl,
                  const __half* __restrict__ CTh, float* __restrict__ S1)
{
    constexpr int STB = 3 * TILE_BYTES;

    extern __shared__ char smem[];
    const uint32_t sb = (uint32_t)__cvta_generic_to_shared(smem);
    const int tid = threadIdx.x;
    const int lane = tid & 31;
    const int warp = tid >> 5;
    const int wm = warp >> 1;
    const int wn = warp & 1;
    const int m0 = blockIdx.y * 128;
    const int n0 = blockIdx.x * 128;
    const int b  = blockIdx.z / SPLITK_SEL;
    const int sl = blockIdx.z % SPLITK_SEL;
    const int kbeg = sl * (MTOK_B / SPLITK_SEL);
    const int NCH = (MTOK_B / SPLITK_SEL) >> 5;

    const __half* Ah = SCTh + (size_t)b * KSEL * MTOK_B;
    const __half* Al = SCTl + (size_t)b * KSEL * MTOK_B;
    const __half* B  = CTh  + (size_t)b * E_DIM * MTOK_B;
    float* C = S1 + (size_t)b * KSEL * E_DIM;

    const int lr0 = tid >> 1;
    const int ls0 = (tid & 1) << 1;

    float acc[2][8][4];
#pragma unroll
    for (int mi = 0; mi < 2; mi++)
#pragma unroll
        for (int ni = 0; ni < 8; ni++)
#pragma unroll
            for (int q = 0; q < 4; q++) acc[mi][ni][q] = 0.f;

    auto load_chunk = [&](int c, int stage) {
        const int kb = kbeg + (c << 5);
        const uint32_t base = sb + stage * STB;
#pragma unroll
        for (int j = 0; j < 2; j++) {
            const int s4 = ls0 + j;
            const uint32_t soff = (uint32_t)(lr0 * ROWPAD + s4 * 8) * 2;
            cp_async16(base + soff,
                       Ah + (size_t)(m0 + lr0) * MTOK_B + kb + s4 * 8);
            cp_async16(base + TILE_BYTES + soff,
                       Al + (size_t)(m0 + lr0) * MTOK_B + kb + s4 * 8);
            cp_async16(base + 2 * TILE_BYTES + soff,
                       B + (size_t)(n0 + lr0) * MTOK_B + kb + s4 * 8);
        }
    };

#pragma unroll
    for (int s = 0; s < GSTAGES - 1; s++) {
        if (s < NCH) load_chunk(s, s);
        cp_commit();
    }

    const int la_i = lane & 7;
    const int la_g = lane >> 3;
    const int a_rowadd = la_i + ((la_g & 1) << 3);
    const int a_coladd = (la_g >> 1) << 3;
    const int b_rowadd = la_i + ((la_g >> 1) << 3);
    const int b_coladd = (la_g & 1) << 3;

    for (int c = 0; c < NCH; c++) {
        const int stage = c % GSTAGES;
        cp_wait_group<GSTAGES - 2>();
        __syncthreads();

        const int nc = c + GSTAGES - 1;
        if (nc < NCH) load_chunk(nc, nc % GSTAGES);
        cp_commit();

        const uint32_t base = sb + stage * STB;
        const uint32_t Bbase = base + 2 * TILE_BYTES;

#pragma unroll
        for (int k16 = 0; k16 < 32; k16 += 16) {
            uint32_t bf[4][4];
#pragma unroll
            for (int nb = 0; nb < 4; nb++) {
                const int row = wn * 64 + nb * 16 + b_rowadd;
                const int col = k16 + b_coladd;
                ldmatrix_x4(bf[nb], Bbase + (uint32_t)(row * ROWPAD + col) * 2);
            }
#pragma unroll
            for (int seg = 0; seg < 2; seg++) {
                const uint32_t Abase = base + seg * TILE_BYTES;
                uint32_t af[2][4];
#pragma unroll
                for (int mi = 0; mi < 2; mi++) {
                    const int row = wm * 32 + mi * 16 + a_rowadd;
                    const int col = k16 + a_coladd;
                    ldmatrix_x4(af[mi], Abase + (uint32_t)(row * ROWPAD + col) * 2);
                }
#pragma unroll
                for (int nb = 0; nb < 4; nb++)
#pragma unroll
                    for (int mi = 0; mi < 2; mi++) {
                        mma_f16(acc[mi][nb * 2 + 0], af[mi], bf[nb][0], bf[nb][1]);
                        mma_f16(acc[mi][nb * 2 + 1], af[mi], bf[nb][2], bf[nb][3]);
                    }
            }
        }
    }

    const int tq = lane >> 2;
    const int tr = lane & 3;
#pragma unroll
    for (int mi = 0; mi < 2; mi++) {
        const int row = m0 + wm * 32 + mi * 16 + tq;
#pragma unroll
        for (int ni = 0; ni < 8; ni++) {
            const int col = n0 + wn * 64 + ni * 8 + tr * 2;
            atomicAdd(&C[(size_t)row * E_DIM + col],           acc[mi][ni][0]);
            atomicAdd(&C[(size_t)row * E_DIM + col + 1],       acc[mi][ni][1]);
            atomicAdd(&C[(size_t)(row + 8) * E_DIM + col],     acc[mi][ni][2]);
            atomicAdd(&C[(size_t)(row + 8) * E_DIM + col + 1], acc[mi][ni][3]);
        }
    }
}

// ---------------------------------------------------------------------------
// mma.sync spatial attention (S=256, step 1), flash-style online softmax.
// Emits fp16 ctx only.
// ---------------------------------------------------------------------------
#define AKS_BYTES  (256 * 72 * 2)
#define AVT_BYTES  (64 * 264 * 2)
#define ATTN_SMEM  (AKS_BYTES + AVT_BYTES + 512 * 4)   // 74704

__global__ __launch_bounds__(256)
void attn_mma(const __half* __restrict__ Q, const __half* __restrict__ K,
              const __half* __restrict__ V,
              __half* __restrict__ OutH,
              const float* __restrict__ rb, int ldx)
{
    const int h = blockIdx.x;
    const int g = blockIdx.y;
    const int qh = blockIdx.z;
    const int base_m = g * N_DIM;
    const size_t baseE = (size_t)base_m * ldx + h * D_DIM;

    extern __shared__ char sm8[];
    __half* Ks = (__half*)sm8;
    __half* Vt = (__half*)(sm8 + AKS_BYTES);
    float*  rbh = (float*)(sm8 + AKS_BYTES + AVT_BYTES);
    const uint32_t sKs = (uint32_t)__cvta_generic_to_shared(Ks);
    const uint32_t sVt = (uint32_t)__cvta_generic_to_shared(Vt);

    const int tid = threadIdx.x;
    const int lane = tid & 31;
    const int warp = tid >> 5;

    for (int i = tid; i < 128 * 8; i += 256) {
        int r = i >> 3, cs = i & 7;
        *(float4*)&Ks[r * 72 + cs * 8] =
            *(const float4*)(Q + baseE + (size_t)(qh * 128 + r) * ldx + cs * 8);
    }
    __syncthreads();

    const int la_i = lane & 7;
    const int la_g = lane >> 3;
    const int a_rowadd = la_i + ((la_g & 1) << 3);
    const int a_coladd = (la_g >> 1) << 3;
    const int b_rowadd = la_i + ((la_g >> 1) << 3);
    const int b_coladd = (la_g & 1) << 3;

    uint32_t Qf[4][4];
    const int wq = warp * 16;
#pragma unroll
    for (int kk = 0; kk < 4; kk++)
        ldmatrix_x4(Qf[kk], sKs + (uint32_t)((wq + a_rowadd) * 72 + kk * 16 + a_coladd) * 2);
    __syncthreads();

    for (int i = tid; i < 256 * 8; i += 256) {
        int r = i >> 3, cs = i & 7;
        *(float4*)&Ks[r * 72 + cs * 8] =
            *(const float4*)(K + baseE + (size_t)r * ldx + cs * 8);
    }
    for (int i = tid; i < 256 * 32; i += 256) {
        int t = i >> 5, d2 = i & 31;
        __half2 v = *(const __half2*)(V + baseE + (size_t)t * ldx + 2 * d2);
        Vt[(2 * d2) * 264 + t]     = __low2half(v);
        Vt[(2 * d2 + 1) * 264 + t] = __high2half(v);
    }
    for (int i = tid; i < 511; i += 256)
        rbh[i] = rb[(size_t)(MAXLEN - 256 + i) * H_DIM + h];
    __syncthreads();

    const int tq = lane >> 2;
    const int tr = lane & 3;
    const int r0 = qh * 128 + wq + tq;
    const int r1 = r0 + 8;

    float o[8][4];
#pragma unroll
    for (int j = 0; j < 8; j++)
#pragma unroll
        for (int q = 0; q < 4; q++) o[j][q] = 0.f;
    float m0 = -1e30f, m1 = -1e30f, l0 = 0.f, l1 = 0.f;

#pragma unroll
    for (int ch = 0; ch < 4; ch++) {
        float s[8][4];
#pragma unroll
        for (int j = 0; j < 8; j++)
#pragma unroll
            for (int q = 0; q < 4; q++) s[j][q] = 0.f;

#pragma unroll
        for (int kk = 0; kk < 4; kk++) {
#pragma unroll
            for (int nb = 0; nb < 4; nb++) {
                uint32_t bf[4];
                ldmatrix_x4(bf, sKs + (uint32_t)((ch * 64 + nb * 16 + b_rowadd) * 72
                                                 + kk * 16 + b_coladd) * 2);
                mma_f16(s[nb * 2 + 0], Qf[kk], bf[0], bf[1]);
                mma_f16(s[nb * 2 + 1], Qf[kk], bf[2], bf[3]);
            }
        }

        float cm0 = -1e30f, cm1 = -1e30f;
#pragma unroll
        for (int j = 0; j < 8; j++) {
            const int c = ch * 64 + j * 8 + 2 * tr;
            s[j][0] = s[j][0] * 0.125f + rbh[c - r0 + 255];
            s[j][1] = s[j][1] * 0.125f + rbh[c + 1 - r0 + 255];
            s[j][2] = s[j][2] * 0.125f + rbh[c - r1 + 255];
            s[j][3] = s[j][3] * 0.125f + rbh[c + 1 - r1 + 255];
            cm0 = fmaxf(cm0, fmaxf(s[j][0], s[j][1]));
            cm1 = fmaxf(cm1, fmaxf(s[j][2], s[j][3]));
        }
        cm0 = fmaxf(cm0, __shfl_xor_sync(0xffffffffu, cm0, 1));
        cm0 = fmaxf(cm0, __shfl_xor_sync(0xffffffffu, cm0, 2));
        cm1 = fmaxf(cm1, __shfl_xor_sync(0xffffffffu, cm1, 1));
        cm1 = fmaxf(cm1, __shfl_xor_sync(0xffffffffu, cm1, 2));

        const float nm0 = fmaxf(m0, cm0), nm1 = fmaxf(m1, cm1);
        const float sc0 = __expf(m0 - nm0), sc1 = __expf(m1 - nm1);
        float rs0 = 0.f, rs1 = 0.f;
#pragma unroll
        for (int j = 0; j < 8; j++) {
            s[j][0] = __expf(s[j][0] - nm0);
            s[j][1] = __expf(s[j][1] - nm0);
            s[j][2] = __expf(s[j][2] - nm1);
            s[j][3] = __expf(s[j][3] - nm1);
            rs0 += s[j][0] + s[j][1];
            rs1 += s[j][2] + s[j][3];
        }
        rs0 += __shfl_xor_sync(0xffffffffu, rs0, 1);
        rs0 += __shfl_xor_sync(0xffffffffu, rs0, 2);
        rs1 += __shfl_xor_sync(0xffffffffu, rs1, 1);
        rs1 += __shfl_xor_sync(0xffffffffu, rs1, 2);
        l0 = l0 * sc0 + rs0;
        l1 = l1 * sc1 + rs1;
        m0 = nm0; m1 = nm1;
#pragma unroll
        for (int j = 0; j < 8; j++) {
            o[j][0] *= sc0; o[j][1] *= sc0;
            o[j][2] *= sc1; o[j][3] *= sc1;
        }

        uint32_t pa[4][4];
#pragma unroll
        for (int kk = 0; kk < 4; kk++) {
            pa[kk][0] = h2pack(s[2 * kk][0], s[2 * kk][1]);
            pa[kk][1] = h2pack(s[2 * kk][2], s[2 * kk][3]);
            pa[kk][2] = h2pack(s[2 * kk + 1][0], s[2 * kk + 1][1]);
            pa[kk][3] = h2pack(s[2 * kk + 1][2], s[2 * kk + 1][3]);
        }

#pragma unroll
        for (int kk = 0; kk < 4; kk++) {
#pragma unroll
            for (int nb = 0; nb < 4; nb++) {
                uint32_t bf[4];
                ldmatrix_x4(bf, sVt + (uint32_t)((nb * 16 + b_rowadd) * 264
                                                 + ch * 64 + kk * 16 + b_coladd) * 2);
                mma_f16(o[nb * 2 + 0], pa[kk], bf[0], bf[1]);
                mma_f16(o[nb * 2 + 1], pa[kk], bf[2], bf[3]);
            }
        }
    }

    const float inv0 = 1.f / l0, inv1 = 1.f / l1;
    const size_t oo0 = (size_t)(base_m + r0) * E_DIM + h * D_DIM;
    const size_t oo1 = (size_t)(base_m + r1) * E_DIM + h * D_DIM;
#pragma unroll
    for (int j = 0; j < 8; j++) {
        const int c = j * 8 + 2 * tr;
        *(__half2*)&OutH[oo0 + c] =
            __floats2half2_rn(o[j][0] * inv0, o[j][1] * inv0);
        *(__half2*)&OutH[oo1 + c] =
            __floats2half2_rn(o[j][2] * inv1, o[j][3] * inv1);
    }
}

// ---------------------------------------------------------------------------
// mma.sync temporal attention (S=32, step N_DIM): one warp per (h,b,n) group.
// Emits fp16 ctx only.
// ---------------------------------------------------------------------------
#define TBUF_HALVES 2560
#define ATTN_T_SMEM (8 * TBUF_HALVES * 2 + 64 * 4)   // 41216

__global__ __launch_bounds__(256)
void attn_mma_t(const __half* __restrict__ Q, const __half* __restrict__ K,
                const __half* __restrict__ V,
                __half* __restrict__ OutH,
                const float* __restrict__ rb, int ldx)
{
    const int h = blockIdx.x;
    const int tid = threadIdx.x;
    const int lane = tid & 31;
    const int warp = tid >> 5;
    const int g = blockIdx.y * 8 + warp;
    const int b = g >> 8, n = g & 255;
    const int base_m = b * MTOK_B + n;
    const size_t baseE = (size_t)base_m * ldx + h * D_DIM;
    const size_t stepE = (size_t)N_DIM * ldx;

    extern __shared__ char smT[];
    __half* buf = (__half*)smT + warp * TBUF_HALVES;
    float* rbh = (float*)(smT + 8 * TBUF_HALVES * 2);
    const uint32_t sb = (uint32_t)__cvta_generic_to_shared(buf);

    for (int i = tid; i < 63; i += 256)
        rbh[i] = rb[(size_t)(MAXLEN - 32 + i) * H_DIM + h];
    __syncthreads();

    const int la_i = lane & 7;
    const int la_g = lane >> 3;
    const int a_rowadd = la_i + ((la_g & 1) << 3);
    const int a_coladd = (la_g >> 1) << 3;
    const int b_rowadd = la_i + ((la_g >> 1) << 3);
    const int b_coladd = (la_g & 1) << 3;
    const int tq = lane >> 2;
    const int tr = lane & 3;

#pragma unroll
    for (int j = 0; j < 8; j++) {
        int idx = lane + j * 32;
        int r = idx >> 3, cs = idx & 7;
        *(float4*)&buf[r * 72 + cs * 8] =
            *(const float4*)(Q + baseE + (size_t)r * stepE + cs * 8);
    }
    __syncwarp();
    uint32_t Qf[2][4][4];
#pragma unroll
    for (int mi = 0; mi < 2; mi++)
#pragma unroll
        for (int kk = 0; kk < 4; kk++)
            ldmatrix_x4(Qf[mi][kk],
                        sb + (uint32_t)((mi * 16 + a_rowadd) * 72 + kk * 16 + a_coladd) * 2);
    __syncwarp();

#pragma unroll
    for (int j = 0; j < 8; j++) {
        int idx = lane + j * 32;
        int r = idx >> 3, cs = idx & 7;
        *(float4*)&buf[r * 72 + cs * 8] =
            *(const float4*)(K + baseE + (size_t)r * stepE + cs * 8);
    }
    __syncwarp();

    float s[2][4][4];
#pragma unroll
    for (int mi = 0; mi < 2; mi++)
#pragma unroll
        for (int ni = 0; ni < 4; ni++)
#pragma unroll
            for (int q = 0; q < 4; q++) s[mi][ni][q] = 0.f;

#pragma unroll
    for (int kk = 0; kk < 4; kk++)
#pragma unroll
        for (int nb = 0; nb < 2; nb++) {
            uint32_t bf[4];
            ldmatrix_x4(bf, sb + (uint32_t)((nb * 16 + b_rowadd) * 72 + kk * 16 + b_coladd) * 2);
#pragma unroll
            for (int mi = 0; mi < 2; mi++) {
                mma_f16(s[mi][nb * 2 + 0], Qf[mi][kk], bf[0], bf[1]);
                mma_f16(s[mi][nb * 2 + 1], Qf[mi][kk], bf[2], bf[3]);
            }
        }
    __syncwarp();

#pragma unroll
    for (int j = 0; j < 32; j++) {
        __half2 v = *(const __half2*)(V + baseE + (size_t)j * stepE + 2 * lane);
        buf[(2 * lane) * 40 + j]     = __low2half(v);
        buf[(2 * lane + 1) * 40 + j] = __high2half(v);
    }
    __syncwarp();

#pragma unroll
    for (int mi = 0; mi < 2; mi++) {
        const int ra = mi * 16 + tq, rb2 = ra + 8;
        float mxa = -1e30f, mxb = -1e30f;
#pragma unroll
        for (int ni = 0; ni < 4; ni++) {
            const int c = ni * 8 + 2 * tr;
            s[mi][ni][0] = s[mi][ni][0] * 0.125f + rbh[c - ra + 31];
            s[mi][ni][1] = s[mi][ni][1] * 0.125f + rbh[c + 1 - ra + 31];
            s[mi][ni][2] = s[mi][ni][2] * 0.125f + rbh[c - rb2 + 31];
            s[mi][ni][3] = s[mi][ni][3] * 0.125f + rbh[c + 1 - rb2 + 31];
            mxa = fmaxf(mxa, fmaxf(s[mi][ni][0], s[mi][ni][1]));
            mxb = fmaxf(mxb, fmaxf(s[mi][ni][2], s[mi][ni][3]));
        }
        mxa = fmaxf(mxa, __shfl_xor_sync(0xffffffffu, mxa, 1));
        mxa = fmaxf(mxa, __shfl_xor_sync(0xffffffffu, mxa, 2));
        mxb = fmaxf(mxb, __shfl_xor_sync(0xffffffffu, mxb, 1));
        mxb = fmaxf(mxb, __shfl_xor_sync(0xffffffffu, mxb, 2));
        float sa = 0.f, sbm = 0.f;
#pragma unroll
        for (int ni = 0; ni < 4; ni++) {
            s[mi][ni][0] = __expf(s[mi][ni][0] - mxa);
            s[mi][ni][1] = __expf(s[mi][ni][1] - mxa);
            s[mi][ni][2] = __expf(s[mi][ni][2] - mxb);
            s[mi][ni][3] = __expf(s[mi][ni][3] - mxb);
            sa += s[mi][ni][0] + s[mi][ni][1];
            sbm += s[mi][ni][2] + s[mi][ni][3];
        }
        sa += __shfl_xor_sync(0xffffffffu, sa, 1);
        sa += __shfl_xor_sync(0xffffffffu, sa, 2);
        sbm += __shfl_xor_sync(0xffffffffu, sbm, 1);
        sbm += __shfl_xor_sync(0xffffffffu, sbm, 2);
        const float ia = 1.f / sa, ib = 1.f / sbm;
#pragma unroll
        for (int ni = 0; ni < 4; ni++) {
            s[mi][ni][0] *= ia; s[mi][ni][1] *= ia;
            s[mi][ni][2] *= ib; s[mi][ni][3] *= ib;
        }
    }

    uint32_t pa[2][2][4];
#pragma unroll
    for (int mi = 0; mi < 2; mi++)
#pragma unroll
        for (int kk = 0; kk < 2; kk++) {
            pa[mi][kk][0] = h2pack(s[mi][2 * kk][0], s[mi][2 * kk][1]);
            pa[mi][kk][1] = h2pack(s[mi][2 * kk][2], s[mi][2 * kk][3]);
            pa[mi][kk][2] = h2pack(s[mi][2 * kk + 1][0], s[mi][2 * kk + 1][1]);
            pa[mi][kk][3] = h2pack(s[mi][2 * kk + 1][2], s[mi][2 * kk + 1][3]);
        }

    float o[2][8][4];
#pragma unroll
    for (int mi = 0; mi < 2; mi++)
#pragma unroll
        for (int ni = 0; ni < 8; ni++)
#pragma unroll
            for (int q = 0; q < 4; q++) o[mi][ni][q] = 0.f;

#pragma unroll
    for (int kk = 0; kk < 2; kk++)
#pragma unroll
        for (int nb = 0; nb < 4; nb++) {
            uint32_t bf[4];
            ldmatrix_x4(bf, sb + (uint32_t)((nb * 16 + b_rowadd) * 40 + kk * 16 + b_coladd) * 2);
#pragma unroll
            for (int mi = 0; mi < 2; mi++) {
                mma_f16(o[mi][nb * 2 + 0], pa[mi][kk], bf[0], bf[1]);
                mma_f16(o[mi][nb * 2 + 1], pa[mi][kk], bf[2], bf[3]);
            }
        }

#pragma unroll
    for (int mi = 0; mi < 2; mi++) {
        const int ra = mi * 16 + tq;
        const size_t oo0 = (size_t)(base_m + ra * N_DIM) * E_DIM + h * D_DIM;
        const size_t oo1 = (size_t)(base_m + (ra + 8) * N_DIM) * E_DIM + h * D_DIM;
#pragma unroll
        for (int ni = 0; ni < 8; ni++) {
            const int c = ni * 8 + 2 * tr;
            *(__half2*)&OutH[oo0 + c] = __floats2half2_rn(o[mi][ni][0], o[mi][ni][1]);
            *(__half2*)&OutH[oo1 + c] = __floats2half2_rn(o[mi][ni][2], o[mi][ni][3]);
        }
    }
}

// ---------------------------------------------------------------------------
// misc elementwise / prep kernels
// ---------------------------------------------------------------------------
__global__ void cvt_hilo(const float* __restrict__ x, __half* __restrict__ hi,
                         __half* __restrict__ lo, int n4)
{
    int i = blockIdx.x * blockDim.x + threadIdx.x;
    if (i >= n4) return;
    float4 v = ((const float4*)x)[i];
    __half h0 = __float2half_rn(v.x);
    __half h1 = __float2half_rn(v.y);
    __half h2 = __float2half_rn(v.z);
    __half h3 = __float2half_rn(v.w);
    __half l0 = __float2half_rn(v.x - __half2float(h0));
    __half l1 = __float2half_rn(v.y - __half2float(h1));
    __half l2 = __float2half_rn(v.z - __half2float(h2));
    __half l3 = __float2half_rn(v.w - __half2float(h3));
    __half2* hp = (__half2*)hi;
    __half2* lp = (__half2*)lo;
    hp[2 * i + 0] = __half2(h0, h1);
    hp[2 * i + 1] = __half2(h2, h3);
    lp[2 * i + 0] = __half2(l0, l1);
    lp[2 * i + 1] = __half2(l2, l3);
}

__global__ void cvt_f16(const float* __restrict__ x, __half* __restrict__ y, int n4)
{
    int i = blockIdx.x * blockDim.x + threadIdx.x;
    if (i >= n4) return;
    float4 v = ((const float4*)x)[i];
    __half2* yp = (__half2*)y;
    yp[2 * i + 0] = __floats2half2_rn(v.x, v.y);
    yp[2 * i + 1] = __floats2half2_rn(v.z, v.w);
}

__global__ void wt_cvt3(const float* __restrict__ W, __half* __restrict__ WTh,
                        __half* __restrict__ WTl, int Kd, int Nd, int type, int slots)
{
    __shared__ float t[32][33];
    const size_t srcoff = (size_t)blockIdx.z * Kd * Nd;
    const size_t dstoff = ((size_t)blockIdx.z * slots + type) * Kd * Nd;
    const float* Wm = W + srcoff;
    __half* Hh = WTh + dstoff;
    __half* Hl = WTl + dstoff;

    int nx = blockIdx.x * 32 + threadIdx.x;
    int k0 = blockIdx.y * 32;
#pragma unroll
    for (int j = 0; j < 4; j++) {
        int kk = k0 + threadIdx.y + j * 8;
        t[threadIdx.y + j * 8][threadIdx.x] = Wm[(size_t)kk * Nd + nx];
    }
    __syncthreads();
    int kx = k0 + threadIdx.x;
#pragma unroll
    for (int j = 0; j < 4; j++) {
        int nn = blockIdx.x * 32 + threadIdx.y + j * 8;
        float v = t[threadIdx.x][threadIdx.y + j * 8];
        __half h = __float2half_rn(v);
        Hh[(size_t)nn * Kd + kx] = h;
        Hl[(size_t)nn * Kd + kx] = __float2half_rn(v - __half2float(h));
    }
}

__global__ void wt_cvt(const float* __restrict__ W, __half* __restrict__ WT,
                       int Kd, int Nd)
{
    __shared__ float t[32][33];
    const size_t moff = (size_t)blockIdx.z * Kd * Nd;
    const float* Wm = W + moff;
    __half* Hh = WT + moff;

    int nx = blockIdx.x * 32 + threadIdx.x;
    int k0 = blockIdx.y * 32;
#pragma unroll
    for (int j = 0; j < 4; j++) {
        int kk = k0 + threadIdx.y + j * 8;
        t[threadIdx.y + j * 8][threadIdx.x] = Wm[(size_t)kk * Nd + nx];
    }
    __syncthreads();
    int kx = k0 + threadIdx.x;
#pragma unroll
    for (int j = 0; j < 4; j++) {
        int nn = blockIdx.x * 32 + threadIdx.y + j * 8;
        Hh[(size_t)nn * Kd + kx] = __float2half_rn(t[threadIdx.x][threadIdx.y + j * 8]);
    }
}

// transpose + hi/lo split: src fp32 [z][R][C] -> dst fp16 [z][C][R]
__global__ void transp_hilo(const float* __restrict__ src, __half* __restrict__ dh,
                            __half* __restrict__ dl, int R, int C)
{
    __shared__ float t[32][33];
    const size_t zo = (size_t)blockIdx.z * R * C;
    const float* S = src + zo;
    __half* Dh = dh + zo;
    __half* Dl = dl ? dl + zo : nullptr;

    int cx = blockIdx.x * 32 + threadIdx.x;
    int r0 = blockIdx.y * 32;
#pragma unroll
    for (int j = 0; j < 4; j++) {
        int rr = r0 + threadIdx.y + j * 8;
        t[threadIdx.y + j * 8][threadIdx.x] = S[(size_t)rr * C + cx];
    }
    __syncthreads();
    int rx = r0 + threadIdx.x;
#pragma unroll
    for (int j = 0; j < 4; j++) {
        int cc = blockIdx.x * 32 + threadIdx.y + j * 8;
        float v = t[threadIdx.x][threadIdx.y + j * 8];
        __half h = __float2half_rn(v);
        Dh[(size_t)cc * R + rx] = h;
        if (Dl) Dl[(size_t)cc * R + rx] = __float2half_rn(v - __half2float(h));
    }
}

// fp16 transpose: src fp16 [z][R][C] -> dst fp16 [z][C][R]
__global__ void transp_h16(const __half* __restrict__ src, __half* __restrict__ dst,
                           int R, int C)
{
    __shared__ __half t[32][33];
    const size_t zo = (size_t)blockIdx.z * R * C;
    const __half* S = src + zo;
    __half* D = dst + zo;

    int cx = blockIdx.x * 32 + threadIdx.x;
    int r0 = blockIdx.y * 32;
#pragma unroll
    for (int j = 0; j < 4; j++) {
        int rr = r0 + threadIdx.y + j * 8;
        t[threadIdx.y + j * 8][threadIdx.x] = S[(size_t)rr * C + cx];
    }
    __syncthreads();
    int rx = r0 + threadIdx.x;
#pragma unroll
    for (int j = 0; j < 4; j++) {
        int cc = blockIdx.x * 32 + threadIdx.y + j * 8;
        D[(size_t)cc * R + rx] = t[threadIdx.x][threadIdx.y + j * 8];
    }
}

__global__ void bias_concat(const float* __restrict__ bq, const float* __restrict__ bk,
                            const float* __restrict__ bv, float* __restrict__ out)
{
    int i = blockIdx.x * blockDim.x + threadIdx.x;
    if (i >= 4 * QKV_N) return;
    int a = i / QKV_N;
    int r = i % QKV_N;
    const float* src = (r < E_DIM) ? bq : (r < 2 * E_DIM) ? bk : bv;
    out[i] = src[a * E_DIM + (r & (E_DIM - 1))];
}

__global__ void bias_comb(const float* __restrict__ wq, const float* __restrict__ wk,
                          const float* __restrict__ wv, const float* __restrict__ bd,
                          const float* __restrict__ bqkv, float* __restrict__ out)
{
    int i = blockIdx.x * blockDim.x + threadIdx.x;
    int z = blockIdx.y;
    const float* W = (i < E_DIM) ? wq : (i < 2 * E_DIM) ? wk : wv;
    int col = i & (E_DIM - 1);
    const float* Wm = W + (size_t)(z + 1) * E_DIM * E_DIM;
    const float* bdz = bd + (size_t)z * E_DIM;
    float s = 0.f;
    for (int k = 0; k < E_DIM; k++)
        s += bdz[k] * Wm[(size_t)k * E_DIM + col];
    out[(size_t)z * QKV_N + i] = s + bqkv[(size_t)(z + 1) * QKV_N + i];
}

__global__ void bias_sel(const float* __restrict__ selw, const float* __restrict__ selb,
                         const float* __restrict__ bd3, float* __restrict__ out)
{
    int k = blockIdx.x * blockDim.x + threadIdx.x;
    if (k >= KSEL) return;
    float s = 0.f;
    for (int e = 0; e < E_DIM; e++)
        s += bd3[e] * selw[(size_t)e * KSEL + k];
    out[k] = s + selb[k];
}

// ---------------------------------------------------------------------------
// Selection softmax / pooling
// ---------------------------------------------------------------------------
__global__ __launch_bounds__(256)
void sel_softmax(float* __restrict__ sc)
{
    const int b = blockIdx.x;
    const int k0 = blockIdx.y * 32;
    const int lane = threadIdx.x & 31;
    const int row = threadIdx.x >> 5;

    float* base = sc + (size_t)b * MTOK_B * KSEL + k0 + lane;

    __shared__ float redA[8][32];
    __shared__ float redB[8][32];

    float mx = -1e30f;
    for (int m = row; m < MTOK_B; m += 8)
        mx = fmaxf(mx, base[(size_t)m * KSEL]);
    redA[row][lane] = mx;
    __syncthreads();
    if (row == 0) {
        float v = redA[0][lane];
#pragma unroll
        for (int r = 1; r < 8; r++) v = fmaxf(v, redA[r][lane]);
        redA[0][lane] = v;
    }
    __syncthreads();
    mx = redA[0][lane];

    float sum = 0.f;
    for (int m = row; m < MTOK_B; m += 8)
        sum += __expf(base[(size_t)m * KSEL] - mx);
    redB[row][lane] = sum;
    __syncthreads();
    if (row == 0) {
        float v = 0.f;
#pragma unroll
        for (int r = 0; r < 8; r++) v += redB[r][lane];
        redB[0][lane] = v;
    }
    __syncthreads();
    float inv = 1.f / redB[0][lane];

    for (int m = row; m < MTOK_B; m += 8) {
        float* p = &base[(size_t)m * KSEL];
        *p = __expf(*p - mx) * inv;
    }
}

__global__ void pool_kernel(const float* __restrict__ sel, float* __restrict__ out)
{
    int idx = blockIdx.x * blockDim.x + threadIdx.x;
    int total = B_DIM * OUT_ROWS * E_DIM;
    if (idx >= total) return;
    int e = idx % E_DIM;
    int r = (idx / E_DIM) % OUT_ROWS;
    int b = idx / (OUT_ROWS * E_DIM);
    const float* sb = sel + (size_t)b * KSEL * E_DIM;
    float v;
    if (r < 256) {
        v = sb[(size_t)r * E_DIM + e];
    } else if (r < 384) {
        int i = (r - 256) * 2;
        v = 0.5f * (sb[(size_t)i * E_DIM + e] + sb[(size_t)(i + 1) * E_DIM + e]);
    } else {
        int i = (r - 384) * 4;
        v = 0.25f * (sb[(size_t)i * E_DIM + e] + sb[(size_t)(i + 1) * E_DIM + e] +
                     sb[(size_t)(i + 2) * E_DIM + e] + sb[(size_t)(i + 3) * E_DIM + e]);
    }
    out[idx] = v;
}

// ---------------------------------------------------------------------------
// Orchestration
// ---------------------------------------------------------------------------
extern "C" void kernel_launch(void* const* d_in, const int* in_sizes, int n_in,
                              void* d_out, int out_size)
{
    (void)in_sizes; (void)n_in; (void)out_size;

    const float* x    = (const float*)d_in[0];
    const float* wq   = (const float*)d_in[1];
    const float* bq   = (const float*)d_in[2];
    const float* wk   = (const float*)d_in[3];
    const float* bk   = (const float*)d_in[4];
    const float* wv   = (const float*)d_in[5];
    const float* bv   = (const float*)d_in[6];
    const float* wd   = (const float*)d_in[7];
    const float* bd   = (const float*)d_in[8];
    const float* rb   = (const float*)d_in[9];
    const float* selw = (const float*)d_in[10];
    const float* selb = (const float*)d_in[11];
    float* out = (float*)d_out;

    float *SCb, *S1b, *SELb, *Bqkv, *Bcomb, *Bias2, *Bzero;
    cudaGetSymbolAddress((void**)&SCb, g_SC);
    cudaGetSymbolAddress((void**)&S1b, g_S1);
    cudaGetSymbolAddress((void**)&SELb, g_SEL);
    cudaGetSymbolAddress((void**)&Bqkv, g_Bqkv);
    cudaGetSymbolAddress((void**)&Bcomb, g_Bcomb);
    cudaGetSymbolAddress((void**)&Bias2, g_Bias2);
    cudaGetSymbolAddress((void**)&Bzero, g_Bzero);

    __half *QKVh, *Ahp, *Ah2p, *Al2p, *WqkvTh, *WqkvTl, *Wd16, *WdT3, *WcT;
    __half *SWTh, *SWTl, *Bsel, *SCTh, *SCTl, *CTh;
    cudaGetSymbolAddress((void**)&QKVh, g_QKVh);
    cudaGetSymbolAddress((void**)&Ahp, g_Ah);
    cudaGetSymbolAddress((void**)&Ah2p, g_Ah2);
    cudaGetSymbolAddress((void**)&Al2p, g_Al2);
    cudaGetSymbolAddress((void**)&WqkvTh, g_WqkvTh);
    cudaGetSymbolAddress((void**)&WqkvTl, g_WqkvTl);
    cudaGetSymbolAddress((void**)&Wd16, g_Wd16);
    cudaGetSymbolAddress((void**)&WdT3, g_WdT3);
    cudaGetSymbolAddress((void**)&WcT, g_WcT);
    cudaGetSymbolAddress((void**)&SWTh, g_SWTh);
    cudaGetSymbolAddress((void**)&SWTl, g_SWTl);
    cudaGetSymbolAddress((void**)&Bsel, g_Bsel);
    cudaGetSymbolAddress((void**)&SCTh, g_SCTh);
    cudaGetSymbolAddress((void**)&SCTl, g_SCTl);
    cudaGetSymbolAddress((void**)&CTh, g_CTh);

    static cudaStream_t s2 = nullptr;
    static cudaEvent_t evF = nullptr, evJ = nullptr;
    if (!s2) {
        cudaStreamCreateWithFlags(&s2, cudaStreamNonBlocking);
        cudaEventCreateWithFlags(&evF, cudaEventDisableTiming);
        cudaEventCreateWithFlags(&evJ, cudaEventDisableTiming);
    }

    const int SMEM1 = GSTAGES * 2 * TILE_B;    // 110592
    const int SMEM2 = GSTAGES * 3 * TILE_B;    // 165888
    const int SMEM_SEL = GSTAGES * 3 * TILE_BYTES;   // 92160
    cudaFuncSetAttribute((const void*)attn_mma,
                         cudaFuncAttributeMaxDynamicSharedMemorySize, ATTN_SMEM);
    cudaFuncSetAttribute((const void*)attn_mma_t,
                         cudaFuncAttributeMaxDynamicSharedMemorySize, ATTN_T_SMEM);
    cudaFuncSetAttribute((const void*)gemm_f16<1>,
                         cudaFuncAttributeMaxDynamicSharedMemorySize, SMEM1);
    cudaFuncSetAttribute((const void*)gemm_f16<2>,
                         cudaFuncAttributeMaxDynamicSharedMemorySize, SMEM2);
    cudaFuncSetAttribute((const void*)gemm_sel_mma,
                         cudaFuncAttributeMaxDynamicSharedMemorySize, SMEM_SEL);

    const dim3 blk(256);
    const dim3 tblk(32, 8);
    const int n4 = MTOK * E_DIM / 4;
    const dim3 gcvt((n4 + 255) / 256);
    const dim3 gQKV(QKV_N / 128, MTOK / 128);
    const size_t MM = (size_t)E_DIM * E_DIM;
    const size_t MM3 = 3 * MM;
    const size_t WCS = (size_t)QKV_N * E_DIM;

    // ---- main stream: weights needed for layer 0 ----
    wt_cvt3<<<dim3(E_DIM / 32, E_DIM / 32, 4), tblk>>>(wq, WqkvTh, WqkvTl, E_DIM, E_DIM, 0, 3);
    wt_cvt3<<<dim3(E_DIM / 32, E_DIM / 32, 4), tblk>>>(wk, WqkvTh, WqkvTl, E_DIM, E_DIM, 1, 3);
    wt_cvt3<<<dim3(E_DIM / 32, E_DIM / 32, 4), tblk>>>(wv, WqkvTh, WqkvTl, E_DIM, E_DIM, 2, 3);
    bias_concat<<<(4 * QKV_N + 255) / 256, blk>>>(bq, bk, bv, Bqkv);

    // ---- fork: fold-weight prep on s2 ----
    cudaEventRecord(evF, 0);
    cudaStreamWaitEvent(s2, evF, 0);

    cvt_f16<<<(int)((4 * MM / 4 + 255) / 256), blk, 0, s2>>>(wd, Wd16, (int)(4 * MM / 4));
    gemm_f16<2><<<dim3(E_DIM / 128, QKV_N / 128, 3), blk, SMEM2, s2>>>(
        WqkvTh + MM3, WqkvTl + MM3, Wd16, Bzero, nullptr,
        WcT, nullptr, E_DIM, E_DIM, MM3, MM, WCS);
    wt_cvt<<<dim3(E_DIM / 32, E_DIM / 32, 1), tblk, 0, s2>>>(wd + 3 * MM, WdT3, E_DIM, E_DIM);
    wt_cvt3<<<dim3(KSEL / 32, E_DIM / 32, 1), tblk, 0, s2>>>(selw, SWTh, SWTl, E_DIM, KSEL, 0, 1);
    gemm_f16<2><<<dim3(E_DIM / 128, KSEL / 128), blk, SMEM2, s2>>>(
        SWTh, SWTl, Wd16 + 3 * MM, Bzero, nullptr,
        Bsel, nullptr, E_DIM, E_DIM, 0, 0, 0);
    bias_comb<<<dim3(QKV_N / 256, 3), blk, 0, s2>>>(wq, wk, wv, bd, Bqkv, Bcomb);
    bias_sel<<<1, 256, 0, s2>>>(selw, selb, bd + 3 * E_DIM, Bias2);
    cudaEventRecord(evJ, s2);

    // ---- main stream: layer 0 ----
    cvt_hilo<<<gcvt, blk>>>(x, Ah2p, Al2p, n4);
    gemm_f16<1><<<gQKV, blk, SMEM1>>>(Ah2p, nullptr, WqkvTh, Bqkv, nullptr,
                                      QKVh, nullptr, QKV_N, E_DIM, 0, 0, 0);
    attn_mma<<<dim3(H_DIM, B_DIM * T_DIM, 2), blk, ATTN_SMEM>>>(
        QKVh, QKVh + E_DIM, QKVh + 2 * E_DIM, Ahp, rb, QKV_N);

    // ---- join: folded weights ready before layer 1 ----
    cudaStreamWaitEvent(0, evJ, 0);

    for (int a = 1; a < 4; a++) {
        gemm_f16<1><<<gQKV, blk, SMEM1>>>(Ahp, nullptr, WcT + (a - 1) * WCS,
                                          Bcomb + (size_t)(a - 1) * QKV_N, nullptr,
                                          QKVh, nullptr, QKV_N, E_DIM, 0, 0, 0);

        const float* rba = rb + (size_t)a * RB_ONE;
        if ((a & 1) == 0) {
            attn_mma<<<dim3(H_DIM, B_DIM * T_DIM, 2), blk, ATTN_SMEM>>>(
                QKVh, QKVh + E_DIM, QKVh + 2 * E_DIM, Ahp, rba, QKV_N);
        } else {
            attn_mma_t<<<dim3(H_DIM, (B_DIM * N_DIM) / 8), blk, ATTN_T_SMEM>>>(
                QKVh, QKVh + E_DIM, QKVh + 2 * E_DIM, Ahp, rba, QKV_N);
        }
    }

    // selection scores on ctx: SC = ctx_hi @ Bsel^T + Bias2
    gemm_f16<1><<<dim3(KSEL / 128, MTOK / 128), blk, SMEM1>>>(
        Ahp, nullptr, Bsel, Bias2, SCb, nullptr, nullptr, KSEL, E_DIM, 0, 0, 0);

    sel_softmax<<<dim3(B_DIM, KSEL / 32), blk>>>(SCb);

    // transposed operands: wts^T hi/lo (exact), ctx^T (fp16 direct)
    transp_hilo<<<dim3(KSEL / 32, MTOK_B / 32, B_DIM), tblk>>>(SCb, SCTh, SCTl, MTOK_B, KSEL);
    transp_h16<<<dim3(E_DIM / 32, MTOK_B / 32, B_DIM), tblk>>>(Ahp, CTh, MTOK_B, E_DIM);

    // S1 = wts^T @ ctx  (mma split-K + fp32 atomics)
    cudaMemsetAsync(S1b, 0, (size_t)B_DIM * KSEL * E_DIM * sizeof(float));
    gemm_sel_mma<<<dim3(E_DIM / 128, KSEL / 128, B_DIM * SPLITK_SEL), blk, SMEM_SEL>>>(
        SCTh, SCTl, CTh, S1b);

    // SEL = S1 @ Wd3 + bd3  (tiny 2-seg GEMM)
    cvt_hilo<<<dim3((B_DIM * KSEL * E_DIM / 4 + 255) / 256), blk>>>(
        S1b, Ah2p, Al2p, B_DIM * KSEL * E_DIM / 4);
    gemm_f16<2><<<dim3(E_DIM / 128, (B_DIM * KSEL) / 128), blk, SMEM2>>>(
        Ah2p, Al2p, WdT3, bd + 3 * E_DIM, SELb, nullptr, nullptr, E_DIM, E_DIM, 0, 0, 0);

    int total = B_DIM * OUT_ROWS * E_DIM;
    pool_kernel<<<(total + 255) / 256, 256>>>(SELb, out);
}